// round 1
// baseline (speedup 1.0000x reference)
#include <cuda_runtime.h>
#include <math.h>

#define N_NODES 50000
#define N_EDGES 400000
#define BATCH 4
#define R (N_NODES*BATCH)      /* 200000 rows (n,b) */
#define RPAD 200064            /* padded to 128-row GEMM tiles */
#define BN_EPS 1e-5f
#define SLOPE 0.01f

/* ---------------- static device scratch (no allocations allowed) -------- */
__device__ __align__(16) float g_deg[N_NODES];
__device__ __align__(16) float g_dis[N_NODES];
__device__ __align__(16) float g_w[N_EDGES];
__device__ __align__(16) int   g_cnt[N_NODES];
__device__ __align__(16) int   g_rowptr[N_NODES+1];
__device__ __align__(16) int   g_cur[N_NODES];
__device__ __align__(16) int   g_col[N_EDGES];
__device__ __align__(16) float g_wcsr[N_EDGES];

__device__ __align__(16) float g_xt[RPAD*4];
__device__ __align__(16) float g_pa[RPAD*4];
__device__ __align__(16) float g_pb[RPAD*4];
__device__ __align__(16) float g_pc[RPAD*4];

__device__ __align__(16) float g_h  [RPAD*64];
__device__ __align__(16) float g_t1 [RPAD*64];
__device__ __align__(16) float g_t2 [RPAD*64];
__device__ __align__(16) float g_t3 [RPAD*64];
__device__ __align__(16) float g_acc[RPAD*64];

__device__ __align__(16) float g_sa[RPAD*2];
__device__ __align__(16) float g_sb[RPAD*2];

/* ---------------- preprocessing --------------------------------------- */
__global__ void k_init() {
    int i = blockIdx.x*blockDim.x + threadIdx.x;
    if (i < N_NODES) { g_deg[i] = 0.f; g_cnt[i] = 0; }
}

__global__ void k_deg(const int* __restrict__ dst, const float* __restrict__ ew) {
    int e = blockIdx.x*blockDim.x + threadIdx.x;
    if (e < N_EDGES) atomicAdd(&g_deg[dst[e]], ew[e]);
}

__global__ void k_dis() {
    int i = blockIdx.x*blockDim.x + threadIdx.x;
    if (i < N_NODES) {
        float d = g_deg[i];
        g_dis[i] = (d > 0.f) ? rsqrtf(fmaxf(d, 1e-30f)) : 0.f;
    }
}

__global__ void k_wh(const int* __restrict__ src, const int* __restrict__ dst,
                     const float* __restrict__ ew) {
    int e = blockIdx.x*blockDim.x + threadIdx.x;
    if (e < N_EDGES) {
        int s = src[e], d = dst[e];
        g_w[e] = g_dis[s] * ew[e] * g_dis[d];
        atomicAdd(&g_cnt[d], 1);
    }
}

__global__ void k_scan() {   /* single-block exclusive scan of g_cnt -> g_rowptr/g_cur */
    __shared__ int sh[1024];
    __shared__ int s_carry;
    int t = threadIdx.x;
    if (t == 0) s_carry = 0;
    __syncthreads();
    for (int base = 0; base < N_NODES; base += 1024) {
        int i = base + t;
        int v = (i < N_NODES) ? g_cnt[i] : 0;
        sh[t] = v;
        __syncthreads();
        for (int off = 1; off < 1024; off <<= 1) {
            int x = (t >= off) ? sh[t-off] : 0;
            __syncthreads();
            sh[t] += x;
            __syncthreads();
        }
        int excl = s_carry + sh[t] - v;
        if (i < N_NODES) { g_rowptr[i] = excl; g_cur[i] = excl; }
        int tot = sh[1023];
        __syncthreads();
        if (t == 0) s_carry += tot;
        __syncthreads();
    }
    if (t == 0) g_rowptr[N_NODES] = N_EDGES;
}

__global__ void k_fill(const int* __restrict__ src, const int* __restrict__ dst) {
    int e = blockIdx.x*blockDim.x + threadIdx.x;
    if (e < N_EDGES) {
        int d = dst[e];
        int p = atomicAdd(&g_cur[d], 1);
        g_col[p]  = src[e];
        g_wcsr[p] = g_w[e];
    }
}

/* x [B,N,4] -> g_xt node-major [N,B,4] = [R,4] */
__global__ void k_xt(const float* __restrict__ x) {
    int t = blockIdx.x*blockDim.x + threadIdx.x;   /* t = b*N + n */
    if (t >= R) return;
    int b = t / N_NODES, n = t - b*N_NODES;
    float4 v = ((const float4*)x)[t];
    ((float4*)g_xt)[n*4 + b] = v;
}

/* ---------------- propagation: out[n] = sum_{e:dst=n} w_e * in[src_e] --- */
template<int V4>   /* V4 float4s per node (4 => F=4 over B=4; 2 => F=2) */
__global__ void k_prop_small(const float* __restrict__ in, float* __restrict__ out) {
    int n = blockIdx.x*blockDim.x + threadIdx.x;
    if (n >= N_NODES) return;
    float4 acc[V4];
    #pragma unroll
    for (int j = 0; j < V4; j++) acc[j] = make_float4(0.f,0.f,0.f,0.f);
    int s = g_rowptr[n], e = g_rowptr[n+1];
    const float4* base = (const float4*)in;
    for (int i = s; i < e; i++) {
        int c = __ldg(&g_col[i]);
        float wv = __ldg(&g_wcsr[i]);
        const float4* p = base + c*V4;
        #pragma unroll
        for (int j = 0; j < V4; j++) {
            float4 v = __ldg(p + j);
            acc[j].x += wv*v.x; acc[j].y += wv*v.y;
            acc[j].z += wv*v.z; acc[j].w += wv*v.w;
        }
    }
    float4* q = (float4*)out + n*V4;
    #pragma unroll
    for (int j = 0; j < V4; j++) q[j] = acc[j];
}

/* F=64 over B=4: 256 floats per node; warp per node */
__global__ void k_prop64(const float* __restrict__ in, float* __restrict__ out) {
    int gt = blockIdx.x*blockDim.x + threadIdx.x;
    int n = gt >> 5, lane = gt & 31;
    if (n >= N_NODES) return;
    int s = g_rowptr[n], e = g_rowptr[n+1];
    float4 a0 = make_float4(0.f,0.f,0.f,0.f), a1 = a0;
    const float4* base = (const float4*)in;
    for (int i = s; i < e; i++) {
        int c = __ldg(&g_col[i]);
        float wv = __ldg(&g_wcsr[i]);
        const float4* p = base + c*64 + lane*2;
        float4 v0 = __ldg(p), v1 = __ldg(p+1);
        a0.x += wv*v0.x; a0.y += wv*v0.y; a0.z += wv*v0.z; a0.w += wv*v0.w;
        a1.x += wv*v1.x; a1.y += wv*v1.y; a1.z += wv*v1.z; a1.w += wv*v1.w;
    }
    float4* q = (float4*)out + n*64 + lane*2;
    q[0] = a0; q[1] = a1;
}

/* ---------------- layer-1 GEMM: acc[r,64] = concat16(r) @ Wc[16,64] + b1 */
__global__ void k_gemm1(const float* __restrict__ W1, const float* __restrict__ b1) {
    __shared__ float sW[1024];
    __shared__ float sB[64];
    int t = threadIdx.x;
    for (int i = t; i < 1024; i += 256) sW[i] = W1[i];
    if (t < 64) sB[t] = b1[t];
    __syncthreads();
    int r = blockIdx.x*256 + t;
    if (r >= R) return;
    float in[16];
    { float4 v;
      v = ((const float4*)g_xt)[r]; in[0]=v.x; in[1]=v.y; in[2]=v.z; in[3]=v.w;
      v = ((const float4*)g_pa)[r]; in[4]=v.x; in[5]=v.y; in[6]=v.z; in[7]=v.w;
      v = ((const float4*)g_pb)[r]; in[8]=v.x; in[9]=v.y; in[10]=v.z; in[11]=v.w;
      v = ((const float4*)g_pc)[r]; in[12]=v.x; in[13]=v.y; in[14]=v.z; in[15]=v.w; }
    #pragma unroll
    for (int g0 = 0; g0 < 64; g0 += 4) {
        float4 a = make_float4(sB[g0], sB[g0+1], sB[g0+2], sB[g0+3]);
        #pragma unroll
        for (int i = 0; i < 16; i++) {
            float4 w = *(const float4*)&sW[i*64 + g0];
            a.x += in[i]*w.x; a.y += in[i]*w.y; a.z += in[i]*w.z; a.w += in[i]*w.w;
        }
        *(float4*)&g_acc[r*64 + g0] = a;
    }
}

/* ---------------- BN (per node over B*F=256) + LeakyReLU --------------- */
__global__ void k_bn(const float* __restrict__ in, const float* __restrict__ gam,
                     const float* __restrict__ bet, float* __restrict__ out) {
    int gt = blockIdx.x*blockDim.x + threadIdx.x;
    int n = gt >> 5, lane = gt & 31;
    if (n >= N_NODES) return;
    const float4* p = (const float4*)in + n*64 + lane*2;
    float4 v0 = p[0], v1 = p[1];
    float s = v0.x+v0.y+v0.z+v0.w + v1.x+v1.y+v1.z+v1.w;
    float q = v0.x*v0.x+v0.y*v0.y+v0.z*v0.z+v0.w*v0.w
            + v1.x*v1.x+v1.y*v1.y+v1.z*v1.z+v1.w*v1.w;
    #pragma unroll
    for (int o = 16; o; o >>= 1) {
        s += __shfl_xor_sync(0xffffffffu, s, o);
        q += __shfl_xor_sync(0xffffffffu, q, o);
    }
    float mu  = s * (1.f/256.f);
    float var = q * (1.f/256.f) - mu*mu;
    float sc  = gam[n] * rsqrtf(var + BN_EPS);
    float bb  = bet[n];
    float4 o0, o1;
    float f;
    f = sc*(v0.x-mu)+bb; o0.x = f > 0.f ? f : SLOPE*f;
    f = sc*(v0.y-mu)+bb; o0.y = f > 0.f ? f : SLOPE*f;
    f = sc*(v0.z-mu)+bb; o0.z = f > 0.f ? f : SLOPE*f;
    f = sc*(v0.w-mu)+bb; o0.w = f > 0.f ? f : SLOPE*f;
    f = sc*(v1.x-mu)+bb; o1.x = f > 0.f ? f : SLOPE*f;
    f = sc*(v1.y-mu)+bb; o1.y = f > 0.f ? f : SLOPE*f;
    f = sc*(v1.z-mu)+bb; o1.z = f > 0.f ? f : SLOPE*f;
    f = sc*(v1.w-mu)+bb; o1.w = f > 0.f ? f : SLOPE*f;
    float4* qo = (float4*)out + n*64 + lane*2;
    qo[0] = o0; qo[1] = o1;
}

/* ---------------- layer-2 fused GEMM: [RPAD,256] @ [256,64] + b2 ------- */
__global__ void __launch_bounds__(128)
k_gemm2(const float* __restrict__ A0, const float* __restrict__ A1,
        const float* __restrict__ A2, const float* __restrict__ A3,
        const float* __restrict__ W2, const float* __restrict__ b2,
        float* __restrict__ out) {
    __shared__ float sA[32*128];
    __shared__ float sW[32*64];
    int t  = threadIdx.x;
    int tx = t & 7;        /* col group: 8 cols  */
    int ty = t >> 3;       /* row group: 8 rows  */
    int r0 = blockIdx.x * 128;
    float4 accA[8], accB[8];
    #pragma unroll
    for (int i = 0; i < 8; i++) { accA[i] = make_float4(0,0,0,0); accB[i] = accA[i]; }

    for (int c = 0; c < 8; c++) {
        int sel = c >> 1;
        const float* Ap = (sel == 0) ? A0 : (sel == 1) ? A1 : (sel == 2) ? A2 : A3;
        int kb = (c & 1) * 32;
        /* load A tile transposed: sA[kk][row] */
        {
            const float4* srcp = (const float4*)(Ap + (size_t)(r0 + t)*64 + kb);
            #pragma unroll
            for (int j = 0; j < 8; j++) {
                float4 v = srcp[j];
                sA[(j*4+0)*128 + t] = v.x;
                sA[(j*4+1)*128 + t] = v.y;
                sA[(j*4+2)*128 + t] = v.z;
                sA[(j*4+3)*128 + t] = v.w;
            }
        }
        /* load W tile: 2048 consecutive floats */
        {
            const float4* srcw = (const float4*)(W2 + sel*4096 + kb*64);
            float4* dw = (float4*)sW;
            #pragma unroll
            for (int j = 0; j < 4; j++) dw[j*128 + t] = srcw[j*128 + t];
        }
        __syncthreads();
        #pragma unroll 8
        for (int kk = 0; kk < 32; kk++) {
            const float* pa_ = &sA[kk*128 + ty*8];
            float4 w0 = *(const float4*)&sW[kk*64 + tx*8];
            float4 w1 = *(const float4*)&sW[kk*64 + tx*8 + 4];
            #pragma unroll
            for (int i = 0; i < 8; i++) {
                float a = pa_[i];
                accA[i].x += a*w0.x; accA[i].y += a*w0.y;
                accA[i].z += a*w0.z; accA[i].w += a*w0.w;
                accB[i].x += a*w1.x; accB[i].y += a*w1.y;
                accB[i].z += a*w1.z; accB[i].w += a*w1.w;
            }
        }
        __syncthreads();
    }
    float4 bb0, bb1;
    bb0.x = b2[tx*8+0]; bb0.y = b2[tx*8+1]; bb0.z = b2[tx*8+2]; bb0.w = b2[tx*8+3];
    bb1.x = b2[tx*8+4]; bb1.y = b2[tx*8+5]; bb1.z = b2[tx*8+6]; bb1.w = b2[tx*8+7];
    #pragma unroll
    for (int i = 0; i < 8; i++) {
        int r = r0 + ty*8 + i;
        float4 oa = accA[i], ob = accB[i];
        oa.x += bb0.x; oa.y += bb0.y; oa.z += bb0.z; oa.w += bb0.w;
        ob.x += bb1.x; ob.y += bb1.y; ob.z += bb1.z; ob.w += bb1.w;
        *(float4*)&out[(size_t)r*64 + tx*8]     = oa;
        *(float4*)&out[(size_t)r*64 + tx*8 + 4] = ob;
    }
}

/* ---------------- layer-3 projections: out[r,2] = h[r,:]@Wk (+add)(+b3) - */
template<bool ADD, bool BIAS>
__global__ void k_gemm3(const float* __restrict__ h, const float* __restrict__ Wk,
                        const float* __restrict__ addend, const float* __restrict__ b3,
                        float* __restrict__ out) {
    __shared__ float sw0[64], sw1[64];
    int t = threadIdx.x;
    if (t < 64) { sw0[t] = Wk[t*2]; sw1[t] = Wk[t*2+1]; }
    __syncthreads();
    int r = blockIdx.x*blockDim.x + t;
    if (r >= R) return;
    float a0 = 0.f, a1 = 0.f;
    if (BIAS) { a0 = b3[0]; a1 = b3[1]; }
    if (ADD)  { float2 ad = *(const float2*)&addend[r*2]; a0 += ad.x; a1 += ad.y; }
    const float4* hp = (const float4*)(h + (size_t)r*64);
    #pragma unroll
    for (int j = 0; j < 16; j++) {
        float4 v = hp[j];
        a0 += v.x*sw0[j*4] + v.y*sw0[j*4+1] + v.z*sw0[j*4+2] + v.w*sw0[j*4+3];
        a1 += v.x*sw1[j*4] + v.y*sw1[j*4+1] + v.z*sw1[j*4+2] + v.w*sw1[j*4+3];
    }
    *(float2*)&out[r*2] = make_float2(a0, a1);
}

/* ---------------- epilogue: denorm + mask + clamp, write [B,N,2] ------- */
__global__ void k_final(const float* __restrict__ pre, const float* __restrict__ mask,
                        const float* __restrict__ mean_y, const float* __restrict__ std_y,
                        const float* __restrict__ vmin, const float* __restrict__ vmax,
                        const float* __restrict__ qmin, const float* __restrict__ qmax,
                        float* __restrict__ out) {
    int t = blockIdx.x*blockDim.x + threadIdx.x;   /* t = b*N + n */
    if (t >= R) return;
    int b = t / N_NODES, n = t - b*N_NODES;
    float2 v = *(const float2*)&pre[(size_t)(n*4 + b)*2];
    float s0 = std_y[n*2], s1 = std_y[n*2+1];
    if (isinf(s0)) s0 = 0.f;
    if (isinf(s1)) s1 = 0.f;
    float o0 = (v.x*s0 + mean_y[n*2])   * mask[n*2];
    float o1 = (v.y*s1 + mean_y[n*2+1]) * mask[n*2+1];
    o0 = fminf(fmaxf(o0, vmin[n]), vmax[n]);
    o1 = fminf(fmaxf(o1, qmin[n]), qmax[n]);
    *(float2*)&out[(size_t)t*2] = make_float2(o0, o1);
}

/* ======================================================================= */
extern "C" void kernel_launch(void* const* d_in, const int* in_sizes, int n_in,
                              void* d_out, int out_size) {
    const float* x      = (const float*)d_in[0];
    const int*   src    = (const int*)  d_in[1];
    const int*   dst    = (const int*)  d_in[2];
    const float* ew     = (const float*)d_in[3];
    const float* W1     = (const float*)d_in[4];
    const float* b1     = (const float*)d_in[5];
    const float* W2     = (const float*)d_in[6];
    const float* b2     = (const float*)d_in[7];
    const float* W3     = (const float*)d_in[8];
    const float* b3     = (const float*)d_in[9];
    const float* g1     = (const float*)d_in[10];
    const float* be1    = (const float*)d_in[11];
    const float* g2     = (const float*)d_in[12];
    const float* be2    = (const float*)d_in[13];
    const float* mask   = (const float*)d_in[14];
    const float* mean_y = (const float*)d_in[15];
    const float* std_y  = (const float*)d_in[16];
    const float* vmin   = (const float*)d_in[17];
    const float* vmax   = (const float*)d_in[18];
    const float* qmin   = (const float*)d_in[19];
    const float* qmax   = (const float*)d_in[20];
    float* out = (float*)d_out;

    float *xt, *pa, *pb, *pc, *h, *t1, *t2, *t3, *acc, *sa, *sb;
    cudaGetSymbolAddress((void**)&xt,  g_xt);
    cudaGetSymbolAddress((void**)&pa,  g_pa);
    cudaGetSymbolAddress((void**)&pb,  g_pb);
    cudaGetSymbolAddress((void**)&pc,  g_pc);
    cudaGetSymbolAddress((void**)&h,   g_h);
    cudaGetSymbolAddress((void**)&t1,  g_t1);
    cudaGetSymbolAddress((void**)&t2,  g_t2);
    cudaGetSymbolAddress((void**)&t3,  g_t3);
    cudaGetSymbolAddress((void**)&acc, g_acc);
    cudaGetSymbolAddress((void**)&sa,  g_sa);
    cudaGetSymbolAddress((void**)&sb,  g_sb);

    const int TB = 256;
    int gN = (N_NODES + TB - 1) / TB;
    int gE = (N_EDGES + TB - 1) / TB;
    int gR = (R + TB - 1) / TB;
    int gW = (N_NODES*32 + TB - 1) / TB;   /* warp-per-node kernels */

    /* preprocessing */
    k_init<<<gN, TB>>>();
    k_deg <<<gE, TB>>>(dst, ew);
    k_dis <<<gN, TB>>>();
    k_wh  <<<gE, TB>>>(src, dst, ew);
    k_scan<<<1, 1024>>>();
    k_fill<<<gE, TB>>>(src, dst);

    /* layer 1: propagate input side (F=4), fused GEMM K=16, BN+LReLU */
    k_xt<<<gR, TB>>>(x);
    k_prop_small<4><<<gN, TB>>>(xt, pa);
    k_prop_small<4><<<gN, TB>>>(pa, pb);
    k_prop_small<4><<<gN, TB>>>(pb, pc);
    k_gemm1<<<(R + 255)/256, 256>>>(W1, b1);
    k_bn<<<gW, TB>>>(acc, g1, be1, h);

    /* layer 2: 3x prop64, fused GEMM K=256, BN+LReLU */
    k_prop64<<<gW, TB>>>(h,  t1);
    k_prop64<<<gW, TB>>>(t1, t2);
    k_prop64<<<gW, TB>>>(t2, t3);
    k_gemm2<<<RPAD/128, 128>>>(h, t1, t2, t3, W2, b2, acc);
    k_bn<<<gW, TB>>>(acc, g2, be2, h);

    /* layer 3: Horner — propagate at F=2 */
    k_gemm3<false,false><<<(R+127)/128, 128>>>(h, W3 + 3*128, nullptr, nullptr, sa);
    k_prop_small<2><<<gN, TB>>>(sa, sb);
    k_gemm3<true, false><<<(R+127)/128, 128>>>(h, W3 + 2*128, sb, nullptr, sa);
    k_prop_small<2><<<gN, TB>>>(sa, sb);
    k_gemm3<true, false><<<(R+127)/128, 128>>>(h, W3 + 1*128, sb, nullptr, sa);
    k_prop_small<2><<<gN, TB>>>(sa, sb);
    k_gemm3<true, true ><<<(R+127)/128, 128>>>(h, W3,         sb, b3,      sa);

    /* epilogue */
    k_final<<<gR, TB>>>(sa, mask, mean_y, std_y, vmin, vmax, qmin, qmax, out);
}

// round 3
// speedup vs baseline: 1.1426x; 1.1426x over previous
#include <cuda_runtime.h>
#include <math.h>
#include <cstdint>

#define N_NODES 50000
#define N_EDGES 400000
#define BATCH 4
#define R (N_NODES*BATCH)      /* 200000 rows (n,b) */
#define RPAD 200064            /* padded to 128-row GEMM tiles */
#define BN_EPS 1e-5f
#define SLOPE 0.01f

/* ---------------- static device scratch (no allocations allowed) -------- */
__device__ __align__(16) float g_deg[N_NODES];
__device__ __align__(16) float g_dis[N_NODES];
__device__ __align__(16) float g_w[N_EDGES];
__device__ __align__(16) int   g_cnt[N_NODES];
__device__ __align__(16) int   g_rowptr[N_NODES+1];
__device__ __align__(16) int   g_cur[N_NODES];
__device__ __align__(16) int   g_col[N_EDGES];
__device__ __align__(16) float g_wcsr[N_EDGES];

__device__ __align__(16) float g_xt[RPAD*4];
__device__ __align__(16) float g_pa[RPAD*4];
__device__ __align__(16) float g_pb[RPAD*4];
__device__ __align__(16) float g_pc[RPAD*4];

__device__ __align__(16) float g_h  [RPAD*64];
__device__ __align__(16) float g_t1 [RPAD*64];
__device__ __align__(16) float g_t2 [RPAD*64];
__device__ __align__(16) float g_t3 [RPAD*64];
__device__ __align__(16) float g_acc[RPAD*64];

__device__ __align__(16) float g_sa[RPAD*2];
__device__ __align__(16) float g_sb[RPAD*2];

/* transposed + tf32-split W2: [64 n][256 k] */
__device__ __align__(16) float g_w2t_hi[64*256];
__device__ __align__(16) float g_w2t_lo[64*256];

__device__ __forceinline__ float tf32r(float x) {
    uint32_t u;
    asm("cvt.rna.tf32.f32 %0, %1;" : "=r"(u) : "f"(x));
    return __uint_as_float(u);
}

#define MMA8(C, a0,a1,a2,a3, b0,b1) \
    asm volatile("mma.sync.aligned.m16n8k8.row.col.f32.tf32.tf32.f32 " \
        "{%0,%1,%2,%3},{%4,%5,%6,%7},{%8,%9},{%0,%1,%2,%3};" \
        : "+f"((C)[0]),"+f"((C)[1]),"+f"((C)[2]),"+f"((C)[3]) \
        : "r"(a0),"r"(a1),"r"(a2),"r"(a3),"r"(b0),"r"(b1))

/* ---------------- preprocessing --------------------------------------- */
__global__ void k_init() {
    int i = blockIdx.x*blockDim.x + threadIdx.x;
    if (i < N_NODES) { g_deg[i] = 0.f; g_cnt[i] = 0; }
}

__global__ void k_deg(const int* __restrict__ dst, const float* __restrict__ ew) {
    int e = blockIdx.x*blockDim.x + threadIdx.x;
    if (e < N_EDGES) atomicAdd(&g_deg[dst[e]], ew[e]);
}

__global__ void k_dis() {
    int i = blockIdx.x*blockDim.x + threadIdx.x;
    if (i < N_NODES) {
        float d = g_deg[i];
        g_dis[i] = (d > 0.f) ? rsqrtf(fmaxf(d, 1e-30f)) : 0.f;
    }
}

__global__ void k_wh(const int* __restrict__ src, const int* __restrict__ dst,
                     const float* __restrict__ ew) {
    int e = blockIdx.x*blockDim.x + threadIdx.x;
    if (e < N_EDGES) {
        int s = src[e], d = dst[e];
        g_w[e] = g_dis[s] * ew[e] * g_dis[d];
        atomicAdd(&g_cnt[d], 1);
    }
}

__global__ void k_scan() {
    __shared__ int sh[1024];
    __shared__ int s_carry;
    int t = threadIdx.x;
    if (t == 0) s_carry = 0;
    __syncthreads();
    for (int base = 0; base < N_NODES; base += 1024) {
        int i = base + t;
        int v = (i < N_NODES) ? g_cnt[i] : 0;
        sh[t] = v;
        __syncthreads();
        for (int off = 1; off < 1024; off <<= 1) {
            int x = (t >= off) ? sh[t-off] : 0;
            __syncthreads();
            sh[t] += x;
            __syncthreads();
        }
        int excl = s_carry + sh[t] - v;
        if (i < N_NODES) { g_rowptr[i] = excl; g_cur[i] = excl; }
        int tot = sh[1023];
        __syncthreads();
        if (t == 0) s_carry += tot;
        __syncthreads();
    }
    if (t == 0) g_rowptr[N_NODES] = N_EDGES;
}

__global__ void k_fill(const int* __restrict__ src, const int* __restrict__ dst) {
    int e = blockIdx.x*blockDim.x + threadIdx.x;
    if (e < N_EDGES) {
        int d = dst[e];
        int p = atomicAdd(&g_cur[d], 1);
        g_col[p]  = src[e];
        g_wcsr[p] = g_w[e];
    }
}

/* x [B,N,4] -> g_xt node-major [N,B,4] = [R,4] */
__global__ void k_xt(const float* __restrict__ x) {
    int t = blockIdx.x*blockDim.x + threadIdx.x;
    if (t >= R) return;
    int b = t / N_NODES, n = t - b*N_NODES;
    float4 v = ((const float4*)x)[t];
    ((float4*)g_xt)[n*4 + b] = v;
}

/* W2 [4][64 k][64 n] -> W2T [64 n][256 k], split hi/lo for 3xTF32 */
__global__ void k_w2prep(const float* __restrict__ W2) {
    int t = blockIdx.x*blockDim.x + threadIdx.x;
    if (t >= 64*256) return;
    int n = t >> 8, k = t & 255;
    int sel = k >> 6, kk = k & 63;
    float v = W2[sel*4096 + kk*64 + n];
    float h = tf32r(v);
    g_w2t_hi[t] = h;
    g_w2t_lo[t] = v - h;
}

/* ---------------- propagation ------------------------------------------ */
template<int V4>
__global__ void k_prop_small(const float* __restrict__ in, float* __restrict__ out) {
    int n = blockIdx.x*blockDim.x + threadIdx.x;
    if (n >= N_NODES) return;
    float4 acc[V4];
    #pragma unroll
    for (int j = 0; j < V4; j++) acc[j] = make_float4(0.f,0.f,0.f,0.f);
    int s = g_rowptr[n], e = g_rowptr[n+1];
    const float4* base = (const float4*)in;
    for (int i = s; i < e; i++) {
        int c = __ldg(&g_col[i]);
        float wv = __ldg(&g_wcsr[i]);
        const float4* p = base + c*V4;
        #pragma unroll
        for (int j = 0; j < V4; j++) {
            float4 v = __ldg(p + j);
            acc[j].x += wv*v.x; acc[j].y += wv*v.y;
            acc[j].z += wv*v.z; acc[j].w += wv*v.w;
        }
    }
    float4* q = (float4*)out + n*V4;
    #pragma unroll
    for (int j = 0; j < V4; j++) q[j] = acc[j];
}

__global__ void k_prop64(const float* __restrict__ in, float* __restrict__ out) {
    int gt = blockIdx.x*blockDim.x + threadIdx.x;
    int n = gt >> 5, lane = gt & 31;
    if (n >= N_NODES) return;
    int s = g_rowptr[n], e = g_rowptr[n+1];
    float4 a0 = make_float4(0.f,0.f,0.f,0.f), a1 = a0;
    const float4* base = (const float4*)in;
    for (int i = s; i < e; i++) {
        int c = __ldg(&g_col[i]);
        float wv = __ldg(&g_wcsr[i]);
        const float4* p = base + c*64 + lane*2;
        float4 v0 = __ldg(p), v1 = __ldg(p+1);
        a0.x += wv*v0.x; a0.y += wv*v0.y; a0.z += wv*v0.z; a0.w += wv*v0.w;
        a1.x += wv*v1.x; a1.y += wv*v1.y; a1.z += wv*v1.z; a1.w += wv*v1.w;
    }
    float4* q = (float4*)out + n*64 + lane*2;
    q[0] = a0; q[1] = a1;
}

/* ---------------- layer-1 GEMM ------------------------------------------ */
__global__ void k_gemm1(const float* __restrict__ W1, const float* __restrict__ b1) {
    __shared__ float sW[1024];
    __shared__ float sB[64];
    int t = threadIdx.x;
    for (int i = t; i < 1024; i += 256) sW[i] = W1[i];
    if (t < 64) sB[t] = b1[t];
    __syncthreads();
    int r = blockIdx.x*256 + t;
    if (r >= R) return;
    float in[16];
    { float4 v;
      v = ((const float4*)g_xt)[r]; in[0]=v.x; in[1]=v.y; in[2]=v.z; in[3]=v.w;
      v = ((const float4*)g_pa)[r]; in[4]=v.x; in[5]=v.y; in[6]=v.z; in[7]=v.w;
      v = ((const float4*)g_pb)[r]; in[8]=v.x; in[9]=v.y; in[10]=v.z; in[11]=v.w;
      v = ((const float4*)g_pc)[r]; in[12]=v.x; in[13]=v.y; in[14]=v.z; in[15]=v.w; }
    #pragma unroll
    for (int g0 = 0; g0 < 64; g0 += 4) {
        float4 a = make_float4(sB[g0], sB[g0+1], sB[g0+2], sB[g0+3]);
        #pragma unroll
        for (int i = 0; i < 16; i++) {
            float4 w = *(const float4*)&sW[i*64 + g0];
            a.x += in[i]*w.x; a.y += in[i]*w.y; a.z += in[i]*w.z; a.w += in[i]*w.w;
        }
        *(float4*)&g_acc[r*64 + g0] = a;
    }
}

/* ---------------- BN (per node over B*F=256) + LeakyReLU --------------- */
__global__ void k_bn(const float* __restrict__ in, const float* __restrict__ gam,
                     const float* __restrict__ bet, float* __restrict__ out) {
    int gt = blockIdx.x*blockDim.x + threadIdx.x;
    int n = gt >> 5, lane = gt & 31;
    if (n >= N_NODES) return;
    const float4* p = (const float4*)in + n*64 + lane*2;
    float4 v0 = p[0], v1 = p[1];
    float s = v0.x+v0.y+v0.z+v0.w + v1.x+v1.y+v1.z+v1.w;
    float q = v0.x*v0.x+v0.y*v0.y+v0.z*v0.z+v0.w*v0.w
            + v1.x*v1.x+v1.y*v1.y+v1.z*v1.z+v1.w*v1.w;
    #pragma unroll
    for (int o = 16; o; o >>= 1) {
        s += __shfl_xor_sync(0xffffffffu, s, o);
        q += __shfl_xor_sync(0xffffffffu, q, o);
    }
    float mu  = s * (1.f/256.f);
    float var = q * (1.f/256.f) - mu*mu;
    float sc  = gam[n] * rsqrtf(var + BN_EPS);
    float bb  = bet[n];
    float4 o0, o1;
    float f;
    f = sc*(v0.x-mu)+bb; o0.x = f > 0.f ? f : SLOPE*f;
    f = sc*(v0.y-mu)+bb; o0.y = f > 0.f ? f : SLOPE*f;
    f = sc*(v0.z-mu)+bb; o0.z = f > 0.f ? f : SLOPE*f;
    f = sc*(v0.w-mu)+bb; o0.w = f > 0.f ? f : SLOPE*f;
    f = sc*(v1.x-mu)+bb; o1.x = f > 0.f ? f : SLOPE*f;
    f = sc*(v1.y-mu)+bb; o1.y = f > 0.f ? f : SLOPE*f;
    f = sc*(v1.z-mu)+bb; o1.z = f > 0.f ? f : SLOPE*f;
    f = sc*(v1.w-mu)+bb; o1.w = f > 0.f ? f : SLOPE*f;
    float4* qo = (float4*)out + n*64 + lane*2;
    qo[0] = o0; qo[1] = o1;
}

/* ---------------- layer-2 GEMM via mma.sync tf32 (3xTF32 split) ---------
 * CTA tile 128x64, K=256 in 8 chunks of 32. 8 warps = 4x2 grid of 32x32
 * warp tiles. Smem holds fragments in mma order; conflict-free vector LDS.
 * Stage layout (floats): aHi[0,4096) aLo[4096,8192) bHi[8192,10240)
 * bLo[10240,12288). Two stages = 24576 floats = 96 KB.                    */
__global__ void __launch_bounds__(256, 2)
k_gemm2_mma(const float* __restrict__ A0, const float* __restrict__ A1,
            const float* __restrict__ A2, const float* __restrict__ A3,
            const float* __restrict__ whi, const float* __restrict__ wlo,
            const float* __restrict__ b2, float* __restrict__ out) {
    extern __shared__ float sm[];
    const int t = threadIdx.x;
    const int lane = t & 31, wid = t >> 5;
    const int wrow = wid >> 1, wcol = wid & 1;
    const int r0 = blockIdx.x * 128;

    /* per-thread writer indices (constant across chunks) */
    int aoff[4], arowg[4];   /* smem float offset (j=0), global row */
    int aks[4];
    #pragma unroll
    for (int i = 0; i < 4; i++) {
        int idx = i*256 + t;
        int row = idx >> 3, c4 = idx & 7;
        int rr = row & 15, mt = row >> 4, ks = c4 >> 1;
        int reg = (rr >> 3) + 2*(c4 & 1);
        int lb = (rr & 7) * 4;
        aoff[i] = (mt*4 + ks)*128 + reg;   /* + ((lb+j)^ks)*4 */
        arowg[i] = row; aks[i] = ks;
    }
    int boff[2], bnrow[2], bks[2];
    #pragma unroll
    for (int i = 0; i < 2; i++) {
        int idx = i*256 + t;
        int n = idx >> 3, c4 = idx & 7;
        int ks = c4 >> 1, reg = c4 & 1, nt = n >> 3;
        boff[i] = 8192 + (nt*4 + ks)*64 + reg;   /* + ((lb+j)^ks)*2 */
        bnrow[i] = n; bks[i] = ks;
    }
    int albj[4], blbj[2];
    #pragma unroll
    for (int i = 0; i < 4; i++) { int idx=i*256+t; albj[i] = ((idx>>3 & 15) & 7)*4; }
    #pragma unroll
    for (int i = 0; i < 2; i++) { int idx=i*256+t; blbj[i] = ((idx>>3) & 7)*4; }
    int ac4[4], bc4[2];
    #pragma unroll
    for (int i = 0; i < 4; i++) ac4[i] = (i*256+t) & 7;
    #pragma unroll
    for (int i = 0; i < 2; i++) bc4[i] = (i*256+t) & 7;

    float c[2][4][4];
    #pragma unroll
    for (int m = 0; m < 2; m++)
        #pragma unroll
        for (int n = 0; n < 4; n++)
            #pragma unroll
            for (int k = 0; k < 4; k++) c[m][n][k] = 0.f;

    float4 pa[4], pbh[2], pbl[2];

    /* prologue: load chunk 0 */
    {
        const float* Ap = A0;
        #pragma unroll
        for (int i = 0; i < 4; i++)
            pa[i] = *(const float4*)(Ap + (size_t)(r0 + arowg[i])*64 + ac4[i]*4);
        #pragma unroll
        for (int i = 0; i < 2; i++) {
            pbh[i] = *(const float4*)(whi + bnrow[i]*256 + bc4[i]*4);
            pbl[i] = *(const float4*)(wlo + bnrow[i]*256 + bc4[i]*4);
        }
    }
    /* store chunk 0 to stage 0 */
    {
        float* base = sm;
        #pragma unroll
        for (int i = 0; i < 4; i++) {
            float v[4] = {pa[i].x, pa[i].y, pa[i].z, pa[i].w};
            #pragma unroll
            for (int j = 0; j < 4; j++) {
                int sw = ((albj[i] + j) ^ aks[i]) * 4;
                float hv = tf32r(v[j]);
                base[aoff[i] + sw] = hv;
                base[4096 + aoff[i] + sw] = v[j] - hv;
            }
        }
        #pragma unroll
        for (int i = 0; i < 2; i++) {
            float hv[4] = {pbh[i].x, pbh[i].y, pbh[i].z, pbh[i].w};
            float lv[4] = {pbl[i].x, pbl[i].y, pbl[i].z, pbl[i].w};
            #pragma unroll
            for (int j = 0; j < 4; j++) {
                int sw = ((blbj[i] + j) ^ bks[i]) * 2;
                base[boff[i] + sw] = hv[j];
                base[2048 + boff[i] + sw] = lv[j];
            }
        }
    }
    __syncthreads();

    #pragma unroll 1
    for (int cc = 0; cc < 8; cc++) {
        int stage = cc & 1;
        /* prefetch next chunk into registers */
        if (cc < 7) {
            int cn = cc + 1;
            const float* Ap = (cn < 2) ? A0 : (cn < 4) ? A1 : (cn < 6) ? A2 : A3;
            int kb = (cn & 1) * 32;
            #pragma unroll
            for (int i = 0; i < 4; i++)
                pa[i] = *(const float4*)(Ap + (size_t)(r0 + arowg[i])*64 + kb + ac4[i]*4);
            #pragma unroll
            for (int i = 0; i < 2; i++) {
                pbh[i] = *(const float4*)(whi + bnrow[i]*256 + cn*32 + bc4[i]*4);
                pbl[i] = *(const float4*)(wlo + bnrow[i]*256 + cn*32 + bc4[i]*4);
            }
        }
        /* compute current stage */
        {
            const float* base = sm + stage*12288;
            #pragma unroll
            for (int ks = 0; ks < 4; ks++) {
                int swz4 = (lane ^ ks) * 4;
                int swz2 = (lane ^ ks) * 2;
                uint32_t ah[2][4], al[2][4];
                #pragma unroll
                for (int mt = 0; mt < 2; mt++) {
                    int mtile = wrow*2 + mt;
                    float4 vh = *(const float4*)(base + (mtile*4+ks)*128 + swz4);
                    float4 vl = *(const float4*)(base + 4096 + (mtile*4+ks)*128 + swz4);
                    ah[mt][0]=__float_as_uint(vh.x); ah[mt][1]=__float_as_uint(vh.y);
                    ah[mt][2]=__float_as_uint(vh.z); ah[mt][3]=__float_as_uint(vh.w);
                    al[mt][0]=__float_as_uint(vl.x); al[mt][1]=__float_as_uint(vl.y);
                    al[mt][2]=__float_as_uint(vl.z); al[mt][3]=__float_as_uint(vl.w);
                }
                uint32_t bh[4][2], bl[4][2];
                #pragma unroll
                for (int nt = 0; nt < 4; nt++) {
                    int ntile = wcol*4 + nt;
                    float2 vh = *(const float2*)(base + 8192 + (ntile*4+ks)*64 + swz2);
                    float2 vl = *(const float2*)(base + 10240 + (ntile*4+ks)*64 + swz2);
                    bh[nt][0]=__float_as_uint(vh.x); bh[nt][1]=__float_as_uint(vh.y);
                    bl[nt][0]=__float_as_uint(vl.x); bl[nt][1]=__float_as_uint(vl.y);
                }
                #pragma unroll
                for (int mt = 0; mt < 2; mt++)
                    #pragma unroll
                    for (int nt = 0; nt < 4; nt++) {
                        MMA8(c[mt][nt], ah[mt][0],ah[mt][1],ah[mt][2],ah[mt][3],
                             bh[nt][0], bh[nt][1]);
                        MMA8(c[mt][nt], ah[mt][0],ah[mt][1],ah[mt][2],ah[mt][3],
                             bl[nt][0], bl[nt][1]);
                        MMA8(c[mt][nt], al[mt][0],al[mt][1],al[mt][2],al[mt][3],
                             bh[nt][0], bh[nt][1]);
                    }
            }
        }
        /* store prefetched chunk into other stage */
        if (cc < 7) {
            float* base = sm + ((cc+1)&1)*12288;
            #pragma unroll
            for (int i = 0; i < 4; i++) {
                float v[4] = {pa[i].x, pa[i].y, pa[i].z, pa[i].w};
                #pragma unroll
                for (int j = 0; j < 4; j++) {
                    int sw = ((albj[i] + j) ^ aks[i]) * 4;
                    float hv = tf32r(v[j]);
                    base[aoff[i] + sw] = hv;
                    base[4096 + aoff[i] + sw] = v[j] - hv;
                }
            }
            #pragma unroll
            for (int i = 0; i < 2; i++) {
                float hv[4] = {pbh[i].x, pbh[i].y, pbh[i].z, pbh[i].w};
                float lv[4] = {pbl[i].x, pbl[i].y, pbl[i].z, pbl[i].w};
                #pragma unroll
                for (int j = 0; j < 4; j++) {
                    int sw = ((blbj[i] + j) ^ bks[i]) * 2;
                    base[boff[i] + sw] = hv[j];
                    base[2048 + boff[i] + sw] = lv[j];
                }
            }
        }
        __syncthreads();
    }

    /* epilogue: c frag (mt,nt): rows g,(g+8); cols 2q,2q+1 */
    const int g = lane >> 2, q = lane & 3;
    #pragma unroll
    for (int mt = 0; mt < 2; mt++) {
        int row0 = r0 + wrow*32 + mt*16 + g;
        #pragma unroll
        for (int nt = 0; nt < 4; nt++) {
            int col = wcol*32 + nt*8 + 2*q;
            float bx = __ldg(&b2[col]), by = __ldg(&b2[col+1]);
            *(float2*)&out[(size_t)row0*64 + col] =
                make_float2(c[mt][nt][0] + bx, c[mt][nt][1] + by);
            *(float2*)&out[(size_t)(row0+8)*64 + col] =
                make_float2(c[mt][nt][2] + bx, c[mt][nt][3] + by);
        }
    }
}

/* ---------------- layer-3 projections ----------------------------------- */
template<bool ADD, bool BIAS>
__global__ void k_gemm3(const float* __restrict__ h, const float* __restrict__ Wk,
                        const float* __restrict__ addend, const float* __restrict__ b3,
                        float* __restrict__ out) {
    __shared__ float sw0[64], sw1[64];
    int t = threadIdx.x;
    if (t < 64) { sw0[t] = Wk[t*2]; sw1[t] = Wk[t*2+1]; }
    __syncthreads();
    int r = blockIdx.x*blockDim.x + t;
    if (r >= R) return;
    float a0 = 0.f, a1 = 0.f;
    if (BIAS) { a0 = b3[0]; a1 = b3[1]; }
    if (ADD)  { float2 ad = *(const float2*)&addend[r*2]; a0 += ad.x; a1 += ad.y; }
    const float4* hp = (const float4*)(h + (size_t)r*64);
    #pragma unroll
    for (int j = 0; j < 16; j++) {
        float4 v = hp[j];
        a0 += v.x*sw0[j*4] + v.y*sw0[j*4+1] + v.z*sw0[j*4+2] + v.w*sw0[j*4+3];
        a1 += v.x*sw1[j*4] + v.y*sw1[j*4+1] + v.z*sw1[j*4+2] + v.w*sw1[j*4+3];
    }
    *(float2*)&out[r*2] = make_float2(a0, a1);
}

/* ---------------- epilogue ---------------------------------------------- */
__global__ void k_final(const float* __restrict__ pre, const float* __restrict__ mask,
                        const float* __restrict__ mean_y, const float* __restrict__ std_y,
                        const float* __restrict__ vmin, const float* __restrict__ vmax,
                        const float* __restrict__ qmin, const float* __restrict__ qmax,
                        float* __restrict__ out) {
    int t = blockIdx.x*blockDim.x + threadIdx.x;
    if (t >= R) return;
    int b = t / N_NODES, n = t - b*N_NODES;
    float2 v = *(const float2*)&pre[(size_t)(n*4 + b)*2];
    float s0 = std_y[n*2], s1 = std_y[n*2+1];
    if (isinf(s0)) s0 = 0.f;
    if (isinf(s1)) s1 = 0.f;
    float o0 = (v.x*s0 + mean_y[n*2])   * mask[n*2];
    float o1 = (v.y*s1 + mean_y[n*2+1]) * mask[n*2+1];
    o0 = fminf(fmaxf(o0, vmin[n]), vmax[n]);
    o1 = fminf(fmaxf(o1, qmin[n]), qmax[n]);
    *(float2*)&out[(size_t)t*2] = make_float2(o0, o1);
}

/* ======================================================================= */
extern "C" void kernel_launch(void* const* d_in, const int* in_sizes, int n_in,
                              void* d_out, int out_size) {
    const float* x      = (const float*)d_in[0];
    const int*   src    = (const int*)  d_in[1];
    const int*   dst    = (const int*)  d_in[2];
    const float* ew     = (const float*)d_in[3];
    const float* W1     = (const float*)d_in[4];
    const float* b1     = (const float*)d_in[5];
    const float* W2     = (const float*)d_in[6];
    const float* b2     = (const float*)d_in[7];
    const float* W3     = (const float*)d_in[8];
    const float* b3     = (const float*)d_in[9];
    const float* g1     = (const float*)d_in[10];
    const float* be1    = (const float*)d_in[11];
    const float* g2     = (const float*)d_in[12];
    const float* be2    = (const float*)d_in[13];
    const float* mask   = (const float*)d_in[14];
    const float* mean_y = (const float*)d_in[15];
    const float* std_y  = (const float*)d_in[16];
    const float* vmin   = (const float*)d_in[17];
    const float* vmax   = (const float*)d_in[18];
    const float* qmin   = (const float*)d_in[19];
    const float* qmax   = (const float*)d_in[20];
    float* out = (float*)d_out;

    float *xt, *pa, *pb, *pc, *h, *t1, *t2, *t3, *acc, *sa, *sb;
    float *w2hi, *w2lo;
    cudaGetSymbolAddress((void**)&xt,  g_xt);
    cudaGetSymbolAddress((void**)&pa,  g_pa);
    cudaGetSymbolAddress((void**)&pb,  g_pb);
    cudaGetSymbolAddress((void**)&pc,  g_pc);
    cudaGetSymbolAddress((void**)&h,   g_h);
    cudaGetSymbolAddress((void**)&t1,  g_t1);
    cudaGetSymbolAddress((void**)&t2,  g_t2);
    cudaGetSymbolAddress((void**)&t3,  g_t3);
    cudaGetSymbolAddress((void**)&acc, g_acc);
    cudaGetSymbolAddress((void**)&sa,  g_sa);
    cudaGetSymbolAddress((void**)&sb,  g_sb);
    cudaGetSymbolAddress((void**)&w2hi, g_w2t_hi);
    cudaGetSymbolAddress((void**)&w2lo, g_w2t_lo);

    static int smem_set = 0;
    if (!smem_set) {
        cudaFuncSetAttribute(k_gemm2_mma, cudaFuncAttributeMaxDynamicSharedMemorySize, 98304);
        smem_set = 1;
    }

    const int TB = 256;
    int gN = (N_NODES + TB - 1) / TB;
    int gE = (N_EDGES + TB - 1) / TB;
    int gR = (R + TB - 1) / TB;
    int gW = (N_NODES*32 + TB - 1) / TB;

    /* preprocessing */
    k_init<<<gN, TB>>>();
    k_deg <<<gE, TB>>>(dst, ew);
    k_dis <<<gN, TB>>>();
    k_wh  <<<gE, TB>>>(src, dst, ew);
    k_scan<<<1, 1024>>>();
    k_fill<<<gE, TB>>>(src, dst);
    k_w2prep<<<(64*256 + TB - 1)/TB, TB>>>(W2);

    /* layer 1 */
    k_xt<<<gR, TB>>>(x);
    k_prop_small<4><<<gN, TB>>>(xt, pa);
    k_prop_small<4><<<gN, TB>>>(pa, pb);
    k_prop_small<4><<<gN, TB>>>(pb, pc);
    k_gemm1<<<(R + 255)/256, 256>>>(W1, b1);
    k_bn<<<gW, TB>>>(acc, g1, be1, h);

    /* layer 2 */
    k_prop64<<<gW, TB>>>(h,  t1);
    k_prop64<<<gW, TB>>>(t1, t2);
    k_prop64<<<gW, TB>>>(t2, t3);
    k_gemm2_mma<<<RPAD/128, 256, 98304>>>(h, t1, t2, t3, w2hi, w2lo, b2, acc);
    k_bn<<<gW, TB>>>(acc, g2, be2, h);

    /* layer 3: Horner at F=2 */
    k_gemm3<false,false><<<(R+127)/128, 128>>>(h, W3 + 3*128, nullptr, nullptr, sa);
    k_prop_small<2><<<gN, TB>>>(sa, sb);
    k_gemm3<true, false><<<(R+127)/128, 128>>>(h, W3 + 2*128, sb, nullptr, sa);
    k_prop_small<2><<<gN, TB>>>(sa, sb);
    k_gemm3<true, false><<<(R+127)/128, 128>>>(h, W3 + 1*128, sb, nullptr, sa);
    k_prop_small<2><<<gN, TB>>>(sa, sb);
    k_gemm3<true, true ><<<(R+127)/128, 128>>>(h, W3,         sb, b3,      sa);

    /* epilogue */
    k_final<<<gR, TB>>>(sa, mask, mean_y, std_y, vmin, vmax, qmin, qmax, out);
}

// round 4
// speedup vs baseline: 1.4972x; 1.3103x over previous
#include <cuda_runtime.h>
#include <math.h>
#include <cstdint>

#define N_NODES 50000
#define N_EDGES 400000
#define BATCH 4
#define R (N_NODES*BATCH)      /* 200000 rows (n,b) */
#define RPAD 200064            /* padded to 128-row GEMM tiles */
#define BN_EPS 1e-5f
#define SLOPE 0.01f
#define NB_SCAN ((N_NODES + 255) / 256)   /* 196 */

/* ---------------- static device scratch (no allocations allowed) -------- */
__device__ __align__(16) float g_deg[N_NODES];
__device__ __align__(16) float g_dis[N_NODES];
__device__ __align__(16) int   g_cnt[N_NODES];
__device__ __align__(16) int   g_rowptr[N_NODES+1];
__device__ __align__(16) int   g_cur[N_NODES];
__device__ __align__(16) int   g_col[N_EDGES];
__device__ __align__(16) float g_wcsr[N_EDGES];
__device__ __align__(16) int   g_bsum[256];
__device__ __align__(16) int   g_boff[256];

__device__ __align__(16) float g_xt[RPAD*4];
__device__ __align__(16) float g_pa[RPAD*4];
__device__ __align__(16) float g_pb[RPAD*4];
__device__ __align__(16) float g_pc[RPAD*4];

__device__ __align__(16) float g_h  [RPAD*64];
__device__ __align__(16) float g_t1 [RPAD*64];
__device__ __align__(16) float g_t2 [RPAD*64];
__device__ __align__(16) float g_t3 [RPAD*64];
__device__ __align__(16) float g_acc[RPAD*64];

__device__ __align__(16) float g_sa[RPAD*2];
__device__ __align__(16) float g_sb[RPAD*2];

/* transposed + tf32-split W2: [64 n][256 k] */
__device__ __align__(16) float g_w2t_hi[64*256];
__device__ __align__(16) float g_w2t_lo[64*256];

__device__ __forceinline__ float tf32r(float x) {
    uint32_t u;
    asm("cvt.rna.tf32.f32 %0, %1;" : "=r"(u) : "f"(x));
    return __uint_as_float(u);
}

#define MMA8(C, a0,a1,a2,a3, b0,b1) \
    asm volatile("mma.sync.aligned.m16n8k8.row.col.f32.tf32.tf32.f32 " \
        "{%0,%1,%2,%3},{%4,%5,%6,%7},{%8,%9},{%0,%1,%2,%3};" \
        : "+f"((C)[0]),"+f"((C)[1]),"+f"((C)[2]),"+f"((C)[3]) \
        : "r"(a0),"r"(a1),"r"(a2),"r"(a3),"r"(b0),"r"(b1))

/* ---------------- preprocessing --------------------------------------- */
__global__ void k_init() {
    int i = blockIdx.x*blockDim.x + threadIdx.x;
    if (i < N_NODES) { g_deg[i] = 0.f; g_cnt[i] = 0; }
}

__global__ void k_deg(const int* __restrict__ dst, const float* __restrict__ ew) {
    int e = blockIdx.x*blockDim.x + threadIdx.x;
    if (e < N_EDGES) {
        int d = dst[e];
        atomicAdd(&g_deg[d], ew[e]);
        atomicAdd(&g_cnt[d], 1);
    }
}

__global__ void k_dis() {
    int i = blockIdx.x*blockDim.x + threadIdx.x;
    if (i < N_NODES) {
        float d = g_deg[i];
        g_dis[i] = (d > 0.f) ? rsqrtf(fmaxf(d, 1e-30f)) : 0.f;
    }
}

/* 3-kernel scan: prescan per block, scan block sums, add offsets */
__global__ void k_scan1() {
    int t = threadIdx.x, b = blockIdx.x;
    int i = b*256 + t;
    int v = (i < N_NODES) ? g_cnt[i] : 0;
    int lane = t & 31, wp = t >> 5;
    int x = v;
    #pragma unroll
    for (int o = 1; o < 32; o <<= 1) {
        int y = __shfl_up_sync(0xffffffffu, x, o);
        if (lane >= o) x += y;
    }
    __shared__ int wt[8];
    if (lane == 31) wt[wp] = x;
    __syncthreads();
    if (wp == 0 && lane < 8) {
        int y = wt[lane];
        #pragma unroll
        for (int o = 1; o < 8; o <<= 1) {
            int z = __shfl_up_sync(0xffu, y, o);
            if (lane >= o) y += z;
        }
        wt[lane] = y;
    }
    __syncthreads();
    int incl = x + (wp ? wt[wp-1] : 0);
    if (i < N_NODES) g_rowptr[i] = incl - v;
    if (t == 255) g_bsum[b] = incl;
}

__global__ void k_scan2() {
    int t = threadIdx.x;
    int v = (t < NB_SCAN) ? g_bsum[t] : 0;
    int lane = t & 31, wp = t >> 5;
    int x = v;
    #pragma unroll
    for (int o = 1; o < 32; o <<= 1) {
        int y = __shfl_up_sync(0xffffffffu, x, o);
        if (lane >= o) x += y;
    }
    __shared__ int wt[8];
    if (lane == 31) wt[wp] = x;
    __syncthreads();
    if (wp == 0 && lane < 8) {
        int y = wt[lane];
        #pragma unroll
        for (int o = 1; o < 8; o <<= 1) {
            int z = __shfl_up_sync(0xffu, y, o);
            if (lane >= o) y += z;
        }
        wt[lane] = y;
    }
    __syncthreads();
    int incl = x + (wp ? wt[wp-1] : 0);
    if (t < NB_SCAN) g_boff[t] = incl - v;
    if (t == 0) g_rowptr[N_NODES] = N_EDGES;
}

__global__ void k_scan3() {
    int i = blockIdx.x*blockDim.x + threadIdx.x;
    if (i < N_NODES) {
        int p = g_rowptr[i] + g_boff[i >> 8];
        g_rowptr[i] = p;
        g_cur[i] = p;
    }
}

/* fill CSR; fuses gcn_norm weight computation */
__global__ void k_fill(const int* __restrict__ src, const int* __restrict__ dst,
                       const float* __restrict__ ew) {
    int e = blockIdx.x*blockDim.x + threadIdx.x;
    if (e < N_EDGES) {
        int s = src[e], d = dst[e];
        int p = atomicAdd(&g_cur[d], 1);
        g_col[p]  = s;
        g_wcsr[p] = g_dis[s] * ew[e] * g_dis[d];
    }
}

/* x [B,N,4] -> g_xt node-major [N,B,4] = [R,4] */
__global__ void k_xt(const float* __restrict__ x) {
    int t = blockIdx.x*blockDim.x + threadIdx.x;
    if (t >= R) return;
    int b = t / N_NODES, n = t - b*N_NODES;
    float4 v = ((const float4*)x)[t];
    ((float4*)g_xt)[n*4 + b] = v;
}

/* W2 [4][64 k][64 n] -> W2T [64 n][256 k], split hi/lo for 3xTF32 */
__global__ void k_w2prep(const float* __restrict__ W2) {
    int t = blockIdx.x*blockDim.x + threadIdx.x;
    if (t >= 64*256) return;
    int n = t >> 8, k = t & 255;
    int sel = k >> 6, kk = k & 63;
    float v = W2[sel*4096 + kk*64 + n];
    float h = tf32r(v);
    g_w2t_hi[t] = h;
    g_w2t_lo[t] = v - h;
}

/* ---------------- propagation ------------------------------------------ */
template<int V4, bool ADD>
__global__ void k_prop_small(const float* __restrict__ in, float* __restrict__ out,
                             const float* __restrict__ add) {
    int n = blockIdx.x*blockDim.x + threadIdx.x;
    if (n >= N_NODES) return;
    float4 acc[V4];
    #pragma unroll
    for (int j = 0; j < V4; j++) acc[j] = make_float4(0.f,0.f,0.f,0.f);
    int s = g_rowptr[n], e = g_rowptr[n+1];
    const float4* base = (const float4*)in;
    for (int i = s; i < e; i++) {
        int c = __ldg(&g_col[i]);
        float wv = __ldg(&g_wcsr[i]);
        const float4* p = base + c*V4;
        #pragma unroll
        for (int j = 0; j < V4; j++) {
            float4 v = __ldg(p + j);
            acc[j].x += wv*v.x; acc[j].y += wv*v.y;
            acc[j].z += wv*v.z; acc[j].w += wv*v.w;
        }
    }
    float4* q = (float4*)out + n*V4;
    #pragma unroll
    for (int j = 0; j < V4; j++) {
        float4 o = acc[j];
        if (ADD) {
            float4 a = ((const float4*)add)[n*V4 + j];
            o.x += a.x; o.y += a.y; o.z += a.z; o.w += a.w;
        }
        q[j] = o;
    }
}

__global__ void k_prop64(const float* __restrict__ in, float* __restrict__ out) {
    int gt = blockIdx.x*blockDim.x + threadIdx.x;
    int n = gt >> 5, lane = gt & 31;
    if (n >= N_NODES) return;
    int s = g_rowptr[n], e = g_rowptr[n+1];
    float4 a0 = make_float4(0.f,0.f,0.f,0.f), a1 = a0;
    const float4* base = (const float4*)in;
    for (int i = s; i < e; i++) {
        int c = __ldg(&g_col[i]);
        float wv = __ldg(&g_wcsr[i]);
        const float4* p = base + c*64 + lane*2;
        float4 v0 = __ldg(p), v1 = __ldg(p+1);
        a0.x += wv*v0.x; a0.y += wv*v0.y; a0.z += wv*v0.z; a0.w += wv*v0.w;
        a1.x += wv*v1.x; a1.y += wv*v1.y; a1.z += wv*v1.z; a1.w += wv*v1.w;
    }
    float4* q = (float4*)out + n*64 + lane*2;
    q[0] = a0; q[1] = a1;
}

/* ---------------- layer-1 GEMM + BN + LeakyReLU (fused) ----------------- */
__global__ void k_gemm1_bn(const float* __restrict__ W1, const float* __restrict__ b1,
                           const float* __restrict__ g1, const float* __restrict__ be1,
                           float* __restrict__ hout) {
    __shared__ float sW[1024];
    __shared__ float sB[64];
    int t = threadIdx.x;
    for (int i = t; i < 1024; i += 256) sW[i] = W1[i];
    if (t < 64) sB[t] = b1[t];
    __syncthreads();
    int r = blockIdx.x*256 + t;
    int rr = r < R ? r : R-1;          /* clamp; groups of 4 fully active or not */
    float in[16];
    { float4 v;
      v = ((const float4*)g_xt)[rr]; in[0]=v.x; in[1]=v.y; in[2]=v.z; in[3]=v.w;
      v = ((const float4*)g_pa)[rr]; in[4]=v.x; in[5]=v.y; in[6]=v.z; in[7]=v.w;
      v = ((const float4*)g_pb)[rr]; in[8]=v.x; in[9]=v.y; in[10]=v.z; in[11]=v.w;
      v = ((const float4*)g_pc)[rr]; in[12]=v.x; in[13]=v.y; in[14]=v.z; in[15]=v.w; }
    float o[64];
    float s = 0.f, q = 0.f;
    #pragma unroll
    for (int g0 = 0; g0 < 64; g0 += 4) {
        float4 a = make_float4(sB[g0], sB[g0+1], sB[g0+2], sB[g0+3]);
        #pragma unroll
        for (int i = 0; i < 16; i++) {
            float4 w = *(const float4*)&sW[i*64 + g0];
            a.x += in[i]*w.x; a.y += in[i]*w.y; a.z += in[i]*w.z; a.w += in[i]*w.w;
        }
        o[g0]=a.x; o[g0+1]=a.y; o[g0+2]=a.z; o[g0+3]=a.w;
        s += a.x+a.y+a.z+a.w;
        q += a.x*a.x+a.y*a.y+a.z*a.z+a.w*a.w;
    }
    /* node stats: reduce over 4-lane group (rows n*4+b consecutive) */
    s += __shfl_xor_sync(0xffffffffu, s, 1);
    q += __shfl_xor_sync(0xffffffffu, q, 1);
    s += __shfl_xor_sync(0xffffffffu, s, 2);
    q += __shfl_xor_sync(0xffffffffu, q, 2);
    if (r >= R) return;
    int n = r >> 2;
    float mu  = s * (1.f/256.f);
    float var = q * (1.f/256.f) - mu*mu;
    float sc  = __ldg(&g1[n]) * rsqrtf(var + BN_EPS);
    float bb  = __ldg(&be1[n]);
    #pragma unroll
    for (int g0 = 0; g0 < 64; g0 += 4) {
        float4 ov;
        float f;
        f = sc*(o[g0+0]-mu)+bb; ov.x = f > 0.f ? f : SLOPE*f;
        f = sc*(o[g0+1]-mu)+bb; ov.y = f > 0.f ? f : SLOPE*f;
        f = sc*(o[g0+2]-mu)+bb; ov.z = f > 0.f ? f : SLOPE*f;
        f = sc*(o[g0+3]-mu)+bb; ov.w = f > 0.f ? f : SLOPE*f;
        *(float4*)&hout[(size_t)r*64 + g0] = ov;
    }
}

/* ---------------- layer-2 GEMM via mma.sync tf32 + fused BN ------------- */
__global__ void __launch_bounds__(256, 2)
k_gemm2_mma(const float* __restrict__ A0, const float* __restrict__ A1,
            const float* __restrict__ A2, const float* __restrict__ A3,
            const float* __restrict__ whi, const float* __restrict__ wlo,
            const float* __restrict__ b2,
            const float* __restrict__ g2, const float* __restrict__ be2,
            float* __restrict__ out) {
    extern __shared__ float sm[];
    const int t = threadIdx.x;
    const int lane = t & 31, wid = t >> 5;
    const int wrow = wid >> 1, wcol = wid & 1;
    const int r0 = blockIdx.x * 128;

    int aoff[4], arowg[4], aks[4];
    #pragma unroll
    for (int i = 0; i < 4; i++) {
        int idx = i*256 + t;
        int row = idx >> 3, c4 = idx & 7;
        int rr = row & 15, mt = row >> 4, ks = c4 >> 1;
        int reg = (rr >> 3) + 2*(c4 & 1);
        aoff[i] = (mt*4 + ks)*128 + reg;
        arowg[i] = row; aks[i] = ks;
    }
    int boff[2], bnrow[2], bks[2];
    #pragma unroll
    for (int i = 0; i < 2; i++) {
        int idx = i*256 + t;
        int n = idx >> 3, c4 = idx & 7;
        int ks = c4 >> 1, reg = c4 & 1, nt = n >> 3;
        boff[i] = 8192 + (nt*4 + ks)*64 + reg;
        bnrow[i] = n; bks[i] = ks;
    }
    int albj[4], blbj[2];
    #pragma unroll
    for (int i = 0; i < 4; i++) { int idx=i*256+t; albj[i] = ((idx>>3 & 15) & 7)*4; }
    #pragma unroll
    for (int i = 0; i < 2; i++) { int idx=i*256+t; blbj[i] = ((idx>>3) & 7)*4; }
    int ac4[4], bc4[2];
    #pragma unroll
    for (int i = 0; i < 4; i++) ac4[i] = (i*256+t) & 7;
    #pragma unroll
    for (int i = 0; i < 2; i++) bc4[i] = (i*256+t) & 7;

    float c[2][4][4];
    #pragma unroll
    for (int m = 0; m < 2; m++)
        #pragma unroll
        for (int n = 0; n < 4; n++)
            #pragma unroll
            for (int k = 0; k < 4; k++) c[m][n][k] = 0.f;

    float4 pa[4], pbh[2], pbl[2];

    /* prologue: load + store chunk 0 */
    {
        #pragma unroll
        for (int i = 0; i < 4; i++)
            pa[i] = *(const float4*)(A0 + (size_t)(r0 + arowg[i])*64 + ac4[i]*4);
        #pragma unroll
        for (int i = 0; i < 2; i++) {
            pbh[i] = *(const float4*)(whi + bnrow[i]*256 + bc4[i]*4);
            pbl[i] = *(const float4*)(wlo + bnrow[i]*256 + bc4[i]*4);
        }
        float* base = sm;
        #pragma unroll
        for (int i = 0; i < 4; i++) {
            float v[4] = {pa[i].x, pa[i].y, pa[i].z, pa[i].w};
            #pragma unroll
            for (int j = 0; j < 4; j++) {
                int sw = ((albj[i] + j) ^ aks[i]) * 4;
                float hv = tf32r(v[j]);
                base[aoff[i] + sw] = hv;
                base[4096 + aoff[i] + sw] = v[j] - hv;
            }
        }
        #pragma unroll
        for (int i = 0; i < 2; i++) {
            float hv[4] = {pbh[i].x, pbh[i].y, pbh[i].z, pbh[i].w};
            float lv[4] = {pbl[i].x, pbl[i].y, pbl[i].z, pbl[i].w};
            #pragma unroll
            for (int j = 0; j < 4; j++) {
                int sw = ((blbj[i] + j) ^ bks[i]) * 2;
                base[boff[i] + sw] = hv[j];
                base[2048 + boff[i] + sw] = lv[j];
            }
        }
    }
    __syncthreads();

    #pragma unroll 1
    for (int cc = 0; cc < 8; cc++) {
        int stage = cc & 1;
        if (cc < 7) {
            int cn = cc + 1;
            const float* Ap = (cn < 2) ? A0 : (cn < 4) ? A1 : (cn < 6) ? A2 : A3;
            int kb = (cn & 1) * 32;
            #pragma unroll
            for (int i = 0; i < 4; i++)
                pa[i] = *(const float4*)(Ap + (size_t)(r0 + arowg[i])*64 + kb + ac4[i]*4);
            #pragma unroll
            for (int i = 0; i < 2; i++) {
                pbh[i] = *(const float4*)(whi + bnrow[i]*256 + cn*32 + bc4[i]*4);
                pbl[i] = *(const float4*)(wlo + bnrow[i]*256 + cn*32 + bc4[i]*4);
            }
        }
        {
            const float* base = sm + stage*12288;
            #pragma unroll
            for (int ks = 0; ks < 4; ks++) {
                int swz4 = (lane ^ ks) * 4;
                int swz2 = (lane ^ ks) * 2;
                uint32_t ah[2][4], al[2][4];
                #pragma unroll
                for (int mt = 0; mt < 2; mt++) {
                    int mtile = wrow*2 + mt;
                    float4 vh = *(const float4*)(base + (mtile*4+ks)*128 + swz4);
                    float4 vl = *(const float4*)(base + 4096 + (mtile*4+ks)*128 + swz4);
                    ah[mt][0]=__float_as_uint(vh.x); ah[mt][1]=__float_as_uint(vh.y);
                    ah[mt][2]=__float_as_uint(vh.z); ah[mt][3]=__float_as_uint(vh.w);
                    al[mt][0]=__float_as_uint(vl.x); al[mt][1]=__float_as_uint(vl.y);
                    al[mt][2]=__float_as_uint(vl.z); al[mt][3]=__float_as_uint(vl.w);
                }
                uint32_t bh[4][2], bl[4][2];
                #pragma unroll
                for (int nt = 0; nt < 4; nt++) {
                    int ntile = wcol*4 + nt;
                    float2 vh = *(const float2*)(base + 8192 + (ntile*4+ks)*64 + swz2);
                    float2 vl = *(const float2*)(base + 10240 + (ntile*4+ks)*64 + swz2);
                    bh[nt][0]=__float_as_uint(vh.x); bh[nt][1]=__float_as_uint(vh.y);
                    bl[nt][0]=__float_as_uint(vl.x); bl[nt][1]=__float_as_uint(vl.y);
                }
                #pragma unroll
                for (int mt = 0; mt < 2; mt++)
                    #pragma unroll
                    for (int nt = 0; nt < 4; nt++) {
                        MMA8(c[mt][nt], ah[mt][0],ah[mt][1],ah[mt][2],ah[mt][3],
                             bh[nt][0], bh[nt][1]);
                        MMA8(c[mt][nt], ah[mt][0],ah[mt][1],ah[mt][2],ah[mt][3],
                             bl[nt][0], bl[nt][1]);
                        MMA8(c[mt][nt], al[mt][0],al[mt][1],al[mt][2],al[mt][3],
                             bh[nt][0], bh[nt][1]);
                    }
            }
        }
        if (cc < 7) {
            float* base = sm + ((cc+1)&1)*12288;
            #pragma unroll
            for (int i = 0; i < 4; i++) {
                float v[4] = {pa[i].x, pa[i].y, pa[i].z, pa[i].w};
                #pragma unroll
                for (int j = 0; j < 4; j++) {
                    int sw = ((albj[i] + j) ^ aks[i]) * 4;
                    float hv = tf32r(v[j]);
                    base[aoff[i] + sw] = hv;
                    base[4096 + aoff[i] + sw] = v[j] - hv;
                }
            }
            #pragma unroll
            for (int i = 0; i < 2; i++) {
                float hv[4] = {pbh[i].x, pbh[i].y, pbh[i].z, pbh[i].w};
                float lv[4] = {pbl[i].x, pbl[i].y, pbl[i].z, pbl[i].w};
                #pragma unroll
                for (int j = 0; j < 4; j++) {
                    int sw = ((blbj[i] + j) ^ bks[i]) * 2;
                    base[boff[i] + sw] = hv[j];
                    base[2048 + boff[i] + sw] = lv[j];
                }
            }
        }
        __syncthreads();
    }

    /* ---- fused BN2 + LeakyReLU epilogue ---- */
    /* stage C (+bias) into smem [128][68] */
    {
        float* so = sm;
        const int g = lane >> 2, q = lane & 3;
        #pragma unroll
        for (int mt = 0; mt < 2; mt++) {
            int lr = wrow*32 + mt*16 + g;
            #pragma unroll
            for (int nt = 0; nt < 4; nt++) {
                int col = wcol*32 + nt*8 + 2*q;
                float bx = __ldg(&b2[col]), by = __ldg(&b2[col+1]);
                so[lr*68+col]       = c[mt][nt][0] + bx;
                so[lr*68+col+1]     = c[mt][nt][1] + by;
                so[(lr+8)*68+col]   = c[mt][nt][2] + bx;
                so[(lr+8)*68+col+1] = c[mt][nt][3] + by;
            }
        }
    }
    __syncthreads();
    {
        const float* so = sm;
        int sub = lane >> 3, c8 = (lane & 7) * 8;
        #pragma unroll
        for (int nn = 0; nn < 4; nn++) {
            int node = wid*4 + nn;
            int gnode = blockIdx.x*32 + node;
            const float* rp = so + (node*4 + sub)*68 + c8;
            float4 v0 = *(const float4*)rp;
            float4 v1 = *(const float4*)(rp + 4);
            float s = v0.x+v0.y+v0.z+v0.w + v1.x+v1.y+v1.z+v1.w;
            float q = v0.x*v0.x+v0.y*v0.y+v0.z*v0.z+v0.w*v0.w
                    + v1.x*v1.x+v1.y*v1.y+v1.z*v1.z+v1.w*v1.w;
            #pragma unroll
            for (int o = 16; o; o >>= 1) {
                s += __shfl_xor_sync(0xffffffffu, s, o);
                q += __shfl_xor_sync(0xffffffffu, q, o);
            }
            if (gnode < N_NODES) {
                float mu  = s * (1.f/256.f);
                float var = q * (1.f/256.f) - mu*mu;
                float sc  = __ldg(&g2[gnode]) * rsqrtf(var + BN_EPS);
                float bb  = __ldg(&be2[gnode]);
                float4 o0, o1;
                float f;
                f = sc*(v0.x-mu)+bb; o0.x = f > 0.f ? f : SLOPE*f;
                f = sc*(v0.y-mu)+bb; o0.y = f > 0.f ? f : SLOPE*f;
                f = sc*(v0.z-mu)+bb; o0.z = f > 0.f ? f : SLOPE*f;
                f = sc*(v0.w-mu)+bb; o0.w = f > 0.f ? f : SLOPE*f;
                f = sc*(v1.x-mu)+bb; o1.x = f > 0.f ? f : SLOPE*f;
                f = sc*(v1.y-mu)+bb; o1.y = f > 0.f ? f : SLOPE*f;
                f = sc*(v1.z-mu)+bb; o1.z = f > 0.f ? f : SLOPE*f;
                f = sc*(v1.w-mu)+bb; o1.w = f > 0.f ? f : SLOPE*f;
                size_t rw = (size_t)(r0 + node*4 + sub)*64 + c8;
                *(float4*)&out[rw]     = o0;
                *(float4*)&out[rw + 4] = o1;
            }
        }
    }
}

/* ---------------- layer-3: all 4 projections in ONE pass over h --------- */
__global__ void k_gemm3_all(const float* __restrict__ h,
                            const float* __restrict__ W3,
                            float* __restrict__ p0, float* __restrict__ p1,
                            float* __restrict__ p2, float* __restrict__ p3) {
    __shared__ float sw[512];   /* W3 [4][64][2] */
    int t = threadIdx.x;
    for (int i = t; i < 512; i += 256) sw[i] = W3[i];
    __syncthreads();
    int r = blockIdx.x*256 + t;
    if (r >= R) return;
    float a[8] = {0,0,0,0,0,0,0,0};
    const float4* hp = (const float4*)(h + (size_t)r*64);
    #pragma unroll
    for (int j = 0; j < 16; j++) {
        float4 v = hp[j];
        #pragma unroll
        for (int k = 0; k < 4; k++) {
            const float* w = &sw[k*128 + j*8];
            a[k*2]   += v.x*w[0] + v.y*w[2] + v.z*w[4] + v.w*w[6];
            a[k*2+1] += v.x*w[1] + v.y*w[3] + v.z*w[5] + v.w*w[7];
        }
    }
    *(float2*)&p0[r*2] = make_float2(a[0], a[1]);
    *(float2*)&p1[r*2] = make_float2(a[2], a[3]);
    *(float2*)&p2[r*2] = make_float2(a[4], a[5]);
    *(float2*)&p3[r*2] = make_float2(a[6], a[7]);
}

/* ---------------- epilogue: +p0+b3, denorm, mask, clamp ----------------- */
__global__ void k_final(const float* __restrict__ pre, const float* __restrict__ p0,
                        const float* __restrict__ b3,
                        const float* __restrict__ mask,
                        const float* __restrict__ mean_y, const float* __restrict__ std_y,
                        const float* __restrict__ vmin, const float* __restrict__ vmax,
                        const float* __restrict__ qmin, const float* __restrict__ qmax,
                        float* __restrict__ out) {
    int t = blockIdx.x*blockDim.x + threadIdx.x;
    if (t >= R) return;
    int b = t / N_NODES, n = t - b*N_NODES;
    int rn = n*4 + b;
    float2 v = *(const float2*)&pre[(size_t)rn*2];
    float2 z = *(const float2*)&p0[(size_t)rn*2];
    float u0 = v.x + z.x + __ldg(&b3[0]);
    float u1 = v.y + z.y + __ldg(&b3[1]);
    float s0 = std_y[n*2], s1 = std_y[n*2+1];
    if (isinf(s0)) s0 = 0.f;
    if (isinf(s1)) s1 = 0.f;
    float o0 = (u0*s0 + mean_y[n*2])   * mask[n*2];
    float o1 = (u1*s1 + mean_y[n*2+1]) * mask[n*2+1];
    o0 = fminf(fmaxf(o0, vmin[n]), vmax[n]);
    o1 = fminf(fmaxf(o1, qmin[n]), qmax[n]);
    *(float2*)&out[(size_t)t*2] = make_float2(o0, o1);
}

/* ======================================================================= */
extern "C" void kernel_launch(void* const* d_in, const int* in_sizes, int n_in,
                              void* d_out, int out_size) {
    const float* x      = (const float*)d_in[0];
    const int*   src    = (const int*)  d_in[1];
    const int*   dst    = (const int*)  d_in[2];
    const float* ew     = (const float*)d_in[3];
    const float* W1     = (const float*)d_in[4];
    const float* b1     = (const float*)d_in[5];
    const float* W2     = (const float*)d_in[6];
    const float* b2     = (const float*)d_in[7];
    const float* W3     = (const float*)d_in[8];
    const float* b3     = (const float*)d_in[9];
    const float* g1     = (const float*)d_in[10];
    const float* be1    = (const float*)d_in[11];
    const float* g2     = (const float*)d_in[12];
    const float* be2    = (const float*)d_in[13];
    const float* mask   = (const float*)d_in[14];
    const float* mean_y = (const float*)d_in[15];
    const float* std_y  = (const float*)d_in[16];
    const float* vmin   = (const float*)d_in[17];
    const float* vmax   = (const float*)d_in[18];
    const float* qmin   = (const float*)d_in[19];
    const float* qmax   = (const float*)d_in[20];
    float* out = (float*)d_out;

    float *xt, *pa, *pb, *pc, *h, *t1, *t2, *t3, *acc, *sa, *sb;
    float *w2hi, *w2lo;
    cudaGetSymbolAddress((void**)&xt,  g_xt);
    cudaGetSymbolAddress((void**)&pa,  g_pa);
    cudaGetSymbolAddress((void**)&pb,  g_pb);
    cudaGetSymbolAddress((void**)&pc,  g_pc);
    cudaGetSymbolAddress((void**)&h,   g_h);
    cudaGetSymbolAddress((void**)&t1,  g_t1);
    cudaGetSymbolAddress((void**)&t2,  g_t2);
    cudaGetSymbolAddress((void**)&t3,  g_t3);
    cudaGetSymbolAddress((void**)&acc, g_acc);
    cudaGetSymbolAddress((void**)&sa,  g_sa);
    cudaGetSymbolAddress((void**)&sb,  g_sb);
    cudaGetSymbolAddress((void**)&w2hi, g_w2t_hi);
    cudaGetSymbolAddress((void**)&w2lo, g_w2t_lo);

    static int smem_set = 0;
    if (!smem_set) {
        cudaFuncSetAttribute(k_gemm2_mma, cudaFuncAttributeMaxDynamicSharedMemorySize, 98304);
        smem_set = 1;
    }

    const int TB = 256;
    int gN = (N_NODES + TB - 1) / TB;
    int gE = (N_EDGES + TB - 1) / TB;
    int gR = (R + TB - 1) / TB;
    int gW = (N_NODES*32 + TB - 1) / TB;

    /* preprocessing */
    k_init <<<gN, TB>>>();
    k_deg  <<<gE, TB>>>(dst, ew);
    k_dis  <<<gN, TB>>>();
    k_scan1<<<NB_SCAN, 256>>>();
    k_scan2<<<1, 256>>>();
    k_scan3<<<gN, TB>>>();
    k_fill <<<gE, TB>>>(src, dst, ew);
    k_w2prep<<<(64*256 + TB - 1)/TB, TB>>>(W2);

    /* layer 1: prop at F=4, fused GEMM+BN+LReLU */
    k_xt<<<gR, TB>>>(x);
    k_prop_small<4,false><<<gN, TB>>>(xt, pa, nullptr);
    k_prop_small<4,false><<<gN, TB>>>(pa, pb, nullptr);
    k_prop_small<4,false><<<gN, TB>>>(pb, pc, nullptr);
    k_gemm1_bn<<<(R + 255)/256, 256>>>(W1, b1, g1, be1, h);

    /* layer 2: 3x prop64, mma GEMM with fused BN -> acc */
    k_prop64<<<gW, TB>>>(h,  t1);
    k_prop64<<<gW, TB>>>(t1, t2);
    k_prop64<<<gW, TB>>>(t2, t3);
    k_gemm2_mma<<<RPAD/128, 256, 98304>>>(h, t1, t2, t3, w2hi, w2lo, b2, g2, be2, acc);

    /* layer 3: one-pass projections, then Horner at F=2
       p0->pb, p1->pa, p2->sb, p3->sa */
    k_gemm3_all<<<(R + 255)/256, 256>>>(acc, W3, pb, pa, sb, sa);
    k_prop_small<2,true ><<<gN, TB>>>(sa, pc, sb);   /* u2 = A p3 + p2 */
    k_prop_small<2,true ><<<gN, TB>>>(pc, sa, pa);   /* u1 = A u2 + p1 */
    k_prop_small<2,false><<<gN, TB>>>(sa, sb, nullptr); /* A u1 */

    /* epilogue (+p0 + b3) */
    k_final<<<gR, TB>>>(sb, pb, b3, mask, mean_y, std_y, vmin, vmax, qmin, qmax, out);
}

// round 5
// speedup vs baseline: 1.6742x; 1.1183x over previous
#include <cuda_runtime.h>
#include <cuda_bf16.h>
#include <math.h>
#include <cstdint>

#define N_NODES 50000
#define N_EDGES 400000
#define BATCH 4
#define R (N_NODES*BATCH)      /* 200000 rows (n,b) */
#define RPAD 200064            /* padded to 128-row GEMM tiles */
#define BN_EPS 1e-5f
#define SLOPE 0.01f
#define NB_SCAN ((N_NODES + 255) / 256)   /* 196 */

/* ---------------- static device scratch (no allocations allowed) -------- */
__device__ __align__(16) float g_deg[N_NODES];
__device__ __align__(16) float g_dis[N_NODES];
__device__ __align__(16) int   g_cnt[N_NODES];
__device__ __align__(16) int   g_rowptr[N_NODES+1];
__device__ __align__(16) int   g_cur[N_NODES];
__device__ __align__(16) int   g_col[N_EDGES];
__device__ __align__(16) float g_wcsr[N_EDGES];
__device__ __align__(16) int   g_bsum[256];
__device__ __align__(16) int   g_boff[256];

__device__ __align__(16) float g_xt[RPAD*4];
__device__ __align__(16) float g_pa[RPAD*4];
__device__ __align__(16) float g_pb[RPAD*4];
__device__ __align__(16) float g_pc[RPAD*4];

__device__ __align__(16) float g_h  [RPAD*64];
__device__ __align__(16) float g_t1 [RPAD*64];
__device__ __align__(16) float g_t2 [RPAD*64];
__device__ __align__(16) float g_t3 [RPAD*64];
__device__ __align__(16) float g_acc[RPAD*64];

__device__ __align__(16) float g_sa[RPAD*2];
__device__ __align__(16) float g_sb[RPAD*2];

/* W2 transposed [64 n][128 kpair], bf16x2-packed hi/lo */
__device__ __align__(16) uint32_t g_w2p_hi[64*128];
__device__ __align__(16) uint32_t g_w2p_lo[64*128];

#define MMA16(C, a0,a1,a2,a3, b0,b1) \
    asm volatile("mma.sync.aligned.m16n8k16.row.col.f32.bf16.bf16.f32 " \
        "{%0,%1,%2,%3},{%4,%5,%6,%7},{%8,%9},{%0,%1,%2,%3};" \
        : "+f"((C)[0]),"+f"((C)[1]),"+f"((C)[2]),"+f"((C)[3]) \
        : "r"(a0),"r"(a1),"r"(a2),"r"(a3),"r"(b0),"r"(b1))

__device__ __forceinline__ uint32_t bf2u(__nv_bfloat162 h) {
    uint32_t u; memcpy(&u, &h, 4); return u;
}
/* split float4 (4 consecutive k) into bf16-pair hi/lo words */
__device__ __forceinline__ void bsplit4(float4 v, uint32_t& h01, uint32_t& h23,
                                        uint32_t& l01, uint32_t& l23) {
    __nv_bfloat162 h0 = __floats2bfloat162_rn(v.x, v.y);
    __nv_bfloat162 h1 = __floats2bfloat162_rn(v.z, v.w);
    float lx = v.x - __low2float(h0),  ly = v.y - __high2float(h0);
    float lz = v.z - __low2float(h1),  lw = v.w - __high2float(h1);
    h01 = bf2u(h0); h23 = bf2u(h1);
    l01 = bf2u(__floats2bfloat162_rn(lx, ly));
    l23 = bf2u(__floats2bfloat162_rn(lz, lw));
}

/* ---------------- preprocessing --------------------------------------- */
__global__ void k_init() {
    int i = blockIdx.x*blockDim.x + threadIdx.x;
    if (i < N_NODES) { g_deg[i] = 0.f; g_cnt[i] = 0; }
}

__global__ void k_deg(const int* __restrict__ dst, const float* __restrict__ ew) {
    int e = blockIdx.x*blockDim.x + threadIdx.x;
    if (e < N_EDGES) {
        int d = dst[e];
        atomicAdd(&g_deg[d], ew[e]);
        atomicAdd(&g_cnt[d], 1);
    }
}

/* 3-kernel scan */
__global__ void k_scan1() {
    int t = threadIdx.x, b = blockIdx.x;
    int i = b*256 + t;
    int v = (i < N_NODES) ? g_cnt[i] : 0;
    int lane = t & 31, wp = t >> 5;
    int x = v;
    #pragma unroll
    for (int o = 1; o < 32; o <<= 1) {
        int y = __shfl_up_sync(0xffffffffu, x, o);
        if (lane >= o) x += y;
    }
    __shared__ int wt[8];
    if (lane == 31) wt[wp] = x;
    __syncthreads();
    if (wp == 0 && lane < 8) {
        int y = wt[lane];
        #pragma unroll
        for (int o = 1; o < 8; o <<= 1) {
            int z = __shfl_up_sync(0xffu, y, o);
            if (lane >= o) y += z;
        }
        wt[lane] = y;
    }
    __syncthreads();
    int incl = x + (wp ? wt[wp-1] : 0);
    if (i < N_NODES) g_rowptr[i] = incl - v;
    if (t == 255) g_bsum[b] = incl;
}

__global__ void k_scan2() {
    int t = threadIdx.x;
    int v = (t < NB_SCAN) ? g_bsum[t] : 0;
    int lane = t & 31, wp = t >> 5;
    int x = v;
    #pragma unroll
    for (int o = 1; o < 32; o <<= 1) {
        int y = __shfl_up_sync(0xffffffffu, x, o);
        if (lane >= o) x += y;
    }
    __shared__ int wt[8];
    if (lane == 31) wt[wp] = x;
    __syncthreads();
    if (wp == 0 && lane < 8) {
        int y = wt[lane];
        #pragma unroll
        for (int o = 1; o < 8; o <<= 1) {
            int z = __shfl_up_sync(0xffu, y, o);
            if (lane >= o) y += z;
        }
        wt[lane] = y;
    }
    __syncthreads();
    int incl = x + (wp ? wt[wp-1] : 0);
    if (t < NB_SCAN) g_boff[t] = incl - v;
    if (t == 0) g_rowptr[N_NODES] = N_EDGES;
}

/* scan add-offsets + dis computation (fused) */
__global__ void k_scan3() {
    int i = blockIdx.x*blockDim.x + threadIdx.x;
    if (i < N_NODES) {
        int p = g_rowptr[i] + g_boff[i >> 8];
        g_rowptr[i] = p;
        g_cur[i] = p;
        float d = g_deg[i];
        g_dis[i] = (d > 0.f) ? rsqrtf(fmaxf(d, 1e-30f)) : 0.f;
    }
}

__global__ void k_fill(const int* __restrict__ src, const int* __restrict__ dst,
                       const float* __restrict__ ew) {
    int e = blockIdx.x*blockDim.x + threadIdx.x;
    if (e < N_EDGES) {
        int s = src[e], d = dst[e];
        int p = atomicAdd(&g_cur[d], 1);
        g_col[p]  = s;
        g_wcsr[p] = g_dis[s] * ew[e] * g_dis[d];
    }
}

/* x [B,N,4] -> node-major [N,B,4] */
__global__ void k_xt(const float* __restrict__ x) {
    int t = blockIdx.x*blockDim.x + threadIdx.x;
    if (t >= R) return;
    int b = t / N_NODES, n = t - b*N_NODES;
    float4 v = ((const float4*)x)[t];
    ((float4*)g_xt)[n*4 + b] = v;
}

/* W2 [4][64 k][64 n] -> [64 n][128 kpair] bf16x2 packed hi/lo */
__global__ void k_w2prep(const float* __restrict__ W2) {
    int t = blockIdx.x*blockDim.x + threadIdx.x;
    if (t >= 64*128) return;
    int n = t >> 7, p = t & 127;
    int k0 = 2*p;
    int sel = k0 >> 6, kk = k0 & 63;
    float v0 = W2[sel*4096 + kk*64 + n];
    float v1 = W2[sel*4096 + (kk+1)*64 + n];
    __nv_bfloat162 h = __floats2bfloat162_rn(v0, v1);
    float l0 = v0 - __low2float(h), l1 = v1 - __high2float(h);
    g_w2p_hi[t] = bf2u(h);
    g_w2p_lo[t] = bf2u(__floats2bfloat162_rn(l0, l1));
}

/* ---------------- propagation ------------------------------------------ */
template<int V4, bool ADD>
__global__ void k_prop_small(const float* __restrict__ in, float* __restrict__ out,
                             const float* __restrict__ add) {
    int n = blockIdx.x*blockDim.x + threadIdx.x;
    if (n >= N_NODES) return;
    float4 acc[V4];
    #pragma unroll
    for (int j = 0; j < V4; j++) acc[j] = make_float4(0.f,0.f,0.f,0.f);
    int s = g_rowptr[n], e = g_rowptr[n+1];
    const float4* base = (const float4*)in;
    for (int i = s; i < e; i++) {
        int c = __ldg(&g_col[i]);
        float wv = __ldg(&g_wcsr[i]);
        const float4* p = base + c*V4;
        #pragma unroll
        for (int j = 0; j < V4; j++) {
            float4 v = __ldg(p + j);
            acc[j].x += wv*v.x; acc[j].y += wv*v.y;
            acc[j].z += wv*v.z; acc[j].w += wv*v.w;
        }
    }
    float4* q = (float4*)out + n*V4;
    #pragma unroll
    for (int j = 0; j < V4; j++) {
        float4 o = acc[j];
        if (ADD) {
            float4 a = ((const float4*)add)[n*V4 + j];
            o.x += a.x; o.y += a.y; o.z += a.z; o.w += a.w;
        }
        q[j] = o;
    }
}

__global__ void k_prop64(const float* __restrict__ in, float* __restrict__ out) {
    int gt = blockIdx.x*blockDim.x + threadIdx.x;
    int n = gt >> 5, lane = gt & 31;
    if (n >= N_NODES) return;
    int s = g_rowptr[n], e = g_rowptr[n+1];
    float4 a0 = make_float4(0.f,0.f,0.f,0.f), a1 = a0;
    const float4* base = (const float4*)in;
    for (int i = s; i < e; i++) {
        int c = __ldg(&g_col[i]);
        float wv = __ldg(&g_wcsr[i]);
        const float4* p = base + c*64 + lane*2;
        float4 v0 = __ldg(p), v1 = __ldg(p+1);
        a0.x += wv*v0.x; a0.y += wv*v0.y; a0.z += wv*v0.z; a0.w += wv*v0.w;
        a1.x += wv*v1.x; a1.y += wv*v1.y; a1.z += wv*v1.z; a1.w += wv*v1.w;
    }
    float4* q = (float4*)out + n*64 + lane*2;
    q[0] = a0; q[1] = a1;
}

/* ---------------- layer-1 GEMM + BN + LeakyReLU (fused) ----------------- */
__global__ void k_gemm1_bn(const float* __restrict__ W1, const float* __restrict__ b1,
                           const float* __restrict__ g1, const float* __restrict__ be1,
                           float* __restrict__ hout) {
    __shared__ float sW[1024];
    __shared__ float sB[64];
    int t = threadIdx.x;
    for (int i = t; i < 1024; i += 256) sW[i] = W1[i];
    if (t < 64) sB[t] = b1[t];
    __syncthreads();
    int r = blockIdx.x*256 + t;
    int rr = r < R ? r : R-1;
    float in[16];
    { float4 v;
      v = ((const float4*)g_xt)[rr]; in[0]=v.x; in[1]=v.y; in[2]=v.z; in[3]=v.w;
      v = ((const float4*)g_pa)[rr]; in[4]=v.x; in[5]=v.y; in[6]=v.z; in[7]=v.w;
      v = ((const float4*)g_pb)[rr]; in[8]=v.x; in[9]=v.y; in[10]=v.z; in[11]=v.w;
      v = ((const float4*)g_pc)[rr]; in[12]=v.x; in[13]=v.y; in[14]=v.z; in[15]=v.w; }
    float o[64];
    float s = 0.f, q = 0.f;
    #pragma unroll
    for (int g0 = 0; g0 < 64; g0 += 4) {
        float4 a = make_float4(sB[g0], sB[g0+1], sB[g0+2], sB[g0+3]);
        #pragma unroll
        for (int i = 0; i < 16; i++) {
            float4 w = *(const float4*)&sW[i*64 + g0];
            a.x += in[i]*w.x; a.y += in[i]*w.y; a.z += in[i]*w.z; a.w += in[i]*w.w;
        }
        o[g0]=a.x; o[g0+1]=a.y; o[g0+2]=a.z; o[g0+3]=a.w;
        s += a.x+a.y+a.z+a.w;
        q += a.x*a.x+a.y*a.y+a.z*a.z+a.w*a.w;
    }
    s += __shfl_xor_sync(0xffffffffu, s, 1);
    q += __shfl_xor_sync(0xffffffffu, q, 1);
    s += __shfl_xor_sync(0xffffffffu, s, 2);
    q += __shfl_xor_sync(0xffffffffu, q, 2);
    if (r >= R) return;
    int n = r >> 2;
    float mu  = s * (1.f/256.f);
    float var = q * (1.f/256.f) - mu*mu;
    float sc  = __ldg(&g1[n]) * rsqrtf(var + BN_EPS);
    float bb  = __ldg(&be1[n]);
    #pragma unroll
    for (int g0 = 0; g0 < 64; g0 += 4) {
        float4 ov;
        float f;
        f = sc*(o[g0+0]-mu)+bb; ov.x = f > 0.f ? f : SLOPE*f;
        f = sc*(o[g0+1]-mu)+bb; ov.y = f > 0.f ? f : SLOPE*f;
        f = sc*(o[g0+2]-mu)+bb; ov.z = f > 0.f ? f : SLOPE*f;
        f = sc*(o[g0+3]-mu)+bb; ov.w = f > 0.f ? f : SLOPE*f;
        *(float4*)&hout[(size_t)r*64 + g0] = ov;
    }
}

/* ---------------- layer-2 GEMM: bf16x3 split mma.sync m16n8k16 ----------
 * CTA 128x64, K=256 in 8 chunks of 32 (= 2 K16 steps). 8 warps 4x2.
 * smem stage (u32): AHI[0,2048) ALO[2048,4096) BHI[4096,5120) BLO[5120,6144)
 * 2 stages = 12288 u32 = 48 KB. Epilogue restages C into sm (34.8 KB).    */
#define STG_U32 6144
__global__ void __launch_bounds__(256, 2)
k_gemm2_mma(const float* __restrict__ A0, const float* __restrict__ A1,
            const float* __restrict__ A2, const float* __restrict__ A3,
            const uint32_t* __restrict__ wph, const uint32_t* __restrict__ wpl,
            const float* __restrict__ b2,
            const float* __restrict__ g2, const float* __restrict__ be2,
            float* __restrict__ out) {
    extern __shared__ uint32_t smu[];
    float* smf = (float*)smu;
    const int t = threadIdx.x;
    const int lane = t & 31, wid = t >> 5;
    const int wrow = wid >> 1, wcol = wid & 1;
    const int r0 = blockIdx.x * 128;

    /* writer index precompute */
    int a_w[4], a_src[4];
    #pragma unroll
    for (int i = 0; i < 4; i++) {
        int idx = i*256 + t;
        int row = idx >> 3, c4 = idx & 7;
        int rr = row & 15, mt = row >> 4;
        int ks = c4 >> 2, regbit = (c4 >> 1) & 1, q0 = (c4 & 1) * 2;
        int g = rr & 7, abit = rr >> 3;
        a_w[i] = (mt*2 + ks)*128 + (g*4 + q0)*4 + abit + 2*regbit;
        a_src[i] = row*64 + c4*4;
    }
    int b_w[2], b_src[2];
    #pragma unroll
    for (int i = 0; i < 2; i++) {
        int idx = i*256 + t;
        int n = idx >> 3, c4 = idx & 7;
        int ks = c4 >> 2, regbit = (c4 >> 1) & 1, q0 = (c4 & 1) * 2;
        int g = n & 7, nt = n >> 3;
        b_w[i] = 4096 + (nt*2 + ks)*64 + (g*4 + q0)*2 + regbit;
        b_src[i] = n*128 + c4*2;
    }

    float c[2][4][4];
    #pragma unroll
    for (int m = 0; m < 2; m++)
        #pragma unroll
        for (int n = 0; n < 4; n++)
            #pragma unroll
            for (int k = 0; k < 4; k++) c[m][n][k] = 0.f;

    float4 pa[4];
    uint2 pbh[2], pbl[2];

    /* prologue: load + store chunk 0 */
    {
        #pragma unroll
        for (int i = 0; i < 4; i++)
            pa[i] = *(const float4*)(A0 + (size_t)r0*64 + a_src[i]);
        #pragma unroll
        for (int i = 0; i < 2; i++) {
            pbh[i] = *(const uint2*)(wph + b_src[i]);
            pbl[i] = *(const uint2*)(wpl + b_src[i]);
        }
        uint32_t* base = smu;
        #pragma unroll
        for (int i = 0; i < 4; i++) {
            uint32_t h01, h23, l01, l23;
            bsplit4(pa[i], h01, h23, l01, l23);
            base[a_w[i]]          = h01;
            base[a_w[i] + 4]      = h23;
            base[2048 + a_w[i]]   = l01;
            base[2048 + a_w[i]+4] = l23;
        }
        #pragma unroll
        for (int i = 0; i < 2; i++) {
            base[b_w[i]]            = pbh[i].x;
            base[b_w[i] + 2]        = pbh[i].y;
            base[1024 + b_w[i]]     = pbl[i].x;
            base[1024 + b_w[i] + 2] = pbl[i].y;
        }
    }
    __syncthreads();

    #pragma unroll 1
    for (int cc = 0; cc < 8; cc++) {
        int stage = cc & 1;
        if (cc < 7) {
            int cn = cc + 1;
            const float* Ap = (cn < 2) ? A0 : (cn < 4) ? A1 : (cn < 6) ? A2 : A3;
            int kb = (cn & 1) * 32;
            #pragma unroll
            for (int i = 0; i < 4; i++)
                pa[i] = *(const float4*)(Ap + (size_t)r0*64 + a_src[i] + kb);
            #pragma unroll
            for (int i = 0; i < 2; i++) {
                pbh[i] = *(const uint2*)(wph + b_src[i] + cn*16);
                pbl[i] = *(const uint2*)(wpl + b_src[i] + cn*16);
            }
        }
        /* compute current stage */
        {
            const uint32_t* base = smu + stage*STG_U32;
            #pragma unroll
            for (int ks = 0; ks < 2; ks++) {
                uint4 ah[2], al[2];
                #pragma unroll
                for (int mt = 0; mt < 2; mt++) {
                    int mtile = wrow*2 + mt;
                    ah[mt] = *(const uint4*)(base + (mtile*2+ks)*128 + lane*4);
                    al[mt] = *(const uint4*)(base + 2048 + (mtile*2+ks)*128 + lane*4);
                }
                uint2 bh[4], bl[4];
                #pragma unroll
                for (int nt = 0; nt < 4; nt++) {
                    int ntile = wcol*4 + nt;
                    bh[nt] = *(const uint2*)(base + 4096 + (ntile*2+ks)*64 + lane*2);
                    bl[nt] = *(const uint2*)(base + 5120 + (ntile*2+ks)*64 + lane*2);
                }
                #pragma unroll
                for (int mt = 0; mt < 2; mt++)
                    #pragma unroll
                    for (int nt = 0; nt < 4; nt++) {
                        MMA16(c[mt][nt], ah[mt].x, ah[mt].y, ah[mt].z, ah[mt].w,
                              bh[nt].x, bh[nt].y);
                        MMA16(c[mt][nt], ah[mt].x, ah[mt].y, ah[mt].z, ah[mt].w,
                              bl[nt].x, bl[nt].y);
                        MMA16(c[mt][nt], al[mt].x, al[mt].y, al[mt].z, al[mt].w,
                              bh[nt].x, bh[nt].y);
                    }
            }
        }
        /* store prefetched chunk into other stage */
        if (cc < 7) {
            uint32_t* base = smu + ((cc+1)&1)*STG_U32;
            #pragma unroll
            for (int i = 0; i < 4; i++) {
                uint32_t h01, h23, l01, l23;
                bsplit4(pa[i], h01, h23, l01, l23);
                base[a_w[i]]          = h01;
                base[a_w[i] + 4]      = h23;
                base[2048 + a_w[i]]   = l01;
                base[2048 + a_w[i]+4] = l23;
            }
            #pragma unroll
            for (int i = 0; i < 2; i++) {
                base[b_w[i]]            = pbh[i].x;
                base[b_w[i] + 2]        = pbh[i].y;
                base[1024 + b_w[i]]     = pbl[i].x;
                base[1024 + b_w[i] + 2] = pbl[i].y;
            }
        }
        __syncthreads();
    }

    /* ---- fused BN2 + LeakyReLU epilogue ---- */
    {
        float* so = smf;
        const int g = lane >> 2, q = lane & 3;
        #pragma unroll
        for (int mt = 0; mt < 2; mt++) {
            int lr = wrow*32 + mt*16 + g;
            #pragma unroll
            for (int nt = 0; nt < 4; nt++) {
                int col = wcol*32 + nt*8 + 2*q;
                float bx = __ldg(&b2[col]), by = __ldg(&b2[col+1]);
                so[lr*68+col]       = c[mt][nt][0] + bx;
                so[lr*68+col+1]     = c[mt][nt][1] + by;
                so[(lr+8)*68+col]   = c[mt][nt][2] + bx;
                so[(lr+8)*68+col+1] = c[mt][nt][3] + by;
            }
        }
    }
    __syncthreads();
    {
        const float* so = smf;
        int sub = lane >> 3, c8 = (lane & 7) * 8;
        #pragma unroll
        for (int nn = 0; nn < 4; nn++) {
            int node = wid*4 + nn;
            int gnode = blockIdx.x*32 + node;
            const float* rp = so + (node*4 + sub)*68 + c8;
            float4 v0 = *(const float4*)rp;
            float4 v1 = *(const float4*)(rp + 4);
            float s = v0.x+v0.y+v0.z+v0.w + v1.x+v1.y+v1.z+v1.w;
            float q = v0.x*v0.x+v0.y*v0.y+v0.z*v0.z+v0.w*v0.w
                    + v1.x*v1.x+v1.y*v1.y+v1.z*v1.z+v1.w*v1.w;
            #pragma unroll
            for (int o = 16; o; o >>= 1) {
                s += __shfl_xor_sync(0xffffffffu, s, o);
                q += __shfl_xor_sync(0xffffffffu, q, o);
            }
            if (gnode < N_NODES) {
                float mu  = s * (1.f/256.f);
                float var = q * (1.f/256.f) - mu*mu;
                float sc  = __ldg(&g2[gnode]) * rsqrtf(var + BN_EPS);
                float bb  = __ldg(&be2[gnode]);
                float4 o0, o1;
                float f;
                f = sc*(v0.x-mu)+bb; o0.x = f > 0.f ? f : SLOPE*f;
                f = sc*(v0.y-mu)+bb; o0.y = f > 0.f ? f : SLOPE*f;
                f = sc*(v0.z-mu)+bb; o0.z = f > 0.f ? f : SLOPE*f;
                f = sc*(v0.w-mu)+bb; o0.w = f > 0.f ? f : SLOPE*f;
                f = sc*(v1.x-mu)+bb; o1.x = f > 0.f ? f : SLOPE*f;
                f = sc*(v1.y-mu)+bb; o1.y = f > 0.f ? f : SLOPE*f;
                f = sc*(v1.z-mu)+bb; o1.z = f > 0.f ? f : SLOPE*f;
                f = sc*(v1.w-mu)+bb; o1.w = f > 0.f ? f : SLOPE*f;
                size_t rw = (size_t)(r0 + node*4 + sub)*64 + c8;
                *(float4*)&out[rw]     = o0;
                *(float4*)&out[rw + 4] = o1;
            }
        }
    }
}

/* ---------------- layer-3: all 4 projections in one pass ---------------- */
__global__ void k_gemm3_all(const float* __restrict__ h,
                            const float* __restrict__ W3,
                            float* __restrict__ p0, float* __restrict__ p1,
                            float* __restrict__ p2, float* __restrict__ p3) {
    __shared__ float sw[512];
    int t = threadIdx.x;
    for (int i = t; i < 512; i += 256) sw[i] = W3[i];
    __syncthreads();
    int r = blockIdx.x*256 + t;
    if (r >= R) return;
    float a[8] = {0,0,0,0,0,0,0,0};
    const float4* hp = (const float4*)(h + (size_t)r*64);
    #pragma unroll
    for (int j = 0; j < 16; j++) {
        float4 v = hp[j];
        #pragma unroll
        for (int k = 0; k < 4; k++) {
            const float* w = &sw[k*128 + j*8];
            a[k*2]   += v.x*w[0] + v.y*w[2] + v.z*w[4] + v.w*w[6];
            a[k*2+1] += v.x*w[1] + v.y*w[3] + v.z*w[5] + v.w*w[7];
        }
    }
    *(float2*)&p0[r*2] = make_float2(a[0], a[1]);
    *(float2*)&p1[r*2] = make_float2(a[2], a[3]);
    *(float2*)&p2[r*2] = make_float2(a[4], a[5]);
    *(float2*)&p3[r*2] = make_float2(a[6], a[7]);
}

/* ---------------- epilogue ---------------------------------------------- */
__global__ void k_final(const float* __restrict__ pre, const float* __restrict__ p0,
                        const float* __restrict__ b3,
                        const float* __restrict__ mask,
                        const float* __restrict__ mean_y, const float* __restrict__ std_y,
                        const float* __restrict__ vmin, const float* __restrict__ vmax,
                        const float* __restrict__ qmin, const float* __restrict__ qmax,
                        float* __restrict__ out) {
    int t = blockIdx.x*blockDim.x + threadIdx.x;
    if (t >= R) return;
    int b = t / N_NODES, n = t - b*N_NODES;
    int rn = n*4 + b;
    float2 v = *(const float2*)&pre[(size_t)rn*2];
    float2 z = *(const float2*)&p0[(size_t)rn*2];
    float u0 = v.x + z.x + __ldg(&b3[0]);
    float u1 = v.y + z.y + __ldg(&b3[1]);
    float s0 = std_y[n*2], s1 = std_y[n*2+1];
    if (isinf(s0)) s0 = 0.f;
    if (isinf(s1)) s1 = 0.f;
    float o0 = (u0*s0 + mean_y[n*2])   * mask[n*2];
    float o1 = (u1*s1 + mean_y[n*2+1]) * mask[n*2+1];
    o0 = fminf(fmaxf(o0, vmin[n]), vmax[n]);
    o1 = fminf(fmaxf(o1, qmin[n]), qmax[n]);
    *(float2*)&out[(size_t)t*2] = make_float2(o0, o1);
}

/* ======================================================================= */
extern "C" void kernel_launch(void* const* d_in, const int* in_sizes, int n_in,
                              void* d_out, int out_size) {
    const float* x      = (const float*)d_in[0];
    const int*   src    = (const int*)  d_in[1];
    const int*   dst    = (const int*)  d_in[2];
    const float* ew     = (const float*)d_in[3];
    const float* W1     = (const float*)d_in[4];
    const float* b1     = (const float*)d_in[5];
    const float* W2     = (const float*)d_in[6];
    const float* b2     = (const float*)d_in[7];
    const float* W3     = (const float*)d_in[8];
    const float* b3     = (const float*)d_in[9];
    const float* g1     = (const float*)d_in[10];
    const float* be1    = (const float*)d_in[11];
    const float* g2     = (const float*)d_in[12];
    const float* be2    = (const float*)d_in[13];
    const float* mask   = (const float*)d_in[14];
    const float* mean_y = (const float*)d_in[15];
    const float* std_y  = (const float*)d_in[16];
    const float* vmin   = (const float*)d_in[17];
    const float* vmax   = (const float*)d_in[18];
    const float* qmin   = (const float*)d_in[19];
    const float* qmax   = (const float*)d_in[20];
    float* out = (float*)d_out;

    float *xt, *pa, *pb, *pc, *h, *t1, *t2, *t3, *acc, *sa, *sb;
    uint32_t *w2ph, *w2pl;
    cudaGetSymbolAddress((void**)&xt,  g_xt);
    cudaGetSymbolAddress((void**)&pa,  g_pa);
    cudaGetSymbolAddress((void**)&pb,  g_pb);
    cudaGetSymbolAddress((void**)&pc,  g_pc);
    cudaGetSymbolAddress((void**)&h,   g_h);
    cudaGetSymbolAddress((void**)&t1,  g_t1);
    cudaGetSymbolAddress((void**)&t2,  g_t2);
    cudaGetSymbolAddress((void**)&t3,  g_t3);
    cudaGetSymbolAddress((void**)&acc, g_acc);
    cudaGetSymbolAddress((void**)&sa,  g_sa);
    cudaGetSymbolAddress((void**)&sb,  g_sb);
    cudaGetSymbolAddress((void**)&w2ph, g_w2p_hi);
    cudaGetSymbolAddress((void**)&w2pl, g_w2p_lo);

    static int smem_set = 0;
    if (!smem_set) {
        cudaFuncSetAttribute(k_gemm2_mma, cudaFuncAttributeMaxDynamicSharedMemorySize, 49152);
        smem_set = 1;
    }

    const int TB = 256;
    int gN = (N_NODES + TB - 1) / TB;
    int gE = (N_EDGES + TB - 1) / TB;
    int gR = (R + TB - 1) / TB;
    int gW = (N_NODES*32 + TB - 1) / TB;

    /* preprocessing */
    k_init <<<gN, TB>>>();
    k_deg  <<<gE, TB>>>(dst, ew);
    k_scan1<<<NB_SCAN, 256>>>();
    k_scan2<<<1, 256>>>();
    k_scan3<<<gN, TB>>>();
    k_fill <<<gE, TB>>>(src, dst, ew);
    k_w2prep<<<(64*128 + TB - 1)/TB, TB>>>(W2);

    /* layer 1: prop at F=4, fused GEMM+BN+LReLU */
    k_xt<<<gR, TB>>>(x);
    k_prop_small<4,false><<<gN, TB>>>(xt, pa, nullptr);
    k_prop_small<4,false><<<gN, TB>>>(pa, pb, nullptr);
    k_prop_small<4,false><<<gN, TB>>>(pb, pc, nullptr);
    k_gemm1_bn<<<(R + 255)/256, 256>>>(W1, b1, g1, be1, h);

    /* layer 2: 3x prop64, bf16x3 mma GEMM with fused BN -> acc */
    k_prop64<<<gW, TB>>>(h,  t1);
    k_prop64<<<gW, TB>>>(t1, t2);
    k_prop64<<<gW, TB>>>(t2, t3);
    k_gemm2_mma<<<RPAD/128, 256, 49152>>>(h, t1, t2, t3, w2ph, w2pl, b2, g2, be2, acc);

    /* layer 3: one-pass projections, Horner at F=2 */
    k_gemm3_all<<<(R + 255)/256, 256>>>(acc, W3, pb, pa, sb, sa);
    k_prop_small<2,true ><<<gN, TB>>>(sa, pc, sb);
    k_prop_small<2,true ><<<gN, TB>>>(pc, sa, pa);
    k_prop_small<2,false><<<gN, TB>>>(sa, sb, nullptr);

    /* epilogue (+p0 + b3) */
    k_final<<<gR, TB>>>(sb, pb, b3, mask, mean_y, std_y, vmin, vmax, qmin, qmax, out);
}

// round 6
// speedup vs baseline: 2.0561x; 1.2281x over previous
#include <cuda_runtime.h>
#include <cuda_fp16.h>
#include <math.h>
#include <cstdint>

#define N_NODES 50000
#define N_EDGES 400000
#define BATCH 4
#define R (N_NODES*BATCH)      /* 200000 rows (n,b) */
#define RPAD 200064            /* padded to 128-row GEMM tiles */
#define BN_EPS 1e-5f
#define SLOPE 0.01f
#define NB_SCAN ((N_NODES + 255) / 256)   /* 196 */

/* ---------------- static device scratch (no allocations allowed) -------- */
__device__ __align__(16) float g_deg[N_NODES];
__device__ __align__(16) float g_dis[N_NODES];
__device__ __align__(16) int   g_cnt[N_NODES];
__device__ __align__(16) int   g_rowptr[N_NODES+1];
__device__ __align__(16) int   g_cur[N_NODES];
__device__ __align__(16) int   g_col[N_EDGES];
__device__ __align__(16) float g_wcsr[N_EDGES];
__device__ __align__(16) int   g_bsum[256];
__device__ __align__(16) int   g_boff[256];

__device__ __align__(16) float g_xt[RPAD*4];
__device__ __align__(16) float g_pa[RPAD*4];
__device__ __align__(16) float g_pb[RPAD*4];
__device__ __align__(16) float g_pc[RPAD*4];

/* fp16 hidden states: [row][64] halfs = [row][32] u32 */
__device__ __align__(16) uint32_t g_h16 [RPAD*32];
__device__ __align__(16) uint32_t g_t116[RPAD*32];
__device__ __align__(16) uint32_t g_t216[RPAD*32];
__device__ __align__(16) uint32_t g_t316[RPAD*32];

__device__ __align__(16) float g_acc[RPAD*64];

__device__ __align__(16) float g_sa[RPAD*2];
__device__ __align__(16) float g_sb[RPAD*2];

/* W2 transposed [64 n][128 kpair], fp16x2-packed hi/lo */
__device__ __align__(16) uint32_t g_w2p_hi[64*128];
__device__ __align__(16) uint32_t g_w2p_lo[64*128];

#define MMAH(C, a0,a1,a2,a3, b0,b1) \
    asm volatile("mma.sync.aligned.m16n8k16.row.col.f32.f16.f16.f32 " \
        "{%0,%1,%2,%3},{%4,%5,%6,%7},{%8,%9},{%0,%1,%2,%3};" \
        : "+f"((C)[0]),"+f"((C)[1]),"+f"((C)[2]),"+f"((C)[3]) \
        : "r"(a0),"r"(a1),"r"(a2),"r"(a3),"r"(b0),"r"(b1))

__device__ __forceinline__ uint32_t h2u(__half2 h) {
    uint32_t u; memcpy(&u, &h, 4); return u;
}
__device__ __forceinline__ __half2 u2h(uint32_t u) {
    __half2 h; memcpy(&h, &u, 4); return h;
}

/* ---------------- preprocessing --------------------------------------- */
__global__ void k_init() {
    int i = blockIdx.x*blockDim.x + threadIdx.x;
    if (i < N_NODES) { g_deg[i] = 0.f; g_cnt[i] = 0; }
}

__global__ void k_deg(const int* __restrict__ dst, const float* __restrict__ ew) {
    int e = blockIdx.x*blockDim.x + threadIdx.x;
    if (e < N_EDGES) {
        int d = dst[e];
        atomicAdd(&g_deg[d], ew[e]);
        atomicAdd(&g_cnt[d], 1);
    }
}

__global__ void k_scan1() {
    int t = threadIdx.x, b = blockIdx.x;
    int i = b*256 + t;
    int v = (i < N_NODES) ? g_cnt[i] : 0;
    int lane = t & 31, wp = t >> 5;
    int x = v;
    #pragma unroll
    for (int o = 1; o < 32; o <<= 1) {
        int y = __shfl_up_sync(0xffffffffu, x, o);
        if (lane >= o) x += y;
    }
    __shared__ int wt[8];
    if (lane == 31) wt[wp] = x;
    __syncthreads();
    if (wp == 0 && lane < 8) {
        int y = wt[lane];
        #pragma unroll
        for (int o = 1; o < 8; o <<= 1) {
            int z = __shfl_up_sync(0xffu, y, o);
            if (lane >= o) y += z;
        }
        wt[lane] = y;
    }
    __syncthreads();
    int incl = x + (wp ? wt[wp-1] : 0);
    if (i < N_NODES) g_rowptr[i] = incl - v;
    if (t == 255) g_bsum[b] = incl;
}

__global__ void k_scan2() {
    int t = threadIdx.x;
    int v = (t < NB_SCAN) ? g_bsum[t] : 0;
    int lane = t & 31, wp = t >> 5;
    int x = v;
    #pragma unroll
    for (int o = 1; o < 32; o <<= 1) {
        int y = __shfl_up_sync(0xffffffffu, x, o);
        if (lane >= o) x += y;
    }
    __shared__ int wt[8];
    if (lane == 31) wt[wp] = x;
    __syncthreads();
    if (wp == 0 && lane < 8) {
        int y = wt[lane];
        #pragma unroll
        for (int o = 1; o < 8; o <<= 1) {
            int z = __shfl_up_sync(0xffu, y, o);
            if (lane >= o) y += z;
        }
        wt[lane] = y;
    }
    __syncthreads();
    int incl = x + (wp ? wt[wp-1] : 0);
    if (t < NB_SCAN) g_boff[t] = incl - v;
    if (t == 0) g_rowptr[N_NODES] = N_EDGES;
}

__global__ void k_scan3() {
    int i = blockIdx.x*blockDim.x + threadIdx.x;
    if (i < N_NODES) {
        int p = g_rowptr[i] + g_boff[i >> 8];
        g_rowptr[i] = p;
        g_cur[i] = p;
        float d = g_deg[i];
        g_dis[i] = (d > 0.f) ? rsqrtf(fmaxf(d, 1e-30f)) : 0.f;
    }
}

__global__ void k_fill(const int* __restrict__ src, const int* __restrict__ dst,
                       const float* __restrict__ ew) {
    int e = blockIdx.x*blockDim.x + threadIdx.x;
    if (e < N_EDGES) {
        int s = src[e], d = dst[e];
        int p = atomicAdd(&g_cur[d], 1);
        g_col[p]  = s;
        g_wcsr[p] = g_dis[s] * ew[e] * g_dis[d];
    }
}

__global__ void k_xt(const float* __restrict__ x) {
    int t = blockIdx.x*blockDim.x + threadIdx.x;
    if (t >= R) return;
    int b = t / N_NODES, n = t - b*N_NODES;
    float4 v = ((const float4*)x)[t];
    ((float4*)g_xt)[n*4 + b] = v;
}

/* W2 [4][64 k][64 n] -> [64 n][128 kpair] fp16x2 packed hi/lo */
__global__ void k_w2prep(const float* __restrict__ W2) {
    int t = blockIdx.x*blockDim.x + threadIdx.x;
    if (t >= 64*128) return;
    int n = t >> 7, p = t & 127;
    int k0 = 2*p;
    int sel = k0 >> 6, kk = k0 & 63;
    float v0 = W2[sel*4096 + kk*64 + n];
    float v1 = W2[sel*4096 + (kk+1)*64 + n];
    __half h0 = __float2half_rn(v0), h1 = __float2half_rn(v1);
    float l0 = v0 - __half2float(h0), l1 = v1 - __half2float(h1);
    g_w2p_hi[t] = h2u(__halves2half2(h0, h1));
    g_w2p_lo[t] = h2u(__floats2half2_rn(l0, l1));
}

/* ---------------- propagation ------------------------------------------ */
template<int V4, bool ADD>
__global__ void k_prop_small(const float* __restrict__ in, float* __restrict__ out,
                             const float* __restrict__ add) {
    int n = blockIdx.x*blockDim.x + threadIdx.x;
    if (n >= N_NODES) return;
    float4 acc[V4];
    #pragma unroll
    for (int j = 0; j < V4; j++) acc[j] = make_float4(0.f,0.f,0.f,0.f);
    int s = g_rowptr[n], e = g_rowptr[n+1];
    const float4* base = (const float4*)in;
    for (int i = s; i < e; i++) {
        int c = __ldg(&g_col[i]);
        float wv = __ldg(&g_wcsr[i]);
        const float4* p = base + c*V4;
        #pragma unroll
        for (int j = 0; j < V4; j++) {
            float4 v = __ldg(p + j);
            acc[j].x += wv*v.x; acc[j].y += wv*v.y;
            acc[j].z += wv*v.z; acc[j].w += wv*v.w;
        }
    }
    float4* q = (float4*)out + n*V4;
    #pragma unroll
    for (int j = 0; j < V4; j++) {
        float4 o = acc[j];
        if (ADD) {
            float4 a = ((const float4*)add)[n*V4 + j];
            o.x += a.x; o.y += a.y; o.z += a.z; o.w += a.w;
        }
        q[j] = o;
    }
}

/* fp16 payload prop: warp per node, 256 halfs/node (8 per lane) */
__global__ void k_prop64h(const uint32_t* __restrict__ in, uint32_t* __restrict__ out) {
    int gt = blockIdx.x*blockDim.x + threadIdx.x;
    int n = gt >> 5, lane = gt & 31;
    if (n >= N_NODES) return;
    int s = g_rowptr[n], e = g_rowptr[n+1];
    float2 a0 = make_float2(0.f,0.f), a1 = a0, a2 = a0, a3 = a0;
    for (int i = s; i < e; i++) {
        int c = __ldg(&g_col[i]);
        float wv = __ldg(&g_wcsr[i]);
        uint4 v = __ldg((const uint4*)(in + c*128 + lane*4));
        float2 f0 = __half22float2(u2h(v.x));
        float2 f1 = __half22float2(u2h(v.y));
        float2 f2 = __half22float2(u2h(v.z));
        float2 f3 = __half22float2(u2h(v.w));
        a0.x += wv*f0.x; a0.y += wv*f0.y;
        a1.x += wv*f1.x; a1.y += wv*f1.y;
        a2.x += wv*f2.x; a2.y += wv*f2.y;
        a3.x += wv*f3.x; a3.y += wv*f3.y;
    }
    uint4 o;
    o.x = h2u(__floats2half2_rn(a0.x, a0.y));
    o.y = h2u(__floats2half2_rn(a1.x, a1.y));
    o.z = h2u(__floats2half2_rn(a2.x, a2.y));
    o.w = h2u(__floats2half2_rn(a3.x, a3.y));
    *(uint4*)(out + n*128 + lane*4) = o;
}

/* ---------------- layer-1 GEMM + BN + LeakyReLU -> fp16 h --------------- */
__global__ void k_gemm1_bn(const float* __restrict__ W1, const float* __restrict__ b1,
                           const float* __restrict__ g1, const float* __restrict__ be1,
                           uint32_t* __restrict__ hout) {
    __shared__ float sW[1024];
    __shared__ float sB[64];
    int t = threadIdx.x;
    for (int i = t; i < 1024; i += 256) sW[i] = W1[i];
    if (t < 64) sB[t] = b1[t];
    __syncthreads();
    int r = blockIdx.x*256 + t;
    int rr = r < R ? r : R-1;
    float in[16];
    { float4 v;
      v = ((const float4*)g_xt)[rr]; in[0]=v.x; in[1]=v.y; in[2]=v.z; in[3]=v.w;
      v = ((const float4*)g_pa)[rr]; in[4]=v.x; in[5]=v.y; in[6]=v.z; in[7]=v.w;
      v = ((const float4*)g_pb)[rr]; in[8]=v.x; in[9]=v.y; in[10]=v.z; in[11]=v.w;
      v = ((const float4*)g_pc)[rr]; in[12]=v.x; in[13]=v.y; in[14]=v.z; in[15]=v.w; }
    float o[64];
    float s = 0.f, q = 0.f;
    #pragma unroll
    for (int g0 = 0; g0 < 64; g0 += 4) {
        float4 a = make_float4(sB[g0], sB[g0+1], sB[g0+2], sB[g0+3]);
        #pragma unroll
        for (int i = 0; i < 16; i++) {
            float4 w = *(const float4*)&sW[i*64 + g0];
            a.x += in[i]*w.x; a.y += in[i]*w.y; a.z += in[i]*w.z; a.w += in[i]*w.w;
        }
        o[g0]=a.x; o[g0+1]=a.y; o[g0+2]=a.z; o[g0+3]=a.w;
        s += a.x+a.y+a.z+a.w;
        q += a.x*a.x+a.y*a.y+a.z*a.z+a.w*a.w;
    }
    s += __shfl_xor_sync(0xffffffffu, s, 1);
    q += __shfl_xor_sync(0xffffffffu, q, 1);
    s += __shfl_xor_sync(0xffffffffu, s, 2);
    q += __shfl_xor_sync(0xffffffffu, q, 2);
    if (r >= R) return;
    int n = r >> 2;
    float mu  = s * (1.f/256.f);
    float var = q * (1.f/256.f) - mu*mu;
    float sc  = __ldg(&g1[n]) * rsqrtf(var + BN_EPS);
    float bb  = __ldg(&be1[n]);
    #pragma unroll
    for (int g0 = 0; g0 < 64; g0 += 4) {
        float f0 = sc*(o[g0+0]-mu)+bb; f0 = f0 > 0.f ? f0 : SLOPE*f0;
        float f1 = sc*(o[g0+1]-mu)+bb; f1 = f1 > 0.f ? f1 : SLOPE*f1;
        float f2 = sc*(o[g0+2]-mu)+bb; f2 = f2 > 0.f ? f2 : SLOPE*f2;
        float f3 = sc*(o[g0+3]-mu)+bb; f3 = f3 > 0.f ? f3 : SLOPE*f3;
        uint2 pk;
        pk.x = h2u(__floats2half2_rn(f0, f1));
        pk.y = h2u(__floats2half2_rn(f2, f3));
        *(uint2*)&hout[(size_t)r*32 + g0/2] = pk;
    }
}

/* ---------------- layer-2 GEMM: fp16 A + fp16-hi/lo B, m16n8k16 ---------
 * CTA 128x64, K=256 in 8 chunks of 32 (2 K16 steps each). 8 warps 4x2.
 * stage (u32): A[0,2048) BHI[2048,3072) BLO[3072,4096); 2 stages = 32 KB.
 * Epilogue restages C into smem (128x68 f32 = 34816 B).                   */
#define STG_U32 4096
__global__ void __launch_bounds__(256, 2)
k_gemm2_mma(const uint32_t* __restrict__ A0, const uint32_t* __restrict__ A1,
            const uint32_t* __restrict__ A2, const uint32_t* __restrict__ A3,
            const uint32_t* __restrict__ wph, const uint32_t* __restrict__ wpl,
            const float* __restrict__ b2,
            const float* __restrict__ g2, const float* __restrict__ be2,
            float* __restrict__ out) {
    extern __shared__ uint32_t smu[];
    float* smf = (float*)smu;
    const int t = threadIdx.x;
    const int lane = t & 31, wid = t >> 5;
    const int wrow = wid >> 1, wcol = wid & 1;
    const int r0 = blockIdx.x * 128;

    int a_w[4], a_src[4];
    #pragma unroll
    for (int i = 0; i < 4; i++) {
        int idx = i*256 + t;
        int row = idx >> 3, c4 = idx & 7;
        int rr = row & 15, mt = row >> 4;
        int ks = c4 >> 2, regbit = (c4 >> 1) & 1, q0 = (c4 & 1) * 2;
        int g = rr & 7, abit = rr >> 3;
        a_w[i] = (mt*2 + ks)*128 + (g*4 + q0)*4 + abit + 2*regbit;
        a_src[i] = row*32 + c4*2;
    }
    int b_w[2], b_src[2];
    #pragma unroll
    for (int i = 0; i < 2; i++) {
        int idx = i*256 + t;
        int n = idx >> 3, c4 = idx & 7;
        int ks = c4 >> 2, regbit = (c4 >> 1) & 1, q0 = (c4 & 1) * 2;
        int g = n & 7, nt = n >> 3;
        b_w[i] = 2048 + (nt*2 + ks)*64 + (g*4 + q0)*2 + regbit;
        b_src[i] = n*128 + c4*2;
    }

    float c[2][4][4];
    #pragma unroll
    for (int m = 0; m < 2; m++)
        #pragma unroll
        for (int n = 0; n < 4; n++)
            #pragma unroll
            for (int k = 0; k < 4; k++) c[m][n][k] = 0.f;

    uint2 pa[4], pbh[2], pbl[2];

    /* prologue: chunk 0 */
    {
        #pragma unroll
        for (int i = 0; i < 4; i++)
            pa[i] = *(const uint2*)(A0 + (size_t)r0*32 + a_src[i]);
        #pragma unroll
        for (int i = 0; i < 2; i++) {
            pbh[i] = *(const uint2*)(wph + b_src[i]);
            pbl[i] = *(const uint2*)(wpl + b_src[i]);
        }
        uint32_t* base = smu;
        #pragma unroll
        for (int i = 0; i < 4; i++) {
            base[a_w[i]]     = pa[i].x;
            base[a_w[i] + 4] = pa[i].y;
        }
        #pragma unroll
        for (int i = 0; i < 2; i++) {
            base[b_w[i]]            = pbh[i].x;
            base[b_w[i] + 2]        = pbh[i].y;
            base[1024 + b_w[i]]     = pbl[i].x;
            base[1024 + b_w[i] + 2] = pbl[i].y;
        }
    }
    __syncthreads();

    #pragma unroll 1
    for (int cc = 0; cc < 8; cc++) {
        int stage = cc & 1;
        if (cc < 7) {
            int cn = cc + 1;
            const uint32_t* Ap = (cn < 2) ? A0 : (cn < 4) ? A1 : (cn < 6) ? A2 : A3;
            int kb = (cn & 1) * 16;
            #pragma unroll
            for (int i = 0; i < 4; i++)
                pa[i] = *(const uint2*)(Ap + (size_t)r0*32 + a_src[i] + kb);
            #pragma unroll
            for (int i = 0; i < 2; i++) {
                pbh[i] = *(const uint2*)(wph + b_src[i] + cn*16);
                pbl[i] = *(const uint2*)(wpl + b_src[i] + cn*16);
            }
        }
        {
            const uint32_t* base = smu + stage*STG_U32;
            #pragma unroll
            for (int ks = 0; ks < 2; ks++) {
                uint4 ah[2];
                #pragma unroll
                for (int mt = 0; mt < 2; mt++) {
                    int mtile = wrow*2 + mt;
                    ah[mt] = *(const uint4*)(base + (mtile*2+ks)*128 + lane*4);
                }
                uint2 bh[4], bl[4];
                #pragma unroll
                for (int nt = 0; nt < 4; nt++) {
                    int ntile = wcol*4 + nt;
                    bh[nt] = *(const uint2*)(base + 2048 + (ntile*2+ks)*64 + lane*2);
                    bl[nt] = *(const uint2*)(base + 3072 + (ntile*2+ks)*64 + lane*2);
                }
                #pragma unroll
                for (int mt = 0; mt < 2; mt++)
                    #pragma unroll
                    for (int nt = 0; nt < 4; nt++) {
                        MMAH(c[mt][nt], ah[mt].x, ah[mt].y, ah[mt].z, ah[mt].w,
                             bh[nt].x, bh[nt].y);
                        MMAH(c[mt][nt], ah[mt].x, ah[mt].y, ah[mt].z, ah[mt].w,
                             bl[nt].x, bl[nt].y);
                    }
            }
        }
        if (cc < 7) {
            uint32_t* base = smu + ((cc+1)&1)*STG_U32;
            #pragma unroll
            for (int i = 0; i < 4; i++) {
                base[a_w[i]]     = pa[i].x;
                base[a_w[i] + 4] = pa[i].y;
            }
            #pragma unroll
            for (int i = 0; i < 2; i++) {
                base[b_w[i]]            = pbh[i].x;
                base[b_w[i] + 2]        = pbh[i].y;
                base[1024 + b_w[i]]     = pbl[i].x;
                base[1024 + b_w[i] + 2] = pbl[i].y;
            }
        }
        __syncthreads();
    }

    /* ---- fused BN2 + LeakyReLU epilogue ---- */
    {
        float* so = smf;
        const int g = lane >> 2, q = lane & 3;
        #pragma unroll
        for (int mt = 0; mt < 2; mt++) {
            int lr = wrow*32 + mt*16 + g;
            #pragma unroll
            for (int nt = 0; nt < 4; nt++) {
                int col = wcol*32 + nt*8 + 2*q;
                float bx = __ldg(&b2[col]), by = __ldg(&b2[col+1]);
                so[lr*68+col]       = c[mt][nt][0] + bx;
                so[lr*68+col+1]     = c[mt][nt][1] + by;
                so[(lr+8)*68+col]   = c[mt][nt][2] + bx;
                so[(lr+8)*68+col+1] = c[mt][nt][3] + by;
            }
        }
    }
    __syncthreads();
    {
        const float* so = smf;
        int sub = lane >> 3, c8 = (lane & 7) * 8;
        #pragma unroll
        for (int nn = 0; nn < 4; nn++) {
            int node = wid*4 + nn;
            int gnode = blockIdx.x*32 + node;
            const float* rp = so + (node*4 + sub)*68 + c8;
            float4 v0 = *(const float4*)rp;
            float4 v1 = *(const float4*)(rp + 4);
            float s = v0.x+v0.y+v0.z+v0.w + v1.x+v1.y+v1.z+v1.w;
            float q = v0.x*v0.x+v0.y*v0.y+v0.z*v0.z+v0.w*v0.w
                    + v1.x*v1.x+v1.y*v1.y+v1.z*v1.z+v1.w*v1.w;
            #pragma unroll
            for (int o = 16; o; o >>= 1) {
                s += __shfl_xor_sync(0xffffffffu, s, o);
                q += __shfl_xor_sync(0xffffffffu, q, o);
            }
            if (gnode < N_NODES) {
                float mu  = s * (1.f/256.f);
                float var = q * (1.f/256.f) - mu*mu;
                float sc  = __ldg(&g2[gnode]) * rsqrtf(var + BN_EPS);
                float bb  = __ldg(&be2[gnode]);
                float4 o0, o1;
                float f;
                f = sc*(v0.x-mu)+bb; o0.x = f > 0.f ? f : SLOPE*f;
                f = sc*(v0.y-mu)+bb; o0.y = f > 0.f ? f : SLOPE*f;
                f = sc*(v0.z-mu)+bb; o0.z = f > 0.f ? f : SLOPE*f;
                f = sc*(v0.w-mu)+bb; o0.w = f > 0.f ? f : SLOPE*f;
                f = sc*(v1.x-mu)+bb; o1.x = f > 0.f ? f : SLOPE*f;
                f = sc*(v1.y-mu)+bb; o1.y = f > 0.f ? f : SLOPE*f;
                f = sc*(v1.z-mu)+bb; o1.z = f > 0.f ? f : SLOPE*f;
                f = sc*(v1.w-mu)+bb; o1.w = f > 0.f ? f : SLOPE*f;
                size_t rw = (size_t)(r0 + node*4 + sub)*64 + c8;
                *(float4*)&out[rw]     = o0;
                *(float4*)&out[rw + 4] = o1;
            }
        }
    }
}

/* ---------------- layer-3: all 4 projections in one pass ---------------- */
__global__ void k_gemm3_all(const float* __restrict__ h,
                            const float* __restrict__ W3,
                            float* __restrict__ p0, float* __restrict__ p1,
                            float* __restrict__ p2, float* __restrict__ p3) {
    __shared__ float sw[512];
    int t = threadIdx.x;
    for (int i = t; i < 512; i += 256) sw[i] = W3[i];
    __syncthreads();
    int r = blockIdx.x*256 + t;
    if (r >= R) return;
    float a[8] = {0,0,0,0,0,0,0,0};
    const float4* hp = (const float4*)(h + (size_t)r*64);
    #pragma unroll
    for (int j = 0; j < 16; j++) {
        float4 v = hp[j];
        #pragma unroll
        for (int k = 0; k < 4; k++) {
            const float* w = &sw[k*128 + j*8];
            a[k*2]   += v.x*w[0] + v.y*w[2] + v.z*w[4] + v.w*w[6];
            a[k*2+1] += v.x*w[1] + v.y*w[3] + v.z*w[5] + v.w*w[7];
        }
    }
    *(float2*)&p0[r*2] = make_float2(a[0], a[1]);
    *(float2*)&p1[r*2] = make_float2(a[2], a[3]);
    *(float2*)&p2[r*2] = make_float2(a[4], a[5]);
    *(float2*)&p3[r*2] = make_float2(a[6], a[7]);
}

/* ---------------- epilogue ---------------------------------------------- */
__global__ void k_final(const float* __restrict__ pre, const float* __restrict__ p0,
                        const float* __restrict__ b3,
                        const float* __restrict__ mask,
                        const float* __restrict__ mean_y, const float* __restrict__ std_y,
                        const float* __restrict__ vmin, const float* __restrict__ vmax,
                        const float* __restrict__ qmin, const float* __restrict__ qmax,
                        float* __restrict__ out) {
    int t = blockIdx.x*blockDim.x + threadIdx.x;
    if (t >= R) return;
    int b = t / N_NODES, n = t - b*N_NODES;
    int rn = n*4 + b;
    float2 v = *(const float2*)&pre[(size_t)rn*2];
    float2 z = *(const float2*)&p0[(size_t)rn*2];
    float u0 = v.x + z.x + __ldg(&b3[0]);
    float u1 = v.y + z.y + __ldg(&b3[1]);
    float s0 = std_y[n*2], s1 = std_y[n*2+1];
    if (isinf(s0)) s0 = 0.f;
    if (isinf(s1)) s1 = 0.f;
    float o0 = (u0*s0 + mean_y[n*2])   * mask[n*2];
    float o1 = (u1*s1 + mean_y[n*2+1]) * mask[n*2+1];
    o0 = fminf(fmaxf(o0, vmin[n]), vmax[n]);
    o1 = fminf(fmaxf(o1, qmin[n]), qmax[n]);
    *(float2*)&out[(size_t)t*2] = make_float2(o0, o1);
}

/* ======================================================================= */
extern "C" void kernel_launch(void* const* d_in, const int* in_sizes, int n_in,
                              void* d_out, int out_size) {
    const float* x      = (const float*)d_in[0];
    const int*   src    = (const int*)  d_in[1];
    const int*   dst    = (const int*)  d_in[2];
    const float* ew     = (const float*)d_in[3];
    const float* W1     = (const float*)d_in[4];
    const float* b1     = (const float*)d_in[5];
    const float* W2     = (const float*)d_in[6];
    const float* b2     = (const float*)d_in[7];
    const float* W3     = (const float*)d_in[8];
    const float* b3     = (const float*)d_in[9];
    const float* g1     = (const float*)d_in[10];
    const float* be1    = (const float*)d_in[11];
    const float* g2     = (const float*)d_in[12];
    const float* be2    = (const float*)d_in[13];
    const float* mask   = (const float*)d_in[14];
    const float* mean_y = (const float*)d_in[15];
    const float* std_y  = (const float*)d_in[16];
    const float* vmin   = (const float*)d_in[17];
    const float* vmax   = (const float*)d_in[18];
    const float* qmin   = (const float*)d_in[19];
    const float* qmax   = (const float*)d_in[20];
    float* out = (float*)d_out;

    float *xt, *pa, *pb, *pc, *acc, *sa, *sb;
    uint32_t *h16, *t116, *t216, *t316, *w2ph, *w2pl;
    cudaGetSymbolAddress((void**)&xt,  g_xt);
    cudaGetSymbolAddress((void**)&pa,  g_pa);
    cudaGetSymbolAddress((void**)&pb,  g_pb);
    cudaGetSymbolAddress((void**)&pc,  g_pc);
    cudaGetSymbolAddress((void**)&acc, g_acc);
    cudaGetSymbolAddress((void**)&sa,  g_sa);
    cudaGetSymbolAddress((void**)&sb,  g_sb);
    cudaGetSymbolAddress((void**)&h16,  g_h16);
    cudaGetSymbolAddress((void**)&t116, g_t116);
    cudaGetSymbolAddress((void**)&t216, g_t216);
    cudaGetSymbolAddress((void**)&t316, g_t316);
    cudaGetSymbolAddress((void**)&w2ph, g_w2p_hi);
    cudaGetSymbolAddress((void**)&w2pl, g_w2p_lo);

    static int smem_set = 0;
    if (!smem_set) {
        cudaFuncSetAttribute(k_gemm2_mma, cudaFuncAttributeMaxDynamicSharedMemorySize, 34816);
        smem_set = 1;
    }

    const int TB = 256;
    int gN = (N_NODES + TB - 1) / TB;
    int gE = (N_EDGES + TB - 1) / TB;
    int gR = (R + TB - 1) / TB;
    int gW = (N_NODES*32 + TB - 1) / TB;

    /* preprocessing */
    k_init <<<gN, TB>>>();
    k_deg  <<<gE, TB>>>(dst, ew);
    k_scan1<<<NB_SCAN, 256>>>();
    k_scan2<<<1, 256>>>();
    k_scan3<<<gN, TB>>>();
    k_fill <<<gE, TB>>>(src, dst, ew);
    k_w2prep<<<(64*128 + TB - 1)/TB, TB>>>(W2);

    /* layer 1: prop at F=4, fused GEMM+BN+LReLU -> fp16 h */
    k_xt<<<gR, TB>>>(x);
    k_prop_small<4,false><<<gN, TB>>>(xt, pa, nullptr);
    k_prop_small<4,false><<<gN, TB>>>(pa, pb, nullptr);
    k_prop_small<4,false><<<gN, TB>>>(pb, pc, nullptr);
    k_gemm1_bn<<<(R + 255)/256, 256>>>(W1, b1, g1, be1, h16);

    /* layer 2: 3x fp16 prop64, fp16 mma GEMM with fused BN -> acc (fp32) */
    k_prop64h<<<gW, TB>>>(h16,  t116);
    k_prop64h<<<gW, TB>>>(t116, t216);
    k_prop64h<<<gW, TB>>>(t216, t316);
    k_gemm2_mma<<<RPAD/128, 256, 34816>>>(h16, t116, t216, t316, w2ph, w2pl,
                                          b2, g2, be2, acc);

    /* layer 3: one-pass projections, Horner at F=2 */
    k_gemm3_all<<<(R + 255)/256, 256>>>(acc, W3, pb, pa, sb, sa);
    k_prop_small<2,true ><<<gN, TB>>>(sa, pc, sb);
    k_prop_small<2,true ><<<gN, TB>>>(pc, sa, pa);
    k_prop_small<2,false><<<gN, TB>>>(sa, sb, nullptr);

    /* epilogue (+p0 + b3) */
    k_final<<<gR, TB>>>(sb, pb, b3, mask, mean_y, std_y, vmin, vmax, qmin, qmax, out);
}

// round 7
// speedup vs baseline: 2.0861x; 1.0146x over previous
#include <cuda_runtime.h>
#include <cuda_fp16.h>
#include <math.h>
#include <cstdint>

#define N_NODES 50000
#define N_EDGES 400000
#define BATCH 4
#define R (N_NODES*BATCH)      /* 200000 rows (n,b) */
#define RPAD 200064            /* padded to 128-row GEMM tiles */
#define BN_EPS 1e-5f
#define SLOPE 0.01f
#define NB_SCAN ((N_NODES + 255) / 256)   /* 196 */

/* ---------------- static device scratch (no allocations allowed) -------- */
__device__ __align__(16) float g_deg[N_NODES];
__device__ __align__(16) float g_dis[N_NODES];
__device__ __align__(16) int   g_cnt[N_NODES];
__device__ __align__(16) int   g_rowptr[N_NODES+1];
__device__ __align__(16) int   g_cur[N_NODES];
__device__ __align__(16) int   g_col[N_EDGES];
__device__ __align__(16) float g_wcsr[N_EDGES];
__device__ __align__(16) int   g_bsum[256];
__device__ __align__(16) int   g_boff[256];

__device__ __align__(16) float g_xt[RPAD*4];
__device__ __align__(16) float g_pa[RPAD*4];
__device__ __align__(16) float g_pb[RPAD*4];
__device__ __align__(16) float g_pc[RPAD*4];

/* fp16 hidden states: [row][64] halfs = [row][32] u32 */
__device__ __align__(16) uint32_t g_h16 [RPAD*32];
__device__ __align__(16) uint32_t g_t116[RPAD*32];
__device__ __align__(16) uint32_t g_t216[RPAD*32];
__device__ __align__(16) uint32_t g_t316[RPAD*32];

__device__ __align__(16) float g_sa[RPAD*2];
__device__ __align__(16) float g_sb[RPAD*2];

/* W2 transposed [64 n][128 kpair], fp16x2-packed hi/lo */
__device__ __align__(16) uint32_t g_w2p_hi[64*128];
__device__ __align__(16) uint32_t g_w2p_lo[64*128];

#define MMAH(C, a0,a1,a2,a3, b0,b1) \
    asm volatile("mma.sync.aligned.m16n8k16.row.col.f32.f16.f16.f32 " \
        "{%0,%1,%2,%3},{%4,%5,%6,%7},{%8,%9},{%0,%1,%2,%3};" \
        : "+f"((C)[0]),"+f"((C)[1]),"+f"((C)[2]),"+f"((C)[3]) \
        : "r"(a0),"r"(a1),"r"(a2),"r"(a3),"r"(b0),"r"(b1))

__device__ __forceinline__ uint32_t h2u(__half2 h) {
    uint32_t u; memcpy(&u, &h, 4); return u;
}
__device__ __forceinline__ __half2 u2h(uint32_t u) {
    __half2 h; memcpy(&h, &u, 4); return h;
}

/* ---------------- preprocessing --------------------------------------- */
__global__ void k_init() {
    int i = blockIdx.x*blockDim.x + threadIdx.x;
    if (i < N_NODES) { g_deg[i] = 0.f; g_cnt[i] = 0; }
}

__global__ void k_deg(const int* __restrict__ dst, const float* __restrict__ ew) {
    int e = blockIdx.x*blockDim.x + threadIdx.x;
    if (e < N_EDGES) {
        int d = dst[e];
        atomicAdd(&g_deg[d], ew[e]);
        atomicAdd(&g_cnt[d], 1);
    }
}

__global__ void k_scan1() {
    int t = threadIdx.x, b = blockIdx.x;
    int i = b*256 + t;
    int v = (i < N_NODES) ? g_cnt[i] : 0;
    int lane = t & 31, wp = t >> 5;
    int x = v;
    #pragma unroll
    for (int o = 1; o < 32; o <<= 1) {
        int y = __shfl_up_sync(0xffffffffu, x, o);
        if (lane >= o) x += y;
    }
    __shared__ int wt[8];
    if (lane == 31) wt[wp] = x;
    __syncthreads();
    if (wp == 0 && lane < 8) {
        int y = wt[lane];
        #pragma unroll
        for (int o = 1; o < 8; o <<= 1) {
            int z = __shfl_up_sync(0xffu, y, o);
            if (lane >= o) y += z;
        }
        wt[lane] = y;
    }
    __syncthreads();
    int incl = x + (wp ? wt[wp-1] : 0);
    if (i < N_NODES) g_rowptr[i] = incl - v;
    if (t == 255) g_bsum[b] = incl;
}

__global__ void k_scan2() {
    int t = threadIdx.x;
    int v = (t < NB_SCAN) ? g_bsum[t] : 0;
    int lane = t & 31, wp = t >> 5;
    int x = v;
    #pragma unroll
    for (int o = 1; o < 32; o <<= 1) {
        int y = __shfl_up_sync(0xffffffffu, x, o);
        if (lane >= o) x += y;
    }
    __shared__ int wt[8];
    if (lane == 31) wt[wp] = x;
    __syncthreads();
    if (wp == 0 && lane < 8) {
        int y = wt[lane];
        #pragma unroll
        for (int o = 1; o < 8; o <<= 1) {
            int z = __shfl_up_sync(0xffu, y, o);
            if (lane >= o) y += z;
        }
        wt[lane] = y;
    }
    __syncthreads();
    int incl = x + (wp ? wt[wp-1] : 0);
    if (t < NB_SCAN) g_boff[t] = incl - v;
    if (t == 0) g_rowptr[N_NODES] = N_EDGES;
}

__global__ void k_scan3() {
    int i = blockIdx.x*blockDim.x + threadIdx.x;
    if (i < N_NODES) {
        int p = g_rowptr[i] + g_boff[i >> 8];
        g_rowptr[i] = p;
        g_cur[i] = p;
        float d = g_deg[i];
        g_dis[i] = (d > 0.f) ? rsqrtf(fmaxf(d, 1e-30f)) : 0.f;
    }
}

__global__ void k_fill(const int* __restrict__ src, const int* __restrict__ dst,
                       const float* __restrict__ ew) {
    int e = blockIdx.x*blockDim.x + threadIdx.x;
    if (e < N_EDGES) {
        int s = src[e], d = dst[e];
        int p = atomicAdd(&g_cur[d], 1);
        g_col[p]  = s;
        g_wcsr[p] = g_dis[s] * ew[e] * g_dis[d];
    }
}

__global__ void k_xt(const float* __restrict__ x) {
    int t = blockIdx.x*blockDim.x + threadIdx.x;
    if (t >= R) return;
    int b = t / N_NODES, n = t - b*N_NODES;
    float4 v = ((const float4*)x)[t];
    ((float4*)g_xt)[n*4 + b] = v;
}

/* W2 [4][64 k][64 n] -> [64 n][128 kpair] fp16x2 packed hi/lo */
__global__ void k_w2prep(const float* __restrict__ W2) {
    int t = blockIdx.x*blockDim.x + threadIdx.x;
    if (t >= 64*128) return;
    int n = t >> 7, p = t & 127;
    int k0 = 2*p;
    int sel = k0 >> 6, kk = k0 & 63;
    float v0 = W2[sel*4096 + kk*64 + n];
    float v1 = W2[sel*4096 + (kk+1)*64 + n];
    __half h0 = __float2half_rn(v0), h1 = __float2half_rn(v1);
    float l0 = v0 - __half2float(h0), l1 = v1 - __half2float(h1);
    g_w2p_hi[t] = h2u(__halves2half2(h0, h1));
    g_w2p_lo[t] = h2u(__floats2half2_rn(l0, l1));
}

/* ---------------- propagation ------------------------------------------ */
template<int V4, bool ADD>
__global__ void k_prop_small(const float* __restrict__ in, float* __restrict__ out,
                             const float* __restrict__ add) {
    int n = blockIdx.x*blockDim.x + threadIdx.x;
    if (n >= N_NODES) return;
    float4 acc[V4];
    #pragma unroll
    for (int j = 0; j < V4; j++) acc[j] = make_float4(0.f,0.f,0.f,0.f);
    int s = g_rowptr[n], e = g_rowptr[n+1];
    const float4* base = (const float4*)in;
    for (int i = s; i < e; i++) {
        int c = __ldg(&g_col[i]);
        float wv = __ldg(&g_wcsr[i]);
        const float4* p = base + c*V4;
        #pragma unroll
        for (int j = 0; j < V4; j++) {
            float4 v = __ldg(p + j);
            acc[j].x += wv*v.x; acc[j].y += wv*v.y;
            acc[j].z += wv*v.z; acc[j].w += wv*v.w;
        }
    }
    float4* q = (float4*)out + n*V4;
    #pragma unroll
    for (int j = 0; j < V4; j++) {
        float4 o = acc[j];
        if (ADD) {
            float4 a = ((const float4*)add)[n*V4 + j];
            o.x += a.x; o.y += a.y; o.z += a.z; o.w += a.w;
        }
        q[j] = o;
    }
}

/* fp16 payload prop: warp per node, 256 halfs/node (8 per lane) */
__global__ void k_prop64h(const uint32_t* __restrict__ in, uint32_t* __restrict__ out) {
    int gt = blockIdx.x*blockDim.x + threadIdx.x;
    int n = gt >> 5, lane = gt & 31;
    if (n >= N_NODES) return;
    int s = g_rowptr[n], e = g_rowptr[n+1];
    float2 a0 = make_float2(0.f,0.f), a1 = a0, a2 = a0, a3 = a0;
    for (int i = s; i < e; i++) {
        int c = __ldg(&g_col[i]);
        float wv = __ldg(&g_wcsr[i]);
        uint4 v = __ldg((const uint4*)(in + c*128 + lane*4));
        float2 f0 = __half22float2(u2h(v.x));
        float2 f1 = __half22float2(u2h(v.y));
        float2 f2 = __half22float2(u2h(v.z));
        float2 f3 = __half22float2(u2h(v.w));
        a0.x += wv*f0.x; a0.y += wv*f0.y;
        a1.x += wv*f1.x; a1.y += wv*f1.y;
        a2.x += wv*f2.x; a2.y += wv*f2.y;
        a3.x += wv*f3.x; a3.y += wv*f3.y;
    }
    uint4 o;
    o.x = h2u(__floats2half2_rn(a0.x, a0.y));
    o.y = h2u(__floats2half2_rn(a1.x, a1.y));
    o.z = h2u(__floats2half2_rn(a2.x, a2.y));
    o.w = h2u(__floats2half2_rn(a3.x, a3.y));
    *(uint4*)(out + n*128 + lane*4) = o;
}

/* ---------------- layer-1 GEMM + BN + LeakyReLU -> fp16 h --------------- */
__global__ void k_gemm1_bn(const float* __restrict__ W1, const float* __restrict__ b1,
                           const float* __restrict__ g1, const float* __restrict__ be1,
                           uint32_t* __restrict__ hout) {
    __shared__ float sW[1024];
    __shared__ float sB[64];
    int t = threadIdx.x;
    for (int i = t; i < 1024; i += 256) sW[i] = W1[i];
    if (t < 64) sB[t] = b1[t];
    __syncthreads();
    int r = blockIdx.x*256 + t;
    int rr = r < R ? r : R-1;
    float in[16];
    { float4 v;
      v = ((const float4*)g_xt)[rr]; in[0]=v.x; in[1]=v.y; in[2]=v.z; in[3]=v.w;
      v = ((const float4*)g_pa)[rr]; in[4]=v.x; in[5]=v.y; in[6]=v.z; in[7]=v.w;
      v = ((const float4*)g_pb)[rr]; in[8]=v.x; in[9]=v.y; in[10]=v.z; in[11]=v.w;
      v = ((const float4*)g_pc)[rr]; in[12]=v.x; in[13]=v.y; in[14]=v.z; in[15]=v.w; }
    float o[64];
    float s = 0.f, q = 0.f;
    #pragma unroll
    for (int g0 = 0; g0 < 64; g0 += 4) {
        float4 a = make_float4(sB[g0], sB[g0+1], sB[g0+2], sB[g0+3]);
        #pragma unroll
        for (int i = 0; i < 16; i++) {
            float4 w = *(const float4*)&sW[i*64 + g0];
            a.x += in[i]*w.x; a.y += in[i]*w.y; a.z += in[i]*w.z; a.w += in[i]*w.w;
        }
        o[g0]=a.x; o[g0+1]=a.y; o[g0+2]=a.z; o[g0+3]=a.w;
        s += a.x+a.y+a.z+a.w;
        q += a.x*a.x+a.y*a.y+a.z*a.z+a.w*a.w;
    }
    s += __shfl_xor_sync(0xffffffffu, s, 1);
    q += __shfl_xor_sync(0xffffffffu, q, 1);
    s += __shfl_xor_sync(0xffffffffu, s, 2);
    q += __shfl_xor_sync(0xffffffffu, q, 2);
    if (r >= R) return;
    int n = r >> 2;
    float mu  = s * (1.f/256.f);
    float var = q * (1.f/256.f) - mu*mu;
    float sc  = __ldg(&g1[n]) * rsqrtf(var + BN_EPS);
    float bb  = __ldg(&be1[n]);
    #pragma unroll
    for (int g0 = 0; g0 < 64; g0 += 4) {
        float f0 = sc*(o[g0+0]-mu)+bb; f0 = f0 > 0.f ? f0 : SLOPE*f0;
        float f1 = sc*(o[g0+1]-mu)+bb; f1 = f1 > 0.f ? f1 : SLOPE*f1;
        float f2 = sc*(o[g0+2]-mu)+bb; f2 = f2 > 0.f ? f2 : SLOPE*f2;
        float f3 = sc*(o[g0+3]-mu)+bb; f3 = f3 > 0.f ? f3 : SLOPE*f3;
        uint2 pk;
        pk.x = h2u(__floats2half2_rn(f0, f1));
        pk.y = h2u(__floats2half2_rn(f2, f3));
        *(uint2*)&hout[(size_t)r*32 + g0/2] = pk;
    }
}

/* ---------------- layer-2 GEMM + fused BN + fused layer-3 projections ---
 * CTA 128x64, K=256 in 8 chunks of 32. stage (u32): A[0,2048) BHI BLO;
 * 2 stages = 32 KB. Epilogue restages C (128x68 f32 = 34816 B overlapping
 * stages) + W3 copy at float offset 8704 (2 KB). Total smem 36864 B.
 * Output: only p0..p3 ([R][2] each) = h @ W3_k after BN+LReLU.            */
#define STG_U32 4096
#define SW3_OFF 8704
__global__ void __launch_bounds__(256, 2)
k_gemm2_mma(const uint32_t* __restrict__ A0, const uint32_t* __restrict__ A1,
            const uint32_t* __restrict__ A2, const uint32_t* __restrict__ A3,
            const uint32_t* __restrict__ wph, const uint32_t* __restrict__ wpl,
            const float* __restrict__ b2,
            const float* __restrict__ g2, const float* __restrict__ be2,
            const float* __restrict__ W3,
            float* __restrict__ p0, float* __restrict__ p1,
            float* __restrict__ p2, float* __restrict__ p3) {
    extern __shared__ uint32_t smu[];
    float* smf = (float*)smu;
    const int t = threadIdx.x;
    const int lane = t & 31, wid = t >> 5;
    const int wrow = wid >> 1, wcol = wid & 1;
    const int r0 = blockIdx.x * 128;

    /* W3 -> smem transposed: sw3t[(k*2+ch)*64 + f] = W3[k*128 + f*2 + ch] */
    #pragma unroll
    for (int i2 = t; i2 < 512; i2 += 256) {
        int kch = i2 >> 6, f = i2 & 63;
        smf[SW3_OFF + i2] = W3[(kch >> 1)*128 + f*2 + (kch & 1)];
    }

    int a_w[4], a_src[4];
    #pragma unroll
    for (int i = 0; i < 4; i++) {
        int idx = i*256 + t;
        int row = idx >> 3, c4 = idx & 7;
        int rr = row & 15, mt = row >> 4;
        int ks = c4 >> 2, regbit = (c4 >> 1) & 1, q0 = (c4 & 1) * 2;
        int g = rr & 7, abit = rr >> 3;
        a_w[i] = (mt*2 + ks)*128 + (g*4 + q0)*4 + abit + 2*regbit;
        a_src[i] = row*32 + c4*2;
    }
    int b_w[2], b_src[2];
    #pragma unroll
    for (int i = 0; i < 2; i++) {
        int idx = i*256 + t;
        int n = idx >> 3, c4 = idx & 7;
        int ks = c4 >> 2, regbit = (c4 >> 1) & 1, q0 = (c4 & 1) * 2;
        int g = n & 7, nt = n >> 3;
        b_w[i] = 2048 + (nt*2 + ks)*64 + (g*4 + q0)*2 + regbit;
        b_src[i] = n*128 + c4*2;
    }

    float c[2][4][4];
    #pragma unroll
    for (int m = 0; m < 2; m++)
        #pragma unroll
        for (int n = 0; n < 4; n++)
            #pragma unroll
            for (int k = 0; k < 4; k++) c[m][n][k] = 0.f;

    uint2 pa[4], pbh[2], pbl[2];

    /* prologue: chunk 0 */
    {
        #pragma unroll
        for (int i = 0; i < 4; i++)
            pa[i] = *(const uint2*)(A0 + (size_t)r0*32 + a_src[i]);
        #pragma unroll
        for (int i = 0; i < 2; i++) {
            pbh[i] = *(const uint2*)(wph + b_src[i]);
            pbl[i] = *(const uint2*)(wpl + b_src[i]);
        }
        uint32_t* base = smu;
        #pragma unroll
        for (int i = 0; i < 4; i++) {
            base[a_w[i]]     = pa[i].x;
            base[a_w[i] + 4] = pa[i].y;
        }
        #pragma unroll
        for (int i = 0; i < 2; i++) {
            base[b_w[i]]            = pbh[i].x;
            base[b_w[i] + 2]        = pbh[i].y;
            base[1024 + b_w[i]]     = pbl[i].x;
            base[1024 + b_w[i] + 2] = pbl[i].y;
        }
    }
    __syncthreads();

    #pragma unroll 1
    for (int cc = 0; cc < 8; cc++) {
        int stage = cc & 1;
        if (cc < 7) {
            int cn = cc + 1;
            const uint32_t* Ap = (cn < 2) ? A0 : (cn < 4) ? A1 : (cn < 6) ? A2 : A3;
            int kb = (cn & 1) * 16;
            #pragma unroll
            for (int i = 0; i < 4; i++)
                pa[i] = *(const uint2*)(Ap + (size_t)r0*32 + a_src[i] + kb);
            #pragma unroll
            for (int i = 0; i < 2; i++) {
                pbh[i] = *(const uint2*)(wph + b_src[i] + cn*16);
                pbl[i] = *(const uint2*)(wpl + b_src[i] + cn*16);
            }
        }
        {
            const uint32_t* base = smu + stage*STG_U32;
            #pragma unroll
            for (int ks = 0; ks < 2; ks++) {
                uint4 ah[2];
                #pragma unroll
                for (int mt = 0; mt < 2; mt++) {
                    int mtile = wrow*2 + mt;
                    ah[mt] = *(const uint4*)(base + (mtile*2+ks)*128 + lane*4);
                }
                uint2 bh[4], bl[4];
                #pragma unroll
                for (int nt = 0; nt < 4; nt++) {
                    int ntile = wcol*4 + nt;
                    bh[nt] = *(const uint2*)(base + 2048 + (ntile*2+ks)*64 + lane*2);
                    bl[nt] = *(const uint2*)(base + 3072 + (ntile*2+ks)*64 + lane*2);
                }
                #pragma unroll
                for (int mt = 0; mt < 2; mt++)
                    #pragma unroll
                    for (int nt = 0; nt < 4; nt++) {
                        MMAH(c[mt][nt], ah[mt].x, ah[mt].y, ah[mt].z, ah[mt].w,
                             bh[nt].x, bh[nt].y);
                        MMAH(c[mt][nt], ah[mt].x, ah[mt].y, ah[mt].z, ah[mt].w,
                             bl[nt].x, bl[nt].y);
                    }
            }
        }
        if (cc < 7) {
            uint32_t* base = smu + ((cc+1)&1)*STG_U32;
            #pragma unroll
            for (int i = 0; i < 4; i++) {
                base[a_w[i]]     = pa[i].x;
                base[a_w[i] + 4] = pa[i].y;
            }
            #pragma unroll
            for (int i = 0; i < 2; i++) {
                base[b_w[i]]            = pbh[i].x;
                base[b_w[i] + 2]        = pbh[i].y;
                base[1024 + b_w[i]]     = pbl[i].x;
                base[1024 + b_w[i] + 2] = pbl[i].y;
            }
        }
        __syncthreads();
    }

    /* ---- fused BN2 + LeakyReLU + W3 projections ---- */
    {
        float* so = smf;
        const int g = lane >> 2, q = lane & 3;
        #pragma unroll
        for (int mt = 0; mt < 2; mt++) {
            int lr = wrow*32 + mt*16 + g;
            #pragma unroll
            for (int nt = 0; nt < 4; nt++) {
                int col = wcol*32 + nt*8 + 2*q;
                float bx = __ldg(&b2[col]), by = __ldg(&b2[col+1]);
                so[lr*68+col]       = c[mt][nt][0] + bx;
                so[lr*68+col+1]     = c[mt][nt][1] + by;
                so[(lr+8)*68+col]   = c[mt][nt][2] + bx;
                so[(lr+8)*68+col+1] = c[mt][nt][3] + by;
            }
        }
    }
    __syncthreads();
    {
        const float* so = smf;
        const float* sw3 = smf + SW3_OFF;
        int sub = lane >> 3, c8 = (lane & 7) * 8;
        #pragma unroll
        for (int nn = 0; nn < 4; nn++) {
            int node = wid*4 + nn;
            int gnode = blockIdx.x*32 + node;
            int gn = gnode < N_NODES ? gnode : N_NODES-1;
            const float* rp = so + (node*4 + sub)*68 + c8;
            float4 v0 = *(const float4*)rp;
            float4 v1 = *(const float4*)(rp + 4);
            float s = v0.x+v0.y+v0.z+v0.w + v1.x+v1.y+v1.z+v1.w;
            float q = v0.x*v0.x+v0.y*v0.y+v0.z*v0.z+v0.w*v0.w
                    + v1.x*v1.x+v1.y*v1.y+v1.z*v1.z+v1.w*v1.w;
            #pragma unroll
            for (int o = 16; o; o >>= 1) {
                s += __shfl_xor_sync(0xffffffffu, s, o);
                q += __shfl_xor_sync(0xffffffffu, q, o);
            }
            float mu  = s * (1.f/256.f);
            float var = q * (1.f/256.f) - mu*mu;
            float sc  = __ldg(&g2[gn]) * rsqrtf(var + BN_EPS);
            float bb  = __ldg(&be2[gn]);
            float o0, o1, o2, o3, o4, o5, o6, o7, f;
            f = sc*(v0.x-mu)+bb; o0 = f > 0.f ? f : SLOPE*f;
            f = sc*(v0.y-mu)+bb; o1 = f > 0.f ? f : SLOPE*f;
            f = sc*(v0.z-mu)+bb; o2 = f > 0.f ? f : SLOPE*f;
            f = sc*(v0.w-mu)+bb; o3 = f > 0.f ? f : SLOPE*f;
            f = sc*(v1.x-mu)+bb; o4 = f > 0.f ? f : SLOPE*f;
            f = sc*(v1.y-mu)+bb; o5 = f > 0.f ? f : SLOPE*f;
            f = sc*(v1.z-mu)+bb; o6 = f > 0.f ? f : SLOPE*f;
            f = sc*(v1.w-mu)+bb; o7 = f > 0.f ? f : SLOPE*f;
            /* per-thread partial projections over its 8 cols */
            float pr[8];
            #pragma unroll
            for (int kch = 0; kch < 8; kch++) {
                const float* w = sw3 + kch*64 + c8;
                float4 w0 = *(const float4*)w;
                float4 w1 = *(const float4*)(w + 4);
                pr[kch] = o0*w0.x + o1*w0.y + o2*w0.z + o3*w0.w
                        + o4*w1.x + o5*w1.y + o6*w1.z + o7*w1.w;
            }
            /* reduce over the 8 lanes of this row */
            #pragma unroll
            for (int m = 1; m <= 4; m <<= 1) {
                #pragma unroll
                for (int kch = 0; kch < 8; kch++)
                    pr[kch] += __shfl_xor_sync(0xffffffffu, pr[kch], m);
            }
            if ((lane & 7) == 0 && gnode < N_NODES) {
                size_t grow = (size_t)(r0 + node*4 + sub)*2;
                *(float2*)&p0[grow] = make_float2(pr[0], pr[1]);
                *(float2*)&p1[grow] = make_float2(pr[2], pr[3]);
                *(float2*)&p2[grow] = make_float2(pr[4], pr[5]);
                *(float2*)&p3[grow] = make_float2(pr[6], pr[7]);
            }
        }
    }
}

/* ---------------- epilogue ---------------------------------------------- */
__global__ void k_final(const float* __restrict__ pre, const float* __restrict__ p0,
                        const float* __restrict__ b3,
                        const float* __restrict__ mask,
                        const float* __restrict__ mean_y, const float* __restrict__ std_y,
                        const float* __restrict__ vmin, const float* __restrict__ vmax,
                        const float* __restrict__ qmin, const float* __restrict__ qmax,
                        float* __restrict__ out) {
    int t = blockIdx.x*blockDim.x + threadIdx.x;
    if (t >= R) return;
    int b = t / N_NODES, n = t - b*N_NODES;
    int rn = n*4 + b;
    float2 v = *(const float2*)&pre[(size_t)rn*2];
    float2 z = *(const float2*)&p0[(size_t)rn*2];
    float u0 = v.x + z.x + __ldg(&b3[0]);
    float u1 = v.y + z.y + __ldg(&b3[1]);
    float s0 = std_y[n*2], s1 = std_y[n*2+1];
    if (isinf(s0)) s0 = 0.f;
    if (isinf(s1)) s1 = 0.f;
    float o0 = (u0*s0 + mean_y[n*2])   * mask[n*2];
    float o1 = (u1*s1 + mean_y[n*2+1]) * mask[n*2+1];
    o0 = fminf(fmaxf(o0, vmin[n]), vmax[n]);
    o1 = fminf(fmaxf(o1, qmin[n]), qmax[n]);
    *(float2*)&out[(size_t)t*2] = make_float2(o0, o1);
}

/* ======================================================================= */
extern "C" void kernel_launch(void* const* d_in, const int* in_sizes, int n_in,
                              void* d_out, int out_size) {
    const float* x      = (const float*)d_in[0];
    const int*   src    = (const int*)  d_in[1];
    const int*   dst    = (const int*)  d_in[2];
    const float* ew     = (const float*)d_in[3];
    const float* W1     = (const float*)d_in[4];
    const float* b1     = (const float*)d_in[5];
    const float* W2     = (const float*)d_in[6];
    const float* b2     = (const float*)d_in[7];
    const float* W3     = (const float*)d_in[8];
    const float* b3     = (const float*)d_in[9];
    const float* g1     = (const float*)d_in[10];
    const float* be1    = (const float*)d_in[11];
    const float* g2     = (const float*)d_in[12];
    const float* be2    = (const float*)d_in[13];
    const float* mask   = (const float*)d_in[14];
    const float* mean_y = (const float*)d_in[15];
    const float* std_y  = (const float*)d_in[16];
    const float* vmin   = (const float*)d_in[17];
    const float* vmax   = (const float*)d_in[18];
    const float* qmin   = (const float*)d_in[19];
    const float* qmax   = (const float*)d_in[20];
    float* out = (float*)d_out;

    float *xt, *pa, *pb, *pc, *sa, *sb;
    uint32_t *h16, *t116, *t216, *t316, *w2ph, *w2pl;
    cudaGetSymbolAddress((void**)&xt,  g_xt);
    cudaGetSymbolAddress((void**)&pa,  g_pa);
    cudaGetSymbolAddress((void**)&pb,  g_pb);
    cudaGetSymbolAddress((void**)&pc,  g_pc);
    cudaGetSymbolAddress((void**)&sa,  g_sa);
    cudaGetSymbolAddress((void**)&sb,  g_sb);
    cudaGetSymbolAddress((void**)&h16,  g_h16);
    cudaGetSymbolAddress((void**)&t116, g_t116);
    cudaGetSymbolAddress((void**)&t216, g_t216);
    cudaGetSymbolAddress((void**)&t316, g_t316);
    cudaGetSymbolAddress((void**)&w2ph, g_w2p_hi);
    cudaGetSymbolAddress((void**)&w2pl, g_w2p_lo);

    static int smem_set = 0;
    if (!smem_set) {
        cudaFuncSetAttribute(k_gemm2_mma, cudaFuncAttributeMaxDynamicSharedMemorySize, 36864);
        smem_set = 1;
    }

    const int TB = 256;
    int gN = (N_NODES + TB - 1) / TB;
    int gE = (N_EDGES + TB - 1) / TB;
    int gR = (R + TB - 1) / TB;
    int gW = (N_NODES*32 + TB - 1) / TB;

    /* preprocessing */
    k_init <<<gN, TB>>>();
    k_deg  <<<gE, TB>>>(dst, ew);
    k_scan1<<<NB_SCAN, 256>>>();
    k_scan2<<<1, 256>>>();
    k_scan3<<<gN, TB>>>();
    k_fill <<<gE, TB>>>(src, dst, ew);
    k_w2prep<<<(64*128 + TB - 1)/TB, TB>>>(W2);

    /* layer 1: prop at F=4, fused GEMM+BN+LReLU -> fp16 h */
    k_xt<<<gR, TB>>>(x);
    k_prop_small<4,false><<<gN, TB>>>(xt, pa, nullptr);
    k_prop_small<4,false><<<gN, TB>>>(pa, pb, nullptr);
    k_prop_small<4,false><<<gN, TB>>>(pb, pc, nullptr);
    k_gemm1_bn<<<(R + 255)/256, 256>>>(W1, b1, g1, be1, h16);

    /* layer 2: 3x fp16 prop64, fused GEMM+BN+projections -> p0..p3 */
    k_prop64h<<<gW, TB>>>(h16,  t116);
    k_prop64h<<<gW, TB>>>(t116, t216);
    k_prop64h<<<gW, TB>>>(t216, t316);
    k_gemm2_mma<<<RPAD/128, 256, 36864>>>(h16, t116, t216, t316, w2ph, w2pl,
                                          b2, g2, be2, W3, pb, pa, sb, sa);

    /* layer 3: Horner at F=2 (p0->pb, p1->pa, p2->sb, p3->sa) */
    k_prop_small<2,true ><<<gN, TB>>>(sa, pc, sb);
    k_prop_small<2,true ><<<gN, TB>>>(pc, sa, pa);
    k_prop_small<2,false><<<gN, TB>>>(sa, sb, nullptr);

    /* epilogue (+p0 + b3) */
    k_final<<<gR, TB>>>(sb, pb, b3, mask, mean_y, std_y, vmin, vmax, qmin, qmax, out);
}

// round 8
// speedup vs baseline: 2.1175x; 1.0150x over previous
#include <cuda_runtime.h>
#include <cuda_fp16.h>
#include <math.h>
#include <cstdint>

#define N_NODES 50000
#define N_EDGES 400000
#define BATCH 4
#define R (N_NODES*BATCH)      /* 200000 rows (n,b) */
#define RPAD 200064            /* padded to 128-row GEMM tiles */
#define BN_EPS 1e-5f
#define SLOPE 0.01f
#define NB_SCAN ((N_NODES + 255) / 256)   /* 196 */

/* ---------------- static device scratch (no allocations allowed) -------- */
__device__ __align__(16) float g_deg[N_NODES];
__device__ __align__(16) float g_dis[N_NODES];
__device__ __align__(16) int   g_cnt[N_NODES];
__device__ __align__(16) int   g_rowptr[N_NODES+1];
__device__ __align__(16) int   g_cur[N_NODES];
__device__ __align__(16) int   g_col[N_EDGES];
__device__ __align__(16) float g_wcsr[N_EDGES];
__device__ __align__(16) int   g_bsum[256];

__device__ __align__(16) float g_xt[RPAD*4];
__device__ __align__(16) float g_pa[RPAD*4];
__device__ __align__(16) float g_pb[RPAD*4];
__device__ __align__(16) float g_pc[RPAD*4];

/* fp16 hidden states: [row][64] halfs = [row][32] u32 */
__device__ __align__(16) uint32_t g_h16 [RPAD*32];
__device__ __align__(16) uint32_t g_t116[RPAD*32];
__device__ __align__(16) uint32_t g_t216[RPAD*32];
__device__ __align__(16) uint32_t g_t316[RPAD*32];

__device__ __align__(16) float g_sa[RPAD*2];
__device__ __align__(16) float g_sb[RPAD*2];

/* W2 transposed [64 n][128 kpair], fp16x2-packed hi/lo */
__device__ __align__(16) uint32_t g_w2p_hi[64*128];
__device__ __align__(16) uint32_t g_w2p_lo[64*128];

#define MMAH(C, a0,a1,a2,a3, b0,b1) \
    asm volatile("mma.sync.aligned.m16n8k16.row.col.f32.f16.f16.f32 " \
        "{%0,%1,%2,%3},{%4,%5,%6,%7},{%8,%9},{%0,%1,%2,%3};" \
        : "+f"((C)[0]),"+f"((C)[1]),"+f"((C)[2]),"+f"((C)[3]) \
        : "r"(a0),"r"(a1),"r"(a2),"r"(a3),"r"(b0),"r"(b1))

__device__ __forceinline__ uint32_t h2u(__half2 h) {
    uint32_t u; memcpy(&u, &h, 4); return u;
}
__device__ __forceinline__ __half2 u2h(uint32_t u) {
    __half2 h; memcpy(&h, &u, 4); return h;
}

/* ---------------- preprocessing --------------------------------------- */
/* fused: zero deg/cnt + transpose x to node-major */
__global__ void k_init_xt(const float* __restrict__ x) {
    int t = blockIdx.x*blockDim.x + threadIdx.x;
    if (t < N_NODES) { g_deg[t] = 0.f; g_cnt[t] = 0; }
    if (t < R) {
        int b = t / N_NODES, n = t - b*N_NODES;
        float4 v = ((const float4*)x)[t];
        ((float4*)g_xt)[n*4 + b] = v;
    }
}

/* fused: degree atomics + W2 split/pack prep (independent work) */
__global__ void k_deg_w2(const int* __restrict__ dst, const float* __restrict__ ew,
                         const float* __restrict__ W2) {
    int e = blockIdx.x*blockDim.x + threadIdx.x;
    if (e < N_EDGES) {
        int d = dst[e];
        atomicAdd(&g_deg[d], ew[e]);
        atomicAdd(&g_cnt[d], 1);
    }
    if (e < 64*128) {
        int n = e >> 7, p = e & 127;
        int k0 = 2*p;
        int sel = k0 >> 6, kk = k0 & 63;
        float v0 = W2[sel*4096 + kk*64 + n];
        float v1 = W2[sel*4096 + (kk+1)*64 + n];
        __half h0 = __float2half_rn(v0), h1 = __float2half_rn(v1);
        float l0 = v0 - __half2float(h0), l1 = v1 - __half2float(h1);
        g_w2p_hi[e] = h2u(__halves2half2(h0, h1));
        g_w2p_lo[e] = h2u(__floats2half2_rn(l0, l1));
    }
}

__global__ void k_scan1() {
    int t = threadIdx.x, b = blockIdx.x;
    int i = b*256 + t;
    int v = (i < N_NODES) ? g_cnt[i] : 0;
    int lane = t & 31, wp = t >> 5;
    int x = v;
    #pragma unroll
    for (int o = 1; o < 32; o <<= 1) {
        int y = __shfl_up_sync(0xffffffffu, x, o);
        if (lane >= o) x += y;
    }
    __shared__ int wt[8];
    if (lane == 31) wt[wp] = x;
    __syncthreads();
    if (wp == 0 && lane < 8) {
        int y = wt[lane];
        #pragma unroll
        for (int o = 1; o < 8; o <<= 1) {
            int z = __shfl_up_sync(0xffu, y, o);
            if (lane >= o) y += z;
        }
        wt[lane] = y;
    }
    __syncthreads();
    int incl = x + (wp ? wt[wp-1] : 0);
    if (i < N_NODES) g_rowptr[i] = incl - v;
    if (t == 255) g_bsum[b] = incl;
}

/* fused scan2+scan3: every block scans the 196 block sums locally, takes
 * its own offset, applies it; also computes dis. */
__global__ void k_scan23() {
    int t = threadIdx.x, b = blockIdx.x;
    int v = (t < NB_SCAN) ? g_bsum[t] : 0;
    int lane = t & 31, wp = t >> 5;
    int x = v;
    #pragma unroll
    for (int o = 1; o < 32; o <<= 1) {
        int y = __shfl_up_sync(0xffffffffu, x, o);
        if (lane >= o) x += y;
    }
    __shared__ int wt[8];
    __shared__ int s_off;
    if (lane == 31) wt[wp] = x;
    __syncthreads();
    if (wp == 0 && lane < 8) {
        int y = wt[lane];
        #pragma unroll
        for (int o = 1; o < 8; o <<= 1) {
            int z = __shfl_up_sync(0xffu, y, o);
            if (lane >= o) y += z;
        }
        wt[lane] = y;
    }
    __syncthreads();
    int incl = x + (wp ? wt[wp-1] : 0);
    if (t == b) s_off = incl - v;         /* exclusive prefix for this block */
    __syncthreads();
    int i = b*256 + t;
    if (i < N_NODES) {
        int p = g_rowptr[i] + s_off;
        g_rowptr[i] = p;
        g_cur[i] = p;
        float d = g_deg[i];
        g_dis[i] = (d > 0.f) ? rsqrtf(fmaxf(d, 1e-30f)) : 0.f;
    }
    if (b == NB_SCAN-1 && t == 0) g_rowptr[N_NODES] = N_EDGES;
}

__global__ void k_fill(const int* __restrict__ src, const int* __restrict__ dst,
                       const float* __restrict__ ew) {
    int e = blockIdx.x*blockDim.x + threadIdx.x;
    if (e < N_EDGES) {
        int s = src[e], d = dst[e];
        int p = atomicAdd(&g_cur[d], 1);
        g_col[p]  = s;
        g_wcsr[p] = g_dis[s] * ew[e] * g_dis[d];
    }
}

/* ---------------- propagation ------------------------------------------ */
template<int V4, bool ADD>
__global__ void k_prop_small(const float* __restrict__ in, float* __restrict__ out,
                             const float* __restrict__ add) {
    int n = blockIdx.x*blockDim.x + threadIdx.x;
    if (n >= N_NODES) return;
    float4 acc[V4];
    #pragma unroll
    for (int j = 0; j < V4; j++) acc[j] = make_float4(0.f,0.f,0.f,0.f);
    int s = g_rowptr[n], e = g_rowptr[n+1];
    const float4* base = (const float4*)in;
    for (int i = s; i < e; i++) {
        int c = __ldg(&g_col[i]);
        float wv = __ldg(&g_wcsr[i]);
        const float4* p = base + c*V4;
        #pragma unroll
        for (int j = 0; j < V4; j++) {
            float4 v = __ldg(p + j);
            acc[j].x += wv*v.x; acc[j].y += wv*v.y;
            acc[j].z += wv*v.z; acc[j].w += wv*v.w;
        }
    }
    float4* q = (float4*)out + n*V4;
    #pragma unroll
    for (int j = 0; j < V4; j++) {
        float4 o = acc[j];
        if (ADD) {
            float4 a = ((const float4*)add)[n*V4 + j];
            o.x += a.x; o.y += a.y; o.z += a.z; o.w += a.w;
        }
        q[j] = o;
    }
}

/* final Horner prop fused with output epilogue:
 * u[n] = (A in)[n] + p0[n] + b3; denorm/mask/clamp; write out [B,N,2] */
__global__ void k_prop2_final(const float* __restrict__ in,
                              const float* __restrict__ p0,
                              const float* __restrict__ b3,
                              const float* __restrict__ mask,
                              const float* __restrict__ mean_y,
                              const float* __restrict__ std_y,
                              const float* __restrict__ vmin, const float* __restrict__ vmax,
                              const float* __restrict__ qmin, const float* __restrict__ qmax,
                              float* __restrict__ out) {
    int n = blockIdx.x*blockDim.x + threadIdx.x;
    if (n >= N_NODES) return;
    float4 a0 = make_float4(0.f,0.f,0.f,0.f), a1 = a0;
    int s = g_rowptr[n], e = g_rowptr[n+1];
    const float4* base = (const float4*)in;
    for (int i = s; i < e; i++) {
        int c = __ldg(&g_col[i]);
        float wv = __ldg(&g_wcsr[i]);
        float4 v0 = __ldg(base + c*2);
        float4 v1 = __ldg(base + c*2 + 1);
        a0.x += wv*v0.x; a0.y += wv*v0.y; a0.z += wv*v0.z; a0.w += wv*v0.w;
        a1.x += wv*v1.x; a1.y += wv*v1.y; a1.z += wv*v1.z; a1.w += wv*v1.w;
    }
    float4 z0 = ((const float4*)p0)[n*2];
    float4 z1 = ((const float4*)p0)[n*2 + 1];
    float b30 = __ldg(&b3[0]), b31 = __ldg(&b3[1]);
    /* u[b][ch]: b0=(a0.x,a0.y) b1=(a0.z,a0.w) b2=(a1.x,a1.y) b3=(a1.z,a1.w) */
    float u[4][2] = {
        {a0.x + z0.x + b30, a0.y + z0.y + b31},
        {a0.z + z0.z + b30, a0.w + z0.w + b31},
        {a1.x + z1.x + b30, a1.y + z1.y + b31},
        {a1.z + z1.z + b30, a1.w + z1.w + b31}
    };
    float s0 = std_y[n*2], s1 = std_y[n*2+1];
    if (isinf(s0)) s0 = 0.f;
    if (isinf(s1)) s1 = 0.f;
    float m0 = mask[n*2], m1 = mask[n*2+1];
    float me0 = mean_y[n*2], me1 = mean_y[n*2+1];
    float vlo = vmin[n], vhi = vmax[n];
    float qlo = qmin[n], qhi = qmax[n];
    #pragma unroll
    for (int b = 0; b < 4; b++) {
        float o0 = (u[b][0]*s0 + me0) * m0;
        float o1 = (u[b][1]*s1 + me1) * m1;
        o0 = fminf(fmaxf(o0, vlo), vhi);
        o1 = fminf(fmaxf(o1, qlo), qhi);
        *(float2*)&out[(size_t)(b*N_NODES + n)*2] = make_float2(o0, o1);
    }
}

/* fp16 payload prop: warp per node, 256 halfs/node (8 per lane) */
__global__ void k_prop64h(const uint32_t* __restrict__ in, uint32_t* __restrict__ out) {
    int gt = blockIdx.x*blockDim.x + threadIdx.x;
    int n = gt >> 5, lane = gt & 31;
    if (n >= N_NODES) return;
    int s = g_rowptr[n], e = g_rowptr[n+1];
    float2 a0 = make_float2(0.f,0.f), a1 = a0, a2 = a0, a3 = a0;
    for (int i = s; i < e; i++) {
        int c = __ldg(&g_col[i]);
        float wv = __ldg(&g_wcsr[i]);
        uint4 v = __ldg((const uint4*)(in + c*128 + lane*4));
        float2 f0 = __half22float2(u2h(v.x));
        float2 f1 = __half22float2(u2h(v.y));
        float2 f2 = __half22float2(u2h(v.z));
        float2 f3 = __half22float2(u2h(v.w));
        a0.x += wv*f0.x; a0.y += wv*f0.y;
        a1.x += wv*f1.x; a1.y += wv*f1.y;
        a2.x += wv*f2.x; a2.y += wv*f2.y;
        a3.x += wv*f3.x; a3.y += wv*f3.y;
    }
    uint4 o;
    o.x = h2u(__floats2half2_rn(a0.x, a0.y));
    o.y = h2u(__floats2half2_rn(a1.x, a1.y));
    o.z = h2u(__floats2half2_rn(a2.x, a2.y));
    o.w = h2u(__floats2half2_rn(a3.x, a3.y));
    *(uint4*)(out + n*128 + lane*4) = o;
}

/* ---------------- layer-1 GEMM + BN + LeakyReLU -> fp16 h --------------- */
__global__ void k_gemm1_bn(const float* __restrict__ W1, const float* __restrict__ b1,
                           const float* __restrict__ g1, const float* __restrict__ be1,
                           uint32_t* __restrict__ hout) {
    __shared__ float sW[1024];
    __shared__ float sB[64];
    int t = threadIdx.x;
    for (int i = t; i < 1024; i += 256) sW[i] = W1[i];
    if (t < 64) sB[t] = b1[t];
    __syncthreads();
    int r = blockIdx.x*256 + t;
    int rr = r < R ? r : R-1;
    float in[16];
    { float4 v;
      v = ((const float4*)g_xt)[rr]; in[0]=v.x; in[1]=v.y; in[2]=v.z; in[3]=v.w;
      v = ((const float4*)g_pa)[rr]; in[4]=v.x; in[5]=v.y; in[6]=v.z; in[7]=v.w;
      v = ((const float4*)g_pb)[rr]; in[8]=v.x; in[9]=v.y; in[10]=v.z; in[11]=v.w;
      v = ((const float4*)g_pc)[rr]; in[12]=v.x; in[13]=v.y; in[14]=v.z; in[15]=v.w; }
    float o[64];
    float s = 0.f, q = 0.f;
    #pragma unroll
    for (int g0 = 0; g0 < 64; g0 += 4) {
        float4 a = make_float4(sB[g0], sB[g0+1], sB[g0+2], sB[g0+3]);
        #pragma unroll
        for (int i = 0; i < 16; i++) {
            float4 w = *(const float4*)&sW[i*64 + g0];
            a.x += in[i]*w.x; a.y += in[i]*w.y; a.z += in[i]*w.z; a.w += in[i]*w.w;
        }
        o[g0]=a.x; o[g0+1]=a.y; o[g0+2]=a.z; o[g0+3]=a.w;
        s += a.x+a.y+a.z+a.w;
        q += a.x*a.x+a.y*a.y+a.z*a.z+a.w*a.w;
    }
    s += __shfl_xor_sync(0xffffffffu, s, 1);
    q += __shfl_xor_sync(0xffffffffu, q, 1);
    s += __shfl_xor_sync(0xffffffffu, s, 2);
    q += __shfl_xor_sync(0xffffffffu, q, 2);
    if (r >= R) return;
    int n = r >> 2;
    float mu  = s * (1.f/256.f);
    float var = q * (1.f/256.f) - mu*mu;
    float sc  = __ldg(&g1[n]) * rsqrtf(var + BN_EPS);
    float bb  = __ldg(&be1[n]);
    #pragma unroll
    for (int g0 = 0; g0 < 64; g0 += 4) {
        float f0 = sc*(o[g0+0]-mu)+bb; f0 = f0 > 0.f ? f0 : SLOPE*f0;
        float f1 = sc*(o[g0+1]-mu)+bb; f1 = f1 > 0.f ? f1 : SLOPE*f1;
        float f2 = sc*(o[g0+2]-mu)+bb; f2 = f2 > 0.f ? f2 : SLOPE*f2;
        float f3 = sc*(o[g0+3]-mu)+bb; f3 = f3 > 0.f ? f3 : SLOPE*f3;
        uint2 pk;
        pk.x = h2u(__floats2half2_rn(f0, f1));
        pk.y = h2u(__floats2half2_rn(f2, f3));
        *(uint2*)&hout[(size_t)r*32 + g0/2] = pk;
    }
}

/* ---------------- layer-2 GEMM + fused BN + fused layer-3 projections --- */
#define STG_U32 4096
#define SW3_OFF 8704
__global__ void __launch_bounds__(256, 2)
k_gemm2_mma(const uint32_t* __restrict__ A0, const uint32_t* __restrict__ A1,
            const uint32_t* __restrict__ A2, const uint32_t* __restrict__ A3,
            const uint32_t* __restrict__ wph, const uint32_t* __restrict__ wpl,
            const float* __restrict__ b2,
            const float* __restrict__ g2, const float* __restrict__ be2,
            const float* __restrict__ W3,
            float* __restrict__ p0, float* __restrict__ p1,
            float* __restrict__ p2, float* __restrict__ p3) {
    extern __shared__ uint32_t smu[];
    float* smf = (float*)smu;
    const int t = threadIdx.x;
    const int lane = t & 31, wid = t >> 5;
    const int wrow = wid >> 1, wcol = wid & 1;
    const int r0 = blockIdx.x * 128;

    #pragma unroll
    for (int i2 = t; i2 < 512; i2 += 256) {
        int kch = i2 >> 6, f = i2 & 63;
        smf[SW3_OFF + i2] = W3[(kch >> 1)*128 + f*2 + (kch & 1)];
    }

    int a_w[4], a_src[4];
    #pragma unroll
    for (int i = 0; i < 4; i++) {
        int idx = i*256 + t;
        int row = idx >> 3, c4 = idx & 7;
        int rr = row & 15, mt = row >> 4;
        int ks = c4 >> 2, regbit = (c4 >> 1) & 1, q0 = (c4 & 1) * 2;
        int g = rr & 7, abit = rr >> 3;
        a_w[i] = (mt*2 + ks)*128 + (g*4 + q0)*4 + abit + 2*regbit;
        a_src[i] = row*32 + c4*2;
    }
    int b_w[2], b_src[2];
    #pragma unroll
    for (int i = 0; i < 2; i++) {
        int idx = i*256 + t;
        int n = idx >> 3, c4 = idx & 7;
        int ks = c4 >> 2, regbit = (c4 >> 1) & 1, q0 = (c4 & 1) * 2;
        int g = n & 7, nt = n >> 3;
        b_w[i] = 2048 + (nt*2 + ks)*64 + (g*4 + q0)*2 + regbit;
        b_src[i] = n*128 + c4*2;
    }

    float c[2][4][4];
    #pragma unroll
    for (int m = 0; m < 2; m++)
        #pragma unroll
        for (int n = 0; n < 4; n++)
            #pragma unroll
            for (int k = 0; k < 4; k++) c[m][n][k] = 0.f;

    uint2 pa[4], pbh[2], pbl[2];

    {
        #pragma unroll
        for (int i = 0; i < 4; i++)
            pa[i] = *(const uint2*)(A0 + (size_t)r0*32 + a_src[i]);
        #pragma unroll
        for (int i = 0; i < 2; i++) {
            pbh[i] = *(const uint2*)(wph + b_src[i]);
            pbl[i] = *(const uint2*)(wpl + b_src[i]);
        }
        uint32_t* base = smu;
        #pragma unroll
        for (int i = 0; i < 4; i++) {
            base[a_w[i]]     = pa[i].x;
            base[a_w[i] + 4] = pa[i].y;
        }
        #pragma unroll
        for (int i = 0; i < 2; i++) {
            base[b_w[i]]            = pbh[i].x;
            base[b_w[i] + 2]        = pbh[i].y;
            base[1024 + b_w[i]]     = pbl[i].x;
            base[1024 + b_w[i] + 2] = pbl[i].y;
        }
    }
    __syncthreads();

    #pragma unroll 1
    for (int cc = 0; cc < 8; cc++) {
        int stage = cc & 1;
        if (cc < 7) {
            int cn = cc + 1;
            const uint32_t* Ap = (cn < 2) ? A0 : (cn < 4) ? A1 : (cn < 6) ? A2 : A3;
            int kb = (cn & 1) * 16;
            #pragma unroll
            for (int i = 0; i < 4; i++)
                pa[i] = *(const uint2*)(Ap + (size_t)r0*32 + a_src[i] + kb);
            #pragma unroll
            for (int i = 0; i < 2; i++) {
                pbh[i] = *(const uint2*)(wph + b_src[i] + cn*16);
                pbl[i] = *(const uint2*)(wpl + b_src[i] + cn*16);
            }
        }
        {
            const uint32_t* base = smu + stage*STG_U32;
            #pragma unroll
            for (int ks = 0; ks < 2; ks++) {
                uint4 ah[2];
                #pragma unroll
                for (int mt = 0; mt < 2; mt++) {
                    int mtile = wrow*2 + mt;
                    ah[mt] = *(const uint4*)(base + (mtile*2+ks)*128 + lane*4);
                }
                uint2 bh[4], bl[4];
                #pragma unroll
                for (int nt = 0; nt < 4; nt++) {
                    int ntile = wcol*4 + nt;
                    bh[nt] = *(const uint2*)(base + 2048 + (ntile*2+ks)*64 + lane*2);
                    bl[nt] = *(const uint2*)(base + 3072 + (ntile*2+ks)*64 + lane*2);
                }
                #pragma unroll
                for (int mt = 0; mt < 2; mt++)
                    #pragma unroll
                    for (int nt = 0; nt < 4; nt++) {
                        MMAH(c[mt][nt], ah[mt].x, ah[mt].y, ah[mt].z, ah[mt].w,
                             bh[nt].x, bh[nt].y);
                        MMAH(c[mt][nt], ah[mt].x, ah[mt].y, ah[mt].z, ah[mt].w,
                             bl[nt].x, bl[nt].y);
                    }
            }
        }
        if (cc < 7) {
            uint32_t* base = smu + ((cc+1)&1)*STG_U32;
            #pragma unroll
            for (int i = 0; i < 4; i++) {
                base[a_w[i]]     = pa[i].x;
                base[a_w[i] + 4] = pa[i].y;
            }
            #pragma unroll
            for (int i = 0; i < 2; i++) {
                base[b_w[i]]            = pbh[i].x;
                base[b_w[i] + 2]        = pbh[i].y;
                base[1024 + b_w[i]]     = pbl[i].x;
                base[1024 + b_w[i] + 2] = pbl[i].y;
            }
        }
        __syncthreads();
    }

    /* ---- fused BN2 + LeakyReLU + W3 projections ---- */
    {
        float* so = smf;
        const int g = lane >> 2, q = lane & 3;
        #pragma unroll
        for (int mt = 0; mt < 2; mt++) {
            int lr = wrow*32 + mt*16 + g;
            #pragma unroll
            for (int nt = 0; nt < 4; nt++) {
                int col = wcol*32 + nt*8 + 2*q;
                float bx = __ldg(&b2[col]), by = __ldg(&b2[col+1]);
                so[lr*68+col]       = c[mt][nt][0] + bx;
                so[lr*68+col+1]     = c[mt][nt][1] + by;
                so[(lr+8)*68+col]   = c[mt][nt][2] + bx;
                so[(lr+8)*68+col+1] = c[mt][nt][3] + by;
            }
        }
    }
    __syncthreads();
    {
        const float* so = smf;
        const float* sw3 = smf + SW3_OFF;
        int sub = lane >> 3, c8 = (lane & 7) * 8;
        #pragma unroll
        for (int nn = 0; nn < 4; nn++) {
            int node = wid*4 + nn;
            int gnode = blockIdx.x*32 + node;
            int gn = gnode < N_NODES ? gnode : N_NODES-1;
            const float* rp = so + (node*4 + sub)*68 + c8;
            float4 v0 = *(const float4*)rp;
            float4 v1 = *(const float4*)(rp + 4);
            float s = v0.x+v0.y+v0.z+v0.w + v1.x+v1.y+v1.z+v1.w;
            float q = v0.x*v0.x+v0.y*v0.y+v0.z*v0.z+v0.w*v0.w
                    + v1.x*v1.x+v1.y*v1.y+v1.z*v1.z+v1.w*v1.w;
            #pragma unroll
            for (int o = 16; o; o >>= 1) {
                s += __shfl_xor_sync(0xffffffffu, s, o);
                q += __shfl_xor_sync(0xffffffffu, q, o);
            }
            float mu  = s * (1.f/256.f);
            float var = q * (1.f/256.f) - mu*mu;
            float sc  = __ldg(&g2[gn]) * rsqrtf(var + BN_EPS);
            float bb  = __ldg(&be2[gn]);
            float o0, o1, o2, o3, o4, o5, o6, o7, f;
            f = sc*(v0.x-mu)+bb; o0 = f > 0.f ? f : SLOPE*f;
            f = sc*(v0.y-mu)+bb; o1 = f > 0.f ? f : SLOPE*f;
            f = sc*(v0.z-mu)+bb; o2 = f > 0.f ? f : SLOPE*f;
            f = sc*(v0.w-mu)+bb; o3 = f > 0.f ? f : SLOPE*f;
            f = sc*(v1.x-mu)+bb; o4 = f > 0.f ? f : SLOPE*f;
            f = sc*(v1.y-mu)+bb; o5 = f > 0.f ? f : SLOPE*f;
            f = sc*(v1.z-mu)+bb; o6 = f > 0.f ? f : SLOPE*f;
            f = sc*(v1.w-mu)+bb; o7 = f > 0.f ? f : SLOPE*f;
            float pr[8];
            #pragma unroll
            for (int kch = 0; kch < 8; kch++) {
                const float* w = sw3 + kch*64 + c8;
                float4 w0 = *(const float4*)w;
                float4 w1 = *(const float4*)(w + 4);
                pr[kch] = o0*w0.x + o1*w0.y + o2*w0.z + o3*w0.w
                        + o4*w1.x + o5*w1.y + o6*w1.z + o7*w1.w;
            }
            #pragma unroll
            for (int m = 1; m <= 4; m <<= 1) {
                #pragma unroll
                for (int kch = 0; kch < 8; kch++)
                    pr[kch] += __shfl_xor_sync(0xffffffffu, pr[kch], m);
            }
            if ((lane & 7) == 0 && gnode < N_NODES) {
                size_t grow = (size_t)(r0 + node*4 + sub)*2;
                *(float2*)&p0[grow] = make_float2(pr[0], pr[1]);
                *(float2*)&p1[grow] = make_float2(pr[2], pr[3]);
                *(float2*)&p2[grow] = make_float2(pr[4], pr[5]);
                *(float2*)&p3[grow] = make_float2(pr[6], pr[7]);
            }
        }
    }
}

/* ======================================================================= */
extern "C" void kernel_launch(void* const* d_in, const int* in_sizes, int n_in,
                              void* d_out, int out_size) {
    const float* x      = (const float*)d_in[0];
    const int*   src    = (const int*)  d_in[1];
    const int*   dst    = (const int*)  d_in[2];
    const float* ew     = (const float*)d_in[3];
    const float* W1     = (const float*)d_in[4];
    const float* b1     = (const float*)d_in[5];
    const float* W2     = (const float*)d_in[6];
    const float* b2     = (const float*)d_in[7];
    const float* W3     = (const float*)d_in[8];
    const float* b3     = (const float*)d_in[9];
    const float* g1     = (const float*)d_in[10];
    const float* be1    = (const float*)d_in[11];
    const float* g2     = (const float*)d_in[12];
    const float* be2    = (const float*)d_in[13];
    const float* mask   = (const float*)d_in[14];
    const float* mean_y = (const float*)d_in[15];
    const float* std_y  = (const float*)d_in[16];
    const float* vmin   = (const float*)d_in[17];
    const float* vmax   = (const float*)d_in[18];
    const float* qmin   = (const float*)d_in[19];
    const float* qmax   = (const float*)d_in[20];
    float* out = (float*)d_out;

    float *xt, *pa, *pb, *pc, *sa, *sb;
    uint32_t *h16, *t116, *t216, *t316, *w2ph, *w2pl;
    cudaGetSymbolAddress((void**)&xt,  g_xt);
    cudaGetSymbolAddress((void**)&pa,  g_pa);
    cudaGetSymbolAddress((void**)&pb,  g_pb);
    cudaGetSymbolAddress((void**)&pc,  g_pc);
    cudaGetSymbolAddress((void**)&sa,  g_sa);
    cudaGetSymbolAddress((void**)&sb,  g_sb);
    cudaGetSymbolAddress((void**)&h16,  g_h16);
    cudaGetSymbolAddress((void**)&t116, g_t116);
    cudaGetSymbolAddress((void**)&t216, g_t216);
    cudaGetSymbolAddress((void**)&t316, g_t316);
    cudaGetSymbolAddress((void**)&w2ph, g_w2p_hi);
    cudaGetSymbolAddress((void**)&w2pl, g_w2p_lo);

    static int smem_set = 0;
    if (!smem_set) {
        cudaFuncSetAttribute(k_gemm2_mma, cudaFuncAttributeMaxDynamicSharedMemorySize, 36864);
        smem_set = 1;
    }

    const int TB = 256;
    int gN = (N_NODES + TB - 1) / TB;
    int gE = (N_EDGES + TB - 1) / TB;
    int gR = (R + TB - 1) / TB;
    int gW = (N_NODES*32 + TB - 1) / TB;

    /* preprocessing (fused) */
    k_init_xt<<<gR, TB>>>(x);
    k_deg_w2 <<<gE, TB>>>(dst, ew, W2);
    k_scan1  <<<NB_SCAN, 256>>>();
    k_scan23 <<<NB_SCAN, 256>>>();
    k_fill   <<<gE, TB>>>(src, dst, ew);

    /* layer 1: prop at F=4, fused GEMM+BN+LReLU -> fp16 h */
    k_prop_small<4,false><<<gN, TB>>>(xt, pa, nullptr);
    k_prop_small<4,false><<<gN, TB>>>(pa, pb, nullptr);
    k_prop_small<4,false><<<gN, TB>>>(pb, pc, nullptr);
    k_gemm1_bn<<<(R + 255)/256, 256>>>(W1, b1, g1, be1, h16);

    /* layer 2: 3x fp16 prop64, fused GEMM+BN+projections -> p0..p3 */
    k_prop64h<<<gW, TB>>>(h16,  t116);
    k_prop64h<<<gW, TB>>>(t116, t216);
    k_prop64h<<<gW, TB>>>(t216, t316);
    k_gemm2_mma<<<RPAD/128, 256, 36864>>>(h16, t116, t216, t316, w2ph, w2pl,
                                          b2, g2, be2, W3, pb, pa, sb, sa);

    /* layer 3: Horner at F=2 (p0->pb, p1->pa, p2->sb, p3->sa) */
    k_prop_small<2,true ><<<gN, TB>>>(sa, pc, sb);   /* u2 = A p3 + p2 */
    k_prop_small<2,true ><<<gN, TB>>>(pc, sa, pa);   /* u1 = A u2 + p1 */
    k_prop2_final<<<gN, TB>>>(sa, pb, b3, mask, mean_y, std_y,
                              vmin, vmax, qmin, qmax, out);
}

// round 9
// speedup vs baseline: 2.1615x; 1.0208x over previous
#include <cuda_runtime.h>
#include <cuda_fp16.h>
#include <math.h>
#include <cstdint>

#define N_NODES 50000
#define N_EDGES 400000
#define BATCH 4
#define R (N_NODES*BATCH)      /* 200000 rows (n,b) */
#define RPAD 200064            /* padded to 128-row GEMM tiles */
#define BN_EPS 1e-5f
#define SLOPE 0.01f
#define NB_SCAN ((N_NODES + 255) / 256)   /* 196 */

/* ---------------- static device scratch (no allocations allowed) -------- */
__device__ __align__(16) float g_deg[N_NODES];
__device__ __align__(16) float g_dis[N_NODES];
__device__ __align__(16) int   g_cnt[N_NODES];
__device__ __align__(16) int   g_rowptr[N_NODES+1];
__device__ __align__(16) int   g_cur[N_NODES];
__device__ __align__(16) int   g_col[N_EDGES];
__device__ __align__(16) float g_wcsr[N_EDGES];
__device__ __align__(16) int   g_bsum[256];

__device__ __align__(16) float g_xt[RPAD*4];
__device__ __align__(16) float g_pa[RPAD*4];
__device__ __align__(16) float g_pb[RPAD*4];
__device__ __align__(16) float g_pc[RPAD*4];

/* fp16 hidden states: [row][64] halfs = [row][32] u32 */
__device__ __align__(16) uint32_t g_h16 [RPAD*32];
__device__ __align__(16) uint32_t g_t116[RPAD*32];
__device__ __align__(16) uint32_t g_t216[RPAD*32];
__device__ __align__(16) uint32_t g_t316[RPAD*32];

__device__ __align__(16) float g_sa[RPAD*2];
__device__ __align__(16) float g_sb[RPAD*2];

/* W2 transposed [64 n][128 kpair], fp16x2-packed hi/lo */
__device__ __align__(16) uint32_t g_w2p_hi[64*128];
__device__ __align__(16) uint32_t g_w2p_lo[64*128];

#define MMAH(C, a0,a1,a2,a3, b0,b1) \
    asm volatile("mma.sync.aligned.m16n8k16.row.col.f32.f16.f16.f32 " \
        "{%0,%1,%2,%3},{%4,%5,%6,%7},{%8,%9},{%0,%1,%2,%3};" \
        : "+f"((C)[0]),"+f"((C)[1]),"+f"((C)[2]),"+f"((C)[3]) \
        : "r"(a0),"r"(a1),"r"(a2),"r"(a3),"r"(b0),"r"(b1))

__device__ __forceinline__ uint32_t h2u(__half2 h) {
    uint32_t u; memcpy(&u, &h, 4); return u;
}
__device__ __forceinline__ __half2 u2h(uint32_t u) {
    __half2 h; memcpy(&h, &u, 4); return h;
}

/* ---------------- preprocessing --------------------------------------- */
__global__ void k_init_xt(const float* __restrict__ x) {
    int t = blockIdx.x*blockDim.x + threadIdx.x;
    if (t < N_NODES) { g_deg[t] = 0.f; g_cnt[t] = 0; }
    if (t < R) {
        int b = t / N_NODES, n = t - b*N_NODES;
        float4 v = ((const float4*)x)[t];
        ((float4*)g_xt)[n*4 + b] = v;
    }
}

__global__ void k_deg_w2(const int* __restrict__ dst, const float* __restrict__ ew,
                         const float* __restrict__ W2) {
    int e = blockIdx.x*blockDim.x + threadIdx.x;
    if (e < N_EDGES) {
        int d = dst[e];
        atomicAdd(&g_deg[d], ew[e]);
        atomicAdd(&g_cnt[d], 1);
    }
    if (e < 64*128) {
        int n = e >> 7, p = e & 127;
        int k0 = 2*p;
        int sel = k0 >> 6, kk = k0 & 63;
        float v0 = W2[sel*4096 + kk*64 + n];
        float v1 = W2[sel*4096 + (kk+1)*64 + n];
        __half h0 = __float2half_rn(v0), h1 = __float2half_rn(v1);
        float l0 = v0 - __half2float(h0), l1 = v1 - __half2float(h1);
        g_w2p_hi[e] = h2u(__halves2half2(h0, h1));
        g_w2p_lo[e] = h2u(__floats2half2_rn(l0, l1));
    }
}

__global__ void k_scan1() {
    int t = threadIdx.x, b = blockIdx.x;
    int i = b*256 + t;
    int v = (i < N_NODES) ? g_cnt[i] : 0;
    int lane = t & 31, wp = t >> 5;
    int x = v;
    #pragma unroll
    for (int o = 1; o < 32; o <<= 1) {
        int y = __shfl_up_sync(0xffffffffu, x, o);
        if (lane >= o) x += y;
    }
    __shared__ int wt[8];
    if (lane == 31) wt[wp] = x;
    __syncthreads();
    if (wp == 0 && lane < 8) {
        int y = wt[lane];
        #pragma unroll
        for (int o = 1; o < 8; o <<= 1) {
            int z = __shfl_up_sync(0xffu, y, o);
            if (lane >= o) y += z;
        }
        wt[lane] = y;
    }
    __syncthreads();
    int incl = x + (wp ? wt[wp-1] : 0);
    if (i < N_NODES) g_rowptr[i] = incl - v;
    if (t == 255) g_bsum[b] = incl;
}

__global__ void k_scan23() {
    int t = threadIdx.x, b = blockIdx.x;
    int v = (t < NB_SCAN) ? g_bsum[t] : 0;
    int lane = t & 31, wp = t >> 5;
    int x = v;
    #pragma unroll
    for (int o = 1; o < 32; o <<= 1) {
        int y = __shfl_up_sync(0xffffffffu, x, o);
        if (lane >= o) x += y;
    }
    __shared__ int wt[8];
    __shared__ int s_off;
    if (lane == 31) wt[wp] = x;
    __syncthreads();
    if (wp == 0 && lane < 8) {
        int y = wt[lane];
        #pragma unroll
        for (int o = 1; o < 8; o <<= 1) {
            int z = __shfl_up_sync(0xffu, y, o);
            if (lane >= o) y += z;
        }
        wt[lane] = y;
    }
    __syncthreads();
    int incl = x + (wp ? wt[wp-1] : 0);
    if (t == b) s_off = incl - v;
    __syncthreads();
    int i = b*256 + t;
    if (i < N_NODES) {
        int p = g_rowptr[i] + s_off;
        g_rowptr[i] = p;
        g_cur[i] = p;
        float d = g_deg[i];
        g_dis[i] = (d > 0.f) ? rsqrtf(fmaxf(d, 1e-30f)) : 0.f;
    }
    if (b == NB_SCAN-1 && t == 0) g_rowptr[N_NODES] = N_EDGES;
}

__global__ void k_fill(const int* __restrict__ src, const int* __restrict__ dst,
                       const float* __restrict__ ew) {
    int e = blockIdx.x*blockDim.x + threadIdx.x;
    if (e < N_EDGES) {
        int s = src[e], d = dst[e];
        int p = atomicAdd(&g_cur[d], 1);
        g_col[p]  = s;
        g_wcsr[p] = g_dis[s] * ew[e] * g_dis[d];
    }
}

/* ---------------- propagation (2-way unrolled edge loops) ---------------- */
template<int V4, bool ADD>
__global__ void k_prop_small(const float* __restrict__ in, float* __restrict__ out,
                             const float* __restrict__ add) {
    int n = blockIdx.x*blockDim.x + threadIdx.x;
    if (n >= N_NODES) return;
    float4 acc[V4];
    #pragma unroll
    for (int j = 0; j < V4; j++) acc[j] = make_float4(0.f,0.f,0.f,0.f);
    int s = g_rowptr[n], e = g_rowptr[n+1];
    const float4* base = (const float4*)in;
    int i = s;
    for (; i + 2 <= e; i += 2) {
        int c0 = __ldg(&g_col[i]),     c1 = __ldg(&g_col[i+1]);
        float w0 = __ldg(&g_wcsr[i]),  w1 = __ldg(&g_wcsr[i+1]);
        float4 v0[V4], v1[V4];
        const float4* p0 = base + c0*V4;
        const float4* p1 = base + c1*V4;
        #pragma unroll
        for (int j = 0; j < V4; j++) { v0[j] = __ldg(p0 + j); v1[j] = __ldg(p1 + j); }
        #pragma unroll
        for (int j = 0; j < V4; j++) {
            acc[j].x += w0*v0[j].x; acc[j].y += w0*v0[j].y;
            acc[j].z += w0*v0[j].z; acc[j].w += w0*v0[j].w;
        }
        #pragma unroll
        for (int j = 0; j < V4; j++) {
            acc[j].x += w1*v1[j].x; acc[j].y += w1*v1[j].y;
            acc[j].z += w1*v1[j].z; acc[j].w += w1*v1[j].w;
        }
    }
    if (i < e) {
        int c = __ldg(&g_col[i]);
        float wv = __ldg(&g_wcsr[i]);
        const float4* p = base + c*V4;
        #pragma unroll
        for (int j = 0; j < V4; j++) {
            float4 v = __ldg(p + j);
            acc[j].x += wv*v.x; acc[j].y += wv*v.y;
            acc[j].z += wv*v.z; acc[j].w += wv*v.w;
        }
    }
    float4* q = (float4*)out + n*V4;
    #pragma unroll
    for (int j = 0; j < V4; j++) {
        float4 o = acc[j];
        if (ADD) {
            float4 a = ((const float4*)add)[n*V4 + j];
            o.x += a.x; o.y += a.y; o.z += a.z; o.w += a.w;
        }
        q[j] = o;
    }
}

/* final Horner prop fused with output epilogue */
__global__ void k_prop2_final(const float* __restrict__ in,
                              const float* __restrict__ p0,
                              const float* __restrict__ b3,
                              const float* __restrict__ mask,
                              const float* __restrict__ mean_y,
                              const float* __restrict__ std_y,
                              const float* __restrict__ vmin, const float* __restrict__ vmax,
                              const float* __restrict__ qmin, const float* __restrict__ qmax,
                              float* __restrict__ out) {
    int n = blockIdx.x*blockDim.x + threadIdx.x;
    if (n >= N_NODES) return;
    float4 a0 = make_float4(0.f,0.f,0.f,0.f), a1 = a0;
    int s = g_rowptr[n], e = g_rowptr[n+1];
    const float4* base = (const float4*)in;
    int i = s;
    for (; i + 2 <= e; i += 2) {
        int c0 = __ldg(&g_col[i]),    c1 = __ldg(&g_col[i+1]);
        float w0 = __ldg(&g_wcsr[i]), w1 = __ldg(&g_wcsr[i+1]);
        float4 x0 = __ldg(base + c0*2), x1 = __ldg(base + c0*2 + 1);
        float4 y0 = __ldg(base + c1*2), y1 = __ldg(base + c1*2 + 1);
        a0.x += w0*x0.x; a0.y += w0*x0.y; a0.z += w0*x0.z; a0.w += w0*x0.w;
        a1.x += w0*x1.x; a1.y += w0*x1.y; a1.z += w0*x1.z; a1.w += w0*x1.w;
        a0.x += w1*y0.x; a0.y += w1*y0.y; a0.z += w1*y0.z; a0.w += w1*y0.w;
        a1.x += w1*y1.x; a1.y += w1*y1.y; a1.z += w1*y1.z; a1.w += w1*y1.w;
    }
    if (i < e) {
        int c = __ldg(&g_col[i]);
        float wv = __ldg(&g_wcsr[i]);
        float4 v0 = __ldg(base + c*2), v1 = __ldg(base + c*2 + 1);
        a0.x += wv*v0.x; a0.y += wv*v0.y; a0.z += wv*v0.z; a0.w += wv*v0.w;
        a1.x += wv*v1.x; a1.y += wv*v1.y; a1.z += wv*v1.z; a1.w += wv*v1.w;
    }
    float4 z0 = ((const float4*)p0)[n*2];
    float4 z1 = ((const float4*)p0)[n*2 + 1];
    float b30 = __ldg(&b3[0]), b31 = __ldg(&b3[1]);
    float u[4][2] = {
        {a0.x + z0.x + b30, a0.y + z0.y + b31},
        {a0.z + z0.z + b30, a0.w + z0.w + b31},
        {a1.x + z1.x + b30, a1.y + z1.y + b31},
        {a1.z + z1.z + b30, a1.w + z1.w + b31}
    };
    float s0 = std_y[n*2], s1 = std_y[n*2+1];
    if (isinf(s0)) s0 = 0.f;
    if (isinf(s1)) s1 = 0.f;
    float m0 = mask[n*2], m1 = mask[n*2+1];
    float me0 = mean_y[n*2], me1 = mean_y[n*2+1];
    float vlo = vmin[n], vhi = vmax[n];
    float qlo = qmin[n], qhi = qmax[n];
    #pragma unroll
    for (int b = 0; b < 4; b++) {
        float o0 = (u[b][0]*s0 + me0) * m0;
        float o1 = (u[b][1]*s1 + me1) * m1;
        o0 = fminf(fmaxf(o0, vlo), vhi);
        o1 = fminf(fmaxf(o1, qlo), qhi);
        *(float2*)&out[(size_t)(b*N_NODES + n)*2] = make_float2(o0, o1);
    }
}

/* fp16 payload prop: warp per node, 2-way unrolled */
__global__ void k_prop64h(const uint32_t* __restrict__ in, uint32_t* __restrict__ out) {
    int gt = blockIdx.x*blockDim.x + threadIdx.x;
    int n = gt >> 5, lane = gt & 31;
    if (n >= N_NODES) return;
    int s = g_rowptr[n], e = g_rowptr[n+1];
    float2 a0 = make_float2(0.f,0.f), a1 = a0, a2 = a0, a3 = a0;
    int i = s;
    for (; i + 2 <= e; i += 2) {
        int c0 = __ldg(&g_col[i]),    c1 = __ldg(&g_col[i+1]);
        float w0 = __ldg(&g_wcsr[i]), w1 = __ldg(&g_wcsr[i+1]);
        uint4 v0 = __ldg((const uint4*)(in + c0*128 + lane*4));
        uint4 v1 = __ldg((const uint4*)(in + c1*128 + lane*4));
        float2 f;
        f = __half22float2(u2h(v0.x)); a0.x += w0*f.x; a0.y += w0*f.y;
        f = __half22float2(u2h(v0.y)); a1.x += w0*f.x; a1.y += w0*f.y;
        f = __half22float2(u2h(v0.z)); a2.x += w0*f.x; a2.y += w0*f.y;
        f = __half22float2(u2h(v0.w)); a3.x += w0*f.x; a3.y += w0*f.y;
        f = __half22float2(u2h(v1.x)); a0.x += w1*f.x; a0.y += w1*f.y;
        f = __half22float2(u2h(v1.y)); a1.x += w1*f.x; a1.y += w1*f.y;
        f = __half22float2(u2h(v1.z)); a2.x += w1*f.x; a2.y += w1*f.y;
        f = __half22float2(u2h(v1.w)); a3.x += w1*f.x; a3.y += w1*f.y;
    }
    if (i < e) {
        int c = __ldg(&g_col[i]);
        float wv = __ldg(&g_wcsr[i]);
        uint4 v = __ldg((const uint4*)(in + c*128 + lane*4));
        float2 f;
        f = __half22float2(u2h(v.x)); a0.x += wv*f.x; a0.y += wv*f.y;
        f = __half22float2(u2h(v.y)); a1.x += wv*f.x; a1.y += wv*f.y;
        f = __half22float2(u2h(v.z)); a2.x += wv*f.x; a2.y += wv*f.y;
        f = __half22float2(u2h(v.w)); a3.x += wv*f.x; a3.y += wv*f.y;
    }
    uint4 o;
    o.x = h2u(__floats2half2_rn(a0.x, a0.y));
    o.y = h2u(__floats2half2_rn(a1.x, a1.y));
    o.z = h2u(__floats2half2_rn(a2.x, a2.y));
    o.w = h2u(__floats2half2_rn(a3.x, a3.y));
    *(uint4*)(out + n*128 + lane*4) = o;
}

/* ---------------- layer-1 GEMM + BN + LeakyReLU -> fp16 h --------------- */
__global__ void k_gemm1_bn(const float* __restrict__ W1, const float* __restrict__ b1,
                           const float* __restrict__ g1, const float* __restrict__ be1,
                           uint32_t* __restrict__ hout) {
    __shared__ float sW[1024];
    __shared__ float sB[64];
    int t = threadIdx.x;
    for (int i = t; i < 1024; i += 256) sW[i] = W1[i];
    if (t < 64) sB[t] = b1[t];
    __syncthreads();
    int r = blockIdx.x*256 + t;
    int rr = r < R ? r : R-1;
    float in[16];
    { float4 v;
      v = ((const float4*)g_xt)[rr]; in[0]=v.x; in[1]=v.y; in[2]=v.z; in[3]=v.w;
      v = ((const float4*)g_pa)[rr]; in[4]=v.x; in[5]=v.y; in[6]=v.z; in[7]=v.w;
      v = ((const float4*)g_pb)[rr]; in[8]=v.x; in[9]=v.y; in[10]=v.z; in[11]=v.w;
      v = ((const float4*)g_pc)[rr]; in[12]=v.x; in[13]=v.y; in[14]=v.z; in[15]=v.w; }
    float o[64];
    float s = 0.f, q = 0.f;
    #pragma unroll
    for (int g0 = 0; g0 < 64; g0 += 4) {
        float4 a = make_float4(sB[g0], sB[g0+1], sB[g0+2], sB[g0+3]);
        #pragma unroll
        for (int i = 0; i < 16; i++) {
            float4 w = *(const float4*)&sW[i*64 + g0];
            a.x += in[i]*w.x; a.y += in[i]*w.y; a.z += in[i]*w.z; a.w += in[i]*w.w;
        }
        o[g0]=a.x; o[g0+1]=a.y; o[g0+2]=a.z; o[g0+3]=a.w;
        s += a.x+a.y+a.z+a.w;
        q += a.x*a.x+a.y*a.y+a.z*a.z+a.w*a.w;
    }
    s += __shfl_xor_sync(0xffffffffu, s, 1);
    q += __shfl_xor_sync(0xffffffffu, q, 1);
    s += __shfl_xor_sync(0xffffffffu, s, 2);
    q += __shfl_xor_sync(0xffffffffu, q, 2);
    if (r >= R) return;
    int n = r >> 2;
    float mu  = s * (1.f/256.f);
    float var = q * (1.f/256.f) - mu*mu;
    float sc  = __ldg(&g1[n]) * rsqrtf(var + BN_EPS);
    float bb  = __ldg(&be1[n]);
    #pragma unroll
    for (int g0 = 0; g0 < 64; g0 += 4) {
        float f0 = sc*(o[g0+0]-mu)+bb; f0 = f0 > 0.f ? f0 : SLOPE*f0;
        float f1 = sc*(o[g0+1]-mu)+bb; f1 = f1 > 0.f ? f1 : SLOPE*f1;
        float f2 = sc*(o[g0+2]-mu)+bb; f2 = f2 > 0.f ? f2 : SLOPE*f2;
        float f3 = sc*(o[g0+3]-mu)+bb; f3 = f3 > 0.f ? f3 : SLOPE*f3;
        uint2 pk;
        pk.x = h2u(__floats2half2_rn(f0, f1));
        pk.y = h2u(__floats2half2_rn(f2, f3));
        *(uint2*)&hout[(size_t)r*32 + g0/2] = pk;
    }
}

/* ---------------- layer-2 GEMM + fused BN + fused layer-3 projections --- */
#define STG_U32 4096
#define SW3_OFF 8704
__global__ void __launch_bounds__(256, 2)
k_gemm2_mma(const uint32_t* __restrict__ A0, const uint32_t* __restrict__ A1,
            const uint32_t* __restrict__ A2, const uint32_t* __restrict__ A3,
            const uint32_t* __restrict__ wph, const uint32_t* __restrict__ wpl,
            const float* __restrict__ b2,
            const float* __restrict__ g2, const float* __restrict__ be2,
            const float* __restrict__ W3,
            float* __restrict__ p0, float* __restrict__ p1,
            float* __restrict__ p2, float* __restrict__ p3) {
    extern __shared__ uint32_t smu[];
    float* smf = (float*)smu;
    const int t = threadIdx.x;
    const int lane = t & 31, wid = t >> 5;
    const int wrow = wid >> 1, wcol = wid & 1;
    const int r0 = blockIdx.x * 128;

    #pragma unroll
    for (int i2 = t; i2 < 512; i2 += 256) {
        int kch = i2 >> 6, f = i2 & 63;
        smf[SW3_OFF + i2] = W3[(kch >> 1)*128 + f*2 + (kch & 1)];
    }

    int a_w[4], a_src[4];
    #pragma unroll
    for (int i = 0; i < 4; i++) {
        int idx = i*256 + t;
        int row = idx >> 3, c4 = idx & 7;
        int rr = row & 15, mt = row >> 4;
        int ks = c4 >> 2, regbit = (c4 >> 1) & 1, q0 = (c4 & 1) * 2;
        int g = rr & 7, abit = rr >> 3;
        a_w[i] = (mt*2 + ks)*128 + (g*4 + q0)*4 + abit + 2*regbit;
        a_src[i] = row*32 + c4*2;
    }
    int b_w[2], b_src[2];
    #pragma unroll
    for (int i = 0; i < 2; i++) {
        int idx = i*256 + t;
        int n = idx >> 3, c4 = idx & 7;
        int ks = c4 >> 2, regbit = (c4 >> 1) & 1, q0 = (c4 & 1) * 2;
        int g = n & 7, nt = n >> 3;
        b_w[i] = 2048 + (nt*2 + ks)*64 + (g*4 + q0)*2 + regbit;
        b_src[i] = n*128 + c4*2;
    }

    float c[2][4][4];
    #pragma unroll
    for (int m = 0; m < 2; m++)
        #pragma unroll
        for (int n = 0; n < 4; n++)
            #pragma unroll
            for (int k = 0; k < 4; k++) c[m][n][k] = 0.f;

    uint2 pa[4], pbh[2], pbl[2];

    {
        #pragma unroll
        for (int i = 0; i < 4; i++)
            pa[i] = *(const uint2*)(A0 + (size_t)r0*32 + a_src[i]);
        #pragma unroll
        for (int i = 0; i < 2; i++) {
            pbh[i] = *(const uint2*)(wph + b_src[i]);
            pbl[i] = *(const uint2*)(wpl + b_src[i]);
        }
        uint32_t* base = smu;
        #pragma unroll
        for (int i = 0; i < 4; i++) {
            base[a_w[i]]     = pa[i].x;
            base[a_w[i] + 4] = pa[i].y;
        }
        #pragma unroll
        for (int i = 0; i < 2; i++) {
            base[b_w[i]]            = pbh[i].x;
            base[b_w[i] + 2]        = pbh[i].y;
            base[1024 + b_w[i]]     = pbl[i].x;
            base[1024 + b_w[i] + 2] = pbl[i].y;
        }
    }
    __syncthreads();

    #pragma unroll 1
    for (int cc = 0; cc < 8; cc++) {
        int stage = cc & 1;
        if (cc < 7) {
            int cn = cc + 1;
            const uint32_t* Ap = (cn < 2) ? A0 : (cn < 4) ? A1 : (cn < 6) ? A2 : A3;
            int kb = (cn & 1) * 16;
            #pragma unroll
            for (int i = 0; i < 4; i++)
                pa[i] = *(const uint2*)(Ap + (size_t)r0*32 + a_src[i] + kb);
            #pragma unroll
            for (int i = 0; i < 2; i++) {
                pbh[i] = *(const uint2*)(wph + b_src[i] + cn*16);
                pbl[i] = *(const uint2*)(wpl + b_src[i] + cn*16);
            }
        }
        {
            const uint32_t* base = smu + stage*STG_U32;
            #pragma unroll
            for (int ks = 0; ks < 2; ks++) {
                uint4 ah[2];
                #pragma unroll
                for (int mt = 0; mt < 2; mt++) {
                    int mtile = wrow*2 + mt;
                    ah[mt] = *(const uint4*)(base + (mtile*2+ks)*128 + lane*4);
                }
                uint2 bh[4], bl[4];
                #pragma unroll
                for (int nt = 0; nt < 4; nt++) {
                    int ntile = wcol*4 + nt;
                    bh[nt] = *(const uint2*)(base + 2048 + (ntile*2+ks)*64 + lane*2);
                    bl[nt] = *(const uint2*)(base + 3072 + (ntile*2+ks)*64 + lane*2);
                }
                #pragma unroll
                for (int mt = 0; mt < 2; mt++)
                    #pragma unroll
                    for (int nt = 0; nt < 4; nt++) {
                        MMAH(c[mt][nt], ah[mt].x, ah[mt].y, ah[mt].z, ah[mt].w,
                             bh[nt].x, bh[nt].y);
                        MMAH(c[mt][nt], ah[mt].x, ah[mt].y, ah[mt].z, ah[mt].w,
                             bl[nt].x, bl[nt].y);
                    }
            }
        }
        if (cc < 7) {
            uint32_t* base = smu + ((cc+1)&1)*STG_U32;
            #pragma unroll
            for (int i = 0; i < 4; i++) {
                base[a_w[i]]     = pa[i].x;
                base[a_w[i] + 4] = pa[i].y;
            }
            #pragma unroll
            for (int i = 0; i < 2; i++) {
                base[b_w[i]]            = pbh[i].x;
                base[b_w[i] + 2]        = pbh[i].y;
                base[1024 + b_w[i]]     = pbl[i].x;
                base[1024 + b_w[i] + 2] = pbl[i].y;
            }
        }
        __syncthreads();
    }

    /* ---- fused BN2 + LeakyReLU + W3 projections ---- */
    {
        float* so = smf;
        const int g = lane >> 2, q = lane & 3;
        #pragma unroll
        for (int mt = 0; mt < 2; mt++) {
            int lr = wrow*32 + mt*16 + g;
            #pragma unroll
            for (int nt = 0; nt < 4; nt++) {
                int col = wcol*32 + nt*8 + 2*q;
                float bx = __ldg(&b2[col]), by = __ldg(&b2[col+1]);
                so[lr*68+col]       = c[mt][nt][0] + bx;
                so[lr*68+col+1]     = c[mt][nt][1] + by;
                so[(lr+8)*68+col]   = c[mt][nt][2] + bx;
                so[(lr+8)*68+col+1] = c[mt][nt][3] + by;
            }
        }
    }
    __syncthreads();
    {
        const float* so = smf;
        const float* sw3 = smf + SW3_OFF;
        int sub = lane >> 3, c8 = (lane & 7) * 8;
        #pragma unroll
        for (int nn = 0; nn < 4; nn++) {
            int node = wid*4 + nn;
            int gnode = blockIdx.x*32 + node;
            int gn = gnode < N_NODES ? gnode : N_NODES-1;
            const float* rp = so + (node*4 + sub)*68 + c8;
            float4 v0 = *(const float4*)rp;
            float4 v1 = *(const float4*)(rp + 4);
            float s = v0.x+v0.y+v0.z+v0.w + v1.x+v1.y+v1.z+v1.w;
            float q = v0.x*v0.x+v0.y*v0.y+v0.z*v0.z+v0.w*v0.w
                    + v1.x*v1.x+v1.y*v1.y+v1.z*v1.z+v1.w*v1.w;
            #pragma unroll
            for (int o = 16; o; o >>= 1) {
                s += __shfl_xor_sync(0xffffffffu, s, o);
                q += __shfl_xor_sync(0xffffffffu, q, o);
            }
            float mu  = s * (1.f/256.f);
            float var = q * (1.f/256.f) - mu*mu;
            float sc  = __ldg(&g2[gn]) * rsqrtf(var + BN_EPS);
            float bb  = __ldg(&be2[gn]);
            float o0, o1, o2, o3, o4, o5, o6, o7, f;
            f = sc*(v0.x-mu)+bb; o0 = f > 0.f ? f : SLOPE*f;
            f = sc*(v0.y-mu)+bb; o1 = f > 0.f ? f : SLOPE*f;
            f = sc*(v0.z-mu)+bb; o2 = f > 0.f ? f : SLOPE*f;
            f = sc*(v0.w-mu)+bb; o3 = f > 0.f ? f : SLOPE*f;
            f = sc*(v1.x-mu)+bb; o4 = f > 0.f ? f : SLOPE*f;
            f = sc*(v1.y-mu)+bb; o5 = f > 0.f ? f : SLOPE*f;
            f = sc*(v1.z-mu)+bb; o6 = f > 0.f ? f : SLOPE*f;
            f = sc*(v1.w-mu)+bb; o7 = f > 0.f ? f : SLOPE*f;
            float pr[8];
            #pragma unroll
            for (int kch = 0; kch < 8; kch++) {
                const float* w = sw3 + kch*64 + c8;
                float4 w0 = *(const float4*)w;
                float4 w1 = *(const float4*)(w + 4);
                pr[kch] = o0*w0.x + o1*w0.y + o2*w0.z + o3*w0.w
                        + o4*w1.x + o5*w1.y + o6*w1.z + o7*w1.w;
            }
            #pragma unroll
            for (int m = 1; m <= 4; m <<= 1) {
                #pragma unroll
                for (int kch = 0; kch < 8; kch++)
                    pr[kch] += __shfl_xor_sync(0xffffffffu, pr[kch], m);
            }
            if ((lane & 7) == 0 && gnode < N_NODES) {
                size_t grow = (size_t)(r0 + node*4 + sub)*2;
                *(float2*)&p0[grow] = make_float2(pr[0], pr[1]);
                *(float2*)&p1[grow] = make_float2(pr[2], pr[3]);
                *(float2*)&p2[grow] = make_float2(pr[4], pr[5]);
                *(float2*)&p3[grow] = make_float2(pr[6], pr[7]);
            }
        }
    }
}

/* ======================================================================= */
extern "C" void kernel_launch(void* const* d_in, const int* in_sizes, int n_in,
                              void* d_out, int out_size) {
    const float* x      = (const float*)d_in[0];
    const int*   src    = (const int*)  d_in[1];
    const int*   dst    = (const int*)  d_in[2];
    const float* ew     = (const float*)d_in[3];
    const float* W1     = (const float*)d_in[4];
    const float* b1     = (const float*)d_in[5];
    const float* W2     = (const float*)d_in[6];
    const float* b2     = (const float*)d_in[7];
    const float* W3     = (const float*)d_in[8];
    const float* b3     = (const float*)d_in[9];
    const float* g1     = (const float*)d_in[10];
    const float* be1    = (const float*)d_in[11];
    const float* g2     = (const float*)d_in[12];
    const float* be2    = (const float*)d_in[13];
    const float* mask   = (const float*)d_in[14];
    const float* mean_y = (const float*)d_in[15];
    const float* std_y  = (const float*)d_in[16];
    const float* vmin   = (const float*)d_in[17];
    const float* vmax   = (const float*)d_in[18];
    const float* qmin   = (const float*)d_in[19];
    const float* qmax   = (const float*)d_in[20];
    float* out = (float*)d_out;

    float *xt, *pa, *pb, *pc, *sa, *sb;
    uint32_t *h16, *t116, *t216, *t316, *w2ph, *w2pl;
    cudaGetSymbolAddress((void**)&xt,  g_xt);
    cudaGetSymbolAddress((void**)&pa,  g_pa);
    cudaGetSymbolAddress((void**)&pb,  g_pb);
    cudaGetSymbolAddress((void**)&pc,  g_pc);
    cudaGetSymbolAddress((void**)&sa,  g_sa);
    cudaGetSymbolAddress((void**)&sb,  g_sb);
    cudaGetSymbolAddress((void**)&h16,  g_h16);
    cudaGetSymbolAddress((void**)&t116, g_t116);
    cudaGetSymbolAddress((void**)&t216, g_t216);
    cudaGetSymbolAddress((void**)&t316, g_t316);
    cudaGetSymbolAddress((void**)&w2ph, g_w2p_hi);
    cudaGetSymbolAddress((void**)&w2pl, g_w2p_lo);

    static int smem_set = 0;
    if (!smem_set) {
        cudaFuncSetAttribute(k_gemm2_mma, cudaFuncAttributeMaxDynamicSharedMemorySize, 36864);
        smem_set = 1;
    }

    const int TB = 256;
    int gN = (N_NODES + TB - 1) / TB;
    int gE = (N_EDGES + TB - 1) / TB;
    int gR = (R + TB - 1) / TB;
    int gW = (N_NODES*32 + TB - 1) / TB;

    /* preprocessing (fused) */
    k_init_xt<<<gR, TB>>>(x);
    k_deg_w2 <<<gE, TB>>>(dst, ew, W2);
    k_scan1  <<<NB_SCAN, 256>>>();
    k_scan23 <<<NB_SCAN, 256>>>();
    k_fill   <<<gE, TB>>>(src, dst, ew);

    /* layer 1: prop at F=4, fused GEMM+BN+LReLU -> fp16 h */
    k_prop_small<4,false><<<gN, TB>>>(xt, pa, nullptr);
    k_prop_small<4,false><<<gN, TB>>>(pa, pb, nullptr);
    k_prop_small<4,false><<<gN, TB>>>(pb, pc, nullptr);
    k_gemm1_bn<<<(R + 255)/256, 256>>>(W1, b1, g1, be1, h16);

    /* layer 2: 3x fp16 prop64, fused GEMM+BN+projections -> p0..p3 */
    k_prop64h<<<gW, TB>>>(h16,  t116);
    k_prop64h<<<gW, TB>>>(t116, t216);
    k_prop64h<<<gW, TB>>>(t216, t316);
    k_gemm2_mma<<<RPAD/128, 256, 36864>>>(h16, t116, t216, t316, w2ph, w2pl,
                                          b2, g2, be2, W3, pb, pa, sb, sa);

    /* layer 3: Horner at F=2 (p0->pb, p1->pa, p2->sb, p3->sa) */
    k_prop_small<2,true ><<<gN, TB>>>(sa, pc, sb);
    k_prop_small<2,true ><<<gN, TB>>>(pc, sa, pa);
    k_prop2_final<<<gN, TB>>>(sa, pb, b3, mask, mean_y, std_y,
                              vmin, vmax, qmin, qmax, out);
}

// round 10
// speedup vs baseline: 2.1968x; 1.0163x over previous
#include <cuda_runtime.h>
#include <cuda_fp16.h>
#include <math.h>
#include <cstdint>

#define N_NODES 50000
#define N_EDGES 400000
#define BATCH 4
#define R (N_NODES*BATCH)      /* 200000 rows (n,b) */
#define RPAD 200064            /* padded to 128-row GEMM tiles */
#define BN_EPS 1e-5f
#define SLOPE 0.01f
#define NB_SCAN ((N_NODES + 255) / 256)   /* 196 */

/* ---------------- static device scratch (no allocations allowed) -------- */
__device__ __align__(16) float g_deg[N_NODES];
__device__ __align__(16) float g_dis[N_NODES];
__device__ __align__(16) int   g_cnt[N_NODES];
__device__ __align__(16) int   g_rowptr[N_NODES+1];
__device__ __align__(16) int   g_cur[N_NODES];
__device__ __align__(16) int   g_col[N_EDGES];
__device__ __align__(16) float g_wcsr[N_EDGES];
__device__ __align__(16) int   g_bsum[256];

__device__ __align__(16) float g_xt[RPAD*4];
__device__ __align__(16) float g_pa[RPAD*4];
__device__ __align__(16) float g_pb[RPAD*4];
__device__ __align__(16) float g_pc[RPAD*4];

/* fp16 hidden states: [row][64] halfs = [row][32] u32 */
__device__ __align__(16) uint32_t g_h16 [RPAD*32];
__device__ __align__(16) uint32_t g_t116[RPAD*32];
__device__ __align__(16) uint32_t g_t216[RPAD*32];
__device__ __align__(16) uint32_t g_t316[RPAD*32];

__device__ __align__(16) float g_sa[RPAD*2];
__device__ __align__(16) float g_sb[RPAD*2];

/* W2 transposed [64 n][128 kpair], fp16x2-packed hi/lo */
__device__ __align__(16) uint32_t g_w2p_hi[64*128];
__device__ __align__(16) uint32_t g_w2p_lo[64*128];
/* W1 transposed [64 n][8 kpair], fp16x2-packed hi/lo (K=16) */
__device__ __align__(16) uint32_t g_w1p_hi[64*8];
__device__ __align__(16) uint32_t g_w1p_lo[64*8];

#define MMAH(C, a0,a1,a2,a3, b0,b1) \
    asm volatile("mma.sync.aligned.m16n8k16.row.col.f32.f16.f16.f32 " \
        "{%0,%1,%2,%3},{%4,%5,%6,%7},{%8,%9},{%0,%1,%2,%3};" \
        : "+f"((C)[0]),"+f"((C)[1]),"+f"((C)[2]),"+f"((C)[3]) \
        : "r"(a0),"r"(a1),"r"(a2),"r"(a3),"r"(b0),"r"(b1))

__device__ __forceinline__ uint32_t h2u(__half2 h) {
    uint32_t u; memcpy(&u, &h, 4); return u;
}
__device__ __forceinline__ __half2 u2h(uint32_t u) {
    __half2 h; memcpy(&h, &u, 4); return h;
}

/* ---------------- preprocessing --------------------------------------- */
__global__ void k_init_xt(const float* __restrict__ x) {
    int t = blockIdx.x*blockDim.x + threadIdx.x;
    if (t < N_NODES) { g_deg[t] = 0.f; g_cnt[t] = 0; }
    if (t < R) {
        int b = t / N_NODES, n = t - b*N_NODES;
        float4 v = ((const float4*)x)[t];
        ((float4*)g_xt)[n*4 + b] = v;
    }
}

__global__ void k_deg_w2(const int* __restrict__ dst, const float* __restrict__ ew,
                         const float* __restrict__ W2, const float* __restrict__ W1) {
    int e = blockIdx.x*blockDim.x + threadIdx.x;
    if (e < N_EDGES) {
        int d = dst[e];
        atomicAdd(&g_deg[d], ew[e]);
        atomicAdd(&g_cnt[d], 1);
    }
    if (e < 64*128) {
        int n = e >> 7, p = e & 127;
        int k0 = 2*p;
        int sel = k0 >> 6, kk = k0 & 63;
        float v0 = W2[sel*4096 + kk*64 + n];
        float v1 = W2[sel*4096 + (kk+1)*64 + n];
        __half h0 = __float2half_rn(v0), h1 = __float2half_rn(v1);
        float l0 = v0 - __half2float(h0), l1 = v1 - __half2float(h1);
        g_w2p_hi[e] = h2u(__halves2half2(h0, h1));
        g_w2p_lo[e] = h2u(__floats2half2_rn(l0, l1));
    }
    if (e < 64*8) {
        int n = e >> 3, p = e & 7;
        int k0 = 2*p;
        float v0 = W1[k0*64 + n];
        float v1 = W1[(k0+1)*64 + n];
        __half h0 = __float2half_rn(v0), h1 = __float2half_rn(v1);
        float l0 = v0 - __half2float(h0), l1 = v1 - __half2float(h1);
        g_w1p_hi[e] = h2u(__halves2half2(h0, h1));
        g_w1p_lo[e] = h2u(__floats2half2_rn(l0, l1));
    }
}

__global__ void k_scan1() {
    int t = threadIdx.x, b = blockIdx.x;
    int i = b*256 + t;
    int v = (i < N_NODES) ? g_cnt[i] : 0;
    int lane = t & 31, wp = t >> 5;
    int x = v;
    #pragma unroll
    for (int o = 1; o < 32; o <<= 1) {
        int y = __shfl_up_sync(0xffffffffu, x, o);
        if (lane >= o) x += y;
    }
    __shared__ int wt[8];
    if (lane == 31) wt[wp] = x;
    __syncthreads();
    if (wp == 0 && lane < 8) {
        int y = wt[lane];
        #pragma unroll
        for (int o = 1; o < 8; o <<= 1) {
            int z = __shfl_up_sync(0xffu, y, o);
            if (lane >= o) y += z;
        }
        wt[lane] = y;
    }
    __syncthreads();
    int incl = x + (wp ? wt[wp-1] : 0);
    if (i < N_NODES) g_rowptr[i] = incl - v;
    if (t == 255) g_bsum[b] = incl;
}

__global__ void k_scan23() {
    int t = threadIdx.x, b = blockIdx.x;
    int v = (t < NB_SCAN) ? g_bsum[t] : 0;
    int lane = t & 31, wp = t >> 5;
    int x = v;
    #pragma unroll
    for (int o = 1; o < 32; o <<= 1) {
        int y = __shfl_up_sync(0xffffffffu, x, o);
        if (lane >= o) x += y;
    }
    __shared__ int wt[8];
    __shared__ int s_off;
    if (lane == 31) wt[wp] = x;
    __syncthreads();
    if (wp == 0 && lane < 8) {
        int y = wt[lane];
        #pragma unroll
        for (int o = 1; o < 8; o <<= 1) {
            int z = __shfl_up_sync(0xffu, y, o);
            if (lane >= o) y += z;
        }
        wt[lane] = y;
    }
    __syncthreads();
    int incl = x + (wp ? wt[wp-1] : 0);
    if (t == b) s_off = incl - v;
    __syncthreads();
    int i = b*256 + t;
    if (i < N_NODES) {
        int p = g_rowptr[i] + s_off;
        g_rowptr[i] = p;
        g_cur[i] = p;
        float d = g_deg[i];
        g_dis[i] = (d > 0.f) ? rsqrtf(fmaxf(d, 1e-30f)) : 0.f;
    }
    if (b == NB_SCAN-1 && t == 0) g_rowptr[N_NODES] = N_EDGES;
}

__global__ void k_fill(const int* __restrict__ src, const int* __restrict__ dst,
                       const float* __restrict__ ew) {
    int e = blockIdx.x*blockDim.x + threadIdx.x;
    if (e < N_EDGES) {
        int s = src[e], d = dst[e];
        int p = atomicAdd(&g_cur[d], 1);
        g_col[p]  = s;
        g_wcsr[p] = g_dis[s] * ew[e] * g_dis[d];
    }
}

/* ---------------- propagation ------------------------------------------ */
template<int V4, bool ADD>
__global__ void k_prop_small(const float* __restrict__ in, float* __restrict__ out,
                             const float* __restrict__ add) {
    int n = blockIdx.x*blockDim.x + threadIdx.x;
    if (n >= N_NODES) return;
    float4 acc[V4];
    #pragma unroll
    for (int j = 0; j < V4; j++) acc[j] = make_float4(0.f,0.f,0.f,0.f);
    int s = g_rowptr[n], e = g_rowptr[n+1];
    const float4* base = (const float4*)in;
    int i = s;
    for (; i + 2 <= e; i += 2) {
        int c0 = __ldg(&g_col[i]),     c1 = __ldg(&g_col[i+1]);
        float w0 = __ldg(&g_wcsr[i]),  w1 = __ldg(&g_wcsr[i+1]);
        float4 v0[V4], v1[V4];
        const float4* p0 = base + c0*V4;
        const float4* p1 = base + c1*V4;
        #pragma unroll
        for (int j = 0; j < V4; j++) { v0[j] = __ldg(p0 + j); v1[j] = __ldg(p1 + j); }
        #pragma unroll
        for (int j = 0; j < V4; j++) {
            acc[j].x += w0*v0[j].x; acc[j].y += w0*v0[j].y;
            acc[j].z += w0*v0[j].z; acc[j].w += w0*v0[j].w;
        }
        #pragma unroll
        for (int j = 0; j < V4; j++) {
            acc[j].x += w1*v1[j].x; acc[j].y += w1*v1[j].y;
            acc[j].z += w1*v1[j].z; acc[j].w += w1*v1[j].w;
        }
    }
    if (i < e) {
        int c = __ldg(&g_col[i]);
        float wv = __ldg(&g_wcsr[i]);
        const float4* p = base + c*V4;
        #pragma unroll
        for (int j = 0; j < V4; j++) {
            float4 v = __ldg(p + j);
            acc[j].x += wv*v.x; acc[j].y += wv*v.y;
            acc[j].z += wv*v.z; acc[j].w += wv*v.w;
        }
    }
    float4* q = (float4*)out + n*V4;
    #pragma unroll
    for (int j = 0; j < V4; j++) {
        float4 o = acc[j];
        if (ADD) {
            float4 a = ((const float4*)add)[n*V4 + j];
            o.x += a.x; o.y += a.y; o.z += a.z; o.w += a.w;
        }
        q[j] = o;
    }
}

/* final Horner prop fused with output epilogue */
__global__ void k_prop2_final(const float* __restrict__ in,
                              const float* __restrict__ p0,
                              const float* __restrict__ b3,
                              const float* __restrict__ mask,
                              const float* __restrict__ mean_y,
                              const float* __restrict__ std_y,
                              const float* __restrict__ vmin, const float* __restrict__ vmax,
                              const float* __restrict__ qmin, const float* __restrict__ qmax,
                              float* __restrict__ out) {
    int n = blockIdx.x*blockDim.x + threadIdx.x;
    if (n >= N_NODES) return;
    float4 a0 = make_float4(0.f,0.f,0.f,0.f), a1 = a0;
    int s = g_rowptr[n], e = g_rowptr[n+1];
    const float4* base = (const float4*)in;
    int i = s;
    for (; i + 2 <= e; i += 2) {
        int c0 = __ldg(&g_col[i]),    c1 = __ldg(&g_col[i+1]);
        float w0 = __ldg(&g_wcsr[i]), w1 = __ldg(&g_wcsr[i+1]);
        float4 x0 = __ldg(base + c0*2), x1 = __ldg(base + c0*2 + 1);
        float4 y0 = __ldg(base + c1*2), y1 = __ldg(base + c1*2 + 1);
        a0.x += w0*x0.x; a0.y += w0*x0.y; a0.z += w0*x0.z; a0.w += w0*x0.w;
        a1.x += w0*x1.x; a1.y += w0*x1.y; a1.z += w0*x1.z; a1.w += w0*x1.w;
        a0.x += w1*y0.x; a0.y += w1*y0.y; a0.z += w1*y0.z; a0.w += w1*y0.w;
        a1.x += w1*y1.x; a1.y += w1*y1.y; a1.z += w1*y1.z; a1.w += w1*y1.w;
    }
    if (i < e) {
        int c = __ldg(&g_col[i]);
        float wv = __ldg(&g_wcsr[i]);
        float4 v0 = __ldg(base + c*2), v1 = __ldg(base + c*2 + 1);
        a0.x += wv*v0.x; a0.y += wv*v0.y; a0.z += wv*v0.z; a0.w += wv*v0.w;
        a1.x += wv*v1.x; a1.y += wv*v1.y; a1.z += wv*v1.z; a1.w += wv*v1.w;
    }
    float4 z0 = ((const float4*)p0)[n*2];
    float4 z1 = ((const float4*)p0)[n*2 + 1];
    float b30 = __ldg(&b3[0]), b31 = __ldg(&b3[1]);
    float u[4][2] = {
        {a0.x + z0.x + b30, a0.y + z0.y + b31},
        {a0.z + z0.z + b30, a0.w + z0.w + b31},
        {a1.x + z1.x + b30, a1.y + z1.y + b31},
        {a1.z + z1.z + b30, a1.w + z1.w + b31}
    };
    float s0 = std_y[n*2], s1 = std_y[n*2+1];
    if (isinf(s0)) s0 = 0.f;
    if (isinf(s1)) s1 = 0.f;
    float m0 = mask[n*2], m1 = mask[n*2+1];
    float me0 = mean_y[n*2], me1 = mean_y[n*2+1];
    float vlo = vmin[n], vhi = vmax[n];
    float qlo = qmin[n], qhi = qmax[n];
    #pragma unroll
    for (int b = 0; b < 4; b++) {
        float o0 = (u[b][0]*s0 + me0) * m0;
        float o1 = (u[b][1]*s1 + me1) * m1;
        o0 = fminf(fmaxf(o0, vlo), vhi);
        o1 = fminf(fmaxf(o1, qlo), qhi);
        *(float2*)&out[(size_t)(b*N_NODES + n)*2] = make_float2(o0, o1);
    }
}

/* fp16 payload prop: warp per node, 4-way predicated edge loop */
__global__ void k_prop64h(const uint32_t* __restrict__ in, uint32_t* __restrict__ out) {
    int gt = blockIdx.x*blockDim.x + threadIdx.x;
    int n = gt >> 5, lane = gt & 31;
    if (n >= N_NODES) return;
    int s = g_rowptr[n], e = g_rowptr[n+1];
    float2 a0 = make_float2(0.f,0.f), a1 = a0, a2 = a0, a3 = a0;
    for (int i = s; i < e; i += 4) {
        int   c[4];
        float w[4];
        uint4 v[4];
        #pragma unroll
        for (int j = 0; j < 4; j++) {
            int idx = i + j;
            bool act = idx < e;
            c[j] = act ? __ldg(&g_col[idx]) : 0;
            w[j] = act ? __ldg(&g_wcsr[idx]) : 0.f;
        }
        #pragma unroll
        for (int j = 0; j < 4; j++)
            v[j] = __ldg((const uint4*)(in + c[j]*128 + lane*4));
        #pragma unroll
        for (int j = 0; j < 4; j++) {
            float2 f;
            f = __half22float2(u2h(v[j].x)); a0.x += w[j]*f.x; a0.y += w[j]*f.y;
            f = __half22float2(u2h(v[j].y)); a1.x += w[j]*f.x; a1.y += w[j]*f.y;
            f = __half22float2(u2h(v[j].z)); a2.x += w[j]*f.x; a2.y += w[j]*f.y;
            f = __half22float2(u2h(v[j].w)); a3.x += w[j]*f.x; a3.y += w[j]*f.y;
        }
    }
    uint4 o;
    o.x = h2u(__floats2half2_rn(a0.x, a0.y));
    o.y = h2u(__floats2half2_rn(a1.x, a1.y));
    o.z = h2u(__floats2half2_rn(a2.x, a2.y));
    o.w = h2u(__floats2half2_rn(a3.x, a3.y));
    *(uint4*)(out + n*128 + lane*4) = o;
}

/* ---------------- layer-1 GEMM on tensor cores + BN + LReLU -> fp16 h ---
 * A = [xt|pa|pb|pc] (K=16 fp32, split hi/lo fp16 on the fly), one k16 step.
 * Same fragment layout as gemm2. Output: fp16 h rows.
 * smem (u32): AHI[0,1024) ALO[1024,2048) BHI[2048,2560) BLO[2560,3072);
 * epilogue reuses smem as float[128*68] (34816 B total dynamic).          */
__global__ void __launch_bounds__(256, 2)
k_gemm1_mma(const float* __restrict__ A0, const float* __restrict__ A1,
            const float* __restrict__ A2, const float* __restrict__ A3,
            const uint32_t* __restrict__ w1h, const uint32_t* __restrict__ w1l,
            const float* __restrict__ b1,
            const float* __restrict__ g1, const float* __restrict__ be1,
            uint32_t* __restrict__ hout) {
    extern __shared__ uint32_t smu[];
    float* smf = (float*)smu;
    const int t = threadIdx.x;
    const int lane = t & 31, wid = t >> 5;
    const int wrow = wid >> 1, wcol = wid & 1;
    const int r0 = blockIdx.x * 128;

    /* B writers: 256 slots = 64 n x 4 c4 */
    {
        int n = t >> 2, c4 = t & 3;
        int regbit = (c4 >> 1) & 1, q0 = (c4 & 1) * 2;
        int g = n & 7, nt = n >> 3;
        int b_w = 2048 + nt*64 + (g*4 + q0)*2 + regbit;
        uint2 vh = *(const uint2*)(w1h + n*8 + c4*2);
        uint2 vl = *(const uint2*)(w1l + n*8 + c4*2);
        smu[b_w]       = vh.x;
        smu[b_w + 2]   = vh.y;
        smu[512 + b_w]     = vl.x;   /* BLO = BHI + 512 */
        smu[512 + b_w + 2] = vl.y;
    }
    /* A writers: 512 slots (2 per thread) */
    #pragma unroll
    for (int sidx = 0; sidx < 2; sidx++) {
        int idx = sidx*256 + t;
        int row = idx >> 2, c4 = idx & 3;
        int rr = row & 15, mt = row >> 4;
        int regbit = (c4 >> 1) & 1, q0 = (c4 & 1) * 2;
        int g = rr & 7, abit = rr >> 3;
        int a_w = mt*128 + (g*4 + q0)*4 + abit + 2*regbit;
        const float* Ap = (c4 == 0) ? A0 : (c4 == 1) ? A1 : (c4 == 2) ? A2 : A3;
        float4 v = *(const float4*)(Ap + (size_t)(r0 + row)*4);
        __half2 h0 = __floats2half2_rn(v.x, v.y);
        __half2 h1 = __floats2half2_rn(v.z, v.w);
        float lx = v.x - __low2float(h0), ly = v.y - __high2float(h0);
        float lz = v.z - __low2float(h1), lw = v.w - __high2float(h1);
        smu[a_w]        = h2u(h0);
        smu[a_w + 4]    = h2u(h1);
        smu[1024 + a_w]     = h2u(__floats2half2_rn(lx, ly));
        smu[1024 + a_w + 4] = h2u(__floats2half2_rn(lz, lw));
    }
    __syncthreads();

    float c[2][4][4];
    #pragma unroll
    for (int m = 0; m < 2; m++)
        #pragma unroll
        for (int n = 0; n < 4; n++)
            #pragma unroll
            for (int k = 0; k < 4; k++) c[m][n][k] = 0.f;

    {
        uint4 ahi[2], alo[2];
        #pragma unroll
        for (int mt = 0; mt < 2; mt++) {
            int mtile = wrow*2 + mt;
            ahi[mt] = *(const uint4*)(smu + mtile*128 + lane*4);
            alo[mt] = *(const uint4*)(smu + 1024 + mtile*128 + lane*4);
        }
        uint2 bh[4], bl[4];
        #pragma unroll
        for (int nt = 0; nt < 4; nt++) {
            int ntile = wcol*4 + nt;
            bh[nt] = *(const uint2*)(smu + 2048 + ntile*64 + lane*2);
            bl[nt] = *(const uint2*)(smu + 2560 + ntile*64 + lane*2);
        }
        #pragma unroll
        for (int mt = 0; mt < 2; mt++)
            #pragma unroll
            for (int nt = 0; nt < 4; nt++) {
                MMAH(c[mt][nt], ahi[mt].x, ahi[mt].y, ahi[mt].z, ahi[mt].w,
                     bh[nt].x, bh[nt].y);
                MMAH(c[mt][nt], ahi[mt].x, ahi[mt].y, ahi[mt].z, ahi[mt].w,
                     bl[nt].x, bl[nt].y);
                MMAH(c[mt][nt], alo[mt].x, alo[mt].y, alo[mt].z, alo[mt].w,
                     bh[nt].x, bh[nt].y);
            }
    }
    __syncthreads();

    /* restage C + b1 into smem [128][68] */
    {
        float* so = smf;
        const int g = lane >> 2, q = lane & 3;
        #pragma unroll
        for (int mt = 0; mt < 2; mt++) {
            int lr = wrow*32 + mt*16 + g;
            #pragma unroll
            for (int nt = 0; nt < 4; nt++) {
                int col = wcol*32 + nt*8 + 2*q;
                float bx = __ldg(&b1[col]), by = __ldg(&b1[col+1]);
                so[lr*68+col]       = c[mt][nt][0] + bx;
                so[lr*68+col+1]     = c[mt][nt][1] + by;
                so[(lr+8)*68+col]   = c[mt][nt][2] + bx;
                so[(lr+8)*68+col+1] = c[mt][nt][3] + by;
            }
        }
    }
    __syncthreads();
    /* BN + LReLU per node; write fp16 h */
    {
        const float* so = smf;
        int sub = lane >> 3, c8 = (lane & 7) * 8;
        #pragma unroll
        for (int nn = 0; nn < 4; nn++) {
            int node = wid*4 + nn;
            int gnode = blockIdx.x*32 + node;
            int gn = gnode < N_NODES ? gnode : N_NODES-1;
            const float* rp = so + (node*4 + sub)*68 + c8;
            float4 v0 = *(const float4*)rp;
            float4 v1 = *(const float4*)(rp + 4);
            float s = v0.x+v0.y+v0.z+v0.w + v1.x+v1.y+v1.z+v1.w;
            float q = v0.x*v0.x+v0.y*v0.y+v0.z*v0.z+v0.w*v0.w
                    + v1.x*v1.x+v1.y*v1.y+v1.z*v1.z+v1.w*v1.w;
            #pragma unroll
            for (int o = 16; o; o >>= 1) {
                s += __shfl_xor_sync(0xffffffffu, s, o);
                q += __shfl_xor_sync(0xffffffffu, q, o);
            }
            float mu  = s * (1.f/256.f);
            float var = q * (1.f/256.f) - mu*mu;
            float sc  = __ldg(&g1[gn]) * rsqrtf(var + BN_EPS);
            float bb  = __ldg(&be1[gn]);
            float o0, o1, o2, o3, o4, o5, o6, o7, f;
            f = sc*(v0.x-mu)+bb; o0 = f > 0.f ? f : SLOPE*f;
            f = sc*(v0.y-mu)+bb; o1 = f > 0.f ? f : SLOPE*f;
            f = sc*(v0.z-mu)+bb; o2 = f > 0.f ? f : SLOPE*f;
            f = sc*(v0.w-mu)+bb; o3 = f > 0.f ? f : SLOPE*f;
            f = sc*(v1.x-mu)+bb; o4 = f > 0.f ? f : SLOPE*f;
            f = sc*(v1.y-mu)+bb; o5 = f > 0.f ? f : SLOPE*f;
            f = sc*(v1.z-mu)+bb; o6 = f > 0.f ? f : SLOPE*f;
            f = sc*(v1.w-mu)+bb; o7 = f > 0.f ? f : SLOPE*f;
            if (gnode < N_NODES) {
                uint4 pk;
                pk.x = h2u(__floats2half2_rn(o0, o1));
                pk.y = h2u(__floats2half2_rn(o2, o3));
                pk.z = h2u(__floats2half2_rn(o4, o5));
                pk.w = h2u(__floats2half2_rn(o6, o7));
                *(uint4*)&hout[(size_t)(r0 + node*4 + sub)*32 + (lane & 7)*4] = pk;
            }
        }
    }
}

/* ---------------- layer-2 GEMM + fused BN + fused layer-3 projections --- */
#define STG_U32 4096
#define SW3_OFF 8704
__global__ void __launch_bounds__(256, 2)
k_gemm2_mma(const uint32_t* __restrict__ A0, const uint32_t* __restrict__ A1,
            const uint32_t* __restrict__ A2, const uint32_t* __restrict__ A3,
            const uint32_t* __restrict__ wph, const uint32_t* __restrict__ wpl,
            const float* __restrict__ b2,
            const float* __restrict__ g2, const float* __restrict__ be2,
            const float* __restrict__ W3,
            float* __restrict__ p0, float* __restrict__ p1,
            float* __restrict__ p2, float* __restrict__ p3) {
    extern __shared__ uint32_t smu[];
    float* smf = (float*)smu;
    const int t = threadIdx.x;
    const int lane = t & 31, wid = t >> 5;
    const int wrow = wid >> 1, wcol = wid & 1;
    const int r0 = blockIdx.x * 128;

    #pragma unroll
    for (int i2 = t; i2 < 512; i2 += 256) {
        int kch = i2 >> 6, f = i2 & 63;
        smf[SW3_OFF + i2] = W3[(kch >> 1)*128 + f*2 + (kch & 1)];
    }

    int a_w[4], a_src[4];
    #pragma unroll
    for (int i = 0; i < 4; i++) {
        int idx = i*256 + t;
        int row = idx >> 3, c4 = idx & 7;
        int rr = row & 15, mt = row >> 4;
        int ks = c4 >> 2, regbit = (c4 >> 1) & 1, q0 = (c4 & 1) * 2;
        int g = rr & 7, abit = rr >> 3;
        a_w[i] = (mt*2 + ks)*128 + (g*4 + q0)*4 + abit + 2*regbit;
        a_src[i] = row*32 + c4*2;
    }
    int b_w[2], b_src[2];
    #pragma unroll
    for (int i = 0; i < 2; i++) {
        int idx = i*256 + t;
        int n = idx >> 3, c4 = idx & 7;
        int ks = c4 >> 2, regbit = (c4 >> 1) & 1, q0 = (c4 & 1) * 2;
        int g = n & 7, nt = n >> 3;
        b_w[i] = 2048 + (nt*2 + ks)*64 + (g*4 + q0)*2 + regbit;
        b_src[i] = n*128 + c4*2;
    }

    float c[2][4][4];
    #pragma unroll
    for (int m = 0; m < 2; m++)
        #pragma unroll
        for (int n = 0; n < 4; n++)
            #pragma unroll
            for (int k = 0; k < 4; k++) c[m][n][k] = 0.f;

    uint2 pa[4], pbh[2], pbl[2];

    {
        #pragma unroll
        for (int i = 0; i < 4; i++)
            pa[i] = *(const uint2*)(A0 + (size_t)r0*32 + a_src[i]);
        #pragma unroll
        for (int i = 0; i < 2; i++) {
            pbh[i] = *(const uint2*)(wph + b_src[i]);
            pbl[i] = *(const uint2*)(wpl + b_src[i]);
        }
        uint32_t* base = smu;
        #pragma unroll
        for (int i = 0; i < 4; i++) {
            base[a_w[i]]     = pa[i].x;
            base[a_w[i] + 4] = pa[i].y;
        }
        #pragma unroll
        for (int i = 0; i < 2; i++) {
            base[b_w[i]]            = pbh[i].x;
            base[b_w[i] + 2]        = pbh[i].y;
            base[1024 + b_w[i]]     = pbl[i].x;
            base[1024 + b_w[i] + 2] = pbl[i].y;
        }
    }
    __syncthreads();

    #pragma unroll 1
    for (int cc = 0; cc < 8; cc++) {
        int stage = cc & 1;
        if (cc < 7) {
            int cn = cc + 1;
            const uint32_t* Ap = (cn < 2) ? A0 : (cn < 4) ? A1 : (cn < 6) ? A2 : A3;
            int kb = (cn & 1) * 16;
            #pragma unroll
            for (int i = 0; i < 4; i++)
                pa[i] = *(const uint2*)(Ap + (size_t)r0*32 + a_src[i] + kb);
            #pragma unroll
            for (int i = 0; i < 2; i++) {
                pbh[i] = *(const uint2*)(wph + b_src[i] + cn*16);
                pbl[i] = *(const uint2*)(wpl + b_src[i] + cn*16);
            }
        }
        {
            const uint32_t* base = smu + stage*STG_U32;
            #pragma unroll
            for (int ks = 0; ks < 2; ks++) {
                uint4 ah[2];
                #pragma unroll
                for (int mt = 0; mt < 2; mt++) {
                    int mtile = wrow*2 + mt;
                    ah[mt] = *(const uint4*)(base + (mtile*2+ks)*128 + lane*4);
                }
                uint2 bh[4], bl[4];
                #pragma unroll
                for (int nt = 0; nt < 4; nt++) {
                    int ntile = wcol*4 + nt;
                    bh[nt] = *(const uint2*)(base + 2048 + (ntile*2+ks)*64 + lane*2);
                    bl[nt] = *(const uint2*)(base + 3072 + (ntile*2+ks)*64 + lane*2);
                }
                #pragma unroll
                for (int mt = 0; mt < 2; mt++)
                    #pragma unroll
                    for (int nt = 0; nt < 4; nt++) {
                        MMAH(c[mt][nt], ah[mt].x, ah[mt].y, ah[mt].z, ah[mt].w,
                             bh[nt].x, bh[nt].y);
                        MMAH(c[mt][nt], ah[mt].x, ah[mt].y, ah[mt].z, ah[mt].w,
                             bl[nt].x, bl[nt].y);
                    }
            }
        }
        if (cc < 7) {
            uint32_t* base = smu + ((cc+1)&1)*STG_U32;
            #pragma unroll
            for (int i = 0; i < 4; i++) {
                base[a_w[i]]     = pa[i].x;
                base[a_w[i] + 4] = pa[i].y;
            }
            #pragma unroll
            for (int i = 0; i < 2; i++) {
                base[b_w[i]]            = pbh[i].x;
                base[b_w[i] + 2]        = pbh[i].y;
                base[1024 + b_w[i]]     = pbl[i].x;
                base[1024 + b_w[i] + 2] = pbl[i].y;
            }
        }
        __syncthreads();
    }

    /* ---- fused BN2 + LeakyReLU + W3 projections ---- */
    {
        float* so = smf;
        const int g = lane >> 2, q = lane & 3;
        #pragma unroll
        for (int mt = 0; mt < 2; mt++) {
            int lr = wrow*32 + mt*16 + g;
            #pragma unroll
            for (int nt = 0; nt < 4; nt++) {
                int col = wcol*32 + nt*8 + 2*q;
                float bx = __ldg(&b2[col]), by = __ldg(&b2[col+1]);
                so[lr*68+col]       = c[mt][nt][0] + bx;
                so[lr*68+col+1]     = c[mt][nt][1] + by;
                so[(lr+8)*68+col]   = c[mt][nt][2] + bx;
                so[(lr+8)*68+col+1] = c[mt][nt][3] + by;
            }
        }
    }
    __syncthreads();
    {
        const float* so = smf;
        const float* sw3 = smf + SW3_OFF;
        int sub = lane >> 3, c8 = (lane & 7) * 8;
        #pragma unroll
        for (int nn = 0; nn < 4; nn++) {
            int node = wid*4 + nn;
            int gnode = blockIdx.x*32 + node;
            int gn = gnode < N_NODES ? gnode : N_NODES-1;
            const float* rp = so + (node*4 + sub)*68 + c8;
            float4 v0 = *(const float4*)rp;
            float4 v1 = *(const float4*)(rp + 4);
            float s = v0.x+v0.y+v0.z+v0.w + v1.x+v1.y+v1.z+v1.w;
            float q = v0.x*v0.x+v0.y*v0.y+v0.z*v0.z+v0.w*v0.w
                    + v1.x*v1.x+v1.y*v1.y+v1.z*v1.z+v1.w*v1.w;
            #pragma unroll
            for (int o = 16; o; o >>= 1) {
                s += __shfl_xor_sync(0xffffffffu, s, o);
                q += __shfl_xor_sync(0xffffffffu, q, o);
            }
            float mu  = s * (1.f/256.f);
            float var = q * (1.f/256.f) - mu*mu;
            float sc  = __ldg(&g2[gn]) * rsqrtf(var + BN_EPS);
            float bb  = __ldg(&be2[gn]);
            float o0, o1, o2, o3, o4, o5, o6, o7, f;
            f = sc*(v0.x-mu)+bb; o0 = f > 0.f ? f : SLOPE*f;
            f = sc*(v0.y-mu)+bb; o1 = f > 0.f ? f : SLOPE*f;
            f = sc*(v0.z-mu)+bb; o2 = f > 0.f ? f : SLOPE*f;
            f = sc*(v0.w-mu)+bb; o3 = f > 0.f ? f : SLOPE*f;
            f = sc*(v1.x-mu)+bb; o4 = f > 0.f ? f : SLOPE*f;
            f = sc*(v1.y-mu)+bb; o5 = f > 0.f ? f : SLOPE*f;
            f = sc*(v1.z-mu)+bb; o6 = f > 0.f ? f : SLOPE*f;
            f = sc*(v1.w-mu)+bb; o7 = f > 0.f ? f : SLOPE*f;
            float pr[8];
            #pragma unroll
            for (int kch = 0; kch < 8; kch++) {
                const float* w = sw3 + kch*64 + c8;
                float4 w0 = *(const float4*)w;
                float4 w1 = *(const float4*)(w + 4);
                pr[kch] = o0*w0.x + o1*w0.y + o2*w0.z + o3*w0.w
                        + o4*w1.x + o5*w1.y + o6*w1.z + o7*w1.w;
            }
            #pragma unroll
            for (int m = 1; m <= 4; m <<= 1) {
                #pragma unroll
                for (int kch = 0; kch < 8; kch++)
                    pr[kch] += __shfl_xor_sync(0xffffffffu, pr[kch], m);
            }
            if ((lane & 7) == 0 && gnode < N_NODES) {
                size_t grow = (size_t)(r0 + node*4 + sub)*2;
                *(float2*)&p0[grow] = make_float2(pr[0], pr[1]);
                *(float2*)&p1[grow] = make_float2(pr[2], pr[3]);
                *(float2*)&p2[grow] = make_float2(pr[4], pr[5]);
                *(float2*)&p3[grow] = make_float2(pr[6], pr[7]);
            }
        }
    }
}

/* ======================================================================= */
extern "C" void kernel_launch(void* const* d_in, const int* in_sizes, int n_in,
                              void* d_out, int out_size) {
    const float* x      = (const float*)d_in[0];
    const int*   src    = (const int*)  d_in[1];
    const int*   dst    = (const int*)  d_in[2];
    const float* ew     = (const float*)d_in[3];
    const float* W1     = (const float*)d_in[4];
    const float* b1     = (const float*)d_in[5];
    const float* W2     = (const float*)d_in[6];
    const float* b2     = (const float*)d_in[7];
    const float* W3     = (const float*)d_in[8];
    const float* b3     = (const float*)d_in[9];
    const float* g1     = (const float*)d_in[10];
    const float* be1    = (const float*)d_in[11];
    const float* g2     = (const float*)d_in[12];
    const float* be2    = (const float*)d_in[13];
    const float* mask   = (const float*)d_in[14];
    const float* mean_y = (const float*)d_in[15];
    const float* std_y  = (const float*)d_in[16];
    const float* vmin   = (const float*)d_in[17];
    const float* vmax   = (const float*)d_in[18];
    const float* qmin   = (const float*)d_in[19];
    const float* qmax   = (const float*)d_in[20];
    float* out = (float*)d_out;

    float *xt, *pa, *pb, *pc, *sa, *sb;
    uint32_t *h16, *t116, *t216, *t316, *w2ph, *w2pl, *w1ph, *w1pl;
    cudaGetSymbolAddress((void**)&xt,  g_xt);
    cudaGetSymbolAddress((void**)&pa,  g_pa);
    cudaGetSymbolAddress((void**)&pb,  g_pb);
    cudaGetSymbolAddress((void**)&pc,  g_pc);
    cudaGetSymbolAddress((void**)&sa,  g_sa);
    cudaGetSymbolAddress((void**)&sb,  g_sb);
    cudaGetSymbolAddress((void**)&h16,  g_h16);
    cudaGetSymbolAddress((void**)&t116, g_t116);
    cudaGetSymbolAddress((void**)&t216, g_t216);
    cudaGetSymbolAddress((void**)&t316, g_t316);
    cudaGetSymbolAddress((void**)&w2ph, g_w2p_hi);
    cudaGetSymbolAddress((void**)&w2pl, g_w2p_lo);
    cudaGetSymbolAddress((void**)&w1ph, g_w1p_hi);
    cudaGetSymbolAddress((void**)&w1pl, g_w1p_lo);

    static int smem_set = 0;
    if (!smem_set) {
        cudaFuncSetAttribute(k_gemm2_mma, cudaFuncAttributeMaxDynamicSharedMemorySize, 36864);
        cudaFuncSetAttribute(k_gemm1_mma, cudaFuncAttributeMaxDynamicSharedMemorySize, 34816);
        smem_set = 1;
    }

    const int TB = 256;
    int gN = (N_NODES + TB - 1) / TB;
    int gE = (N_EDGES + TB - 1) / TB;
    int gR = (R + TB - 1) / TB;
    int gW = (N_NODES*32 + TB - 1) / TB;

    /* preprocessing (fused) */
    k_init_xt<<<gR, TB>>>(x);
    k_deg_w2 <<<gE, TB>>>(dst, ew, W2, W1);
    k_scan1  <<<NB_SCAN, 256>>>();
    k_scan23 <<<NB_SCAN, 256>>>();
    k_fill   <<<gE, TB>>>(src, dst, ew);

    /* layer 1: prop at F=4 (fp32), tensor-core GEMM+BN+LReLU -> fp16 h */
    k_prop_small<4,false><<<gN, TB>>>(xt, pa, nullptr);
    k_prop_small<4,false><<<gN, TB>>>(pa, pb, nullptr);
    k_prop_small<4,false><<<gN, TB>>>(pb, pc, nullptr);
    k_gemm1_mma<<<RPAD/128, 256, 34816>>>(xt, pa, pb, pc, w1ph, w1pl,
                                          b1, g1, be1, h16);

    /* layer 2: 3x fp16 prop64, fused GEMM+BN+projections -> p0..p3 */
    k_prop64h<<<gW, TB>>>(h16,  t116);
    k_prop64h<<<gW, TB>>>(t116, t216);
    k_prop64h<<<gW, TB>>>(t216, t316);
    k_gemm2_mma<<<RPAD/128, 256, 36864>>>(h16, t116, t216, t316, w2ph, w2pl,
                                          b2, g2, be2, W3, pb, pa, sb, sa);

    /* layer 3: Horner at F=2 (p0->pb, p1->pa, p2->sb, p3->sa) */
    k_prop_small<2,true ><<<gN, TB>>>(sa, pc, sb);
    k_prop_small<2,true ><<<gN, TB>>>(pc, sa, pa);
    k_prop2_final<<<gN, TB>>>(sa, pb, b3, mask, mean_y, std_y,
                              vmin, vmax, qmin, qmax, out);
}

// round 11
// speedup vs baseline: 2.3160x; 1.0543x over previous
#include <cuda_runtime.h>
#include <cuda_fp16.h>
#include <math.h>
#include <cstdint>

#define N_NODES 50000
#define N_EDGES 400000
#define BATCH 4
#define R (N_NODES*BATCH)      /* 200000 rows (n,b) */
#define RPAD 200064            /* padded to 128-row GEMM tiles */
#define BN_EPS 1e-5f
#define SLOPE 0.01f
#define NB_SCAN ((N_NODES + 255) / 256)   /* 196 */

/* ---------------- static device scratch (no allocations allowed) -------- */
__device__ __align__(16) float g_deg[N_NODES];
__device__ __align__(16) float g_dis[N_NODES];
__device__ __align__(16) int   g_cnt[N_NODES];
__device__ __align__(16) int   g_rowptr[N_NODES+1];
__device__ __align__(16) int   g_cur[N_NODES];
__device__ __align__(16) int   g_col[N_EDGES];
__device__ __align__(16) float g_wcsr[N_EDGES];
__device__ __align__(16) int   g_bsum[256];

__device__ __align__(16) float g_xt[RPAD*4];
__device__ __align__(16) float g_pa[RPAD*4];
__device__ __align__(16) float g_pb[RPAD*4];
__device__ __align__(16) float g_pc[RPAD*4];

/* fp16 hidden states: [row][64] halfs = [row][32] u32 */
__device__ __align__(16) uint32_t g_h16 [RPAD*32];
__device__ __align__(16) uint32_t g_t116[RPAD*32];
__device__ __align__(16) uint32_t g_t216[RPAD*32];
__device__ __align__(16) uint32_t g_t316[RPAD*32];

__device__ __align__(16) float g_sa[RPAD*2];
__device__ __align__(16) float g_sb[RPAD*2];

/* W2 transposed [64 n][128 kpair], fp16x2-packed */
__device__ __align__(16) uint32_t g_w2p_hi[64*128];
/* W1 transposed [64 n][8 kpair], fp16x2-packed hi/lo (K=16) */
__device__ __align__(16) uint32_t g_w1p_hi[64*8];
__device__ __align__(16) uint32_t g_w1p_lo[64*8];

#define MMAH(C, a0,a1,a2,a3, b0,b1) \
    asm volatile("mma.sync.aligned.m16n8k16.row.col.f32.f16.f16.f32 " \
        "{%0,%1,%2,%3},{%4,%5,%6,%7},{%8,%9},{%0,%1,%2,%3};" \
        : "+f"((C)[0]),"+f"((C)[1]),"+f"((C)[2]),"+f"((C)[3]) \
        : "r"(a0),"r"(a1),"r"(a2),"r"(a3),"r"(b0),"r"(b1))

__device__ __forceinline__ uint32_t h2u(__half2 h) {
    uint32_t u; memcpy(&u, &h, 4); return u;
}
__device__ __forceinline__ __half2 u2h(uint32_t u) {
    __half2 h; memcpy(&h, &u, 4); return h;
}

/* ---------------- preprocessing --------------------------------------- */
__global__ void k_init_xt(const float* __restrict__ x) {
    int t = blockIdx.x*blockDim.x + threadIdx.x;
    if (t < N_NODES) { g_deg[t] = 0.f; g_cnt[t] = 0; }
    if (t < R) {
        int b = t / N_NODES, n = t - b*N_NODES;
        float4 v = ((const float4*)x)[t];
        ((float4*)g_xt)[n*4 + b] = v;
    }
}

__global__ void k_deg_w2(const int* __restrict__ dst, const float* __restrict__ ew,
                         const float* __restrict__ W2, const float* __restrict__ W1) {
    int e = blockIdx.x*blockDim.x + threadIdx.x;
    if (e < N_EDGES) {
        int d = dst[e];
        atomicAdd(&g_deg[d], ew[e]);
        atomicAdd(&g_cnt[d], 1);
    }
    if (e < 64*128) {
        int n = e >> 7, p = e & 127;
        int k0 = 2*p;
        int sel = k0 >> 6, kk = k0 & 63;
        float v0 = W2[sel*4096 + kk*64 + n];
        float v1 = W2[sel*4096 + (kk+1)*64 + n];
        g_w2p_hi[e] = h2u(__floats2half2_rn(v0, v1));
    }
    if (e < 64*8) {
        int n = e >> 3, p = e & 7;
        int k0 = 2*p;
        float v0 = W1[k0*64 + n];
        float v1 = W1[(k0+1)*64 + n];
        __half h0 = __float2half_rn(v0), h1 = __float2half_rn(v1);
        float l0 = v0 - __half2float(h0), l1 = v1 - __half2float(h1);
        g_w1p_hi[e] = h2u(__halves2half2(h0, h1));
        g_w1p_lo[e] = h2u(__floats2half2_rn(l0, l1));
    }
}

__global__ void k_scan1() {
    int t = threadIdx.x, b = blockIdx.x;
    int i = b*256 + t;
    int v = (i < N_NODES) ? g_cnt[i] : 0;
    int lane = t & 31, wp = t >> 5;
    int x = v;
    #pragma unroll
    for (int o = 1; o < 32; o <<= 1) {
        int y = __shfl_up_sync(0xffffffffu, x, o);
        if (lane >= o) x += y;
    }
    __shared__ int wt[8];
    if (lane == 31) wt[wp] = x;
    __syncthreads();
    if (wp == 0 && lane < 8) {
        int y = wt[lane];
        #pragma unroll
        for (int o = 1; o < 8; o <<= 1) {
            int z = __shfl_up_sync(0xffu, y, o);
            if (lane >= o) y += z;
        }
        wt[lane] = y;
    }
    __syncthreads();
    int incl = x + (wp ? wt[wp-1] : 0);
    if (i < N_NODES) g_rowptr[i] = incl - v;
    if (t == 255) g_bsum[b] = incl;
}

__global__ void k_scan23() {
    int t = threadIdx.x, b = blockIdx.x;
    int v = (t < NB_SCAN) ? g_bsum[t] : 0;
    int lane = t & 31, wp = t >> 5;
    int x = v;
    #pragma unroll
    for (int o = 1; o < 32; o <<= 1) {
        int y = __shfl_up_sync(0xffffffffu, x, o);
        if (lane >= o) x += y;
    }
    __shared__ int wt[8];
    __shared__ int s_off;
    if (lane == 31) wt[wp] = x;
    __syncthreads();
    if (wp == 0 && lane < 8) {
        int y = wt[lane];
        #pragma unroll
        for (int o = 1; o < 8; o <<= 1) {
            int z = __shfl_up_sync(0xffu, y, o);
            if (lane >= o) y += z;
        }
        wt[lane] = y;
    }
    __syncthreads();
    int incl = x + (wp ? wt[wp-1] : 0);
    if (t == b) s_off = incl - v;
    __syncthreads();
    int i = b*256 + t;
    if (i < N_NODES) {
        int p = g_rowptr[i] + s_off;
        g_rowptr[i] = p;
        g_cur[i] = p;
        float d = g_deg[i];
        g_dis[i] = (d > 0.f) ? rsqrtf(fmaxf(d, 1e-30f)) : 0.f;
    }
    if (b == NB_SCAN-1 && t == 0) g_rowptr[N_NODES] = N_EDGES;
}

__global__ void k_fill(const int* __restrict__ src, const int* __restrict__ dst,
                       const float* __restrict__ ew) {
    int e = blockIdx.x*blockDim.x + threadIdx.x;
    if (e < N_EDGES) {
        int s = src[e], d = dst[e];
        int p = atomicAdd(&g_cur[d], 1);
        g_col[p]  = s;
        g_wcsr[p] = g_dis[s] * ew[e] * g_dis[d];
    }
}

/* ---------------- propagation ------------------------------------------ */
template<int V4, bool ADD>
__global__ void k_prop_small(const float* __restrict__ in, float* __restrict__ out,
                             const float* __restrict__ add) {
    int n = blockIdx.x*blockDim.x + threadIdx.x;
    if (n >= N_NODES) return;
    float4 acc[V4];
    #pragma unroll
    for (int j = 0; j < V4; j++) acc[j] = make_float4(0.f,0.f,0.f,0.f);
    int s = g_rowptr[n], e = g_rowptr[n+1];
    const float4* base = (const float4*)in;
    int i = s;
    for (; i + 2 <= e; i += 2) {
        int c0 = __ldg(&g_col[i]),     c1 = __ldg(&g_col[i+1]);
        float w0 = __ldg(&g_wcsr[i]),  w1 = __ldg(&g_wcsr[i+1]);
        float4 v0[V4], v1[V4];
        const float4* p0 = base + c0*V4;
        const float4* p1 = base + c1*V4;
        #pragma unroll
        for (int j = 0; j < V4; j++) { v0[j] = __ldg(p0 + j); v1[j] = __ldg(p1 + j); }
        #pragma unroll
        for (int j = 0; j < V4; j++) {
            acc[j].x += w0*v0[j].x; acc[j].y += w0*v0[j].y;
            acc[j].z += w0*v0[j].z; acc[j].w += w0*v0[j].w;
        }
        #pragma unroll
        for (int j = 0; j < V4; j++) {
            acc[j].x += w1*v1[j].x; acc[j].y += w1*v1[j].y;
            acc[j].z += w1*v1[j].z; acc[j].w += w1*v1[j].w;
        }
    }
    if (i < e) {
        int c = __ldg(&g_col[i]);
        float wv = __ldg(&g_wcsr[i]);
        const float4* p = base + c*V4;
        #pragma unroll
        for (int j = 0; j < V4; j++) {
            float4 v = __ldg(p + j);
            acc[j].x += wv*v.x; acc[j].y += wv*v.y;
            acc[j].z += wv*v.z; acc[j].w += wv*v.w;
        }
    }
    float4* q = (float4*)out + n*V4;
    #pragma unroll
    for (int j = 0; j < V4; j++) {
        float4 o = acc[j];
        if (ADD) {
            float4 a = ((const float4*)add)[n*V4 + j];
            o.x += a.x; o.y += a.y; o.z += a.z; o.w += a.w;
        }
        q[j] = o;
    }
}

/* final Horner prop fused with output epilogue */
__global__ void k_prop2_final(const float* __restrict__ in,
                              const float* __restrict__ p0,
                              const float* __restrict__ b3,
                              const float* __restrict__ mask,
                              const float* __restrict__ mean_y,
                              const float* __restrict__ std_y,
                              const float* __restrict__ vmin, const float* __restrict__ vmax,
                              const float* __restrict__ qmin, const float* __restrict__ qmax,
                              float* __restrict__ out) {
    int n = blockIdx.x*blockDim.x + threadIdx.x;
    if (n >= N_NODES) return;
    float4 a0 = make_float4(0.f,0.f,0.f,0.f), a1 = a0;
    int s = g_rowptr[n], e = g_rowptr[n+1];
    const float4* base = (const float4*)in;
    int i = s;
    for (; i + 2 <= e; i += 2) {
        int c0 = __ldg(&g_col[i]),    c1 = __ldg(&g_col[i+1]);
        float w0 = __ldg(&g_wcsr[i]), w1 = __ldg(&g_wcsr[i+1]);
        float4 x0 = __ldg(base + c0*2), x1 = __ldg(base + c0*2 + 1);
        float4 y0 = __ldg(base + c1*2), y1 = __ldg(base + c1*2 + 1);
        a0.x += w0*x0.x; a0.y += w0*x0.y; a0.z += w0*x0.z; a0.w += w0*x0.w;
        a1.x += w0*x1.x; a1.y += w0*x1.y; a1.z += w0*x1.z; a1.w += w0*x1.w;
        a0.x += w1*y0.x; a0.y += w1*y0.y; a0.z += w1*y0.z; a0.w += w1*y0.w;
        a1.x += w1*y1.x; a1.y += w1*y1.y; a1.z += w1*y1.z; a1.w += w1*y1.w;
    }
    if (i < e) {
        int c = __ldg(&g_col[i]);
        float wv = __ldg(&g_wcsr[i]);
        float4 v0 = __ldg(base + c*2), v1 = __ldg(base + c*2 + 1);
        a0.x += wv*v0.x; a0.y += wv*v0.y; a0.z += wv*v0.z; a0.w += wv*v0.w;
        a1.x += wv*v1.x; a1.y += wv*v1.y; a1.z += wv*v1.z; a1.w += wv*v1.w;
    }
    float4 z0 = ((const float4*)p0)[n*2];
    float4 z1 = ((const float4*)p0)[n*2 + 1];
    float b30 = __ldg(&b3[0]), b31 = __ldg(&b3[1]);
    float u[4][2] = {
        {a0.x + z0.x + b30, a0.y + z0.y + b31},
        {a0.z + z0.z + b30, a0.w + z0.w + b31},
        {a1.x + z1.x + b30, a1.y + z1.y + b31},
        {a1.z + z1.z + b30, a1.w + z1.w + b31}
    };
    float s0 = std_y[n*2], s1 = std_y[n*2+1];
    if (isinf(s0)) s0 = 0.f;
    if (isinf(s1)) s1 = 0.f;
    float m0 = mask[n*2], m1 = mask[n*2+1];
    float me0 = mean_y[n*2], me1 = mean_y[n*2+1];
    float vlo = vmin[n], vhi = vmax[n];
    float qlo = qmin[n], qhi = qmax[n];
    #pragma unroll
    for (int b = 0; b < 4; b++) {
        float o0 = (u[b][0]*s0 + me0) * m0;
        float o1 = (u[b][1]*s1 + me1) * m1;
        o0 = fminf(fmaxf(o0, vlo), vhi);
        o1 = fminf(fmaxf(o1, qlo), qhi);
        *(float2*)&out[(size_t)(b*N_NODES + n)*2] = make_float2(o0, o1);
    }
}

/* fp16 payload prop: warp per node, 4-way predicated edge loop */
__global__ void k_prop64h(const uint32_t* __restrict__ in, uint32_t* __restrict__ out) {
    int gt = blockIdx.x*blockDim.x + threadIdx.x;
    int n = gt >> 5, lane = gt & 31;
    if (n >= N_NODES) return;
    int s = g_rowptr[n], e = g_rowptr[n+1];
    float2 a0 = make_float2(0.f,0.f), a1 = a0, a2 = a0, a3 = a0;
    for (int i = s; i < e; i += 4) {
        int   c[4];
        float w[4];
        uint4 v[4];
        #pragma unroll
        for (int j = 0; j < 4; j++) {
            int idx = i + j;
            bool act = idx < e;
            c[j] = act ? __ldg(&g_col[idx]) : 0;
            w[j] = act ? __ldg(&g_wcsr[idx]) : 0.f;
        }
        #pragma unroll
        for (int j = 0; j < 4; j++)
            v[j] = __ldg((const uint4*)(in + c[j]*128 + lane*4));
        #pragma unroll
        for (int j = 0; j < 4; j++) {
            float2 f;
            f = __half22float2(u2h(v[j].x)); a0.x += w[j]*f.x; a0.y += w[j]*f.y;
            f = __half22float2(u2h(v[j].y)); a1.x += w[j]*f.x; a1.y += w[j]*f.y;
            f = __half22float2(u2h(v[j].z)); a2.x += w[j]*f.x; a2.y += w[j]*f.y;
            f = __half22float2(u2h(v[j].w)); a3.x += w[j]*f.x; a3.y += w[j]*f.y;
        }
    }
    uint4 o;
    o.x = h2u(__floats2half2_rn(a0.x, a0.y));
    o.y = h2u(__floats2half2_rn(a1.x, a1.y));
    o.z = h2u(__floats2half2_rn(a2.x, a2.y));
    o.w = h2u(__floats2half2_rn(a3.x, a3.y));
    *(uint4*)(out + n*128 + lane*4) = o;
}

/* ---------------- layer-1 GEMM on tensor cores + BN + LReLU -> fp16 h --- */
__global__ void __launch_bounds__(256, 2)
k_gemm1_mma(const float* __restrict__ A0, const float* __restrict__ A1,
            const float* __restrict__ A2, const float* __restrict__ A3,
            const uint32_t* __restrict__ w1h, const uint32_t* __restrict__ w1l,
            const float* __restrict__ b1,
            const float* __restrict__ g1, const float* __restrict__ be1,
            uint32_t* __restrict__ hout) {
    extern __shared__ uint32_t smu[];
    float* smf = (float*)smu;
    const int t = threadIdx.x;
    const int lane = t & 31, wid = t >> 5;
    const int wrow = wid >> 1, wcol = wid & 1;
    const int r0 = blockIdx.x * 128;

    {
        int n = t >> 2, c4 = t & 3;
        int regbit = (c4 >> 1) & 1, q0 = (c4 & 1) * 2;
        int g = n & 7, nt = n >> 3;
        int b_w = 2048 + nt*64 + (g*4 + q0)*2 + regbit;
        uint2 vh = *(const uint2*)(w1h + n*8 + c4*2);
        uint2 vl = *(const uint2*)(w1l + n*8 + c4*2);
        smu[b_w]       = vh.x;
        smu[b_w + 2]   = vh.y;
        smu[512 + b_w]     = vl.x;
        smu[512 + b_w + 2] = vl.y;
    }
    #pragma unroll
    for (int sidx = 0; sidx < 2; sidx++) {
        int idx = sidx*256 + t;
        int row = idx >> 2, c4 = idx & 3;
        int rr = row & 15, mt = row >> 4;
        int regbit = (c4 >> 1) & 1, q0 = (c4 & 1) * 2;
        int g = rr & 7, abit = rr >> 3;
        int a_w = mt*128 + (g*4 + q0)*4 + abit + 2*regbit;
        const float* Ap = (c4 == 0) ? A0 : (c4 == 1) ? A1 : (c4 == 2) ? A2 : A3;
        float4 v = *(const float4*)(Ap + (size_t)(r0 + row)*4);
        __half2 h0 = __floats2half2_rn(v.x, v.y);
        __half2 h1 = __floats2half2_rn(v.z, v.w);
        float lx = v.x - __low2float(h0), ly = v.y - __high2float(h0);
        float lz = v.z - __low2float(h1), lw = v.w - __high2float(h1);
        smu[a_w]        = h2u(h0);
        smu[a_w + 4]    = h2u(h1);
        smu[1024 + a_w]     = h2u(__floats2half2_rn(lx, ly));
        smu[1024 + a_w + 4] = h2u(__floats2half2_rn(lz, lw));
    }
    __syncthreads();

    float c[2][4][4];
    #pragma unroll
    for (int m = 0; m < 2; m++)
        #pragma unroll
        for (int n = 0; n < 4; n++)
            #pragma unroll
            for (int k = 0; k < 4; k++) c[m][n][k] = 0.f;

    {
        uint4 ahi[2], alo[2];
        #pragma unroll
        for (int mt = 0; mt < 2; mt++) {
            int mtile = wrow*2 + mt;
            ahi[mt] = *(const uint4*)(smu + mtile*128 + lane*4);
            alo[mt] = *(const uint4*)(smu + 1024 + mtile*128 + lane*4);
        }
        uint2 bh[4], bl[4];
        #pragma unroll
        for (int nt = 0; nt < 4; nt++) {
            int ntile = wcol*4 + nt;
            bh[nt] = *(const uint2*)(smu + 2048 + ntile*64 + lane*2);
            bl[nt] = *(const uint2*)(smu + 2560 + ntile*64 + lane*2);
        }
        #pragma unroll
        for (int mt = 0; mt < 2; mt++)
            #pragma unroll
            for (int nt = 0; nt < 4; nt++) {
                MMAH(c[mt][nt], ahi[mt].x, ahi[mt].y, ahi[mt].z, ahi[mt].w,
                     bh[nt].x, bh[nt].y);
                MMAH(c[mt][nt], ahi[mt].x, ahi[mt].y, ahi[mt].z, ahi[mt].w,
                     bl[nt].x, bl[nt].y);
                MMAH(c[mt][nt], alo[mt].x, alo[mt].y, alo[mt].z, alo[mt].w,
                     bh[nt].x, bh[nt].y);
            }
    }
    __syncthreads();

    {
        float* so = smf;
        const int g = lane >> 2, q = lane & 3;
        #pragma unroll
        for (int mt = 0; mt < 2; mt++) {
            int lr = wrow*32 + mt*16 + g;
            #pragma unroll
            for (int nt = 0; nt < 4; nt++) {
                int col = wcol*32 + nt*8 + 2*q;
                float bx = __ldg(&b1[col]), by = __ldg(&b1[col+1]);
                so[lr*68+col]       = c[mt][nt][0] + bx;
                so[lr*68+col+1]     = c[mt][nt][1] + by;
                so[(lr+8)*68+col]   = c[mt][nt][2] + bx;
                so[(lr+8)*68+col+1] = c[mt][nt][3] + by;
            }
        }
    }
    __syncthreads();
    {
        const float* so = smf;
        int sub = lane >> 3, c8 = (lane & 7) * 8;
        #pragma unroll
        for (int nn = 0; nn < 4; nn++) {
            int node = wid*4 + nn;
            int gnode = blockIdx.x*32 + node;
            int gn = gnode < N_NODES ? gnode : N_NODES-1;
            const float* rp = so + (node*4 + sub)*68 + c8;
            float4 v0 = *(const float4*)rp;
            float4 v1 = *(const float4*)(rp + 4);
            float s = v0.x+v0.y+v0.z+v0.w + v1.x+v1.y+v1.z+v1.w;
            float q = v0.x*v0.x+v0.y*v0.y+v0.z*v0.z+v0.w*v0.w
                    + v1.x*v1.x+v1.y*v1.y+v1.z*v1.z+v1.w*v1.w;
            #pragma unroll
            for (int o = 16; o; o >>= 1) {
                s += __shfl_xor_sync(0xffffffffu, s, o);
                q += __shfl_xor_sync(0xffffffffu, q, o);
            }
            float mu  = s * (1.f/256.f);
            float var = q * (1.f/256.f) - mu*mu;
            float sc  = __ldg(&g1[gn]) * rsqrtf(var + BN_EPS);
            float bb  = __ldg(&be1[gn]);
            float o0, o1, o2, o3, o4, o5, o6, o7, f;
            f = sc*(v0.x-mu)+bb; o0 = f > 0.f ? f : SLOPE*f;
            f = sc*(v0.y-mu)+bb; o1 = f > 0.f ? f : SLOPE*f;
            f = sc*(v0.z-mu)+bb; o2 = f > 0.f ? f : SLOPE*f;
            f = sc*(v0.w-mu)+bb; o3 = f > 0.f ? f : SLOPE*f;
            f = sc*(v1.x-mu)+bb; o4 = f > 0.f ? f : SLOPE*f;
            f = sc*(v1.y-mu)+bb; o5 = f > 0.f ? f : SLOPE*f;
            f = sc*(v1.z-mu)+bb; o6 = f > 0.f ? f : SLOPE*f;
            f = sc*(v1.w-mu)+bb; o7 = f > 0.f ? f : SLOPE*f;
            if (gnode < N_NODES) {
                uint4 pk;
                pk.x = h2u(__floats2half2_rn(o0, o1));
                pk.y = h2u(__floats2half2_rn(o2, o3));
                pk.z = h2u(__floats2half2_rn(o4, o5));
                pk.w = h2u(__floats2half2_rn(o6, o7));
                *(uint4*)&hout[(size_t)(r0 + node*4 + sub)*32 + (lane & 7)*4] = pk;
            }
        }
    }
}

/* ---------------- layer-2 GEMM (fp16 A, fp16 B) + BN + projections ------
 * stage (u32): A[0,2048) BHI[2048,3072); 2 stages = 6144 u32 = 24 KB.
 * Epilogue smem float[128*68]=34816 B + W3 512 floats at SW3_OFF.        */
#define STG_U32 3072
#define SW3_OFF 8704
__global__ void __launch_bounds__(256, 2)
k_gemm2_mma(const uint32_t* __restrict__ A0, const uint32_t* __restrict__ A1,
            const uint32_t* __restrict__ A2, const uint32_t* __restrict__ A3,
            const uint32_t* __restrict__ wph,
            const float* __restrict__ b2,
            const float* __restrict__ g2, const float* __restrict__ be2,
            const float* __restrict__ W3,
            float* __restrict__ p0, float* __restrict__ p1,
            float* __restrict__ p2, float* __restrict__ p3) {
    extern __shared__ uint32_t smu[];
    float* smf = (float*)smu;
    const int t = threadIdx.x;
    const int lane = t & 31, wid = t >> 5;
    const int wrow = wid >> 1, wcol = wid & 1;
    const int r0 = blockIdx.x * 128;

    #pragma unroll
    for (int i2 = t; i2 < 512; i2 += 256) {
        int kch = i2 >> 6, f = i2 & 63;
        smf[SW3_OFF + i2] = W3[(kch >> 1)*128 + f*2 + (kch & 1)];
    }

    int a_w[4], a_src[4];
    #pragma unroll
    for (int i = 0; i < 4; i++) {
        int idx = i*256 + t;
        int row = idx >> 3, c4 = idx & 7;
        int rr = row & 15, mt = row >> 4;
        int ks = c4 >> 2, regbit = (c4 >> 1) & 1, q0 = (c4 & 1) * 2;
        int g = rr & 7, abit = rr >> 3;
        a_w[i] = (mt*2 + ks)*128 + (g*4 + q0)*4 + abit + 2*regbit;
        a_src[i] = row*32 + c4*2;
    }
    int b_w[2], b_src[2];
    #pragma unroll
    for (int i = 0; i < 2; i++) {
        int idx = i*256 + t;
        int n = idx >> 3, c4 = idx & 7;
        int ks = c4 >> 2, regbit = (c4 >> 1) & 1, q0 = (c4 & 1) * 2;
        int g = n & 7, nt = n >> 3;
        b_w[i] = 2048 + (nt*2 + ks)*64 + (g*4 + q0)*2 + regbit;
        b_src[i] = n*128 + c4*2;
    }

    float c[2][4][4];
    #pragma unroll
    for (int m = 0; m < 2; m++)
        #pragma unroll
        for (int n = 0; n < 4; n++)
            #pragma unroll
            for (int k = 0; k < 4; k++) c[m][n][k] = 0.f;

    uint2 pa[4], pbh[2];

    {
        #pragma unroll
        for (int i = 0; i < 4; i++)
            pa[i] = *(const uint2*)(A0 + (size_t)r0*32 + a_src[i]);
        #pragma unroll
        for (int i = 0; i < 2; i++)
            pbh[i] = *(const uint2*)(wph + b_src[i]);
        uint32_t* base = smu;
        #pragma unroll
        for (int i = 0; i < 4; i++) {
            base[a_w[i]]     = pa[i].x;
            base[a_w[i] + 4] = pa[i].y;
        }
        #pragma unroll
        for (int i = 0; i < 2; i++) {
            base[b_w[i]]     = pbh[i].x;
            base[b_w[i] + 2] = pbh[i].y;
        }
    }
    __syncthreads();

    #pragma unroll 1
    for (int cc = 0; cc < 8; cc++) {
        int stage = cc & 1;
        if (cc < 7) {
            int cn = cc + 1;
            const uint32_t* Ap = (cn < 2) ? A0 : (cn < 4) ? A1 : (cn < 6) ? A2 : A3;
            int kb = (cn & 1) * 16;
            #pragma unroll
            for (int i = 0; i < 4; i++)
                pa[i] = *(const uint2*)(Ap + (size_t)r0*32 + a_src[i] + kb);
            #pragma unroll
            for (int i = 0; i < 2; i++)
                pbh[i] = *(const uint2*)(wph + b_src[i] + cn*16);
        }
        {
            const uint32_t* base = smu + stage*STG_U32;
            #pragma unroll
            for (int ks = 0; ks < 2; ks++) {
                uint4 ah[2];
                #pragma unroll
                for (int mt = 0; mt < 2; mt++) {
                    int mtile = wrow*2 + mt;
                    ah[mt] = *(const uint4*)(base + (mtile*2+ks)*128 + lane*4);
                }
                uint2 bh[4];
                #pragma unroll
                for (int nt = 0; nt < 4; nt++) {
                    int ntile = wcol*4 + nt;
                    bh[nt] = *(const uint2*)(base + 2048 + (ntile*2+ks)*64 + lane*2);
                }
                #pragma unroll
                for (int mt = 0; mt < 2; mt++)
                    #pragma unroll
                    for (int nt = 0; nt < 4; nt++)
                        MMAH(c[mt][nt], ah[mt].x, ah[mt].y, ah[mt].z, ah[mt].w,
                             bh[nt].x, bh[nt].y);
            }
        }
        if (cc < 7) {
            uint32_t* base = smu + ((cc+1)&1)*STG_U32;
            #pragma unroll
            for (int i = 0; i < 4; i++) {
                base[a_w[i]]     = pa[i].x;
                base[a_w[i] + 4] = pa[i].y;
            }
            #pragma unroll
            for (int i = 0; i < 2; i++) {
                base[b_w[i]]     = pbh[i].x;
                base[b_w[i] + 2] = pbh[i].y;
            }
        }
        __syncthreads();
    }

    /* ---- fused BN2 + LeakyReLU + W3 projections ---- */
    {
        float* so = smf;
        const int g = lane >> 2, q = lane & 3;
        #pragma unroll
        for (int mt = 0; mt < 2; mt++) {
            int lr = wrow*32 + mt*16 + g;
            #pragma unroll
            for (int nt = 0; nt < 4; nt++) {
                int col = wcol*32 + nt*8 + 2*q;
                float bx = __ldg(&b2[col]), by = __ldg(&b2[col+1]);
                so[lr*68+col]       = c[mt][nt][0] + bx;
                so[lr*68+col+1]     = c[mt][nt][1] + by;
                so[(lr+8)*68+col]   = c[mt][nt][2] + bx;
                so[(lr+8)*68+col+1] = c[mt][nt][3] + by;
            }
        }
    }
    __syncthreads();
    {
        const float* so = smf;
        const float* sw3 = smf + SW3_OFF;
        int sub = lane >> 3, c8 = (lane & 7) * 8;
        #pragma unroll
        for (int nn = 0; nn < 4; nn++) {
            int node = wid*4 + nn;
            int gnode = blockIdx.x*32 + node;
            int gn = gnode < N_NODES ? gnode : N_NODES-1;
            const float* rp = so + (node*4 + sub)*68 + c8;
            float4 v0 = *(const float4*)rp;
            float4 v1 = *(const float4*)(rp + 4);
            float s = v0.x+v0.y+v0.z+v0.w + v1.x+v1.y+v1.z+v1.w;
            float q = v0.x*v0.x+v0.y*v0.y+v0.z*v0.z+v0.w*v0.w
                    + v1.x*v1.x+v1.y*v1.y+v1.z*v1.z+v1.w*v1.w;
            #pragma unroll
            for (int o = 16; o; o >>= 1) {
                s += __shfl_xor_sync(0xffffffffu, s, o);
                q += __shfl_xor_sync(0xffffffffu, q, o);
            }
            float mu  = s * (1.f/256.f);
            float var = q * (1.f/256.f) - mu*mu;
            float sc  = __ldg(&g2[gn]) * rsqrtf(var + BN_EPS);
            float bb  = __ldg(&be2[gn]);
            float o0, o1, o2, o3, o4, o5, o6, o7, f;
            f = sc*(v0.x-mu)+bb; o0 = f > 0.f ? f : SLOPE*f;
            f = sc*(v0.y-mu)+bb; o1 = f > 0.f ? f : SLOPE*f;
            f = sc*(v0.z-mu)+bb; o2 = f > 0.f ? f : SLOPE*f;
            f = sc*(v0.w-mu)+bb; o3 = f > 0.f ? f : SLOPE*f;
            f = sc*(v1.x-mu)+bb; o4 = f > 0.f ? f : SLOPE*f;
            f = sc*(v1.y-mu)+bb; o5 = f > 0.f ? f : SLOPE*f;
            f = sc*(v1.z-mu)+bb; o6 = f > 0.f ? f : SLOPE*f;
            f = sc*(v1.w-mu)+bb; o7 = f > 0.f ? f : SLOPE*f;
            float pr[8];
            #pragma unroll
            for (int kch = 0; kch < 8; kch++) {
                const float* w = sw3 + kch*64 + c8;
                float4 w0 = *(const float4*)w;
                float4 w1 = *(const float4*)(w + 4);
                pr[kch] = o0*w0.x + o1*w0.y + o2*w0.z + o3*w0.w
                        + o4*w1.x + o5*w1.y + o6*w1.z + o7*w1.w;
            }
            #pragma unroll
            for (int m = 1; m <= 4; m <<= 1) {
                #pragma unroll
                for (int kch = 0; kch < 8; kch++)
                    pr[kch] += __shfl_xor_sync(0xffffffffu, pr[kch], m);
            }
            if ((lane & 7) == 0 && gnode < N_NODES) {
                size_t grow = (size_t)(r0 + node*4 + sub)*2;
                *(float2*)&p0[grow] = make_float2(pr[0], pr[1]);
                *(float2*)&p1[grow] = make_float2(pr[2], pr[3]);
                *(float2*)&p2[grow] = make_float2(pr[4], pr[5]);
                *(float2*)&p3[grow] = make_float2(pr[6], pr[7]);
            }
        }
    }
}

/* ======================================================================= */
extern "C" void kernel_launch(void* const* d_in, const int* in_sizes, int n_in,
                              void* d_out, int out_size) {
    const float* x      = (const float*)d_in[0];
    const int*   src    = (const int*)  d_in[1];
    const int*   dst    = (const int*)  d_in[2];
    const float* ew     = (const float*)d_in[3];
    const float* W1     = (const float*)d_in[4];
    const float* b1     = (const float*)d_in[5];
    const float* W2     = (const float*)d_in[6];
    const float* b2     = (const float*)d_in[7];
    const float* W3     = (const float*)d_in[8];
    const float* b3     = (const float*)d_in[9];
    const float* g1     = (const float*)d_in[10];
    const float* be1    = (const float*)d_in[11];
    const float* g2     = (const float*)d_in[12];
    const float* be2    = (const float*)d_in[13];
    const float* mask   = (const float*)d_in[14];
    const float* mean_y = (const float*)d_in[15];
    const float* std_y  = (const float*)d_in[16];
    const float* vmin   = (const float*)d_in[17];
    const float* vmax   = (const float*)d_in[18];
    const float* qmin   = (const float*)d_in[19];
    const float* qmax   = (const float*)d_in[20];
    float* out = (float*)d_out;

    float *xt, *pa, *pb, *pc, *sa, *sb;
    uint32_t *h16, *t116, *t216, *t316, *w2ph, *w1ph, *w1pl;
    cudaGetSymbolAddress((void**)&xt,  g_xt);
    cudaGetSymbolAddress((void**)&pa,  g_pa);
    cudaGetSymbolAddress((void**)&pb,  g_pb);
    cudaGetSymbolAddress((void**)&pc,  g_pc);
    cudaGetSymbolAddress((void**)&sa,  g_sa);
    cudaGetSymbolAddress((void**)&sb,  g_sb);
    cudaGetSymbolAddress((void**)&h16,  g_h16);
    cudaGetSymbolAddress((void**)&t116, g_t116);
    cudaGetSymbolAddress((void**)&t216, g_t216);
    cudaGetSymbolAddress((void**)&t316, g_t316);
    cudaGetSymbolAddress((void**)&w2ph, g_w2p_hi);
    cudaGetSymbolAddress((void**)&w1ph, g_w1p_hi);
    cudaGetSymbolAddress((void**)&w1pl, g_w1p_lo);

    static int smem_set = 0;
    if (!smem_set) {
        cudaFuncSetAttribute(k_gemm2_mma, cudaFuncAttributeMaxDynamicSharedMemorySize, 36864);
        cudaFuncSetAttribute(k_gemm1_mma, cudaFuncAttributeMaxDynamicSharedMemorySize, 34816);
        smem_set = 1;
    }

    const int TB = 256;
    int gN = (N_NODES + TB - 1) / TB;
    int gE = (N_EDGES + TB - 1) / TB;
    int gR = (R + TB - 1) / TB;
    int gW = (N_NODES*32 + TB - 1) / TB;

    /* preprocessing (fused) */
    k_init_xt<<<gR, TB>>>(x);
    k_deg_w2 <<<gE, TB>>>(dst, ew, W2, W1);
    k_scan1  <<<NB_SCAN, 256>>>();
    k_scan23 <<<NB_SCAN, 256>>>();
    k_fill   <<<gE, TB>>>(src, dst, ew);

    /* layer 1: prop at F=4 (fp32), tensor-core GEMM+BN+LReLU -> fp16 h */
    k_prop_small<4,false><<<gN, TB>>>(xt, pa, nullptr);
    k_prop_small<4,false><<<gN, TB>>>(pa, pb, nullptr);
    k_prop_small<4,false><<<gN, TB>>>(pb, pc, nullptr);
    k_gemm1_mma<<<RPAD/128, 256, 34816>>>(xt, pa, pb, pc, w1ph, w1pl,
                                          b1, g1, be1, h16);

    /* layer 2: 3x fp16 prop64, fused GEMM+BN+projections -> p0..p3 */
    k_prop64h<<<gW, TB>>>(h16,  t116);
    k_prop64h<<<gW, TB>>>(t116, t216);
    k_prop64h<<<gW, TB>>>(t216, t316);
    k_gemm2_mma<<<RPAD/128, 256, 36864>>>(h16, t116, t216, t316, w2ph,
                                          b2, g2, be2, W3, pb, pa, sb, sa);

    /* layer 3: Horner at F=2 (p0->pb, p1->pa, p2->sb, p3->sa) */
    k_prop_small<2,true ><<<gN, TB>>>(sa, pc, sb);
    k_prop_small<2,true ><<<gN, TB>>>(pc, sa, pa);
    k_prop2_final<<<gN, TB>>>(sa, pb, b3, mask, mean_y, std_y,
                              vmin, vmax, qmin, qmax, out);
}

// round 13
// speedup vs baseline: 2.4431x; 1.0549x over previous
#include <cuda_runtime.h>
#include <cuda_fp16.h>
#include <math.h>
#include <cstdint>

#define N_NODES 50000
#define N_EDGES 400000
#define BATCH 4
#define R (N_NODES*BATCH)      /* 200000 rows (n,b) */
#define RPAD 200064            /* padded to 128-row GEMM tiles */
#define BN_EPS 1e-5f
#define SLOPE 0.01f
#define NB_SCAN ((N_NODES + 255) / 256)   /* 196 */

/* ---------------- static device scratch (no allocations allowed) -------- */
__device__ __align__(16) float g_deg[N_NODES];
__device__ __align__(16) float g_dis[N_NODES];
__device__ __align__(16) int   g_cnt[N_NODES];
__device__ __align__(16) int   g_rowptr[N_NODES+1];
__device__ __align__(16) int   g_cur[N_NODES];
__device__ __align__(16) int   g_col[N_EDGES];
__device__ __align__(16) float g_wcsr[N_EDGES];
__device__ __align__(16) int   g_bsum[256];

/* fp16 layer-1 features: [row][4 halfs] = [row][2 u32]; node owns 4 rows */
__device__ __align__(16) uint32_t g_x16 [RPAD*2];
__device__ __align__(16) uint32_t g_pa16[RPAD*2];
__device__ __align__(16) uint32_t g_pb16[RPAD*2];
__device__ __align__(16) uint32_t g_pc16[RPAD*2];

/* float scratch for layer-3 p-values ([R][2] each) */
__device__ __align__(16) float g_pa[RPAD*4];
__device__ __align__(16) float g_pb[RPAD*4];
__device__ __align__(16) float g_pc[RPAD*4];
__device__ __align__(16) float g_sa[RPAD*2];
__device__ __align__(16) float g_sb[RPAD*2];

/* fp16 hidden states: [row][64] halfs = [row][32] u32 */
__device__ __align__(16) uint32_t g_h16 [RPAD*32];
__device__ __align__(16) uint32_t g_t116[RPAD*32];
__device__ __align__(16) uint32_t g_t216[RPAD*32];
__device__ __align__(16) uint32_t g_t316[RPAD*32];

/* W2 transposed [64 n][128 kpair], fp16x2-packed */
__device__ __align__(16) uint32_t g_w2p_hi[64*128];
/* W1 transposed [64 n][8 kpair], fp16x2-packed hi/lo (K=16) */
__device__ __align__(16) uint32_t g_w1p_hi[64*8];
__device__ __align__(16) uint32_t g_w1p_lo[64*8];

#define MMAH(C, a0,a1,a2,a3, b0,b1) \
    asm volatile("mma.sync.aligned.m16n8k16.row.col.f32.f16.f16.f32 " \
        "{%0,%1,%2,%3},{%4,%5,%6,%7},{%8,%9},{%0,%1,%2,%3};" \
        : "+f"((C)[0]),"+f"((C)[1]),"+f"((C)[2]),"+f"((C)[3]) \
        : "r"(a0),"r"(a1),"r"(a2),"r"(a3),"r"(b0),"r"(b1))

__device__ __forceinline__ uint32_t h2u(__half2 h) {
    uint32_t u; memcpy(&u, &h, 4); return u;
}
__device__ __forceinline__ __half2 u2h(uint32_t u) {
    __half2 h; memcpy(&h, &u, 4); return h;
}

/* ---------------- preprocessing --------------------------------------- */
__global__ void k_init_xt(const float* __restrict__ x) {
    int t = blockIdx.x*blockDim.x + threadIdx.x;
    if (t < N_NODES) { g_deg[t] = 0.f; g_cnt[t] = 0; }
    if (t < R) {
        int b = t / N_NODES, n = t - b*N_NODES;
        float4 v = ((const float4*)x)[t];
        uint2 pk;
        pk.x = h2u(__floats2half2_rn(v.x, v.y));
        pk.y = h2u(__floats2half2_rn(v.z, v.w));
        *(uint2*)&g_x16[(size_t)(n*4 + b)*2] = pk;
    }
}

__global__ void k_deg_w2(const int* __restrict__ dst, const float* __restrict__ ew,
                         const float* __restrict__ W2, const float* __restrict__ W1) {
    int e = blockIdx.x*blockDim.x + threadIdx.x;
    if (e < N_EDGES) {
        int d = dst[e];
        atomicAdd(&g_deg[d], ew[e]);
        atomicAdd(&g_cnt[d], 1);
    }
    if (e < 64*128) {
        int n = e >> 7, p = e & 127;
        int k0 = 2*p;
        int sel = k0 >> 6, kk = k0 & 63;
        float v0 = W2[sel*4096 + kk*64 + n];
        float v1 = W2[sel*4096 + (kk+1)*64 + n];
        g_w2p_hi[e] = h2u(__floats2half2_rn(v0, v1));
    }
    if (e < 64*8) {
        int n = e >> 3, p = e & 7;
        int k0 = 2*p;
        float v0 = W1[k0*64 + n];
        float v1 = W1[(k0+1)*64 + n];
        __half h0 = __float2half_rn(v0), h1 = __float2half_rn(v1);
        float l0 = v0 - __half2float(h0), l1 = v1 - __half2float(h1);
        g_w1p_hi[e] = h2u(__halves2half2(h0, h1));
        g_w1p_lo[e] = h2u(__floats2half2_rn(l0, l1));
    }
}

__global__ void k_scan1() {
    int t = threadIdx.x, b = blockIdx.x;
    int i = b*256 + t;
    int v = (i < N_NODES) ? g_cnt[i] : 0;
    int lane = t & 31, wp = t >> 5;
    int x = v;
    #pragma unroll
    for (int o = 1; o < 32; o <<= 1) {
        int y = __shfl_up_sync(0xffffffffu, x, o);
        if (lane >= o) x += y;
    }
    __shared__ int wt[8];
    if (lane == 31) wt[wp] = x;
    __syncthreads();
    if (wp == 0 && lane < 8) {
        int y = wt[lane];
        #pragma unroll
        for (int o = 1; o < 8; o <<= 1) {
            int z = __shfl_up_sync(0xffu, y, o);
            if (lane >= o) y += z;
        }
        wt[lane] = y;
    }
    __syncthreads();
    int incl = x + (wp ? wt[wp-1] : 0);
    if (i < N_NODES) g_rowptr[i] = incl - v;
    if (t == 255) g_bsum[b] = incl;
}

__global__ void k_scan23() {
    int t = threadIdx.x, b = blockIdx.x;
    int v = (t < NB_SCAN) ? g_bsum[t] : 0;
    int lane = t & 31, wp = t >> 5;
    int x = v;
    #pragma unroll
    for (int o = 1; o < 32; o <<= 1) {
        int y = __shfl_up_sync(0xffffffffu, x, o);
        if (lane >= o) x += y;
    }
    __shared__ int wt[8];
    __shared__ int s_off;
    if (lane == 31) wt[wp] = x;
    __syncthreads();
    if (wp == 0 && lane < 8) {
        int y = wt[lane];
        #pragma unroll
        for (int o = 1; o < 8; o <<= 1) {
            int z = __shfl_up_sync(0xffu, y, o);
            if (lane >= o) y += z;
        }
        wt[lane] = y;
    }
    __syncthreads();
    int incl = x + (wp ? wt[wp-1] : 0);
    if (t == b) s_off = incl - v;
    __syncthreads();
    int i = b*256 + t;
    if (i < N_NODES) {
        int p = g_rowptr[i] + s_off;
        g_rowptr[i] = p;
        g_cur[i] = p;
        float d = g_deg[i];
        g_dis[i] = (d > 0.f) ? rsqrtf(fmaxf(d, 1e-30f)) : 0.f;
    }
    if (b == NB_SCAN-1 && t == 0) g_rowptr[N_NODES] = N_EDGES;
}

__global__ void k_fill(const int* __restrict__ src, const int* __restrict__ dst,
                       const float* __restrict__ ew) {
    int e = blockIdx.x*blockDim.x + threadIdx.x;
    if (e < N_EDGES) {
        int s = src[e], d = dst[e];
        int p = atomicAdd(&g_cur[d], 1);
        g_col[p]  = s;
        g_wcsr[p] = g_dis[s] * ew[e] * g_dis[d];
    }
}

/* ---------------- propagation ------------------------------------------ */
/* fp16 F=4 prop over all 4 batch rows: 8 u32 (16 halfs) per node */
__global__ void k_prop4h(const uint32_t* __restrict__ in, uint32_t* __restrict__ out) {
    int n = blockIdx.x*blockDim.x + threadIdx.x;
    if (n >= N_NODES) return;
    float4 a0 = make_float4(0.f,0.f,0.f,0.f), a1 = a0, a2 = a0, a3 = a0;
    int s = g_rowptr[n], e = g_rowptr[n+1];
    int i = s;
    for (; i + 2 <= e; i += 2) {
        int c0 = __ldg(&g_col[i]),    c1 = __ldg(&g_col[i+1]);
        float w0 = __ldg(&g_wcsr[i]), w1 = __ldg(&g_wcsr[i+1]);
        uint4 u0a = __ldg((const uint4*)(in + c0*8));
        uint4 u0b = __ldg((const uint4*)(in + c0*8 + 4));
        uint4 u1a = __ldg((const uint4*)(in + c1*8));
        uint4 u1b = __ldg((const uint4*)(in + c1*8 + 4));
        float2 f;
        f = __half22float2(u2h(u0a.x)); a0.x += w0*f.x; a0.y += w0*f.y;
        f = __half22float2(u2h(u0a.y)); a0.z += w0*f.x; a0.w += w0*f.y;
        f = __half22float2(u2h(u0a.z)); a1.x += w0*f.x; a1.y += w0*f.y;
        f = __half22float2(u2h(u0a.w)); a1.z += w0*f.x; a1.w += w0*f.y;
        f = __half22float2(u2h(u0b.x)); a2.x += w0*f.x; a2.y += w0*f.y;
        f = __half22float2(u2h(u0b.y)); a2.z += w0*f.x; a2.w += w0*f.y;
        f = __half22float2(u2h(u0b.z)); a3.x += w0*f.x; a3.y += w0*f.y;
        f = __half22float2(u2h(u0b.w)); a3.z += w0*f.x; a3.w += w0*f.y;
        f = __half22float2(u2h(u1a.x)); a0.x += w1*f.x; a0.y += w1*f.y;
        f = __half22float2(u2h(u1a.y)); a0.z += w1*f.x; a0.w += w1*f.y;
        f = __half22float2(u2h(u1a.z)); a1.x += w1*f.x; a1.y += w1*f.y;
        f = __half22float2(u2h(u1a.w)); a1.z += w1*f.x; a1.w += w1*f.y;
        f = __half22float2(u2h(u1b.x)); a2.x += w1*f.x; a2.y += w1*f.y;
        f = __half22float2(u2h(u1b.y)); a2.z += w1*f.x; a2.w += w1*f.y;
        f = __half22float2(u2h(u1b.z)); a3.x += w1*f.x; a3.y += w1*f.y;
        f = __half22float2(u2h(u1b.w)); a3.z += w1*f.x; a3.w += w1*f.y;
    }
    if (i < e) {
        int c = __ldg(&g_col[i]);
        float wv = __ldg(&g_wcsr[i]);
        uint4 ua = __ldg((const uint4*)(in + c*8));
        uint4 ub = __ldg((const uint4*)(in + c*8 + 4));
        float2 f;
        f = __half22float2(u2h(ua.x)); a0.x += wv*f.x; a0.y += wv*f.y;
        f = __half22float2(u2h(ua.y)); a0.z += wv*f.x; a0.w += wv*f.y;
        f = __half22float2(u2h(ua.z)); a1.x += wv*f.x; a1.y += wv*f.y;
        f = __half22float2(u2h(ua.w)); a1.z += wv*f.x; a1.w += wv*f.y;
        f = __half22float2(u2h(ub.x)); a2.x += wv*f.x; a2.y += wv*f.y;
        f = __half22float2(u2h(ub.y)); a2.z += wv*f.x; a2.w += wv*f.y;
        f = __half22float2(u2h(ub.z)); a3.x += wv*f.x; a3.y += wv*f.y;
        f = __half22float2(u2h(ub.w)); a3.z += wv*f.x; a3.w += wv*f.y;
    }
    uint4 oa, ob;
    oa.x = h2u(__floats2half2_rn(a0.x, a0.y));
    oa.y = h2u(__floats2half2_rn(a0.z, a0.w));
    oa.z = h2u(__floats2half2_rn(a1.x, a1.y));
    oa.w = h2u(__floats2half2_rn(a1.z, a1.w));
    ob.x = h2u(__floats2half2_rn(a2.x, a2.y));
    ob.y = h2u(__floats2half2_rn(a2.z, a2.w));
    ob.z = h2u(__floats2half2_rn(a3.x, a3.y));
    ob.w = h2u(__floats2half2_rn(a3.z, a3.w));
    *(uint4*)(out + n*8)     = oa;
    *(uint4*)(out + n*8 + 4) = ob;
}

/* fp32 F=2 prop (layer-3 Horner), 2-way unrolled */
template<bool ADD>
__global__ void k_prop2(const float* __restrict__ in, float* __restrict__ out,
                        const float* __restrict__ add) {
    int n = blockIdx.x*blockDim.x + threadIdx.x;
    if (n >= N_NODES) return;
    float4 a0 = make_float4(0.f,0.f,0.f,0.f), a1 = a0;
    int s = g_rowptr[n], e = g_rowptr[n+1];
    const float4* base = (const float4*)in;
    int i = s;
    for (; i + 2 <= e; i += 2) {
        int c0 = __ldg(&g_col[i]),    c1 = __ldg(&g_col[i+1]);
        float w0 = __ldg(&g_wcsr[i]), w1 = __ldg(&g_wcsr[i+1]);
        float4 x0 = __ldg(base + c0*2), x1 = __ldg(base + c0*2 + 1);
        float4 y0 = __ldg(base + c1*2), y1 = __ldg(base + c1*2 + 1);
        a0.x += w0*x0.x; a0.y += w0*x0.y; a0.z += w0*x0.z; a0.w += w0*x0.w;
        a1.x += w0*x1.x; a1.y += w0*x1.y; a1.z += w0*x1.z; a1.w += w0*x1.w;
        a0.x += w1*y0.x; a0.y += w1*y0.y; a0.z += w1*y0.z; a0.w += w1*y0.w;
        a1.x += w1*y1.x; a1.y += w1*y1.y; a1.z += w1*y1.z; a1.w += w1*y1.w;
    }
    if (i < e) {
        int c = __ldg(&g_col[i]);
        float wv = __ldg(&g_wcsr[i]);
        float4 v0 = __ldg(base + c*2), v1 = __ldg(base + c*2 + 1);
        a0.x += wv*v0.x; a0.y += wv*v0.y; a0.z += wv*v0.z; a0.w += wv*v0.w;
        a1.x += wv*v1.x; a1.y += wv*v1.y; a1.z += wv*v1.z; a1.w += wv*v1.w;
    }
    float4* q = (float4*)out + n*2;
    if (ADD) {
        float4 d0 = ((const float4*)add)[n*2];
        float4 d1 = ((const float4*)add)[n*2 + 1];
        a0.x += d0.x; a0.y += d0.y; a0.z += d0.z; a0.w += d0.w;
        a1.x += d1.x; a1.y += d1.y; a1.z += d1.z; a1.w += d1.w;
    }
    q[0] = a0; q[1] = a1;
}

/* final Horner prop fused with output epilogue */
__global__ void k_prop2_final(const float* __restrict__ in,
                              const float* __restrict__ p0,
                              const float* __restrict__ b3,
                              const float* __restrict__ mask,
                              const float* __restrict__ mean_y,
                              const float* __restrict__ std_y,
                              const float* __restrict__ vmin, const float* __restrict__ vmax,
                              const float* __restrict__ qmin, const float* __restrict__ qmax,
                              float* __restrict__ out) {
    int n = blockIdx.x*blockDim.x + threadIdx.x;
    if (n >= N_NODES) return;
    float4 a0 = make_float4(0.f,0.f,0.f,0.f), a1 = a0;
    int s = g_rowptr[n], e = g_rowptr[n+1];
    const float4* base = (const float4*)in;
    int i = s;
    for (; i + 2 <= e; i += 2) {
        int c0 = __ldg(&g_col[i]),    c1 = __ldg(&g_col[i+1]);
        float w0 = __ldg(&g_wcsr[i]), w1 = __ldg(&g_wcsr[i+1]);
        float4 x0 = __ldg(base + c0*2), x1 = __ldg(base + c0*2 + 1);
        float4 y0 = __ldg(base + c1*2), y1 = __ldg(base + c1*2 + 1);
        a0.x += w0*x0.x; a0.y += w0*x0.y; a0.z += w0*x0.z; a0.w += w0*x0.w;
        a1.x += w0*x1.x; a1.y += w0*x1.y; a1.z += w0*x1.z; a1.w += w0*x1.w;
        a0.x += w1*y0.x; a0.y += w1*y0.y; a0.z += w1*y0.z; a0.w += w1*y0.w;
        a1.x += w1*y1.x; a1.y += w1*y1.y; a1.z += w1*y1.z; a1.w += w1*y1.w;
    }
    if (i < e) {
        int c = __ldg(&g_col[i]);
        float wv = __ldg(&g_wcsr[i]);
        float4 v0 = __ldg(base + c*2), v1 = __ldg(base + c*2 + 1);
        a0.x += wv*v0.x; a0.y += wv*v0.y; a0.z += wv*v0.z; a0.w += wv*v0.w;
        a1.x += wv*v1.x; a1.y += wv*v1.y; a1.z += wv*v1.z; a1.w += wv*v1.w;
    }
    float4 z0 = ((const float4*)p0)[n*2];
    float4 z1 = ((const float4*)p0)[n*2 + 1];
    float b30 = __ldg(&b3[0]), b31 = __ldg(&b3[1]);
    float u[4][2] = {
        {a0.x + z0.x + b30, a0.y + z0.y + b31},
        {a0.z + z0.z + b30, a0.w + z0.w + b31},
        {a1.x + z1.x + b30, a1.y + z1.y + b31},
        {a1.z + z1.z + b30, a1.w + z1.w + b31}
    };
    float s0 = std_y[n*2], s1 = std_y[n*2+1];
    if (isinf(s0)) s0 = 0.f;
    if (isinf(s1)) s1 = 0.f;
    float m0 = mask[n*2], m1 = mask[n*2+1];
    float me0 = mean_y[n*2], me1 = mean_y[n*2+1];
    float vlo = vmin[n], vhi = vmax[n];
    float qlo = qmin[n], qhi = qmax[n];
    #pragma unroll
    for (int b = 0; b < 4; b++) {
        float o0 = (u[b][0]*s0 + me0) * m0;
        float o1 = (u[b][1]*s1 + me1) * m1;
        o0 = fminf(fmaxf(o0, vlo), vhi);
        o1 = fminf(fmaxf(o1, qlo), qhi);
        *(float2*)&out[(size_t)(b*N_NODES + n)*2] = make_float2(o0, o1);
    }
}

/* fp16 payload prop: warp per node, 4-way predicated edge loop */
__global__ void k_prop64h(const uint32_t* __restrict__ in, uint32_t* __restrict__ out) {
    int gt = blockIdx.x*blockDim.x + threadIdx.x;
    int n = gt >> 5, lane = gt & 31;
    if (n >= N_NODES) return;
    int s = g_rowptr[n], e = g_rowptr[n+1];
    float2 a0 = make_float2(0.f,0.f), a1 = a0, a2 = a0, a3 = a0;
    for (int i = s; i < e; i += 4) {
        int   c[4];
        float w[4];
        uint4 v[4];
        #pragma unroll
        for (int j = 0; j < 4; j++) {
            int idx = i + j;
            bool act = idx < e;
            c[j] = act ? __ldg(&g_col[idx]) : 0;
            w[j] = act ? __ldg(&g_wcsr[idx]) : 0.f;
        }
        #pragma unroll
        for (int j = 0; j < 4; j++)
            v[j] = __ldg((const uint4*)(in + c[j]*128 + lane*4));
        #pragma unroll
        for (int j = 0; j < 4; j++) {
            float2 f;
            f = __half22float2(u2h(v[j].x)); a0.x += w[j]*f.x; a0.y += w[j]*f.y;
            f = __half22float2(u2h(v[j].y)); a1.x += w[j]*f.x; a1.y += w[j]*f.y;
            f = __half22float2(u2h(v[j].z)); a2.x += w[j]*f.x; a2.y += w[j]*f.y;
            f = __half22float2(u2h(v[j].w)); a3.x += w[j]*f.x; a3.y += w[j]*f.y;
        }
    }
    uint4 o;
    o.x = h2u(__floats2half2_rn(a0.x, a0.y));
    o.y = h2u(__floats2half2_rn(a1.x, a1.y));
    o.z = h2u(__floats2half2_rn(a2.x, a2.y));
    o.w = h2u(__floats2half2_rn(a3.x, a3.y));
    *(uint4*)(out + n*128 + lane*4) = o;
}

/* ---------------- layer-1 GEMM (fp16 A direct) + BN + LReLU -> fp16 h --- */
__global__ void __launch_bounds__(256, 2)
k_gemm1_mma(const uint32_t* __restrict__ A0, const uint32_t* __restrict__ A1,
            const uint32_t* __restrict__ A2, const uint32_t* __restrict__ A3,
            const uint32_t* __restrict__ w1h, const uint32_t* __restrict__ w1l,
            const float* __restrict__ b1,
            const float* __restrict__ g1, const float* __restrict__ be1,
            uint32_t* __restrict__ hout) {
    extern __shared__ uint32_t smu[];
    float* smf = (float*)smu;
    const int t = threadIdx.x;
    const int lane = t & 31, wid = t >> 5;
    const int wrow = wid >> 1, wcol = wid & 1;
    const int r0 = blockIdx.x * 128;

    {
        int n = t >> 2, c4 = t & 3;
        int regbit = (c4 >> 1) & 1, q0 = (c4 & 1) * 2;
        int g = n & 7, nt = n >> 3;
        int b_w = 1024 + nt*64 + (g*4 + q0)*2 + regbit;
        uint2 vh = *(const uint2*)(w1h + n*8 + c4*2);
        uint2 vl = *(const uint2*)(w1l + n*8 + c4*2);
        smu[b_w]       = vh.x;
        smu[b_w + 2]   = vh.y;
        smu[512 + b_w]     = vl.x;
        smu[512 + b_w + 2] = vl.y;
    }
    #pragma unroll
    for (int sidx = 0; sidx < 2; sidx++) {
        int idx = sidx*256 + t;
        int row = idx >> 2, c4 = idx & 3;
        int rr = row & 15, mt = row >> 4;
        int regbit = (c4 >> 1) & 1, q0 = (c4 & 1) * 2;
        int g = rr & 7, abit = rr >> 3;
        int a_w = mt*128 + (g*4 + q0)*4 + abit + 2*regbit;
        const uint32_t* Ap = (c4 == 0) ? A0 : (c4 == 1) ? A1 : (c4 == 2) ? A2 : A3;
        uint2 v = *(const uint2*)(Ap + (size_t)(r0 + row)*2);
        smu[a_w]     = v.x;
        smu[a_w + 4] = v.y;
    }
    __syncthreads();

    float c[2][4][4];
    #pragma unroll
    for (int m = 0; m < 2; m++)
        #pragma unroll
        for (int n = 0; n < 4; n++)
            #pragma unroll
            for (int k = 0; k < 4; k++) c[m][n][k] = 0.f;

    {
        uint4 ah[2];
        #pragma unroll
        for (int mt = 0; mt < 2; mt++) {
            int mtile = wrow*2 + mt;
            ah[mt] = *(const uint4*)(smu + mtile*128 + lane*4);
        }
        uint2 bh[4], bl[4];
        #pragma unroll
        for (int nt = 0; nt < 4; nt++) {
            int ntile = wcol*4 + nt;
            bh[nt] = *(const uint2*)(smu + 1024 + ntile*64 + lane*2);
            bl[nt] = *(const uint2*)(smu + 1536 + ntile*64 + lane*2);
        }
        #pragma unroll
        for (int mt = 0; mt < 2; mt++)
            #pragma unroll
            for (int nt = 0; nt < 4; nt++) {
                MMAH(c[mt][nt], ah[mt].x, ah[mt].y, ah[mt].z, ah[mt].w,
                     bh[nt].x, bh[nt].y);
                MMAH(c[mt][nt], ah[mt].x, ah[mt].y, ah[mt].z, ah[mt].w,
                     bl[nt].x, bl[nt].y);
            }
    }
    __syncthreads();

    {
        float* so = smf;
        const int g = lane >> 2, q = lane & 3;
        #pragma unroll
        for (int mt = 0; mt < 2; mt++) {
            int lr = wrow*32 + mt*16 + g;
            #pragma unroll
            for (int nt = 0; nt < 4; nt++) {
                int col = wcol*32 + nt*8 + 2*q;
                float bx = __ldg(&b1[col]), by = __ldg(&b1[col+1]);
                so[lr*68+col]       = c[mt][nt][0] + bx;
                so[lr*68+col+1]     = c[mt][nt][1] + by;
                so[(lr+8)*68+col]   = c[mt][nt][2] + bx;
                so[(lr+8)*68+col+1] = c[mt][nt][3] + by;
            }
        }
    }
    __syncthreads();
    {
        const float* so = smf;
        int sub = lane >> 3, c8 = (lane & 7) * 8;
        #pragma unroll
        for (int nn = 0; nn < 4; nn++) {
            int node = wid*4 + nn;
            int gnode = blockIdx.x*32 + node;
            int gn = gnode < N_NODES ? gnode : N_NODES-1;
            const float* rp = so + (node*4 + sub)*68 + c8;
            float4 v0 = *(const float4*)rp;
            float4 v1 = *(const float4*)(rp + 4);
            float s = v0.x+v0.y+v0.z+v0.w + v1.x+v1.y+v1.z+v1.w;
            float q = v0.x*v0.x+v0.y*v0.y+v0.z*v0.z+v0.w*v0.w
                    + v1.x*v1.x+v1.y*v1.y+v1.z*v1.z+v1.w*v1.w;
            #pragma unroll
            for (int o = 16; o; o >>= 1) {
                s += __shfl_xor_sync(0xffffffffu, s, o);
                q += __shfl_xor_sync(0xffffffffu, q, o);
            }
            float mu  = s * (1.f/256.f);
            float var = q * (1.f/256.f) - mu*mu;
            float sc  = __ldg(&g1[gn]) * rsqrtf(var + BN_EPS);
            float bb  = __ldg(&be1[gn]);
            float o0, o1, o2, o3, o4, o5, o6, o7, f;
            f = sc*(v0.x-mu)+bb; o0 = f > 0.f ? f : SLOPE*f;
            f = sc*(v0.y-mu)+bb; o1 = f > 0.f ? f : SLOPE*f;
            f = sc*(v0.z-mu)+bb; o2 = f > 0.f ? f : SLOPE*f;
            f = sc*(v0.w-mu)+bb; o3 = f > 0.f ? f : SLOPE*f;
            f = sc*(v1.x-mu)+bb; o4 = f > 0.f ? f : SLOPE*f;
            f = sc*(v1.y-mu)+bb; o5 = f > 0.f ? f : SLOPE*f;
            f = sc*(v1.z-mu)+bb; o6 = f > 0.f ? f : SLOPE*f;
            f = sc*(v1.w-mu)+bb; o7 = f > 0.f ? f : SLOPE*f;
            if (gnode < N_NODES) {
                uint4 pk;
                pk.x = h2u(__floats2half2_rn(o0, o1));
                pk.y = h2u(__floats2half2_rn(o2, o3));
                pk.z = h2u(__floats2half2_rn(o4, o5));
                pk.w = h2u(__floats2half2_rn(o6, o7));
                *(uint4*)&hout[(size_t)(r0 + node*4 + sub)*32 + (lane & 7)*4] = pk;
            }
        }
    }
}

/* ---------------- layer-2 GEMM (fp16 A, fp16 B) + BN + projections ------ */
#define STG_U32 3072
#define SW3_OFF 8704
__global__ void __launch_bounds__(256, 2)
k_gemm2_mma(const uint32_t* __restrict__ A0, const uint32_t* __restrict__ A1,
            const uint32_t* __restrict__ A2, const uint32_t* __restrict__ A3,
            const uint32_t* __restrict__ wph,
            const float* __restrict__ b2,
            const float* __restrict__ g2, const float* __restrict__ be2,
            const float* __restrict__ W3,
            float* __restrict__ p0, float* __restrict__ p1,
            float* __restrict__ p2, float* __restrict__ p3) {
    extern __shared__ uint32_t smu[];
    float* smf = (float*)smu;
    const int t = threadIdx.x;
    const int lane = t & 31, wid = t >> 5;
    const int wrow = wid >> 1, wcol = wid & 1;
    const int r0 = blockIdx.x * 128;

    #pragma unroll
    for (int i2 = t; i2 < 512; i2 += 256) {
        int kch = i2 >> 6, f = i2 & 63;
        smf[SW3_OFF + i2] = W3[(kch >> 1)*128 + f*2 + (kch & 1)];
    }

    int a_w[4], a_src[4];
    #pragma unroll
    for (int i = 0; i < 4; i++) {
        int idx = i*256 + t;
        int row = idx >> 3, c4 = idx & 7;
        int rr = row & 15, mt = row >> 4;
        int ks = c4 >> 2, regbit = (c4 >> 1) & 1, q0 = (c4 & 1) * 2;
        int g = rr & 7, abit = rr >> 3;
        a_w[i] = (mt*2 + ks)*128 + (g*4 + q0)*4 + abit + 2*regbit;
        a_src[i] = row*32 + c4*2;
    }
    int b_w[2], b_src[2];
    #pragma unroll
    for (int i = 0; i < 2; i++) {
        int idx = i*256 + t;
        int n = idx >> 3, c4 = idx & 7;
        int ks = c4 >> 2, regbit = (c4 >> 1) & 1, q0 = (c4 & 1) * 2;
        int g = n & 7, nt = n >> 3;
        b_w[i] = 2048 + (nt*2 + ks)*64 + (g*4 + q0)*2 + regbit;
        b_src[i] = n*128 + c4*2;
    }

    float c[2][4][4];
    #pragma unroll
    for (int m = 0; m < 2; m++)
        #pragma unroll
        for (int n = 0; n < 4; n++)
            #pragma unroll
            for (int k = 0; k < 4; k++) c[m][n][k] = 0.f;

    uint2 pa[4], pbh[2];

    {
        #pragma unroll
        for (int i = 0; i < 4; i++)
            pa[i] = *(const uint2*)(A0 + (size_t)r0*32 + a_src[i]);
        #pragma unroll
        for (int i = 0; i < 2; i++)
            pbh[i] = *(const uint2*)(wph + b_src[i]);
        uint32_t* base = smu;
        #pragma unroll
        for (int i = 0; i < 4; i++) {
            base[a_w[i]]     = pa[i].x;
            base[a_w[i] + 4] = pa[i].y;
        }
        #pragma unroll
        for (int i = 0; i < 2; i++) {
            base[b_w[i]]     = pbh[i].x;
            base[b_w[i] + 2] = pbh[i].y;
        }
    }
    __syncthreads();

    #pragma unroll 1
    for (int cc = 0; cc < 8; cc++) {
        int stage = cc & 1;
        if (cc < 7) {
            int cn = cc + 1;
            const uint32_t* Ap = (cn < 2) ? A0 : (cn < 4) ? A1 : (cn < 6) ? A2 : A3;
            int kb = (cn & 1) * 16;
            #pragma unroll
            for (int i = 0; i < 4; i++)
                pa[i] = *(const uint2*)(Ap + (size_t)r0*32 + a_src[i] + kb);
            #pragma unroll
            for (int i = 0; i < 2; i++)
                pbh[i] = *(const uint2*)(wph + b_src[i] + cn*16);
        }
        {
            const uint32_t* base = smu + stage*STG_U32;
            #pragma unroll
            for (int ks = 0; ks < 2; ks++) {
                uint4 ah[2];
                #pragma unroll
                for (int mt = 0; mt < 2; mt++) {
                    int mtile = wrow*2 + mt;
                    ah[mt] = *(const uint4*)(base + (mtile*2+ks)*128 + lane*4);
                }
                uint2 bh[4];
                #pragma unroll
                for (int nt = 0; nt < 4; nt++) {
                    int ntile = wcol*4 + nt;
                    bh[nt] = *(const uint2*)(base + 2048 + (ntile*2+ks)*64 + lane*2);
                }
                #pragma unroll
                for (int mt = 0; mt < 2; mt++)
                    #pragma unroll
                    for (int nt = 0; nt < 4; nt++)
                        MMAH(c[mt][nt], ah[mt].x, ah[mt].y, ah[mt].z, ah[mt].w,
                             bh[nt].x, bh[nt].y);
            }
        }
        if (cc < 7) {
            uint32_t* base = smu + ((cc+1)&1)*STG_U32;
            #pragma unroll
            for (int i = 0; i < 4; i++) {
                base[a_w[i]]     = pa[i].x;
                base[a_w[i] + 4] = pa[i].y;
            }
            #pragma unroll
            for (int i = 0; i < 2; i++) {
                base[b_w[i]]     = pbh[i].x;
                base[b_w[i] + 2] = pbh[i].y;
            }
        }
        __syncthreads();
    }

    /* ---- fused BN2 + LeakyReLU + W3 projections ---- */
    {
        float* so = smf;
        const int g = lane >> 2, q = lane & 3;
        #pragma unroll
        for (int mt = 0; mt < 2; mt++) {
            int lr = wrow*32 + mt*16 + g;
            #pragma unroll
            for (int nt = 0; nt < 4; nt++) {
                int col = wcol*32 + nt*8 + 2*q;
                float bx = __ldg(&b2[col]), by = __ldg(&b2[col+1]);
                so[lr*68+col]       = c[mt][nt][0] + bx;
                so[lr*68+col+1]     = c[mt][nt][1] + by;
                so[(lr+8)*68+col]   = c[mt][nt][2] + bx;
                so[(lr+8)*68+col+1] = c[mt][nt][3] + by;
            }
        }
    }
    __syncthreads();
    {
        const float* so = smf;
        const float* sw3 = smf + SW3_OFF;
        int sub = lane >> 3, c8 = (lane & 7) * 8;
        #pragma unroll
        for (int nn = 0; nn < 4; nn++) {
            int node = wid*4 + nn;
            int gnode = blockIdx.x*32 + node;
            int gn = gnode < N_NODES ? gnode : N_NODES-1;
            const float* rp = so + (node*4 + sub)*68 + c8;
            float4 v0 = *(const float4*)rp;
            float4 v1 = *(const float4*)(rp + 4);
            float s = v0.x+v0.y+v0.z+v0.w + v1.x+v1.y+v1.z+v1.w;
            float q = v0.x*v0.x+v0.y*v0.y+v0.z*v0.z+v0.w*v0.w
                    + v1.x*v1.x+v1.y*v1.y+v1.z*v1.z+v1.w*v1.w;
            #pragma unroll
            for (int o = 16; o; o >>= 1) {
                s += __shfl_xor_sync(0xffffffffu, s, o);
                q += __shfl_xor_sync(0xffffffffu, q, o);
            }
            float mu  = s * (1.f/256.f);
            float var = q * (1.f/256.f) - mu*mu;
            float sc  = __ldg(&g2[gn]) * rsqrtf(var + BN_EPS);
            float bb  = __ldg(&be2[gn]);
            float o0, o1, o2, o3, o4, o5, o6, o7, f;
            f = sc*(v0.x-mu)+bb; o0 = f > 0.f ? f : SLOPE*f;
            f = sc*(v0.y-mu)+bb; o1 = f > 0.f ? f : SLOPE*f;
            f = sc*(v0.z-mu)+bb; o2 = f > 0.f ? f : SLOPE*f;
            f = sc*(v0.w-mu)+bb; o3 = f > 0.f ? f : SLOPE*f;
            f = sc*(v1.x-mu)+bb; o4 = f > 0.f ? f : SLOPE*f;
            f = sc*(v1.y-mu)+bb; o5 = f > 0.f ? f : SLOPE*f;
            f = sc*(v1.z-mu)+bb; o6 = f > 0.f ? f : SLOPE*f;
            f = sc*(v1.w-mu)+bb; o7 = f > 0.f ? f : SLOPE*f;
            float pr[8];
            #pragma unroll
            for (int kch = 0; kch < 8; kch++) {
                const float* w = sw3 + kch*64 + c8;
                float4 w0 = *(const float4*)w;
                float4 w1 = *(const float4*)(w + 4);
                pr[kch] = o0*w0.x + o1*w0.y + o2*w0.z + o3*w0.w
                        + o4*w1.x + o5*w1.y + o6*w1.z + o7*w1.w;
            }
            #pragma unroll
            for (int m = 1; m <= 4; m <<= 1) {
                #pragma unroll
                for (int kch = 0; kch < 8; kch++)
                    pr[kch] += __shfl_xor_sync(0xffffffffu, pr[kch], m);
            }
            if ((lane & 7) == 0 && gnode < N_NODES) {
                size_t grow = (size_t)(r0 + node*4 + sub)*2;
                *(float2*)&p0[grow] = make_float2(pr[0], pr[1]);
                *(float2*)&p1[grow] = make_float2(pr[2], pr[3]);
                *(float2*)&p2[grow] = make_float2(pr[4], pr[5]);
                *(float2*)&p3[grow] = make_float2(pr[6], pr[7]);
            }
        }
    }
}

/* ======================================================================= */
extern "C" void kernel_launch(void* const* d_in, const int* in_sizes, int n_in,
                              void* d_out, int out_size) {
    const float* x      = (const float*)d_in[0];
    const int*   src    = (const int*)  d_in[1];
    const int*   dst    = (const int*)  d_in[2];
    const float* ew     = (const float*)d_in[3];
    const float* W1     = (const float*)d_in[4];
    const float* b1     = (const float*)d_in[5];
    const float* W2     = (const float*)d_in[6];
    const float* b2     = (const float*)d_in[7];
    const float* W3     = (const float*)d_in[8];
    const float* b3     = (const float*)d_in[9];
    const float* g1     = (const float*)d_in[10];
    const float* be1    = (const float*)d_in[11];
    const float* g2     = (const float*)d_in[12];
    const float* be2    = (const float*)d_in[13];
    const float* mask   = (const float*)d_in[14];
    const float* mean_y = (const float*)d_in[15];
    const float* std_y  = (const float*)d_in[16];
    const float* vmin   = (const float*)d_in[17];
    const float* vmax   = (const float*)d_in[18];
    const float* qmin   = (const float*)d_in[19];
    const float* qmax   = (const float*)d_in[20];
    float* out = (float*)d_out;

    float *pa, *pb, *pc, *sa, *sb;
    uint32_t *x16, *pa16, *pb16, *pc16;
    uint32_t *h16, *t116, *t216, *t316, *w2ph, *w1ph, *w1pl;
    cudaGetSymbolAddress((void**)&pa,  g_pa);
    cudaGetSymbolAddress((void**)&pb,  g_pb);
    cudaGetSymbolAddress((void**)&pc,  g_pc);
    cudaGetSymbolAddress((void**)&sa,  g_sa);
    cudaGetSymbolAddress((void**)&sb,  g_sb);
    cudaGetSymbolAddress((void**)&x16,  g_x16);
    cudaGetSymbolAddress((void**)&pa16, g_pa16);
    cudaGetSymbolAddress((void**)&pb16, g_pb16);
    cudaGetSymbolAddress((void**)&pc16, g_pc16);
    cudaGetSymbolAddress((void**)&h16,  g_h16);
    cudaGetSymbolAddress((void**)&t116, g_t116);
    cudaGetSymbolAddress((void**)&t216, g_t216);
    cudaGetSymbolAddress((void**)&t316, g_t316);
    cudaGetSymbolAddress((void**)&w2ph, g_w2p_hi);
    cudaGetSymbolAddress((void**)&w1ph, g_w1p_hi);
    cudaGetSymbolAddress((void**)&w1pl, g_w1p_lo);

    static int smem_set = 0;
    if (!smem_set) {
        cudaFuncSetAttribute(k_gemm2_mma, cudaFuncAttributeMaxDynamicSharedMemorySize, 36864);
        cudaFuncSetAttribute(k_gemm1_mma, cudaFuncAttributeMaxDynamicSharedMemorySize, 34816);
        smem_set = 1;
    }

    const int TB = 256;
    int gN = (N_NODES + TB - 1) / TB;
    int gE = (N_EDGES + TB - 1) / TB;
    int gR = (R + TB - 1) / TB;
    int gW = (N_NODES*32 + TB - 1) / TB;

    /* preprocessing (fused) */
    k_init_xt<<<gR, TB>>>(x);
    k_deg_w2 <<<gE, TB>>>(dst, ew, W2, W1);
    k_scan1  <<<NB_SCAN, 256>>>();
    k_scan23 <<<NB_SCAN, 256>>>();
    k_fill   <<<gE, TB>>>(src, dst, ew);

    /* layer 1: fp16 prop at F=4 (all 4 batch rows), GEMM+BN+LReLU -> fp16 h */
    k_prop4h<<<gN, TB>>>(x16,  pa16);
    k_prop4h<<<gN, TB>>>(pa16, pb16);
    k_prop4h<<<gN, TB>>>(pb16, pc16);
    k_gemm1_mma<<<RPAD/128, 256, 34816>>>(x16, pa16, pb16, pc16, w1ph, w1pl,
                                          b1, g1, be1, h16);

    /* layer 2: 3x fp16 prop64, fused GEMM+BN+projections -> p0..p3 */
    k_prop64h<<<gW, TB>>>(h16,  t116);
    k_prop64h<<<gW, TB>>>(t116, t216);
    k_prop64h<<<gW, TB>>>(t216, t316);
    k_gemm2_mma<<<RPAD/128, 256, 36864>>>(h16, t116, t216, t316, w2ph,
                                          b2, g2, be2, W3, pb, pa, sb, sa);

    /* layer 3: Horner at F=2 (p0->pb, p1->pa, p2->sb, p3->sa) */
    k_prop2<true ><<<gN, TB>>>(sa, pc, sb);
    k_prop2<true ><<<gN, TB>>>(pc, sa, pa);
    k_prop2_final<<<gN, TB>>>(sa, pb, b3, mask, mean_y, std_y,
                              vmin, vmax, qmin, qmax, out);
}

// round 14
// speedup vs baseline: 2.6416x; 1.0813x over previous
#include <cuda_runtime.h>
#include <cuda_fp16.h>
#include <math.h>
#include <cstdint>

#define N_NODES 50000
#define N_EDGES 400000
#define BATCH 4
#define R (N_NODES*BATCH)      /* 200000 rows (n,b) */
#define RPAD 200064            /* padded to 128-row GEMM tiles */
#define BN_EPS 1e-5f
#define SLOPE 0.01f
#define NB_SCAN ((N_NODES + 255) / 256)   /* 196 */

/* ---------------- static device scratch (no allocations allowed) -------- */
__device__ __align__(16) float g_deg[N_NODES];
__device__ __align__(16) float g_dis[N_NODES];
__device__ __align__(16) int   g_cnt[N_NODES];
__device__ __align__(16) int   g_rowptr[N_NODES+1];
__device__ __align__(16) int   g_cur[N_NODES];
__device__ __align__(16) int   g_col[N_EDGES];
__device__ __align__(16) float g_wcsr[N_EDGES];
__device__ __align__(16) int   g_bsum[256];

/* fp16 layer-1 features: [row][4 halfs] = [row][2 u32]; node owns 4 rows */
__device__ __align__(16) uint32_t g_x16 [RPAD*2];
__device__ __align__(16) uint32_t g_pa16[RPAD*2];
__device__ __align__(16) uint32_t g_pb16[RPAD*2];
__device__ __align__(16) uint32_t g_pc16[RPAD*2];

/* float scratch for layer-3 p-values ([R][2] each) */
__device__ __align__(16) float g_pa[RPAD*4];
__device__ __align__(16) float g_pb[RPAD*4];
__device__ __align__(16) float g_pc[RPAD*4];
__device__ __align__(16) float g_sa[RPAD*2];
__device__ __align__(16) float g_sb[RPAD*2];

/* fp16 hidden states: [row][64] halfs = [row][32] u32 */
__device__ __align__(16) uint32_t g_h16 [RPAD*32];
__device__ __align__(16) uint32_t g_t116[RPAD*32];
__device__ __align__(16) uint32_t g_t216[RPAD*32];
__device__ __align__(16) uint32_t g_t316[RPAD*32];

/* W2 transposed [64 n][128 kpair], fp16x2-packed */
__device__ __align__(16) uint32_t g_w2p_hi[64*128];
/* W1 transposed [64 n][8 kpair], fp16x2-packed hi/lo (K=16) */
__device__ __align__(16) uint32_t g_w1p_hi[64*8];
__device__ __align__(16) uint32_t g_w1p_lo[64*8];

#define MMAH(C, a0,a1,a2,a3, b0,b1) \
    asm volatile("mma.sync.aligned.m16n8k16.row.col.f32.f16.f16.f32 " \
        "{%0,%1,%2,%3},{%4,%5,%6,%7},{%8,%9},{%0,%1,%2,%3};" \
        : "+f"((C)[0]),"+f"((C)[1]),"+f"((C)[2]),"+f"((C)[3]) \
        : "r"(a0),"r"(a1),"r"(a2),"r"(a3),"r"(b0),"r"(b1))

__device__ __forceinline__ uint32_t h2u(__half2 h) {
    uint32_t u; memcpy(&u, &h, 4); return u;
}
__device__ __forceinline__ __half2 u2h(uint32_t u) {
    __half2 h; memcpy(&h, &u, 4); return h;
}

/* ---------------- preprocessing --------------------------------------- */
__global__ void k_init_xt(const float* __restrict__ x) {
    int t = blockIdx.x*blockDim.x + threadIdx.x;
    if (t < N_NODES) { g_deg[t] = 0.f; g_cnt[t] = 0; }
    if (t < R) {
        int b = t / N_NODES, n = t - b*N_NODES;
        float4 v = ((const float4*)x)[t];
        uint2 pk;
        pk.x = h2u(__floats2half2_rn(v.x, v.y));
        pk.y = h2u(__floats2half2_rn(v.z, v.w));
        *(uint2*)&g_x16[(size_t)(n*4 + b)*2] = pk;
    }
}

__global__ void k_deg_w2(const int* __restrict__ dst, const float* __restrict__ ew,
                         const float* __restrict__ W2, const float* __restrict__ W1) {
    int e = blockIdx.x*blockDim.x + threadIdx.x;
    if (e < N_EDGES) {
        int d = dst[e];
        atomicAdd(&g_deg[d], ew[e]);
        atomicAdd(&g_cnt[d], 1);
    }
    if (e < 64*128) {
        int n = e >> 7, p = e & 127;
        int k0 = 2*p;
        int sel = k0 >> 6, kk = k0 & 63;
        float v0 = W2[sel*4096 + kk*64 + n];
        float v1 = W2[sel*4096 + (kk+1)*64 + n];
        g_w2p_hi[e] = h2u(__floats2half2_rn(v0, v1));
    }
    if (e < 64*8) {
        int n = e >> 3, p = e & 7;
        int k0 = 2*p;
        float v0 = W1[k0*64 + n];
        float v1 = W1[(k0+1)*64 + n];
        __half h0 = __float2half_rn(v0), h1 = __float2half_rn(v1);
        float l0 = v0 - __half2float(h0), l1 = v1 - __half2float(h1);
        g_w1p_hi[e] = h2u(__halves2half2(h0, h1));
        g_w1p_lo[e] = h2u(__floats2half2_rn(l0, l1));
    }
}

__global__ void k_scan1() {
    int t = threadIdx.x, b = blockIdx.x;
    int i = b*256 + t;
    int v = (i < N_NODES) ? g_cnt[i] : 0;
    int lane = t & 31, wp = t >> 5;
    int x = v;
    #pragma unroll
    for (int o = 1; o < 32; o <<= 1) {
        int y = __shfl_up_sync(0xffffffffu, x, o);
        if (lane >= o) x += y;
    }
    __shared__ int wt[8];
    if (lane == 31) wt[wp] = x;
    __syncthreads();
    if (wp == 0 && lane < 8) {
        int y = wt[lane];
        #pragma unroll
        for (int o = 1; o < 8; o <<= 1) {
            int z = __shfl_up_sync(0xffu, y, o);
            if (lane >= o) y += z;
        }
        wt[lane] = y;
    }
    __syncthreads();
    int incl = x + (wp ? wt[wp-1] : 0);
    if (i < N_NODES) g_rowptr[i] = incl - v;
    if (t == 255) g_bsum[b] = incl;
}

__global__ void k_scan23() {
    int t = threadIdx.x, b = blockIdx.x;
    int v = (t < NB_SCAN) ? g_bsum[t] : 0;
    int lane = t & 31, wp = t >> 5;
    int x = v;
    #pragma unroll
    for (int o = 1; o < 32; o <<= 1) {
        int y = __shfl_up_sync(0xffffffffu, x, o);
        if (lane >= o) x += y;
    }
    __shared__ int wt[8];
    __shared__ int s_off;
    if (lane == 31) wt[wp] = x;
    __syncthreads();
    if (wp == 0 && lane < 8) {
        int y = wt[lane];
        #pragma unroll
        for (int o = 1; o < 8; o <<= 1) {
            int z = __shfl_up_sync(0xffu, y, o);
            if (lane >= o) y += z;
        }
        wt[lane] = y;
    }
    __syncthreads();
    int incl = x + (wp ? wt[wp-1] : 0);
    if (t == b) s_off = incl - v;
    __syncthreads();
    int i = b*256 + t;
    if (i < N_NODES) {
        int p = g_rowptr[i] + s_off;
        g_rowptr[i] = p;
        g_cur[i] = p;
        float d = g_deg[i];
        g_dis[i] = (d > 0.f) ? rsqrtf(fmaxf(d, 1e-30f)) : 0.f;
    }
    if (b == NB_SCAN-1 && t == 0) g_rowptr[N_NODES] = N_EDGES;
}

__global__ void k_fill(const int* __restrict__ src, const int* __restrict__ dst,
                       const float* __restrict__ ew) {
    int e = blockIdx.x*blockDim.x + threadIdx.x;
    if (e < N_EDGES) {
        int s = src[e], d = dst[e];
        int p = atomicAdd(&g_cur[d], 1);
        g_col[p]  = s;
        g_wcsr[p] = g_dis[s] * ew[e] * g_dis[d];
    }
}

/* ---------------- propagation ------------------------------------------ */
/* fp16 F=4 prop: 4 threads per node, thread j owns batch row j (uint2) */
__global__ void k_prop4h(const uint32_t* __restrict__ in, uint32_t* __restrict__ out) {
    int gt = blockIdx.x*blockDim.x + threadIdx.x;
    int n = gt >> 2, j = gt & 3;
    if (n >= N_NODES) return;
    float4 acc = make_float4(0.f,0.f,0.f,0.f);
    int s = g_rowptr[n], e = g_rowptr[n+1];
    int i = s;
    for (; i + 2 <= e; i += 2) {
        int c0 = __ldg(&g_col[i]),    c1 = __ldg(&g_col[i+1]);
        float w0 = __ldg(&g_wcsr[i]), w1 = __ldg(&g_wcsr[i+1]);
        uint2 v0 = __ldg((const uint2*)(in + c0*8 + j*2));
        uint2 v1 = __ldg((const uint2*)(in + c1*8 + j*2));
        float2 f;
        f = __half22float2(u2h(v0.x)); acc.x += w0*f.x; acc.y += w0*f.y;
        f = __half22float2(u2h(v0.y)); acc.z += w0*f.x; acc.w += w0*f.y;
        f = __half22float2(u2h(v1.x)); acc.x += w1*f.x; acc.y += w1*f.y;
        f = __half22float2(u2h(v1.y)); acc.z += w1*f.x; acc.w += w1*f.y;
    }
    if (i < e) {
        int c = __ldg(&g_col[i]);
        float wv = __ldg(&g_wcsr[i]);
        uint2 v = __ldg((const uint2*)(in + c*8 + j*2));
        float2 f;
        f = __half22float2(u2h(v.x)); acc.x += wv*f.x; acc.y += wv*f.y;
        f = __half22float2(u2h(v.y)); acc.z += wv*f.x; acc.w += wv*f.y;
    }
    uint2 pk;
    pk.x = h2u(__floats2half2_rn(acc.x, acc.y));
    pk.y = h2u(__floats2half2_rn(acc.z, acc.w));
    *(uint2*)(out + n*8 + j*2) = pk;
}

/* fp32 F=2 prop (layer-3 Horner): 4 threads per node, row j */
template<bool ADD>
__global__ void k_prop2(const float* __restrict__ in, float* __restrict__ out,
                        const float* __restrict__ add) {
    int gt = blockIdx.x*blockDim.x + threadIdx.x;
    int n = gt >> 2, j = gt & 3;
    if (n >= N_NODES) return;
    float2 acc = make_float2(0.f, 0.f);
    int s = g_rowptr[n], e = g_rowptr[n+1];
    int i = s;
    for (; i + 2 <= e; i += 2) {
        int c0 = __ldg(&g_col[i]),    c1 = __ldg(&g_col[i+1]);
        float w0 = __ldg(&g_wcsr[i]), w1 = __ldg(&g_wcsr[i+1]);
        float2 v0 = __ldg((const float2*)(in + (size_t)(c0*4 + j)*2));
        float2 v1 = __ldg((const float2*)(in + (size_t)(c1*4 + j)*2));
        acc.x += w0*v0.x; acc.y += w0*v0.y;
        acc.x += w1*v1.x; acc.y += w1*v1.y;
    }
    if (i < e) {
        int c = __ldg(&g_col[i]);
        float wv = __ldg(&g_wcsr[i]);
        float2 v = __ldg((const float2*)(in + (size_t)(c*4 + j)*2));
        acc.x += wv*v.x; acc.y += wv*v.y;
    }
    if (ADD) {
        float2 d = *(const float2*)(add + (size_t)(n*4 + j)*2);
        acc.x += d.x; acc.y += d.y;
    }
    *(float2*)(out + (size_t)(n*4 + j)*2) = acc;
}

/* final Horner prop fused with output epilogue: 4 threads/node, j = batch */
__global__ void k_prop2_final(const float* __restrict__ in,
                              const float* __restrict__ p0,
                              const float* __restrict__ b3,
                              const float* __restrict__ mask,
                              const float* __restrict__ mean_y,
                              const float* __restrict__ std_y,
                              const float* __restrict__ vmin, const float* __restrict__ vmax,
                              const float* __restrict__ qmin, const float* __restrict__ qmax,
                              float* __restrict__ out) {
    int gt = blockIdx.x*blockDim.x + threadIdx.x;
    int n = gt >> 2, j = gt & 3;
    if (n >= N_NODES) return;
    float2 acc = make_float2(0.f, 0.f);
    int s = g_rowptr[n], e = g_rowptr[n+1];
    int i = s;
    for (; i + 2 <= e; i += 2) {
        int c0 = __ldg(&g_col[i]),    c1 = __ldg(&g_col[i+1]);
        float w0 = __ldg(&g_wcsr[i]), w1 = __ldg(&g_wcsr[i+1]);
        float2 v0 = __ldg((const float2*)(in + (size_t)(c0*4 + j)*2));
        float2 v1 = __ldg((const float2*)(in + (size_t)(c1*4 + j)*2));
        acc.x += w0*v0.x; acc.y += w0*v0.y;
        acc.x += w1*v1.x; acc.y += w1*v1.y;
    }
    if (i < e) {
        int c = __ldg(&g_col[i]);
        float wv = __ldg(&g_wcsr[i]);
        float2 v = __ldg((const float2*)(in + (size_t)(c*4 + j)*2));
        acc.x += wv*v.x; acc.y += wv*v.y;
    }
    float2 z = *(const float2*)(p0 + (size_t)(n*4 + j)*2);
    float u0 = acc.x + z.x + __ldg(&b3[0]);
    float u1 = acc.y + z.y + __ldg(&b3[1]);
    float s0 = std_y[n*2], s1 = std_y[n*2+1];
    if (isinf(s0)) s0 = 0.f;
    if (isinf(s1)) s1 = 0.f;
    float o0 = (u0*s0 + mean_y[n*2])   * mask[n*2];
    float o1 = (u1*s1 + mean_y[n*2+1]) * mask[n*2+1];
    o0 = fminf(fmaxf(o0, vmin[n]), vmax[n]);
    o1 = fminf(fmaxf(o1, qmin[n]), qmax[n]);
    *(float2*)&out[(size_t)(j*N_NODES + n)*2] = make_float2(o0, o1);
}

/* fp16 payload prop: warp per node, 4-way predicated edge loop */
__global__ void k_prop64h(const uint32_t* __restrict__ in, uint32_t* __restrict__ out) {
    int gt = blockIdx.x*blockDim.x + threadIdx.x;
    int n = gt >> 5, lane = gt & 31;
    if (n >= N_NODES) return;
    int s = g_rowptr[n], e = g_rowptr[n+1];
    float2 a0 = make_float2(0.f,0.f), a1 = a0, a2 = a0, a3 = a0;
    for (int i = s; i < e; i += 4) {
        int   c[4];
        float w[4];
        uint4 v[4];
        #pragma unroll
        for (int j = 0; j < 4; j++) {
            int idx = i + j;
            bool act = idx < e;
            c[j] = act ? __ldg(&g_col[idx]) : 0;
            w[j] = act ? __ldg(&g_wcsr[idx]) : 0.f;
        }
        #pragma unroll
        for (int j = 0; j < 4; j++)
            v[j] = __ldg((const uint4*)(in + c[j]*128 + lane*4));
        #pragma unroll
        for (int j = 0; j < 4; j++) {
            float2 f;
            f = __half22float2(u2h(v[j].x)); a0.x += w[j]*f.x; a0.y += w[j]*f.y;
            f = __half22float2(u2h(v[j].y)); a1.x += w[j]*f.x; a1.y += w[j]*f.y;
            f = __half22float2(u2h(v[j].z)); a2.x += w[j]*f.x; a2.y += w[j]*f.y;
            f = __half22float2(u2h(v[j].w)); a3.x += w[j]*f.x; a3.y += w[j]*f.y;
        }
    }
    uint4 o;
    o.x = h2u(__floats2half2_rn(a0.x, a0.y));
    o.y = h2u(__floats2half2_rn(a1.x, a1.y));
    o.z = h2u(__floats2half2_rn(a2.x, a2.y));
    o.w = h2u(__floats2half2_rn(a3.x, a3.y));
    *(uint4*)(out + n*128 + lane*4) = o;
}

/* ---------------- layer-1 GEMM (fp16 A direct) + BN + LReLU -> fp16 h --- */
__global__ void __launch_bounds__(256, 2)
k_gemm1_mma(const uint32_t* __restrict__ A0, const uint32_t* __restrict__ A1,
            const uint32_t* __restrict__ A2, const uint32_t* __restrict__ A3,
            const uint32_t* __restrict__ w1h, const uint32_t* __restrict__ w1l,
            const float* __restrict__ b1,
            const float* __restrict__ g1, const float* __restrict__ be1,
            uint32_t* __restrict__ hout) {
    extern __shared__ uint32_t smu[];
    float* smf = (float*)smu;
    const int t = threadIdx.x;
    const int lane = t & 31, wid = t >> 5;
    const int wrow = wid >> 1, wcol = wid & 1;
    const int r0 = blockIdx.x * 128;

    {
        int n = t >> 2, c4 = t & 3;
        int regbit = (c4 >> 1) & 1, q0 = (c4 & 1) * 2;
        int g = n & 7, nt = n >> 3;
        int b_w = 1024 + nt*64 + (g*4 + q0)*2 + regbit;
        uint2 vh = *(const uint2*)(w1h + n*8 + c4*2);
        uint2 vl = *(const uint2*)(w1l + n*8 + c4*2);
        smu[b_w]       = vh.x;
        smu[b_w + 2]   = vh.y;
        smu[512 + b_w]     = vl.x;
        smu[512 + b_w + 2] = vl.y;
    }
    #pragma unroll
    for (int sidx = 0; sidx < 2; sidx++) {
        int idx = sidx*256 + t;
        int row = idx >> 2, c4 = idx & 3;
        int rr = row & 15, mt = row >> 4;
        int regbit = (c4 >> 1) & 1, q0 = (c4 & 1) * 2;
        int g = rr & 7, abit = rr >> 3;
        int a_w = mt*128 + (g*4 + q0)*4 + abit + 2*regbit;
        const uint32_t* Ap = (c4 == 0) ? A0 : (c4 == 1) ? A1 : (c4 == 2) ? A2 : A3;
        uint2 v = *(const uint2*)(Ap + (size_t)(r0 + row)*2);
        smu[a_w]     = v.x;
        smu[a_w + 4] = v.y;
    }
    __syncthreads();

    float c[2][4][4];
    #pragma unroll
    for (int m = 0; m < 2; m++)
        #pragma unroll
        for (int n = 0; n < 4; n++)
            #pragma unroll
            for (int k = 0; k < 4; k++) c[m][n][k] = 0.f;

    {
        uint4 ah[2];
        #pragma unroll
        for (int mt = 0; mt < 2; mt++) {
            int mtile = wrow*2 + mt;
            ah[mt] = *(const uint4*)(smu + mtile*128 + lane*4);
        }
        uint2 bh[4], bl[4];
        #pragma unroll
        for (int nt = 0; nt < 4; nt++) {
            int ntile = wcol*4 + nt;
            bh[nt] = *(const uint2*)(smu + 1024 + ntile*64 + lane*2);
            bl[nt] = *(const uint2*)(smu + 1536 + ntile*64 + lane*2);
        }
        #pragma unroll
        for (int mt = 0; mt < 2; mt++)
            #pragma unroll
            for (int nt = 0; nt < 4; nt++) {
                MMAH(c[mt][nt], ah[mt].x, ah[mt].y, ah[mt].z, ah[mt].w,
                     bh[nt].x, bh[nt].y);
                MMAH(c[mt][nt], ah[mt].x, ah[mt].y, ah[mt].z, ah[mt].w,
                     bl[nt].x, bl[nt].y);
            }
    }
    __syncthreads();

    {
        float* so = smf;
        const int g = lane >> 2, q = lane & 3;
        #pragma unroll
        for (int mt = 0; mt < 2; mt++) {
            int lr = wrow*32 + mt*16 + g;
            #pragma unroll
            for (int nt = 0; nt < 4; nt++) {
                int col = wcol*32 + nt*8 + 2*q;
                float bx = __ldg(&b1[col]), by = __ldg(&b1[col+1]);
                so[lr*68+col]       = c[mt][nt][0] + bx;
                so[lr*68+col+1]     = c[mt][nt][1] + by;
                so[(lr+8)*68+col]   = c[mt][nt][2] + bx;
                so[(lr+8)*68+col+1] = c[mt][nt][3] + by;
            }
        }
    }
    __syncthreads();
    {
        const float* so = smf;
        int sub = lane >> 3, c8 = (lane & 7) * 8;
        #pragma unroll
        for (int nn = 0; nn < 4; nn++) {
            int node = wid*4 + nn;
            int gnode = blockIdx.x*32 + node;
            int gn = gnode < N_NODES ? gnode : N_NODES-1;
            const float* rp = so + (node*4 + sub)*68 + c8;
            float4 v0 = *(const float4*)rp;
            float4 v1 = *(const float4*)(rp + 4);
            float s = v0.x+v0.y+v0.z+v0.w + v1.x+v1.y+v1.z+v1.w;
            float q = v0.x*v0.x+v0.y*v0.y+v0.z*v0.z+v0.w*v0.w
                    + v1.x*v1.x+v1.y*v1.y+v1.z*v1.z+v1.w*v1.w;
            #pragma unroll
            for (int o = 16; o; o >>= 1) {
                s += __shfl_xor_sync(0xffffffffu, s, o);
                q += __shfl_xor_sync(0xffffffffu, q, o);
            }
            float mu  = s * (1.f/256.f);
            float var = q * (1.f/256.f) - mu*mu;
            float sc  = __ldg(&g1[gn]) * rsqrtf(var + BN_EPS);
            float bb  = __ldg(&be1[gn]);
            float o0, o1, o2, o3, o4, o5, o6, o7, f;
            f = sc*(v0.x-mu)+bb; o0 = f > 0.f ? f : SLOPE*f;
            f = sc*(v0.y-mu)+bb; o1 = f > 0.f ? f : SLOPE*f;
            f = sc*(v0.z-mu)+bb; o2 = f > 0.f ? f : SLOPE*f;
            f = sc*(v0.w-mu)+bb; o3 = f > 0.f ? f : SLOPE*f;
            f = sc*(v1.x-mu)+bb; o4 = f > 0.f ? f : SLOPE*f;
            f = sc*(v1.y-mu)+bb; o5 = f > 0.f ? f : SLOPE*f;
            f = sc*(v1.z-mu)+bb; o6 = f > 0.f ? f : SLOPE*f;
            f = sc*(v1.w-mu)+bb; o7 = f > 0.f ? f : SLOPE*f;
            if (gnode < N_NODES) {
                uint4 pk;
                pk.x = h2u(__floats2half2_rn(o0, o1));
                pk.y = h2u(__floats2half2_rn(o2, o3));
                pk.z = h2u(__floats2half2_rn(o4, o5));
                pk.w = h2u(__floats2half2_rn(o6, o7));
                *(uint4*)&hout[(size_t)(r0 + node*4 + sub)*32 + (lane & 7)*4] = pk;
            }
        }
    }
}

/* ---------------- layer-2 GEMM (fp16 A, fp16 B) + BN + projections ------ */
#define STG_U32 3072
#define SW3_OFF 8704
__global__ void __launch_bounds__(256, 2)
k_gemm2_mma(const uint32_t* __restrict__ A0, const uint32_t* __restrict__ A1,
            const uint32_t* __restrict__ A2, const uint32_t* __restrict__ A3,
            const uint32_t* __restrict__ wph,
            const float* __restrict__ b2,
            const float* __restrict__ g2, const float* __restrict__ be2,
            const float* __restrict__ W3,
            float* __restrict__ p0, float* __restrict__ p1,
            float* __restrict__ p2, float* __restrict__ p3) {
    extern __shared__ uint32_t smu[];
    float* smf = (float*)smu;
    const int t = threadIdx.x;
    const int lane = t & 31, wid = t >> 5;
    const int wrow = wid >> 1, wcol = wid & 1;
    const int r0 = blockIdx.x * 128;

    #pragma unroll
    for (int i2 = t; i2 < 512; i2 += 256) {
        int kch = i2 >> 6, f = i2 & 63;
        smf[SW3_OFF + i2] = W3[(kch >> 1)*128 + f*2 + (kch & 1)];
    }

    int a_w[4], a_src[4];
    #pragma unroll
    for (int i = 0; i < 4; i++) {
        int idx = i*256 + t;
        int row = idx >> 3, c4 = idx & 7;
        int rr = row & 15, mt = row >> 4;
        int ks = c4 >> 2, regbit = (c4 >> 1) & 1, q0 = (c4 & 1) * 2;
        int g = rr & 7, abit = rr >> 3;
        a_w[i] = (mt*2 + ks)*128 + (g*4 + q0)*4 + abit + 2*regbit;
        a_src[i] = row*32 + c4*2;
    }
    int b_w[2], b_src[2];
    #pragma unroll
    for (int i = 0; i < 2; i++) {
        int idx = i*256 + t;
        int n = idx >> 3, c4 = idx & 7;
        int ks = c4 >> 2, regbit = (c4 >> 1) & 1, q0 = (c4 & 1) * 2;
        int g = n & 7, nt = n >> 3;
        b_w[i] = 2048 + (nt*2 + ks)*64 + (g*4 + q0)*2 + regbit;
        b_src[i] = n*128 + c4*2;
    }

    float c[2][4][4];
    #pragma unroll
    for (int m = 0; m < 2; m++)
        #pragma unroll
        for (int n = 0; n < 4; n++)
            #pragma unroll
            for (int k = 0; k < 4; k++) c[m][n][k] = 0.f;

    uint2 pa[4], pbh[2];

    {
        #pragma unroll
        for (int i = 0; i < 4; i++)
            pa[i] = *(const uint2*)(A0 + (size_t)r0*32 + a_src[i]);
        #pragma unroll
        for (int i = 0; i < 2; i++)
            pbh[i] = *(const uint2*)(wph + b_src[i]);
        uint32_t* base = smu;
        #pragma unroll
        for (int i = 0; i < 4; i++) {
            base[a_w[i]]     = pa[i].x;
            base[a_w[i] + 4] = pa[i].y;
        }
        #pragma unroll
        for (int i = 0; i < 2; i++) {
            base[b_w[i]]     = pbh[i].x;
            base[b_w[i] + 2] = pbh[i].y;
        }
    }
    __syncthreads();

    #pragma unroll 1
    for (int cc = 0; cc < 8; cc++) {
        int stage = cc & 1;
        if (cc < 7) {
            int cn = cc + 1;
            const uint32_t* Ap = (cn < 2) ? A0 : (cn < 4) ? A1 : (cn < 6) ? A2 : A3;
            int kb = (cn & 1) * 16;
            #pragma unroll
            for (int i = 0; i < 4; i++)
                pa[i] = *(const uint2*)(Ap + (size_t)r0*32 + a_src[i] + kb);
            #pragma unroll
            for (int i = 0; i < 2; i++)
                pbh[i] = *(const uint2*)(wph + b_src[i] + cn*16);
        }
        {
            const uint32_t* base = smu + stage*STG_U32;
            #pragma unroll
            for (int ks = 0; ks < 2; ks++) {
                uint4 ah[2];
                #pragma unroll
                for (int mt = 0; mt < 2; mt++) {
                    int mtile = wrow*2 + mt;
                    ah[mt] = *(const uint4*)(base + (mtile*2+ks)*128 + lane*4);
                }
                uint2 bh[4];
                #pragma unroll
                for (int nt = 0; nt < 4; nt++) {
                    int ntile = wcol*4 + nt;
                    bh[nt] = *(const uint2*)(base + 2048 + (ntile*2+ks)*64 + lane*2);
                }
                #pragma unroll
                for (int mt = 0; mt < 2; mt++)
                    #pragma unroll
                    for (int nt = 0; nt < 4; nt++)
                        MMAH(c[mt][nt], ah[mt].x, ah[mt].y, ah[mt].z, ah[mt].w,
                             bh[nt].x, bh[nt].y);
            }
        }
        if (cc < 7) {
            uint32_t* base = smu + ((cc+1)&1)*STG_U32;
            #pragma unroll
            for (int i = 0; i < 4; i++) {
                base[a_w[i]]     = pa[i].x;
                base[a_w[i] + 4] = pa[i].y;
            }
            #pragma unroll
            for (int i = 0; i < 2; i++) {
                base[b_w[i]]     = pbh[i].x;
                base[b_w[i] + 2] = pbh[i].y;
            }
        }
        __syncthreads();
    }

    /* ---- fused BN2 + LeakyReLU + W3 projections ---- */
    {
        float* so = smf;
        const int g = lane >> 2, q = lane & 3;
        #pragma unroll
        for (int mt = 0; mt < 2; mt++) {
            int lr = wrow*32 + mt*16 + g;
            #pragma unroll
            for (int nt = 0; nt < 4; nt++) {
                int col = wcol*32 + nt*8 + 2*q;
                float bx = __ldg(&b2[col]), by = __ldg(&b2[col+1]);
                so[lr*68+col]       = c[mt][nt][0] + bx;
                so[lr*68+col+1]     = c[mt][nt][1] + by;
                so[(lr+8)*68+col]   = c[mt][nt][2] + bx;
                so[(lr+8)*68+col+1] = c[mt][nt][3] + by;
            }
        }
    }
    __syncthreads();
    {
        const float* so = smf;
        const float* sw3 = smf + SW3_OFF;
        int sub = lane >> 3, c8 = (lane & 7) * 8;
        #pragma unroll
        for (int nn = 0; nn < 4; nn++) {
            int node = wid*4 + nn;
            int gnode = blockIdx.x*32 + node;
            int gn = gnode < N_NODES ? gnode : N_NODES-1;
            const float* rp = so + (node*4 + sub)*68 + c8;
            float4 v0 = *(const float4*)rp;
            float4 v1 = *(const float4*)(rp + 4);
            float s = v0.x+v0.y+v0.z+v0.w + v1.x+v1.y+v1.z+v1.w;
            float q = v0.x*v0.x+v0.y*v0.y+v0.z*v0.z+v0.w*v0.w
                    + v1.x*v1.x+v1.y*v1.y+v1.z*v1.z+v1.w*v1.w;
            #pragma unroll
            for (int o = 16; o; o >>= 1) {
                s += __shfl_xor_sync(0xffffffffu, s, o);
                q += __shfl_xor_sync(0xffffffffu, q, o);
            }
            float mu  = s * (1.f/256.f);
            float var = q * (1.f/256.f) - mu*mu;
            float sc  = __ldg(&g2[gn]) * rsqrtf(var + BN_EPS);
            float bb  = __ldg(&be2[gn]);
            float o0, o1, o2, o3, o4, o5, o6, o7, f;
            f = sc*(v0.x-mu)+bb; o0 = f > 0.f ? f : SLOPE*f;
            f = sc*(v0.y-mu)+bb; o1 = f > 0.f ? f : SLOPE*f;
            f = sc*(v0.z-mu)+bb; o2 = f > 0.f ? f : SLOPE*f;
            f = sc*(v0.w-mu)+bb; o3 = f > 0.f ? f : SLOPE*f;
            f = sc*(v1.x-mu)+bb; o4 = f > 0.f ? f : SLOPE*f;
            f = sc*(v1.y-mu)+bb; o5 = f > 0.f ? f : SLOPE*f;
            f = sc*(v1.z-mu)+bb; o6 = f > 0.f ? f : SLOPE*f;
            f = sc*(v1.w-mu)+bb; o7 = f > 0.f ? f : SLOPE*f;
            float pr[8];
            #pragma unroll
            for (int kch = 0; kch < 8; kch++) {
                const float* w = sw3 + kch*64 + c8;
                float4 w0 = *(const float4*)w;
                float4 w1 = *(const float4*)(w + 4);
                pr[kch] = o0*w0.x + o1*w0.y + o2*w0.z + o3*w0.w
                        + o4*w1.x + o5*w1.y + o6*w1.z + o7*w1.w;
            }
            #pragma unroll
            for (int m = 1; m <= 4; m <<= 1) {
                #pragma unroll
                for (int kch = 0; kch < 8; kch++)
                    pr[kch] += __shfl_xor_sync(0xffffffffu, pr[kch], m);
            }
            if ((lane & 7) == 0 && gnode < N_NODES) {
                size_t grow = (size_t)(r0 + node*4 + sub)*2;
                *(float2*)&p0[grow] = make_float2(pr[0], pr[1]);
                *(float2*)&p1[grow] = make_float2(pr[2], pr[3]);
                *(float2*)&p2[grow] = make_float2(pr[4], pr[5]);
                *(float2*)&p3[grow] = make_float2(pr[6], pr[7]);
            }
        }
    }
}

/* ======================================================================= */
extern "C" void kernel_launch(void* const* d_in, const int* in_sizes, int n_in,
                              void* d_out, int out_size) {
    const float* x      = (const float*)d_in[0];
    const int*   src    = (const int*)  d_in[1];
    const int*   dst    = (const int*)  d_in[2];
    const float* ew     = (const float*)d_in[3];
    const float* W1     = (const float*)d_in[4];
    const float* b1     = (const float*)d_in[5];
    const float* W2     = (const float*)d_in[6];
    const float* b2     = (const float*)d_in[7];
    const float* W3     = (const float*)d_in[8];
    const float* b3     = (const float*)d_in[9];
    const float* g1     = (const float*)d_in[10];
    const float* be1    = (const float*)d_in[11];
    const float* g2     = (const float*)d_in[12];
    const float* be2    = (const float*)d_in[13];
    const float* mask   = (const float*)d_in[14];
    const float* mean_y = (const float*)d_in[15];
    const float* std_y  = (const float*)d_in[16];
    const float* vmin   = (const float*)d_in[17];
    const float* vmax   = (const float*)d_in[18];
    const float* qmin   = (const float*)d_in[19];
    const float* qmax   = (const float*)d_in[20];
    float* out = (float*)d_out;

    float *pa, *pb, *pc, *sa, *sb;
    uint32_t *x16, *pa16, *pb16, *pc16;
    uint32_t *h16, *t116, *t216, *t316, *w2ph, *w1ph, *w1pl;
    cudaGetSymbolAddress((void**)&pa,  g_pa);
    cudaGetSymbolAddress((void**)&pb,  g_pb);
    cudaGetSymbolAddress((void**)&pc,  g_pc);
    cudaGetSymbolAddress((void**)&sa,  g_sa);
    cudaGetSymbolAddress((void**)&sb,  g_sb);
    cudaGetSymbolAddress((void**)&x16,  g_x16);
    cudaGetSymbolAddress((void**)&pa16, g_pa16);
    cudaGetSymbolAddress((void**)&pb16, g_pb16);
    cudaGetSymbolAddress((void**)&pc16, g_pc16);
    cudaGetSymbolAddress((void**)&h16,  g_h16);
    cudaGetSymbolAddress((void**)&t116, g_t116);
    cudaGetSymbolAddress((void**)&t216, g_t216);
    cudaGetSymbolAddress((void**)&t316, g_t316);
    cudaGetSymbolAddress((void**)&w2ph, g_w2p_hi);
    cudaGetSymbolAddress((void**)&w1ph, g_w1p_hi);
    cudaGetSymbolAddress((void**)&w1pl, g_w1p_lo);

    static int smem_set = 0;
    if (!smem_set) {
        cudaFuncSetAttribute(k_gemm2_mma, cudaFuncAttributeMaxDynamicSharedMemorySize, 36864);
        cudaFuncSetAttribute(k_gemm1_mma, cudaFuncAttributeMaxDynamicSharedMemorySize, 34816);
        smem_set = 1;
    }

    const int TB = 256;
    int gE  = (N_EDGES + TB - 1) / TB;
    int gR  = (R + TB - 1) / TB;
    int gR4 = (N_NODES*4 + TB - 1) / TB;    /* 4 threads per node */
    int gW  = (N_NODES*32 + TB - 1) / TB;

    /* preprocessing (fused) */
    k_init_xt<<<gR, TB>>>(x);
    k_deg_w2 <<<gE, TB>>>(dst, ew, W2, W1);
    k_scan1  <<<NB_SCAN, 256>>>();
    k_scan23 <<<NB_SCAN, 256>>>();
    k_fill   <<<gE, TB>>>(src, dst, ew);

    /* layer 1: fp16 prop at F=4 (4 thr/node), GEMM+BN+LReLU -> fp16 h */
    k_prop4h<<<gR4, TB>>>(x16,  pa16);
    k_prop4h<<<gR4, TB>>>(pa16, pb16);
    k_prop4h<<<gR4, TB>>>(pb16, pc16);
    k_gemm1_mma<<<RPAD/128, 256, 34816>>>(x16, pa16, pb16, pc16, w1ph, w1pl,
                                          b1, g1, be1, h16);

    /* layer 2: 3x fp16 prop64, fused GEMM+BN+projections -> p0..p3 */
    k_prop64h<<<gW, TB>>>(h16,  t116);
    k_prop64h<<<gW, TB>>>(t116, t216);
    k_prop64h<<<gW, TB>>>(t216, t316);
    k_gemm2_mma<<<RPAD/128, 256, 36864>>>(h16, t116, t216, t316, w2ph,
                                          b2, g2, be2, W3, pb, pa, sb, sa);

    /* layer 3: Horner at F=2, 4 thr/node (p0->pb, p1->pa, p2->sb, p3->sa) */
    k_prop2<true ><<<gR4, TB>>>(sa, pc, sb);
    k_prop2<true ><<<gR4, TB>>>(pc, sa, pa);
    k_prop2_final<<<gR4, TB>>>(sa, pb, b3, mask, mean_y, std_y,
                               vmin, vmax, qmin, qmax, out);
}

// round 15
// speedup vs baseline: 2.6859x; 1.0168x over previous
#include <cuda_runtime.h>
#include <cuda_fp16.h>
#include <math.h>
#include <cstdint>

#define N_NODES 50000
#define N_EDGES 400000
#define BATCH 4
#define R (N_NODES*BATCH)      /* 200000 rows (n,b) */
#define RPAD 200064            /* padded to 128-row GEMM tiles */
#define BN_EPS 1e-5f
#define SLOPE 0.01f
#define NB_SCAN ((N_NODES + 255) / 256)   /* 196 */

/* ---------------- static device scratch (no allocations allowed) -------- */
__device__ __align__(16) float g_deg[N_NODES];      /* zeroed by tail kernel */
__device__ __align__(16) float g_dis[N_NODES];
__device__ __align__(16) int   g_cnt[N_NODES];      /* zeroed by tail kernel */
__device__ __align__(16) int   g_rowptr[N_NODES+1];
__device__ __align__(16) int   g_cur[N_NODES];
__device__ __align__(16) int   g_col[N_EDGES];
__device__ __align__(16) float g_wcsr[N_EDGES];
__device__ __align__(16) int   g_bsum[256];
__device__ __align__(16) int   g_flag[256];         /* zeroed by tail kernel */

/* fp16 layer-1 features: [row][4 halfs] = [row][2 u32]; node owns 4 rows */
__device__ __align__(16) uint32_t g_x16 [RPAD*2];
__device__ __align__(16) uint32_t g_pa16[RPAD*2];
__device__ __align__(16) uint32_t g_pb16[RPAD*2];
__device__ __align__(16) uint32_t g_pc16[RPAD*2];

/* float scratch for layer-3 p-values ([R][2] each) */
__device__ __align__(16) float g_pa[RPAD*4];
__device__ __align__(16) float g_pb[RPAD*4];
__device__ __align__(16) float g_pc[RPAD*4];
__device__ __align__(16) float g_sa[RPAD*2];
__device__ __align__(16) float g_sb[RPAD*2];

/* fp16 hidden states: [row][64] halfs = [row][32] u32 */
__device__ __align__(16) uint32_t g_h16 [RPAD*32];
__device__ __align__(16) uint32_t g_t116[RPAD*32];
__device__ __align__(16) uint32_t g_t216[RPAD*32];
__device__ __align__(16) uint32_t g_t316[RPAD*32];

/* W2 transposed [64 n][128 kpair], fp16x2-packed */
__device__ __align__(16) uint32_t g_w2p_hi[64*128];
/* W1 transposed [64 n][8 kpair], fp16x2-packed hi/lo (K=16) */
__device__ __align__(16) uint32_t g_w1p_hi[64*8];
__device__ __align__(16) uint32_t g_w1p_lo[64*8];

#define MMAH(C, a0,a1,a2,a3, b0,b1) \
    asm volatile("mma.sync.aligned.m16n8k16.row.col.f32.f16.f16.f32 " \
        "{%0,%1,%2,%3},{%4,%5,%6,%7},{%8,%9},{%0,%1,%2,%3};" \
        : "+f"((C)[0]),"+f"((C)[1]),"+f"((C)[2]),"+f"((C)[3]) \
        : "r"(a0),"r"(a1),"r"(a2),"r"(a3),"r"(b0),"r"(b1))

__device__ __forceinline__ uint32_t h2u(__half2 h) {
    uint32_t u; memcpy(&u, &h, 4); return u;
}
__device__ __forceinline__ __half2 u2h(uint32_t u) {
    __half2 h; memcpy(&h, &u, 4); return h;
}

/* ---------------- preprocessing --------------------------------------- */
/* degree atomics + x->fp16 transpose + W1/W2 prep (deg/cnt pre-zeroed by
 * previous call's tail kernel; statically zero on first call) */
__global__ void k_deg_w2(const int* __restrict__ dst, const float* __restrict__ ew,
                         const float* __restrict__ x,
                         const float* __restrict__ W2, const float* __restrict__ W1) {
    int e = blockIdx.x*blockDim.x + threadIdx.x;
    if (e < N_EDGES) {
        int d = dst[e];
        atomicAdd(&g_deg[d], ew[e]);
        atomicAdd(&g_cnt[d], 1);
    }
    if (e < R) {
        int b = e / N_NODES, n = e - b*N_NODES;
        float4 v = ((const float4*)x)[e];
        uint2 pk;
        pk.x = h2u(__floats2half2_rn(v.x, v.y));
        pk.y = h2u(__floats2half2_rn(v.z, v.w));
        *(uint2*)&g_x16[(size_t)(n*4 + b)*2] = pk;
    }
    if (e < 64*128) {
        int n = e >> 7, p = e & 127;
        int k0 = 2*p;
        int sel = k0 >> 6, kk = k0 & 63;
        float v0 = W2[sel*4096 + kk*64 + n];
        float v1 = W2[sel*4096 + (kk+1)*64 + n];
        g_w2p_hi[e] = h2u(__floats2half2_rn(v0, v1));
    }
    if (e < 64*8) {
        int n = e >> 3, p = e & 7;
        int k0 = 2*p;
        float v0 = W1[k0*64 + n];
        float v1 = W1[(k0+1)*64 + n];
        __half h0 = __float2half_rn(v0), h1 = __float2half_rn(v1);
        float l0 = v0 - __half2float(h0), l1 = v1 - __half2float(h1);
        g_w1p_hi[e] = h2u(__halves2half2(h0, h1));
        g_w1p_lo[e] = h2u(__floats2half2_rn(l0, l1));
    }
}

/* single-pass scan with decoupled lookback; also computes dis and cur */
__global__ void k_scan() {
    int t = threadIdx.x, b = blockIdx.x;
    int i = b*256 + t;
    int v = (i < N_NODES) ? g_cnt[i] : 0;
    int lane = t & 31, wp = t >> 5;
    int x = v;
    #pragma unroll
    for (int o = 1; o < 32; o <<= 1) {
        int y = __shfl_up_sync(0xffffffffu, x, o);
        if (lane >= o) x += y;
    }
    __shared__ int wt[8];
    __shared__ int s_off;
    if (lane == 31) wt[wp] = x;
    if (t == 0) s_off = 0;
    __syncthreads();
    if (wp == 0 && lane < 8) {
        int y = wt[lane];
        #pragma unroll
        for (int o = 1; o < 8; o <<= 1) {
            int z = __shfl_up_sync(0xffu, y, o);
            if (lane >= o) y += z;
        }
        wt[lane] = y;
    }
    __syncthreads();
    int incl = x + (wp ? wt[wp-1] : 0);
    if (t == 0) {
        g_bsum[b] = wt[7];              /* block total */
        __threadfence();
        atomicExch(&g_flag[b], 1);
    }
    /* lookback: thread t reads predecessor t's total */
    int part = 0;
    if (t < b) {
        while (atomicAdd(&g_flag[t], 0) == 0) { }
        part = g_bsum[t];
    }
    #pragma unroll
    for (int o = 16; o; o >>= 1) part += __shfl_xor_sync(0xffffffffu, part, o);
    if (lane == 0 && part != 0) atomicAdd(&s_off, part);
    __syncthreads();
    if (i < N_NODES) {
        int p = incl - v + s_off;
        g_rowptr[i] = p;
        g_cur[i] = p;
        float d = g_deg[i];
        g_dis[i] = (d > 0.f) ? rsqrtf(fmaxf(d, 1e-30f)) : 0.f;
    }
    if (b == NB_SCAN-1 && t == 255) g_rowptr[N_NODES] = N_EDGES;
}

__global__ void k_fill(const int* __restrict__ src, const int* __restrict__ dst,
                       const float* __restrict__ ew) {
    int e = blockIdx.x*blockDim.x + threadIdx.x;
    if (e < N_EDGES) {
        int s = src[e], d = dst[e];
        int p = atomicAdd(&g_cur[d], 1);
        g_col[p]  = s;
        g_wcsr[p] = g_dis[s] * ew[e] * g_dis[d];
    }
}

/* ---------------- propagation ------------------------------------------ */
/* fp16 F=4 prop: 4 threads per node, thread j owns batch row j (uint2) */
__global__ void k_prop4h(const uint32_t* __restrict__ in, uint32_t* __restrict__ out) {
    int gt = blockIdx.x*blockDim.x + threadIdx.x;
    int n = gt >> 2, j = gt & 3;
    if (n >= N_NODES) return;
    float4 acc = make_float4(0.f,0.f,0.f,0.f);
    int s = g_rowptr[n], e = g_rowptr[n+1];
    int i = s;
    for (; i + 2 <= e; i += 2) {
        int c0 = __ldg(&g_col[i]),    c1 = __ldg(&g_col[i+1]);
        float w0 = __ldg(&g_wcsr[i]), w1 = __ldg(&g_wcsr[i+1]);
        uint2 v0 = __ldg((const uint2*)(in + c0*8 + j*2));
        uint2 v1 = __ldg((const uint2*)(in + c1*8 + j*2));
        float2 f;
        f = __half22float2(u2h(v0.x)); acc.x += w0*f.x; acc.y += w0*f.y;
        f = __half22float2(u2h(v0.y)); acc.z += w0*f.x; acc.w += w0*f.y;
        f = __half22float2(u2h(v1.x)); acc.x += w1*f.x; acc.y += w1*f.y;
        f = __half22float2(u2h(v1.y)); acc.z += w1*f.x; acc.w += w1*f.y;
    }
    if (i < e) {
        int c = __ldg(&g_col[i]);
        float wv = __ldg(&g_wcsr[i]);
        uint2 v = __ldg((const uint2*)(in + c*8 + j*2));
        float2 f;
        f = __half22float2(u2h(v.x)); acc.x += wv*f.x; acc.y += wv*f.y;
        f = __half22float2(u2h(v.y)); acc.z += wv*f.x; acc.w += wv*f.y;
    }
    uint2 pk;
    pk.x = h2u(__floats2half2_rn(acc.x, acc.y));
    pk.y = h2u(__floats2half2_rn(acc.z, acc.w));
    *(uint2*)(out + n*8 + j*2) = pk;
}

/* fp32 F=2 prop (layer-3 Horner): 4 threads per node, row j */
template<bool ADD>
__global__ void k_prop2(const float* __restrict__ in, float* __restrict__ out,
                        const float* __restrict__ add) {
    int gt = blockIdx.x*blockDim.x + threadIdx.x;
    int n = gt >> 2, j = gt & 3;
    if (n >= N_NODES) return;
    float2 acc = make_float2(0.f, 0.f);
    int s = g_rowptr[n], e = g_rowptr[n+1];
    int i = s;
    for (; i + 2 <= e; i += 2) {
        int c0 = __ldg(&g_col[i]),    c1 = __ldg(&g_col[i+1]);
        float w0 = __ldg(&g_wcsr[i]), w1 = __ldg(&g_wcsr[i+1]);
        float2 v0 = __ldg((const float2*)(in + (size_t)(c0*4 + j)*2));
        float2 v1 = __ldg((const float2*)(in + (size_t)(c1*4 + j)*2));
        acc.x += w0*v0.x; acc.y += w0*v0.y;
        acc.x += w1*v1.x; acc.y += w1*v1.y;
    }
    if (i < e) {
        int c = __ldg(&g_col[i]);
        float wv = __ldg(&g_wcsr[i]);
        float2 v = __ldg((const float2*)(in + (size_t)(c*4 + j)*2));
        acc.x += wv*v.x; acc.y += wv*v.y;
    }
    if (ADD) {
        float2 d = *(const float2*)(add + (size_t)(n*4 + j)*2);
        acc.x += d.x; acc.y += d.y;
    }
    *(float2*)(out + (size_t)(n*4 + j)*2) = acc;
}

/* final Horner prop fused with output epilogue + next-call state zeroing */
__global__ void k_prop2_final(const float* __restrict__ in,
                              const float* __restrict__ p0,
                              const float* __restrict__ b3,
                              const float* __restrict__ mask,
                              const float* __restrict__ mean_y,
                              const float* __restrict__ std_y,
                              const float* __restrict__ vmin, const float* __restrict__ vmax,
                              const float* __restrict__ qmin, const float* __restrict__ qmax,
                              float* __restrict__ out) {
    int gt = blockIdx.x*blockDim.x + threadIdx.x;
    /* re-zero accumulation state for the next graph replay */
    if (gt < N_NODES) { g_deg[gt] = 0.f; g_cnt[gt] = 0; }
    if (gt < 256) g_flag[gt] = 0;
    int n = gt >> 2, j = gt & 3;
    if (n >= N_NODES) return;
    float2 acc = make_float2(0.f, 0.f);
    int s = g_rowptr[n], e = g_rowptr[n+1];
    int i = s;
    for (; i + 2 <= e; i += 2) {
        int c0 = __ldg(&g_col[i]),    c1 = __ldg(&g_col[i+1]);
        float w0 = __ldg(&g_wcsr[i]), w1 = __ldg(&g_wcsr[i+1]);
        float2 v0 = __ldg((const float2*)(in + (size_t)(c0*4 + j)*2));
        float2 v1 = __ldg((const float2*)(in + (size_t)(c1*4 + j)*2));
        acc.x += w0*v0.x; acc.y += w0*v0.y;
        acc.x += w1*v1.x; acc.y += w1*v1.y;
    }
    if (i < e) {
        int c = __ldg(&g_col[i]);
        float wv = __ldg(&g_wcsr[i]);
        float2 v = __ldg((const float2*)(in + (size_t)(c*4 + j)*2));
        acc.x += wv*v.x; acc.y += wv*v.y;
    }
    float2 z = *(const float2*)(p0 + (size_t)(n*4 + j)*2);
    float u0 = acc.x + z.x + __ldg(&b3[0]);
    float u1 = acc.y + z.y + __ldg(&b3[1]);
    float s0 = std_y[n*2], s1 = std_y[n*2+1];
    if (isinf(s0)) s0 = 0.f;
    if (isinf(s1)) s1 = 0.f;
    float o0 = (u0*s0 + mean_y[n*2])   * mask[n*2];
    float o1 = (u1*s1 + mean_y[n*2+1]) * mask[n*2+1];
    o0 = fminf(fmaxf(o0, vmin[n]), vmax[n]);
    o1 = fminf(fmaxf(o1, qmin[n]), qmax[n]);
    *(float2*)&out[(size_t)(j*N_NODES + n)*2] = make_float2(o0, o1);
}

/* fp16 payload prop: warp per node, 4-way predicated edge loop */
__global__ void k_prop64h(const uint32_t* __restrict__ in, uint32_t* __restrict__ out) {
    int gt = blockIdx.x*blockDim.x + threadIdx.x;
    int n = gt >> 5, lane = gt & 31;
    if (n >= N_NODES) return;
    int s = g_rowptr[n], e = g_rowptr[n+1];
    float2 a0 = make_float2(0.f,0.f), a1 = a0, a2 = a0, a3 = a0;
    for (int i = s; i < e; i += 4) {
        int   c[4];
        float w[4];
        uint4 v[4];
        #pragma unroll
        for (int j = 0; j < 4; j++) {
            int idx = i + j;
            bool act = idx < e;
            c[j] = act ? __ldg(&g_col[idx]) : 0;
            w[j] = act ? __ldg(&g_wcsr[idx]) : 0.f;
        }
        #pragma unroll
        for (int j = 0; j < 4; j++)
            v[j] = __ldg((const uint4*)(in + c[j]*128 + lane*4));
        #pragma unroll
        for (int j = 0; j < 4; j++) {
            float2 f;
            f = __half22float2(u2h(v[j].x)); a0.x += w[j]*f.x; a0.y += w[j]*f.y;
            f = __half22float2(u2h(v[j].y)); a1.x += w[j]*f.x; a1.y += w[j]*f.y;
            f = __half22float2(u2h(v[j].z)); a2.x += w[j]*f.x; a2.y += w[j]*f.y;
            f = __half22float2(u2h(v[j].w)); a3.x += w[j]*f.x; a3.y += w[j]*f.y;
        }
    }
    uint4 o;
    o.x = h2u(__floats2half2_rn(a0.x, a0.y));
    o.y = h2u(__floats2half2_rn(a1.x, a1.y));
    o.z = h2u(__floats2half2_rn(a2.x, a2.y));
    o.w = h2u(__floats2half2_rn(a3.x, a3.y));
    *(uint4*)(out + n*128 + lane*4) = o;
}

/* ---------------- layer-1 GEMM (fp16 A direct) + BN + LReLU -> fp16 h --- */
__global__ void __launch_bounds__(256, 2)
k_gemm1_mma(const uint32_t* __restrict__ A0, const uint32_t* __restrict__ A1,
            const uint32_t* __restrict__ A2, const uint32_t* __restrict__ A3,
            const uint32_t* __restrict__ w1h, const uint32_t* __restrict__ w1l,
            const float* __restrict__ b1,
            const float* __restrict__ g1, const float* __restrict__ be1,
            uint32_t* __restrict__ hout) {
    extern __shared__ uint32_t smu[];
    float* smf = (float*)smu;
    const int t = threadIdx.x;
    const int lane = t & 31, wid = t >> 5;
    const int wrow = wid >> 1, wcol = wid & 1;
    const int r0 = blockIdx.x * 128;

    {
        int n = t >> 2, c4 = t & 3;
        int regbit = (c4 >> 1) & 1, q0 = (c4 & 1) * 2;
        int g = n & 7, nt = n >> 3;
        int b_w = 1024 + nt*64 + (g*4 + q0)*2 + regbit;
        uint2 vh = *(const uint2*)(w1h + n*8 + c4*2);
        uint2 vl = *(const uint2*)(w1l + n*8 + c4*2);
        smu[b_w]       = vh.x;
        smu[b_w + 2]   = vh.y;
        smu[512 + b_w]     = vl.x;
        smu[512 + b_w + 2] = vl.y;
    }
    #pragma unroll
    for (int sidx = 0; sidx < 2; sidx++) {
        int idx = sidx*256 + t;
        int row = idx >> 2, c4 = idx & 3;
        int rr = row & 15, mt = row >> 4;
        int regbit = (c4 >> 1) & 1, q0 = (c4 & 1) * 2;
        int g = rr & 7, abit = rr >> 3;
        int a_w = mt*128 + (g*4 + q0)*4 + abit + 2*regbit;
        const uint32_t* Ap = (c4 == 0) ? A0 : (c4 == 1) ? A1 : (c4 == 2) ? A2 : A3;
        uint2 v = *(const uint2*)(Ap + (size_t)(r0 + row)*2);
        smu[a_w]     = v.x;
        smu[a_w + 4] = v.y;
    }
    __syncthreads();

    float c[2][4][4];
    #pragma unroll
    for (int m = 0; m < 2; m++)
        #pragma unroll
        for (int n = 0; n < 4; n++)
            #pragma unroll
            for (int k = 0; k < 4; k++) c[m][n][k] = 0.f;

    {
        uint4 ah[2];
        #pragma unroll
        for (int mt = 0; mt < 2; mt++) {
            int mtile = wrow*2 + mt;
            ah[mt] = *(const uint4*)(smu + mtile*128 + lane*4);
        }
        uint2 bh[4], bl[4];
        #pragma unroll
        for (int nt = 0; nt < 4; nt++) {
            int ntile = wcol*4 + nt;
            bh[nt] = *(const uint2*)(smu + 1024 + ntile*64 + lane*2);
            bl[nt] = *(const uint2*)(smu + 1536 + ntile*64 + lane*2);
        }
        #pragma unroll
        for (int mt = 0; mt < 2; mt++)
            #pragma unroll
            for (int nt = 0; nt < 4; nt++) {
                MMAH(c[mt][nt], ah[mt].x, ah[mt].y, ah[mt].z, ah[mt].w,
                     bh[nt].x, bh[nt].y);
                MMAH(c[mt][nt], ah[mt].x, ah[mt].y, ah[mt].z, ah[mt].w,
                     bl[nt].x, bl[nt].y);
            }
    }
    __syncthreads();

    {
        float* so = smf;
        const int g = lane >> 2, q = lane & 3;
        #pragma unroll
        for (int mt = 0; mt < 2; mt++) {
            int lr = wrow*32 + mt*16 + g;
            #pragma unroll
            for (int nt = 0; nt < 4; nt++) {
                int col = wcol*32 + nt*8 + 2*q;
                float bx = __ldg(&b1[col]), by = __ldg(&b1[col+1]);
                so[lr*68+col]       = c[mt][nt][0] + bx;
                so[lr*68+col+1]     = c[mt][nt][1] + by;
                so[(lr+8)*68+col]   = c[mt][nt][2] + bx;
                so[(lr+8)*68+col+1] = c[mt][nt][3] + by;
            }
        }
    }
    __syncthreads();
    {
        const float* so = smf;
        int sub = lane >> 3, c8 = (lane & 7) * 8;
        #pragma unroll
        for (int nn = 0; nn < 4; nn++) {
            int node = wid*4 + nn;
            int gnode = blockIdx.x*32 + node;
            int gn = gnode < N_NODES ? gnode : N_NODES-1;
            const float* rp = so + (node*4 + sub)*68 + c8;
            float4 v0 = *(const float4*)rp;
            float4 v1 = *(const float4*)(rp + 4);
            float s = v0.x+v0.y+v0.z+v0.w + v1.x+v1.y+v1.z+v1.w;
            float q = v0.x*v0.x+v0.y*v0.y+v0.z*v0.z+v0.w*v0.w
                    + v1.x*v1.x+v1.y*v1.y+v1.z*v1.z+v1.w*v1.w;
            #pragma unroll
            for (int o = 16; o; o >>= 1) {
                s += __shfl_xor_sync(0xffffffffu, s, o);
                q += __shfl_xor_sync(0xffffffffu, q, o);
            }
            float mu  = s * (1.f/256.f);
            float var = q * (1.f/256.f) - mu*mu;
            float sc  = __ldg(&g1[gn]) * rsqrtf(var + BN_EPS);
            float bb  = __ldg(&be1[gn]);
            float o0, o1, o2, o3, o4, o5, o6, o7, f;
            f = sc*(v0.x-mu)+bb; o0 = f > 0.f ? f : SLOPE*f;
            f = sc*(v0.y-mu)+bb; o1 = f > 0.f ? f : SLOPE*f;
            f = sc*(v0.z-mu)+bb; o2 = f > 0.f ? f : SLOPE*f;
            f = sc*(v0.w-mu)+bb; o3 = f > 0.f ? f : SLOPE*f;
            f = sc*(v1.x-mu)+bb; o4 = f > 0.f ? f : SLOPE*f;
            f = sc*(v1.y-mu)+bb; o5 = f > 0.f ? f : SLOPE*f;
            f = sc*(v1.z-mu)+bb; o6 = f > 0.f ? f : SLOPE*f;
            f = sc*(v1.w-mu)+bb; o7 = f > 0.f ? f : SLOPE*f;
            if (gnode < N_NODES) {
                uint4 pk;
                pk.x = h2u(__floats2half2_rn(o0, o1));
                pk.y = h2u(__floats2half2_rn(o2, o3));
                pk.z = h2u(__floats2half2_rn(o4, o5));
                pk.w = h2u(__floats2half2_rn(o6, o7));
                *(uint4*)&hout[(size_t)(r0 + node*4 + sub)*32 + (lane & 7)*4] = pk;
            }
        }
    }
}

/* ---------------- layer-2 GEMM (fp16 A, fp16 B) + BN + projections ------ */
#define STG_U32 3072
#define SW3_OFF 8704
__global__ void __launch_bounds__(256, 2)
k_gemm2_mma(const uint32_t* __restrict__ A0, const uint32_t* __restrict__ A1,
            const uint32_t* __restrict__ A2, const uint32_t* __restrict__ A3,
            const uint32_t* __restrict__ wph,
            const float* __restrict__ b2,
            const float* __restrict__ g2, const float* __restrict__ be2,
            const float* __restrict__ W3,
            float* __restrict__ p0, float* __restrict__ p1,
            float* __restrict__ p2, float* __restrict__ p3) {
    extern __shared__ uint32_t smu[];
    float* smf = (float*)smu;
    const int t = threadIdx.x;
    const int lane = t & 31, wid = t >> 5;
    const int wrow = wid >> 1, wcol = wid & 1;
    const int r0 = blockIdx.x * 128;

    #pragma unroll
    for (int i2 = t; i2 < 512; i2 += 256) {
        int kch = i2 >> 6, f = i2 & 63;
        smf[SW3_OFF + i2] = W3[(kch >> 1)*128 + f*2 + (kch & 1)];
    }

    int a_w[4], a_src[4];
    #pragma unroll
    for (int i = 0; i < 4; i++) {
        int idx = i*256 + t;
        int row = idx >> 3, c4 = idx & 7;
        int rr = row & 15, mt = row >> 4;
        int ks = c4 >> 2, regbit = (c4 >> 1) & 1, q0 = (c4 & 1) * 2;
        int g = rr & 7, abit = rr >> 3;
        a_w[i] = (mt*2 + ks)*128 + (g*4 + q0)*4 + abit + 2*regbit;
        a_src[i] = row*32 + c4*2;
    }
    int b_w[2], b_src[2];
    #pragma unroll
    for (int i = 0; i < 2; i++) {
        int idx = i*256 + t;
        int n = idx >> 3, c4 = idx & 7;
        int ks = c4 >> 2, regbit = (c4 >> 1) & 1, q0 = (c4 & 1) * 2;
        int g = n & 7, nt = n >> 3;
        b_w[i] = 2048 + (nt*2 + ks)*64 + (g*4 + q0)*2 + regbit;
        b_src[i] = n*128 + c4*2;
    }

    float c[2][4][4];
    #pragma unroll
    for (int m = 0; m < 2; m++)
        #pragma unroll
        for (int n = 0; n < 4; n++)
            #pragma unroll
            for (int k = 0; k < 4; k++) c[m][n][k] = 0.f;

    uint2 pa[4], pbh[2];

    {
        #pragma unroll
        for (int i = 0; i < 4; i++)
            pa[i] = *(const uint2*)(A0 + (size_t)r0*32 + a_src[i]);
        #pragma unroll
        for (int i = 0; i < 2; i++)
            pbh[i] = *(const uint2*)(wph + b_src[i]);
        uint32_t* base = smu;
        #pragma unroll
        for (int i = 0; i < 4; i++) {
            base[a_w[i]]     = pa[i].x;
            base[a_w[i] + 4] = pa[i].y;
        }
        #pragma unroll
        for (int i = 0; i < 2; i++) {
            base[b_w[i]]     = pbh[i].x;
            base[b_w[i] + 2] = pbh[i].y;
        }
    }
    __syncthreads();

    #pragma unroll 1
    for (int cc = 0; cc < 8; cc++) {
        int stage = cc & 1;
        if (cc < 7) {
            int cn = cc + 1;
            const uint32_t* Ap = (cn < 2) ? A0 : (cn < 4) ? A1 : (cn < 6) ? A2 : A3;
            int kb = (cn & 1) * 16;
            #pragma unroll
            for (int i = 0; i < 4; i++)
                pa[i] = *(const uint2*)(Ap + (size_t)r0*32 + a_src[i] + kb);
            #pragma unroll
            for (int i = 0; i < 2; i++)
                pbh[i] = *(const uint2*)(wph + b_src[i] + cn*16);
        }
        {
            const uint32_t* base = smu + stage*STG_U32;
            #pragma unroll
            for (int ks = 0; ks < 2; ks++) {
                uint4 ah[2];
                #pragma unroll
                for (int mt = 0; mt < 2; mt++) {
                    int mtile = wrow*2 + mt;
                    ah[mt] = *(const uint4*)(base + (mtile*2+ks)*128 + lane*4);
                }
                uint2 bh[4];
                #pragma unroll
                for (int nt = 0; nt < 4; nt++) {
                    int ntile = wcol*4 + nt;
                    bh[nt] = *(const uint2*)(base + 2048 + (ntile*2+ks)*64 + lane*2);
                }
                #pragma unroll
                for (int mt = 0; mt < 2; mt++)
                    #pragma unroll
                    for (int nt = 0; nt < 4; nt++)
                        MMAH(c[mt][nt], ah[mt].x, ah[mt].y, ah[mt].z, ah[mt].w,
                             bh[nt].x, bh[nt].y);
            }
        }
        if (cc < 7) {
            uint32_t* base = smu + ((cc+1)&1)*STG_U32;
            #pragma unroll
            for (int i = 0; i < 4; i++) {
                base[a_w[i]]     = pa[i].x;
                base[a_w[i] + 4] = pa[i].y;
            }
            #pragma unroll
            for (int i = 0; i < 2; i++) {
                base[b_w[i]]     = pbh[i].x;
                base[b_w[i] + 2] = pbh[i].y;
            }
        }
        __syncthreads();
    }

    /* ---- fused BN2 + LeakyReLU + W3 projections ---- */
    {
        float* so = smf;
        const int g = lane >> 2, q = lane & 3;
        #pragma unroll
        for (int mt = 0; mt < 2; mt++) {
            int lr = wrow*32 + mt*16 + g;
            #pragma unroll
            for (int nt = 0; nt < 4; nt++) {
                int col = wcol*32 + nt*8 + 2*q;
                float bx = __ldg(&b2[col]), by = __ldg(&b2[col+1]);
                so[lr*68+col]       = c[mt][nt][0] + bx;
                so[lr*68+col+1]     = c[mt][nt][1] + by;
                so[(lr+8)*68+col]   = c[mt][nt][2] + bx;
                so[(lr+8)*68+col+1] = c[mt][nt][3] + by;
            }
        }
    }
    __syncthreads();
    {
        const float* so = smf;
        const float* sw3 = smf + SW3_OFF;
        int sub = lane >> 3, c8 = (lane & 7) * 8;
        #pragma unroll
        for (int nn = 0; nn < 4; nn++) {
            int node = wid*4 + nn;
            int gnode = blockIdx.x*32 + node;
            int gn = gnode < N_NODES ? gnode : N_NODES-1;
            const float* rp = so + (node*4 + sub)*68 + c8;
            float4 v0 = *(const float4*)rp;
            float4 v1 = *(const float4*)(rp + 4);
            float s = v0.x+v0.y+v0.z+v0.w + v1.x+v1.y+v1.z+v1.w;
            float q = v0.x*v0.x+v0.y*v0.y+v0.z*v0.z+v0.w*v0.w
                    + v1.x*v1.x+v1.y*v1.y+v1.z*v1.z+v1.w*v1.w;
            #pragma unroll
            for (int o = 16; o; o >>= 1) {
                s += __shfl_xor_sync(0xffffffffu, s, o);
                q += __shfl_xor_sync(0xffffffffu, q, o);
            }
            float mu  = s * (1.f/256.f);
            float var = q * (1.f/256.f) - mu*mu;
            float sc  = __ldg(&g2[gn]) * rsqrtf(var + BN_EPS);
            float bb  = __ldg(&be2[gn]);
            float o0, o1, o2, o3, o4, o5, o6, o7, f;
            f = sc*(v0.x-mu)+bb; o0 = f > 0.f ? f : SLOPE*f;
            f = sc*(v0.y-mu)+bb; o1 = f > 0.f ? f : SLOPE*f;
            f = sc*(v0.z-mu)+bb; o2 = f > 0.f ? f : SLOPE*f;
            f = sc*(v0.w-mu)+bb; o3 = f > 0.f ? f : SLOPE*f;
            f = sc*(v1.x-mu)+bb; o4 = f > 0.f ? f : SLOPE*f;
            f = sc*(v1.y-mu)+bb; o5 = f > 0.f ? f : SLOPE*f;
            f = sc*(v1.z-mu)+bb; o6 = f > 0.f ? f : SLOPE*f;
            f = sc*(v1.w-mu)+bb; o7 = f > 0.f ? f : SLOPE*f;
            float pr[8];
            #pragma unroll
            for (int kch = 0; kch < 8; kch++) {
                const float* w = sw3 + kch*64 + c8;
                float4 w0 = *(const float4*)w;
                float4 w1 = *(const float4*)(w + 4);
                pr[kch] = o0*w0.x + o1*w0.y + o2*w0.z + o3*w0.w
                        + o4*w1.x + o5*w1.y + o6*w1.z + o7*w1.w;
            }
            #pragma unroll
            for (int m = 1; m <= 4; m <<= 1) {
                #pragma unroll
                for (int kch = 0; kch < 8; kch++)
                    pr[kch] += __shfl_xor_sync(0xffffffffu, pr[kch], m);
            }
            if ((lane & 7) == 0 && gnode < N_NODES) {
                size_t grow = (size_t)(r0 + node*4 + sub)*2;
                *(float2*)&p0[grow] = make_float2(pr[0], pr[1]);
                *(float2*)&p1[grow] = make_float2(pr[2], pr[3]);
                *(float2*)&p2[grow] = make_float2(pr[4], pr[5]);
                *(float2*)&p3[grow] = make_float2(pr[6], pr[7]);
            }
        }
    }
}

/* ======================================================================= */
extern "C" void kernel_launch(void* const* d_in, const int* in_sizes, int n_in,
                              void* d_out, int out_size) {
    const float* x      = (const float*)d_in[0];
    const int*   src    = (const int*)  d_in[1];
    const int*   dst    = (const int*)  d_in[2];
    const float* ew     = (const float*)d_in[3];
    const float* W1     = (const float*)d_in[4];
    const float* b1     = (const float*)d_in[5];
    const float* W2     = (const float*)d_in[6];
    const float* b2     = (const float*)d_in[7];
    const float* W3     = (const float*)d_in[8];
    const float* b3     = (const float*)d_in[9];
    const float* g1     = (const float*)d_in[10];
    const float* be1    = (const float*)d_in[11];
    const float* g2     = (const float*)d_in[12];
    const float* be2    = (const float*)d_in[13];
    const float* mask   = (const float*)d_in[14];
    const float* mean_y = (const float*)d_in[15];
    const float* std_y  = (const float*)d_in[16];
    const float* vmin   = (const float*)d_in[17];
    const float* vmax   = (const float*)d_in[18];
    const float* qmin   = (const float*)d_in[19];
    const float* qmax   = (const float*)d_in[20];
    float* out = (float*)d_out;

    float *pa, *pb, *pc, *sa, *sb;
    uint32_t *x16, *pa16, *pb16, *pc16;
    uint32_t *h16, *t116, *t216, *t316, *w2ph, *w1ph, *w1pl;
    cudaGetSymbolAddress((void**)&pa,  g_pa);
    cudaGetSymbolAddress((void**)&pb,  g_pb);
    cudaGetSymbolAddress((void**)&pc,  g_pc);
    cudaGetSymbolAddress((void**)&sa,  g_sa);
    cudaGetSymbolAddress((void**)&sb,  g_sb);
    cudaGetSymbolAddress((void**)&x16,  g_x16);
    cudaGetSymbolAddress((void**)&pa16, g_pa16);
    cudaGetSymbolAddress((void**)&pb16, g_pb16);
    cudaGetSymbolAddress((void**)&pc16, g_pc16);
    cudaGetSymbolAddress((void**)&h16,  g_h16);
    cudaGetSymbolAddress((void**)&t116, g_t116);
    cudaGetSymbolAddress((void**)&t216, g_t216);
    cudaGetSymbolAddress((void**)&t316, g_t316);
    cudaGetSymbolAddress((void**)&w2ph, g_w2p_hi);
    cudaGetSymbolAddress((void**)&w1ph, g_w1p_hi);
    cudaGetSymbolAddress((void**)&w1pl, g_w1p_lo);

    static int smem_set = 0;
    if (!smem_set) {
        cudaFuncSetAttribute(k_gemm2_mma, cudaFuncAttributeMaxDynamicSharedMemorySize, 36864);
        cudaFuncSetAttribute(k_gemm1_mma, cudaFuncAttributeMaxDynamicSharedMemorySize, 34816);
        smem_set = 1;
    }

    const int TB = 256;
    int gE  = (N_EDGES + TB - 1) / TB;
    int gR4 = (N_NODES*4 + TB - 1) / TB;    /* 4 threads per node */
    int gW  = (N_NODES*32 + TB - 1) / TB;

    /* preprocessing: deg/cnt zeroed by previous call's tail (static 0 first) */
    k_deg_w2<<<gE, TB>>>(dst, ew, x, W2, W1);
    k_scan  <<<NB_SCAN, 256>>>();
    k_fill  <<<gE, TB>>>(src, dst, ew);

    /* layer 1: fp16 prop at F=4 (4 thr/node), GEMM+BN+LReLU -> fp16 h */
    k_prop4h<<<gR4, TB>>>(x16,  pa16);
    k_prop4h<<<gR4, TB>>>(pa16, pb16);
    k_prop4h<<<gR4, TB>>>(pb16, pc16);
    k_gemm1_mma<<<RPAD/128, 256, 34816>>>(x16, pa16, pb16, pc16, w1ph, w1pl,
                                          b1, g1, be1, h16);

    /* layer 2: 3x fp16 prop64, fused GEMM+BN+projections -> p0..p3 */
    k_prop64h<<<gW, TB>>>(h16,  t116);
    k_prop64h<<<gW, TB>>>(t116, t216);
    k_prop64h<<<gW, TB>>>(t216, t316);
    k_gemm2_mma<<<RPAD/128, 256, 36864>>>(h16, t116, t216, t316, w2ph,
                                          b2, g2, be2, W3, pb, pa, sb, sa);

    /* layer 3: Horner at F=2, 4 thr/node (p0->pb, p1->pa, p2->sb, p3->sa) */
    k_prop2<true ><<<gR4, TB>>>(sa, pc, sb);
    k_prop2<true ><<<gR4, TB>>>(pc, sa, pa);
    k_prop2_final<<<gR4, TB>>>(sa, pb, b3, mask, mean_y, std_y,
                               vmin, vmax, qmin, qmax, out);
}

// round 16
// speedup vs baseline: 2.7072x; 1.0079x over previous
#include <cuda_runtime.h>
#include <cuda_fp16.h>
#include <math.h>
#include <cstdint>

#define N_NODES 50000
#define N_EDGES 400000
#define BATCH 4
#define R (N_NODES*BATCH)      /* 200000 rows (n,b) */
#define RPAD 200064            /* padded to 128-row GEMM tiles */
#define BN_EPS 1e-5f
#define SLOPE 0.01f
#define NB_SCAN ((N_NODES + 255) / 256)   /* 196 */
#define DEG_SCALE 1099511627776.0         /* 2^40 */

/* ---------------- static device scratch (no allocations allowed) -------- */
__device__ __align__(16) unsigned long long g_deg64[N_NODES]; /* zeroed by tail */
__device__ __align__(16) float g_dis[N_NODES];
__device__ __align__(16) int   g_rowptr[N_NODES+1];
__device__ __align__(16) int   g_cur[N_NODES];
__device__ __align__(16) int   g_col[N_EDGES];
__device__ __align__(16) float g_wcsr[N_EDGES];
__device__ __align__(16) int   g_bsum[256];
__device__ __align__(16) int   g_flag[256];         /* zeroed by tail kernel */

/* fp16 layer-1 features: [row][4 halfs] = [row][2 u32]; node owns 4 rows */
__device__ __align__(16) uint32_t g_x16 [RPAD*2];
__device__ __align__(16) uint32_t g_pa16[RPAD*2];
__device__ __align__(16) uint32_t g_pb16[RPAD*2];
__device__ __align__(16) uint32_t g_pc16[RPAD*2];

/* float scratch for layer-3 p-values ([R][2] each) */
__device__ __align__(16) float g_pa[RPAD*4];
__device__ __align__(16) float g_pb[RPAD*4];
__device__ __align__(16) float g_pc[RPAD*4];
__device__ __align__(16) float g_sa[RPAD*2];
__device__ __align__(16) float g_sb[RPAD*2];

/* fp16 hidden states: [row][64] halfs = [row][32] u32 */
__device__ __align__(16) uint32_t g_h16 [RPAD*32];
__device__ __align__(16) uint32_t g_t116[RPAD*32];
__device__ __align__(16) uint32_t g_t216[RPAD*32];
__device__ __align__(16) uint32_t g_t316[RPAD*32];

/* W2 transposed [64 n][128 kpair], fp16x2-packed */
__device__ __align__(16) uint32_t g_w2p_hi[64*128];
/* W1 transposed [64 n][8 kpair], fp16x2-packed hi/lo (K=16) */
__device__ __align__(16) uint32_t g_w1p_hi[64*8];
__device__ __align__(16) uint32_t g_w1p_lo[64*8];

#define MMAH(C, a0,a1,a2,a3, b0,b1) \
    asm volatile("mma.sync.aligned.m16n8k16.row.col.f32.f16.f16.f32 " \
        "{%0,%1,%2,%3},{%4,%5,%6,%7},{%8,%9},{%0,%1,%2,%3};" \
        : "+f"((C)[0]),"+f"((C)[1]),"+f"((C)[2]),"+f"((C)[3]) \
        : "r"(a0),"r"(a1),"r"(a2),"r"(a3),"r"(b0),"r"(b1))

__device__ __forceinline__ uint32_t h2u(__half2 h) {
    uint32_t u; memcpy(&u, &h, 4); return u;
}
__device__ __forceinline__ __half2 u2h(uint32_t u) {
    __half2 h; memcpy(&h, &u, 4); return h;
}

/* ---------------- preprocessing --------------------------------------- */
/* packed deg/cnt atomic + x->fp16 transpose + W1/W2 prep */
__global__ void k_deg_w2(const int* __restrict__ dst, const float* __restrict__ ew,
                         const float* __restrict__ x,
                         const float* __restrict__ W2, const float* __restrict__ W1) {
    int e = blockIdx.x*blockDim.x + threadIdx.x;
    if (e < N_EDGES) {
        int d = dst[e];
        unsigned long long pk =
            (1ULL << 52) |
            (unsigned long long)__double2ll_rn((double)ew[e] * DEG_SCALE);
        atomicAdd(&g_deg64[d], pk);
    }
    if (e < R) {
        int b = e / N_NODES, n = e - b*N_NODES;
        float4 v = ((const float4*)x)[e];
        uint2 pk;
        pk.x = h2u(__floats2half2_rn(v.x, v.y));
        pk.y = h2u(__floats2half2_rn(v.z, v.w));
        *(uint2*)&g_x16[(size_t)(n*4 + b)*2] = pk;
    }
    if (e < 64*128) {
        int n = e >> 7, p = e & 127;
        int k0 = 2*p;
        int sel = k0 >> 6, kk = k0 & 63;
        float v0 = W2[sel*4096 + kk*64 + n];
        float v1 = W2[sel*4096 + (kk+1)*64 + n];
        g_w2p_hi[e] = h2u(__floats2half2_rn(v0, v1));
    }
    if (e < 64*8) {
        int n = e >> 3, p = e & 7;
        int k0 = 2*p;
        float v0 = W1[k0*64 + n];
        float v1 = W1[(k0+1)*64 + n];
        __half h0 = __float2half_rn(v0), h1 = __float2half_rn(v1);
        float l0 = v0 - __half2float(h0), l1 = v1 - __half2float(h1);
        g_w1p_hi[e] = h2u(__halves2half2(h0, h1));
        g_w1p_lo[e] = h2u(__floats2half2_rn(l0, l1));
    }
}

/* single-pass scan with decoupled lookback; also computes dis and cur */
__global__ void k_scan() {
    int t = threadIdx.x, b = blockIdx.x;
    int i = b*256 + t;
    unsigned long long pk = (i < N_NODES) ? g_deg64[i] : 0ULL;
    int v = (int)(pk >> 52);
    float deg = (float)((double)(pk & ((1ULL << 52) - 1ULL)) * (1.0 / DEG_SCALE));
    int lane = t & 31, wp = t >> 5;
    int x = v;
    #pragma unroll
    for (int o = 1; o < 32; o <<= 1) {
        int y = __shfl_up_sync(0xffffffffu, x, o);
        if (lane >= o) x += y;
    }
    __shared__ int wt[8];
    __shared__ int s_off;
    if (lane == 31) wt[wp] = x;
    if (t == 0) s_off = 0;
    __syncthreads();
    if (wp == 0 && lane < 8) {
        int y = wt[lane];
        #pragma unroll
        for (int o = 1; o < 8; o <<= 1) {
            int z = __shfl_up_sync(0xffu, y, o);
            if (lane >= o) y += z;
        }
        wt[lane] = y;
    }
    __syncthreads();
    int incl = x + (wp ? wt[wp-1] : 0);
    if (t == 0) {
        g_bsum[b] = wt[7];
        __threadfence();
        atomicExch(&g_flag[b], 1);
    }
    int part = 0;
    if (t < b) {
        while (atomicAdd(&g_flag[t], 0) == 0) { }
        part = g_bsum[t];
    }
    #pragma unroll
    for (int o = 16; o; o >>= 1) part += __shfl_xor_sync(0xffffffffu, part, o);
    if (lane == 0 && part != 0) atomicAdd(&s_off, part);
    __syncthreads();
    if (i < N_NODES) {
        int p = incl - v + s_off;
        g_rowptr[i] = p;
        g_cur[i] = p;
        g_dis[i] = (deg > 0.f) ? rsqrtf(fmaxf(deg, 1e-30f)) : 0.f;
    }
    if (b == NB_SCAN-1 && t == 255) g_rowptr[N_NODES] = N_EDGES;
}

__global__ void k_fill(const int* __restrict__ src, const int* __restrict__ dst,
                       const float* __restrict__ ew) {
    int e = blockIdx.x*blockDim.x + threadIdx.x;
    if (e < N_EDGES) {
        int s = src[e], d = dst[e];
        int p = atomicAdd(&g_cur[d], 1);
        g_col[p]  = s;
        g_wcsr[p] = g_dis[s] * ew[e] * g_dis[d];
    }
}

/* ---------------- propagation ------------------------------------------ */
/* fp16 F=4 prop: 4 threads per node, row j; 4-way predicated edge loop */
__global__ void k_prop4h(const uint32_t* __restrict__ in, uint32_t* __restrict__ out) {
    int gt = blockIdx.x*blockDim.x + threadIdx.x;
    int n = gt >> 2, j = gt & 3;
    if (n >= N_NODES) return;
    float4 acc = make_float4(0.f,0.f,0.f,0.f);
    int s = g_rowptr[n], e = g_rowptr[n+1];
    for (int i = s; i < e; i += 4) {
        int   c[4];
        float w[4];
        uint2 v[4];
        #pragma unroll
        for (int k = 0; k < 4; k++) {
            int idx = i + k;
            bool act = idx < e;
            c[k] = act ? __ldg(&g_col[idx]) : 0;
            w[k] = act ? __ldg(&g_wcsr[idx]) : 0.f;
        }
        #pragma unroll
        for (int k = 0; k < 4; k++)
            v[k] = __ldg((const uint2*)(in + c[k]*8 + j*2));
        #pragma unroll
        for (int k = 0; k < 4; k++) {
            float2 f;
            f = __half22float2(u2h(v[k].x)); acc.x += w[k]*f.x; acc.y += w[k]*f.y;
            f = __half22float2(u2h(v[k].y)); acc.z += w[k]*f.x; acc.w += w[k]*f.y;
        }
    }
    uint2 pk;
    pk.x = h2u(__floats2half2_rn(acc.x, acc.y));
    pk.y = h2u(__floats2half2_rn(acc.z, acc.w));
    *(uint2*)(out + n*8 + j*2) = pk;
}

/* fp32 F=2 prop (layer-3 Horner): 4 thr/node, 4-way predicated loop */
template<bool ADD>
__global__ void k_prop2(const float* __restrict__ in, float* __restrict__ out,
                        const float* __restrict__ add) {
    int gt = blockIdx.x*blockDim.x + threadIdx.x;
    int n = gt >> 2, j = gt & 3;
    if (n >= N_NODES) return;
    float2 acc = make_float2(0.f, 0.f);
    int s = g_rowptr[n], e = g_rowptr[n+1];
    for (int i = s; i < e; i += 4) {
        int   c[4];
        float w[4];
        float2 v[4];
        #pragma unroll
        for (int k = 0; k < 4; k++) {
            int idx = i + k;
            bool act = idx < e;
            c[k] = act ? __ldg(&g_col[idx]) : 0;
            w[k] = act ? __ldg(&g_wcsr[idx]) : 0.f;
        }
        #pragma unroll
        for (int k = 0; k < 4; k++)
            v[k] = __ldg((const float2*)(in + (size_t)(c[k]*4 + j)*2));
        #pragma unroll
        for (int k = 0; k < 4; k++) {
            acc.x += w[k]*v[k].x; acc.y += w[k]*v[k].y;
        }
    }
    if (ADD) {
        float2 d = *(const float2*)(add + (size_t)(n*4 + j)*2);
        acc.x += d.x; acc.y += d.y;
    }
    *(float2*)(out + (size_t)(n*4 + j)*2) = acc;
}

/* final Horner prop fused with output epilogue + next-call state zeroing */
__global__ void k_prop2_final(const float* __restrict__ in,
                              const float* __restrict__ p0,
                              const float* __restrict__ b3,
                              const float* __restrict__ mask,
                              const float* __restrict__ mean_y,
                              const float* __restrict__ std_y,
                              const float* __restrict__ vmin, const float* __restrict__ vmax,
                              const float* __restrict__ qmin, const float* __restrict__ qmax,
                              float* __restrict__ out) {
    int gt = blockIdx.x*blockDim.x + threadIdx.x;
    /* re-zero accumulation state for the next graph replay */
    if (gt < N_NODES) g_deg64[gt] = 0ULL;
    if (gt < 256) g_flag[gt] = 0;
    int n = gt >> 2, j = gt & 3;
    if (n >= N_NODES) return;
    float2 acc = make_float2(0.f, 0.f);
    int s = g_rowptr[n], e = g_rowptr[n+1];
    for (int i = s; i < e; i += 4) {
        int   c[4];
        float w[4];
        float2 v[4];
        #pragma unroll
        for (int k = 0; k < 4; k++) {
            int idx = i + k;
            bool act = idx < e;
            c[k] = act ? __ldg(&g_col[idx]) : 0;
            w[k] = act ? __ldg(&g_wcsr[idx]) : 0.f;
        }
        #pragma unroll
        for (int k = 0; k < 4; k++)
            v[k] = __ldg((const float2*)(in + (size_t)(c[k]*4 + j)*2));
        #pragma unroll
        for (int k = 0; k < 4; k++) {
            acc.x += w[k]*v[k].x; acc.y += w[k]*v[k].y;
        }
    }
    float2 z = *(const float2*)(p0 + (size_t)(n*4 + j)*2);
    float u0 = acc.x + z.x + __ldg(&b3[0]);
    float u1 = acc.y + z.y + __ldg(&b3[1]);
    float s0 = std_y[n*2], s1 = std_y[n*2+1];
    if (isinf(s0)) s0 = 0.f;
    if (isinf(s1)) s1 = 0.f;
    float o0 = (u0*s0 + mean_y[n*2])   * mask[n*2];
    float o1 = (u1*s1 + mean_y[n*2+1]) * mask[n*2+1];
    o0 = fminf(fmaxf(o0, vmin[n]), vmax[n]);
    o1 = fminf(fmaxf(o1, qmin[n]), qmax[n]);
    *(float2*)&out[(size_t)(j*N_NODES + n)*2] = make_float2(o0, o1);
}

/* fp16 payload prop: warp per node, 4-way predicated edge loop */
__global__ void k_prop64h(const uint32_t* __restrict__ in, uint32_t* __restrict__ out) {
    int gt = blockIdx.x*blockDim.x + threadIdx.x;
    int n = gt >> 5, lane = gt & 31;
    if (n >= N_NODES) return;
    int s = g_rowptr[n], e = g_rowptr[n+1];
    float2 a0 = make_float2(0.f,0.f), a1 = a0, a2 = a0, a3 = a0;
    for (int i = s; i < e; i += 4) {
        int   c[4];
        float w[4];
        uint4 v[4];
        #pragma unroll
        for (int j = 0; j < 4; j++) {
            int idx = i + j;
            bool act = idx < e;
            c[j] = act ? __ldg(&g_col[idx]) : 0;
            w[j] = act ? __ldg(&g_wcsr[idx]) : 0.f;
        }
        #pragma unroll
        for (int j = 0; j < 4; j++)
            v[j] = __ldg((const uint4*)(in + c[j]*128 + lane*4));
        #pragma unroll
        for (int j = 0; j < 4; j++) {
            float2 f;
            f = __half22float2(u2h(v[j].x)); a0.x += w[j]*f.x; a0.y += w[j]*f.y;
            f = __half22float2(u2h(v[j].y)); a1.x += w[j]*f.x; a1.y += w[j]*f.y;
            f = __half22float2(u2h(v[j].z)); a2.x += w[j]*f.x; a2.y += w[j]*f.y;
            f = __half22float2(u2h(v[j].w)); a3.x += w[j]*f.x; a3.y += w[j]*f.y;
        }
    }
    uint4 o;
    o.x = h2u(__floats2half2_rn(a0.x, a0.y));
    o.y = h2u(__floats2half2_rn(a1.x, a1.y));
    o.z = h2u(__floats2half2_rn(a2.x, a2.y));
    o.w = h2u(__floats2half2_rn(a3.x, a3.y));
    *(uint4*)(out + n*128 + lane*4) = o;
}

/* ---------------- layer-1 GEMM (fp16 A direct) + BN + LReLU -> fp16 h --- */
__global__ void __launch_bounds__(256, 2)
k_gemm1_mma(const uint32_t* __restrict__ A0, const uint32_t* __restrict__ A1,
            const uint32_t* __restrict__ A2, const uint32_t* __restrict__ A3,
            const uint32_t* __restrict__ w1h, const uint32_t* __restrict__ w1l,
            const float* __restrict__ b1,
            const float* __restrict__ g1, const float* __restrict__ be1,
            uint32_t* __restrict__ hout) {
    extern __shared__ uint32_t smu[];
    float* smf = (float*)smu;
    const int t = threadIdx.x;
    const int lane = t & 31, wid = t >> 5;
    const int wrow = wid >> 1, wcol = wid & 1;
    const int r0 = blockIdx.x * 128;

    {
        int n = t >> 2, c4 = t & 3;
        int regbit = (c4 >> 1) & 1, q0 = (c4 & 1) * 2;
        int g = n & 7, nt = n >> 3;
        int b_w = 1024 + nt*64 + (g*4 + q0)*2 + regbit;
        uint2 vh = *(const uint2*)(w1h + n*8 + c4*2);
        uint2 vl = *(const uint2*)(w1l + n*8 + c4*2);
        smu[b_w]       = vh.x;
        smu[b_w + 2]   = vh.y;
        smu[512 + b_w]     = vl.x;
        smu[512 + b_w + 2] = vl.y;
    }
    #pragma unroll
    for (int sidx = 0; sidx < 2; sidx++) {
        int idx = sidx*256 + t;
        int row = idx >> 2, c4 = idx & 3;
        int rr = row & 15, mt = row >> 4;
        int regbit = (c4 >> 1) & 1, q0 = (c4 & 1) * 2;
        int g = rr & 7, abit = rr >> 3;
        int a_w = mt*128 + (g*4 + q0)*4 + abit + 2*regbit;
        const uint32_t* Ap = (c4 == 0) ? A0 : (c4 == 1) ? A1 : (c4 == 2) ? A2 : A3;
        uint2 v = *(const uint2*)(Ap + (size_t)(r0 + row)*2);
        smu[a_w]     = v.x;
        smu[a_w + 4] = v.y;
    }
    __syncthreads();

    float c[2][4][4];
    #pragma unroll
    for (int m = 0; m < 2; m++)
        #pragma unroll
        for (int n = 0; n < 4; n++)
            #pragma unroll
            for (int k = 0; k < 4; k++) c[m][n][k] = 0.f;

    {
        uint4 ah[2];
        #pragma unroll
        for (int mt = 0; mt < 2; mt++) {
            int mtile = wrow*2 + mt;
            ah[mt] = *(const uint4*)(smu + mtile*128 + lane*4);
        }
        uint2 bh[4], bl[4];
        #pragma unroll
        for (int nt = 0; nt < 4; nt++) {
            int ntile = wcol*4 + nt;
            bh[nt] = *(const uint2*)(smu + 1024 + ntile*64 + lane*2);
            bl[nt] = *(const uint2*)(smu + 1536 + ntile*64 + lane*2);
        }
        #pragma unroll
        for (int mt = 0; mt < 2; mt++)
            #pragma unroll
            for (int nt = 0; nt < 4; nt++) {
                MMAH(c[mt][nt], ah[mt].x, ah[mt].y, ah[mt].z, ah[mt].w,
                     bh[nt].x, bh[nt].y);
                MMAH(c[mt][nt], ah[mt].x, ah[mt].y, ah[mt].z, ah[mt].w,
                     bl[nt].x, bl[nt].y);
            }
    }
    __syncthreads();

    {
        float* so = smf;
        const int g = lane >> 2, q = lane & 3;
        #pragma unroll
        for (int mt = 0; mt < 2; mt++) {
            int lr = wrow*32 + mt*16 + g;
            #pragma unroll
            for (int nt = 0; nt < 4; nt++) {
                int col = wcol*32 + nt*8 + 2*q;
                float bx = __ldg(&b1[col]), by = __ldg(&b1[col+1]);
                so[lr*68+col]       = c[mt][nt][0] + bx;
                so[lr*68+col+1]     = c[mt][nt][1] + by;
                so[(lr+8)*68+col]   = c[mt][nt][2] + bx;
                so[(lr+8)*68+col+1] = c[mt][nt][3] + by;
            }
        }
    }
    __syncthreads();
    {
        const float* so = smf;
        int sub = lane >> 3, c8 = (lane & 7) * 8;
        #pragma unroll
        for (int nn = 0; nn < 4; nn++) {
            int node = wid*4 + nn;
            int gnode = blockIdx.x*32 + node;
            int gn = gnode < N_NODES ? gnode : N_NODES-1;
            const float* rp = so + (node*4 + sub)*68 + c8;
            float4 v0 = *(const float4*)rp;
            float4 v1 = *(const float4*)(rp + 4);
            float s = v0.x+v0.y+v0.z+v0.w + v1.x+v1.y+v1.z+v1.w;
            float q = v0.x*v0.x+v0.y*v0.y+v0.z*v0.z+v0.w*v0.w
                    + v1.x*v1.x+v1.y*v1.y+v1.z*v1.z+v1.w*v1.w;
            #pragma unroll
            for (int o = 16; o; o >>= 1) {
                s += __shfl_xor_sync(0xffffffffu, s, o);
                q += __shfl_xor_sync(0xffffffffu, q, o);
            }
            float mu  = s * (1.f/256.f);
            float var = q * (1.f/256.f) - mu*mu;
            float sc  = __ldg(&g1[gn]) * rsqrtf(var + BN_EPS);
            float bb  = __ldg(&be1[gn]);
            float o0, o1, o2, o3, o4, o5, o6, o7, f;
            f = sc*(v0.x-mu)+bb; o0 = f > 0.f ? f : SLOPE*f;
            f = sc*(v0.y-mu)+bb; o1 = f > 0.f ? f : SLOPE*f;
            f = sc*(v0.z-mu)+bb; o2 = f > 0.f ? f : SLOPE*f;
            f = sc*(v0.w-mu)+bb; o3 = f > 0.f ? f : SLOPE*f;
            f = sc*(v1.x-mu)+bb; o4 = f > 0.f ? f : SLOPE*f;
            f = sc*(v1.y-mu)+bb; o5 = f > 0.f ? f : SLOPE*f;
            f = sc*(v1.z-mu)+bb; o6 = f > 0.f ? f : SLOPE*f;
            f = sc*(v1.w-mu)+bb; o7 = f > 0.f ? f : SLOPE*f;
            if (gnode < N_NODES) {
                uint4 pk;
                pk.x = h2u(__floats2half2_rn(o0, o1));
                pk.y = h2u(__floats2half2_rn(o2, o3));
                pk.z = h2u(__floats2half2_rn(o4, o5));
                pk.w = h2u(__floats2half2_rn(o6, o7));
                *(uint4*)&hout[(size_t)(r0 + node*4 + sub)*32 + (lane & 7)*4] = pk;
            }
        }
    }
}

/* ---------------- layer-2 GEMM (fp16 A, fp16 B) + BN + projections ------ */
#define STG_U32 3072
#define SW3_OFF 8704
__global__ void __launch_bounds__(256, 2)
k_gemm2_mma(const uint32_t* __restrict__ A0, const uint32_t* __restrict__ A1,
            const uint32_t* __restrict__ A2, const uint32_t* __restrict__ A3,
            const uint32_t* __restrict__ wph,
            const float* __restrict__ b2,
            const float* __restrict__ g2, const float* __restrict__ be2,
            const float* __restrict__ W3,
            float* __restrict__ p0, float* __restrict__ p1,
            float* __restrict__ p2, float* __restrict__ p3) {
    extern __shared__ uint32_t smu[];
    float* smf = (float*)smu;
    const int t = threadIdx.x;
    const int lane = t & 31, wid = t >> 5;
    const int wrow = wid >> 1, wcol = wid & 1;
    const int r0 = blockIdx.x * 128;

    #pragma unroll
    for (int i2 = t; i2 < 512; i2 += 256) {
        int kch = i2 >> 6, f = i2 & 63;
        smf[SW3_OFF + i2] = W3[(kch >> 1)*128 + f*2 + (kch & 1)];
    }

    int a_w[4], a_src[4];
    #pragma unroll
    for (int i = 0; i < 4; i++) {
        int idx = i*256 + t;
        int row = idx >> 3, c4 = idx & 7;
        int rr = row & 15, mt = row >> 4;
        int ks = c4 >> 2, regbit = (c4 >> 1) & 1, q0 = (c4 & 1) * 2;
        int g = rr & 7, abit = rr >> 3;
        a_w[i] = (mt*2 + ks)*128 + (g*4 + q0)*4 + abit + 2*regbit;
        a_src[i] = row*32 + c4*2;
    }
    int b_w[2], b_src[2];
    #pragma unroll
    for (int i = 0; i < 2; i++) {
        int idx = i*256 + t;
        int n = idx >> 3, c4 = idx & 7;
        int ks = c4 >> 2, regbit = (c4 >> 1) & 1, q0 = (c4 & 1) * 2;
        int g = n & 7, nt = n >> 3;
        b_w[i] = 2048 + (nt*2 + ks)*64 + (g*4 + q0)*2 + regbit;
        b_src[i] = n*128 + c4*2;
    }

    float c[2][4][4];
    #pragma unroll
    for (int m = 0; m < 2; m++)
        #pragma unroll
        for (int n = 0; n < 4; n++)
            #pragma unroll
            for (int k = 0; k < 4; k++) c[m][n][k] = 0.f;

    uint2 pa[4], pbh[2];

    {
        #pragma unroll
        for (int i = 0; i < 4; i++)
            pa[i] = *(const uint2*)(A0 + (size_t)r0*32 + a_src[i]);
        #pragma unroll
        for (int i = 0; i < 2; i++)
            pbh[i] = *(const uint2*)(wph + b_src[i]);
        uint32_t* base = smu;
        #pragma unroll
        for (int i = 0; i < 4; i++) {
            base[a_w[i]]     = pa[i].x;
            base[a_w[i] + 4] = pa[i].y;
        }
        #pragma unroll
        for (int i = 0; i < 2; i++) {
            base[b_w[i]]     = pbh[i].x;
            base[b_w[i] + 2] = pbh[i].y;
        }
    }
    __syncthreads();

    #pragma unroll 1
    for (int cc = 0; cc < 8; cc++) {
        int stage = cc & 1;
        if (cc < 7) {
            int cn = cc + 1;
            const uint32_t* Ap = (cn < 2) ? A0 : (cn < 4) ? A1 : (cn < 6) ? A2 : A3;
            int kb = (cn & 1) * 16;
            #pragma unroll
            for (int i = 0; i < 4; i++)
                pa[i] = *(const uint2*)(Ap + (size_t)r0*32 + a_src[i] + kb);
            #pragma unroll
            for (int i = 0; i < 2; i++)
                pbh[i] = *(const uint2*)(wph + b_src[i] + cn*16);
        }
        {
            const uint32_t* base = smu + stage*STG_U32;
            #pragma unroll
            for (int ks = 0; ks < 2; ks++) {
                uint4 ah[2];
                #pragma unroll
                for (int mt = 0; mt < 2; mt++) {
                    int mtile = wrow*2 + mt;
                    ah[mt] = *(const uint4*)(base + (mtile*2+ks)*128 + lane*4);
                }
                uint2 bh[4];
                #pragma unroll
                for (int nt = 0; nt < 4; nt++) {
                    int ntile = wcol*4 + nt;
                    bh[nt] = *(const uint2*)(base + 2048 + (ntile*2+ks)*64 + lane*2);
                }
                #pragma unroll
                for (int mt = 0; mt < 2; mt++)
                    #pragma unroll
                    for (int nt = 0; nt < 4; nt++)
                        MMAH(c[mt][nt], ah[mt].x, ah[mt].y, ah[mt].z, ah[mt].w,
                             bh[nt].x, bh[nt].y);
            }
        }
        if (cc < 7) {
            uint32_t* base = smu + ((cc+1)&1)*STG_U32;
            #pragma unroll
            for (int i = 0; i < 4; i++) {
                base[a_w[i]]     = pa[i].x;
                base[a_w[i] + 4] = pa[i].y;
            }
            #pragma unroll
            for (int i = 0; i < 2; i++) {
                base[b_w[i]]     = pbh[i].x;
                base[b_w[i] + 2] = pbh[i].y;
            }
        }
        __syncthreads();
    }

    /* ---- fused BN2 + LeakyReLU + W3 projections ---- */
    {
        float* so = smf;
        const int g = lane >> 2, q = lane & 3;
        #pragma unroll
        for (int mt = 0; mt < 2; mt++) {
            int lr = wrow*32 + mt*16 + g;
            #pragma unroll
            for (int nt = 0; nt < 4; nt++) {
                int col = wcol*32 + nt*8 + 2*q;
                float bx = __ldg(&b2[col]), by = __ldg(&b2[col+1]);
                so[lr*68+col]       = c[mt][nt][0] + bx;
                so[lr*68+col+1]     = c[mt][nt][1] + by;
                so[(lr+8)*68+col]   = c[mt][nt][2] + bx;
                so[(lr+8)*68+col+1] = c[mt][nt][3] + by;
            }
        }
    }
    __syncthreads();
    {
        const float* so = smf;
        const float* sw3 = smf + SW3_OFF;
        int sub = lane >> 3, c8 = (lane & 7) * 8;
        #pragma unroll
        for (int nn = 0; nn < 4; nn++) {
            int node = wid*4 + nn;
            int gnode = blockIdx.x*32 + node;
            int gn = gnode < N_NODES ? gnode : N_NODES-1;
            const float* rp = so + (node*4 + sub)*68 + c8;
            float4 v0 = *(const float4*)rp;
            float4 v1 = *(const float4*)(rp + 4);
            float s = v0.x+v0.y+v0.z+v0.w + v1.x+v1.y+v1.z+v1.w;
            float q = v0.x*v0.x+v0.y*v0.y+v0.z*v0.z+v0.w*v0.w
                    + v1.x*v1.x+v1.y*v1.y+v1.z*v1.z+v1.w*v1.w;
            #pragma unroll
            for (int o = 16; o; o >>= 1) {
                s += __shfl_xor_sync(0xffffffffu, s, o);
                q += __shfl_xor_sync(0xffffffffu, q, o);
            }
            float mu  = s * (1.f/256.f);
            float var = q * (1.f/256.f) - mu*mu;
            float sc  = __ldg(&g2[gn]) * rsqrtf(var + BN_EPS);
            float bb  = __ldg(&be2[gn]);
            float o0, o1, o2, o3, o4, o5, o6, o7, f;
            f = sc*(v0.x-mu)+bb; o0 = f > 0.f ? f : SLOPE*f;
            f = sc*(v0.y-mu)+bb; o1 = f > 0.f ? f : SLOPE*f;
            f = sc*(v0.z-mu)+bb; o2 = f > 0.f ? f : SLOPE*f;
            f = sc*(v0.w-mu)+bb; o3 = f > 0.f ? f : SLOPE*f;
            f = sc*(v1.x-mu)+bb; o4 = f > 0.f ? f : SLOPE*f;
            f = sc*(v1.y-mu)+bb; o5 = f > 0.f ? f : SLOPE*f;
            f = sc*(v1.z-mu)+bb; o6 = f > 0.f ? f : SLOPE*f;
            f = sc*(v1.w-mu)+bb; o7 = f > 0.f ? f : SLOPE*f;
            float pr[8];
            #pragma unroll
            for (int kch = 0; kch < 8; kch++) {
                const float* w = sw3 + kch*64 + c8;
                float4 w0 = *(const float4*)w;
                float4 w1 = *(const float4*)(w + 4);
                pr[kch] = o0*w0.x + o1*w0.y + o2*w0.z + o3*w0.w
                        + o4*w1.x + o5*w1.y + o6*w1.z + o7*w1.w;
            }
            #pragma unroll
            for (int m = 1; m <= 4; m <<= 1) {
                #pragma unroll
                for (int kch = 0; kch < 8; kch++)
                    pr[kch] += __shfl_xor_sync(0xffffffffu, pr[kch], m);
            }
            if ((lane & 7) == 0 && gnode < N_NODES) {
                size_t grow = (size_t)(r0 + node*4 + sub)*2;
                *(float2*)&p0[grow] = make_float2(pr[0], pr[1]);
                *(float2*)&p1[grow] = make_float2(pr[2], pr[3]);
                *(float2*)&p2[grow] = make_float2(pr[4], pr[5]);
                *(float2*)&p3[grow] = make_float2(pr[6], pr[7]);
            }
        }
    }
}

/* ======================================================================= */
extern "C" void kernel_launch(void* const* d_in, const int* in_sizes, int n_in,
                              void* d_out, int out_size) {
    const float* x      = (const float*)d_in[0];
    const int*   src    = (const int*)  d_in[1];
    const int*   dst    = (const int*)  d_in[2];
    const float* ew     = (const float*)d_in[3];
    const float* W1     = (const float*)d_in[4];
    const float* b1     = (const float*)d_in[5];
    const float* W2     = (const float*)d_in[6];
    const float* b2     = (const float*)d_in[7];
    const float* W3     = (const float*)d_in[8];
    const float* b3     = (const float*)d_in[9];
    const float* g1     = (const float*)d_in[10];
    const float* be1    = (const float*)d_in[11];
    const float* g2     = (const float*)d_in[12];
    const float* be2    = (const float*)d_in[13];
    const float* mask   = (const float*)d_in[14];
    const float* mean_y = (const float*)d_in[15];
    const float* std_y  = (const float*)d_in[16];
    const float* vmin   = (const float*)d_in[17];
    const float* vmax   = (const float*)d_in[18];
    const float* qmin   = (const float*)d_in[19];
    const float* qmax   = (const float*)d_in[20];
    float* out = (float*)d_out;

    float *pa, *pb, *pc, *sa, *sb;
    uint32_t *x16, *pa16, *pb16, *pc16;
    uint32_t *h16, *t116, *t216, *t316, *w2ph, *w1ph, *w1pl;
    cudaGetSymbolAddress((void**)&pa,  g_pa);
    cudaGetSymbolAddress((void**)&pb,  g_pb);
    cudaGetSymbolAddress((void**)&pc,  g_pc);
    cudaGetSymbolAddress((void**)&sa,  g_sa);
    cudaGetSymbolAddress((void**)&sb,  g_sb);
    cudaGetSymbolAddress((void**)&x16,  g_x16);
    cudaGetSymbolAddress((void**)&pa16, g_pa16);
    cudaGetSymbolAddress((void**)&pb16, g_pb16);
    cudaGetSymbolAddress((void**)&pc16, g_pc16);
    cudaGetSymbolAddress((void**)&h16,  g_h16);
    cudaGetSymbolAddress((void**)&t116, g_t116);
    cudaGetSymbolAddress((void**)&t216, g_t216);
    cudaGetSymbolAddress((void**)&t316, g_t316);
    cudaGetSymbolAddress((void**)&w2ph, g_w2p_hi);
    cudaGetSymbolAddress((void**)&w1ph, g_w1p_hi);
    cudaGetSymbolAddress((void**)&w1pl, g_w1p_lo);

    static int smem_set = 0;
    if (!smem_set) {
        cudaFuncSetAttribute(k_gemm2_mma, cudaFuncAttributeMaxDynamicSharedMemorySize, 36864);
        cudaFuncSetAttribute(k_gemm1_mma, cudaFuncAttributeMaxDynamicSharedMemorySize, 34816);
        smem_set = 1;
    }

    const int TB = 256;
    int gE  = (N_EDGES + TB - 1) / TB;
    int gR4 = (N_NODES*4 + TB - 1) / TB;    /* 4 threads per node */
    int gW  = (N_NODES*32 + TB - 1) / TB;

    /* preprocessing: deg64 zeroed by previous call's tail (static 0 first) */
    k_deg_w2<<<gE, TB>>>(dst, ew, x, W2, W1);
    k_scan  <<<NB_SCAN, 256>>>();
    k_fill  <<<gE, TB>>>(src, dst, ew);

    /* layer 1: fp16 prop at F=4 (4 thr/node), GEMM+BN+LReLU -> fp16 h */
    k_prop4h<<<gR4, TB>>>(x16,  pa16);
    k_prop4h<<<gR4, TB>>>(pa16, pb16);
    k_prop4h<<<gR4, TB>>>(pb16, pc16);
    k_gemm1_mma<<<RPAD/128, 256, 34816>>>(x16, pa16, pb16, pc16, w1ph, w1pl,
                                          b1, g1, be1, h16);

    /* layer 2: 3x fp16 prop64, fused GEMM+BN+projections -> p0..p3 */
    k_prop64h<<<gW, TB>>>(h16,  t116);
    k_prop64h<<<gW, TB>>>(t116, t216);
    k_prop64h<<<gW, TB>>>(t216, t316);
    k_gemm2_mma<<<RPAD/128, 256, 36864>>>(h16, t116, t216, t316, w2ph,
                                          b2, g2, be2, W3, pb, pa, sb, sa);

    /* layer 3: Horner at F=2, 4 thr/node (p0->pb, p1->pa, p2->sb, p3->sa) */
    k_prop2<true ><<<gR4, TB>>>(sa, pc, sb);
    k_prop2<true ><<<gR4, TB>>>(pc, sa, pa);
    k_prop2_final<<<gR4, TB>>>(sa, pb, b3, mask, mean_y, std_y,
                               vmin, vmax, qmin, qmax, out);
}